// round 4
// baseline (speedup 1.0000x reference)
#include <cuda_runtime.h>
#include <math.h>

// ---------------- problem constants ----------------
#define BB     16
#define LCTX   512
#define KVAR   16
#define HPRED  96
#define DM     512
#define NST    16
#define NLAY   3
#define DFF    2048
#define PATCH  16
#define STRIDEP 8
#define PP     63            // (512-16)/8+1
#define DIN    1024          // 2*DM
#define RNK    32            // DT_RANK
#define SEQ    (KVAR*PP)     // 1008 tokens per batch
#define TT     (BB*SEQ)      // 16128 total tokens
#define EPSF   1e-5f
#define HWLD   (PP*DM)       // 32256 head_w row length

// ---------------- scratch (device globals; padded for scan prefetch) ----
__device__ float g_mean[BB*KVAR];
__device__ float g_std[BB*KVAR];
__device__ float g_z   [TT*DM];
__device__ float g_tmp [TT*DM];
__device__ float g_hln [TT*DM];
__device__ float g_u   [TT*DIN + DIN];
__device__ float g_zg  [TT*DIN + DIN];
__device__ float g_xdbl[TT*64 + 64];
__device__ float g_delta[TT*DIN + DIN];
__device__ float g_y2  [TT*DIN];
__device__ float g_hff [TT*DFF];
__device__ float g_headp[PP*BB*KVAR*HPRED];

// ---------------- helpers ----------------
__device__ __forceinline__ float siluf(float x){ return x / (1.f + __expf(-x)); }
__device__ __forceinline__ float softplusf(float x){
    return fmaxf(x, 0.f) + log1pf(expf(-fabsf(x)));
}
__device__ __forceinline__ float geluf(float x){
    return 0.5f * x * (1.f + erff(x * 0.70710678118654752f));
}

__device__ __forceinline__ void cp16(void* smem, const void* g){
    unsigned a = (unsigned)__cvta_generic_to_shared(smem);
    asm volatile("cp.async.cg.shared.global [%0], [%1], 16;" :: "r"(a), "l"(g));
}
__device__ __forceinline__ void cp_commit(){ asm volatile("cp.async.commit_group;"); }

__device__ __forceinline__ void mma_tf32(float* c, const unsigned* a, const unsigned* b){
    asm volatile("mma.sync.aligned.m16n8k8.row.col.f32.tf32.tf32.f32 "
        "{%0,%1,%2,%3}, {%4,%5,%6,%7}, {%8,%9}, {%0,%1,%2,%3};"
        : "+f"(c[0]),"+f"(c[1]),"+f"(c[2]),"+f"(c[3])
        : "r"(a[0]),"r"(a[1]),"r"(a[2]),"r"(a[3]), "r"(b[0]),"r"(b[1]));
}

// ---------------- per-(b,k) mean/std over L ----------------
__global__ void stats_kernel(const float* __restrict__ x){
    int bk = blockIdx.x; int b = bk >> 4, k = bk & 15;
    int tid = threadIdx.x;
    float s = 0.f, q = 0.f;
    for (int l = tid; l < LCTX; l += 256){
        float v = x[(b*LCTX + l)*KVAR + k];
        s += v; q += v*v;
    }
    __shared__ float sh[64];
#pragma unroll
    for (int o = 16; o; o >>= 1){
        s += __shfl_xor_sync(~0u, s, o);
        q += __shfl_xor_sync(~0u, q, o);
    }
    int w = tid >> 5;
    if ((tid & 31) == 0){ sh[w] = s; sh[w+32] = q; }
    __syncthreads();
    if (tid == 0){
        float S = 0.f, Q = 0.f;
        for (int i = 0; i < 8; i++){ S += sh[i]; Q += sh[32+i]; }
        float mu  = S * (1.f/LCTX);
        float var = Q * (1.f/LCTX) - mu*mu;
        g_mean[bk] = mu;
        g_std[bk]  = sqrtf(var + EPSF);
    }
}

// ---------------- patch embedding + pos + var embed ----------------
__global__ void embed_kernel(const float* __restrict__ x,
                             const float* __restrict__ pw,
                             const float* __restrict__ pb,
                             const float* __restrict__ pos,
                             const float* __restrict__ vemb){
    int row = blockIdx.x;                    // token row in [0,TT)
    int b = row / SEQ, rem = row % SEQ;
    int p = rem >> 4, k = rem & 15;
    int bk = b*KVAR + k;
    __shared__ float xs[PATCH];
    int tid = threadIdx.x;                   // 128
    if (tid < PATCH){
        float v = x[(b*LCTX + p*STRIDEP + tid)*KVAR + k];
        xs[tid] = (v - g_mean[bk]) / g_std[bk];
    }
    __syncthreads();
#pragma unroll
    for (int j = 0; j < 4; j++){
        int d = tid + j*128;
        float acc = pb[d] + pos[p*DM + d] + vemb[k*DM + d];
        const float4* w4 = (const float4*)(pw + d*PATCH);
#pragma unroll
        for (int t4 = 0; t4 < 4; t4++){
            float4 w = w4[t4];
            acc += xs[t4*4+0]*w.x + xs[t4*4+1]*w.y + xs[t4*4+2]*w.z + xs[t4*4+3]*w.w;
        }
        g_z[row*DM + d] = acc;
    }
}

// ---------------- epilogue modes ----------------
enum { EP_NONE=0, EP_SPLIT=1, EP_SOFTPLUS=2, EP_GELU=3, EP_BIAS_RES=4, EP_RES=5 };

template<int EP>
__device__ __forceinline__ void ep_store(float* __restrict__ out0, float* __restrict__ out1,
                                         int ldo, const float* __restrict__ bias,
                                         const float* __restrict__ res,
                                         int row, int col, float v0, float v1){
    if (EP == EP_NONE){
        out0[(size_t)row*ldo + col    ] = v0;
        out0[(size_t)row*ldo + col + 1] = v1;
    } else if (EP == EP_SPLIT){
        if (col < DIN){
            out0[(size_t)row*DIN + col    ] = siluf(v0);
            out0[(size_t)row*DIN + col + 1] = siluf(v1);
        } else {
            out1[(size_t)row*DIN + col - DIN    ] = v0;
            out1[(size_t)row*DIN + col - DIN + 1] = v1;
        }
    } else if (EP == EP_SOFTPLUS){
        out0[(size_t)row*ldo + col    ] = softplusf(v0 + bias[col]);
        out0[(size_t)row*ldo + col + 1] = softplusf(v1 + bias[col+1]);
    } else if (EP == EP_GELU){
        out0[(size_t)row*ldo + col    ] = geluf(v0 + bias[col]);
        out0[(size_t)row*ldo + col + 1] = geluf(v1 + bias[col+1]);
    } else if (EP == EP_BIAS_RES){
        out0[(size_t)row*ldo + col    ] = v0 + bias[col]   + res[(size_t)row*ldo + col];
        out0[(size_t)row*ldo + col + 1] = v1 + bias[col+1] + res[(size_t)row*ldo + col + 1];
    } else { // EP_RES
        out0[(size_t)row*ldo + col    ] = v0 + res[(size_t)row*ldo + col];
        out0[(size_t)row*ldo + col + 1] = v1 + res[(size_t)row*ldo + col + 1];
    }
}

// ---------------- tf32 NT GEMM, 128x128 block, 3-stage cp.async ---------
// 8 warps as 2(M) x 4(N), warp tile 64x32. Dynamic smem: 15360 floats.
#define GT_ASZ 2560                 // 128*20 floats per stage
#define GT_BOFF 7680                // 3 stages of A

template<int EP>
__global__ void __launch_bounds__(256) gemm_tc(const float* __restrict__ A, int lda,
                        const float* __restrict__ W, int Kd,
                        float* __restrict__ out0, float* __restrict__ out1, int ldo,
                        const float* __restrict__ bias, const float* __restrict__ res){
    extern __shared__ float sm[];
    int tid = threadIdx.x;
    int nt = blockIdx.x, mt = blockIdx.y;
    int lane = tid & 31, wid = tid >> 5;
    int warpM = wid & 1, warpN = wid >> 1;      // 2 x 4
    int grp = lane >> 2, tig = lane & 3;

    const float* Abase = A + (size_t)(mt*128)*lda;
    const float* Wbase = W + (size_t)(nt*128)*Kd;

    int r  = tid >> 2;              // 0..63
    int kk = (tid & 3) * 4;

    float acc[4][4][4];
#pragma unroll
    for (int i = 0; i < 4; i++)
#pragma unroll
        for (int j = 0; j < 4; j++)
#pragma unroll
            for (int h = 0; h < 4; h++) acc[i][j][h] = 0.f;

    int nK = Kd >> 4;

    auto issue = [&](int stage){
        int buf = stage % 3;
        int ko = stage * 16;
        cp16(&sm[buf*GT_ASZ + r*20 + kk],               Abase + (size_t)r*lda      + ko + kk);
        cp16(&sm[buf*GT_ASZ + (r+64)*20 + kk],          Abase + (size_t)(r+64)*lda + ko + kk);
        cp16(&sm[GT_BOFF + buf*GT_ASZ + r*20 + kk],     Wbase + (size_t)r*Kd       + ko + kk);
        cp16(&sm[GT_BOFF + buf*GT_ASZ + (r+64)*20 + kk],Wbase + (size_t)(r+64)*Kd  + ko + kk);
        cp_commit();
    };

    issue(0);
    if (nK > 1) issue(1);

    for (int kt = 0; kt < nK; kt++){
        if (kt + 1 < nK) asm volatile("cp.async.wait_group 1;");
        else             asm volatile("cp.async.wait_group 0;");
        __syncthreads();                 // stage kt visible; compute kt-1 done in all warps
        if (kt + 2 < nK) issue(kt + 2);  // overwrites buffer (kt-1)%3 — safe after barrier

        const float* Abuf = &sm[(kt % 3)*GT_ASZ];
        const float* Bbuf = &sm[GT_BOFF + (kt % 3)*GT_ASZ];
#pragma unroll
        for (int k0 = 0; k0 < 16; k0 += 8){
            unsigned a[4][4], b[4][2];
#pragma unroll
            for (int i = 0; i < 4; i++){
                int row = warpM*64 + i*16;
                a[i][0] = __float_as_uint(Abuf[(row+grp  )*20 + k0+tig  ]);
                a[i][1] = __float_as_uint(Abuf[(row+grp+8)*20 + k0+tig  ]);
                a[i][2] = __float_as_uint(Abuf[(row+grp  )*20 + k0+tig+4]);
                a[i][3] = __float_as_uint(Abuf[(row+grp+8)*20 + k0+tig+4]);
            }
#pragma unroll
            for (int j = 0; j < 4; j++){
                int n = warpN*32 + j*8;
                b[j][0] = __float_as_uint(Bbuf[(n+grp)*20 + k0+tig  ]);
                b[j][1] = __float_as_uint(Bbuf[(n+grp)*20 + k0+tig+4]);
            }
#pragma unroll
            for (int i = 0; i < 4; i++)
#pragma unroll
                for (int j = 0; j < 4; j++)
                    mma_tf32(acc[i][j], a[i], b[j]);
        }
    }

#pragma unroll
    for (int i = 0; i < 4; i++){
#pragma unroll
        for (int j = 0; j < 4; j++){
            int col = nt*128 + warpN*32 + j*8 + 2*tig;
#pragma unroll
            for (int h = 0; h < 2; h++){
                int row = mt*128 + warpM*64 + i*16 + grp + h*8;
                ep_store<EP>(out0, out1, ldo, bias, res, row, col,
                             acc[i][j][h*2+0], acc[i][j][h*2+1]);
            }
        }
    }
}

// ---------------- tf32 NT GEMM, 32x64 block, 3-stage (streaming x_proj) --
// 4 warps, each 32(M) x 16(N). Static smem ~23KB.
template<int EP>
__global__ void __launch_bounds__(128) gemm_tc32(const float* __restrict__ A, int lda,
                        const float* __restrict__ W, int Kd,
                        float* __restrict__ out0, float* __restrict__ out1, int ldo,
                        const float* __restrict__ bias, const float* __restrict__ res){
    __shared__ float As[3][32][20];
    __shared__ float Bs[3][64][20];
    int tid = threadIdx.x;
    int nt = blockIdx.x, mt = blockIdx.y;
    int lane = tid & 31, wid = tid >> 5;        // wid = warpN (0..3)
    int grp = lane >> 2, tig = lane & 3;

    const float* Abase = A + (size_t)(mt*32)*lda;
    const float* Wbase = W + (size_t)(nt*64)*Kd;

    int r  = tid >> 2;              // 0..31
    int kk = (tid & 3) * 4;

    float acc[2][2][4];
#pragma unroll
    for (int i = 0; i < 2; i++)
#pragma unroll
        for (int j = 0; j < 2; j++)
#pragma unroll
            for (int h = 0; h < 4; h++) acc[i][j][h] = 0.f;

    int nK = Kd >> 4;

    auto issue = [&](int stage){
        int buf = stage % 3;
        int ko = stage * 16;
        cp16(&As[buf][r][kk],      Abase + (size_t)r*lda       + ko + kk);
        cp16(&Bs[buf][r][kk],      Wbase + (size_t)r*Kd        + ko + kk);
        cp16(&Bs[buf][r+32][kk],   Wbase + (size_t)(r+32)*Kd   + ko + kk);
        cp_commit();
    };

    issue(0);
    if (nK > 1) issue(1);

    for (int kt = 0; kt < nK; kt++){
        if (kt + 1 < nK) asm volatile("cp.async.wait_group 1;");
        else             asm volatile("cp.async.wait_group 0;");
        __syncthreads();
        if (kt + 2 < nK) issue(kt + 2);
        int st = kt % 3;
#pragma unroll
        for (int k0 = 0; k0 < 16; k0 += 8){
            unsigned a[2][4], b[2][2];
#pragma unroll
            for (int i = 0; i < 2; i++){
                int row = i*16;
                a[i][0] = __float_as_uint(As[st][row+grp  ][k0+tig  ]);
                a[i][1] = __float_as_uint(As[st][row+grp+8][k0+tig  ]);
                a[i][2] = __float_as_uint(As[st][row+grp  ][k0+tig+4]);
                a[i][3] = __float_as_uint(As[st][row+grp+8][k0+tig+4]);
            }
#pragma unroll
            for (int j = 0; j < 2; j++){
                int n = wid*16 + j*8;
                b[j][0] = __float_as_uint(Bs[st][n+grp][k0+tig  ]);
                b[j][1] = __float_as_uint(Bs[st][n+grp][k0+tig+4]);
            }
#pragma unroll
            for (int i = 0; i < 2; i++)
#pragma unroll
                for (int j = 0; j < 2; j++)
                    mma_tf32(acc[i][j], a[i], b[j]);
        }
    }

#pragma unroll
    for (int i = 0; i < 2; i++){
#pragma unroll
        for (int j = 0; j < 2; j++){
            int col = nt*64 + wid*16 + j*8 + 2*tig;
#pragma unroll
            for (int h = 0; h < 2; h++){
                int row = mt*32 + i*16 + grp + h*8;
                ep_store<EP>(out0, out1, ldo, bias, res, row, col,
                             acc[i][j][h*2+0], acc[i][j][h*2+1]);
            }
        }
    }
}

// ---------------- layer norm (warp per row of 512); optional 2nd LN ----
template<bool DOUBLE>
__global__ void ln_kernel(const float* __restrict__ in,
                          const float* __restrict__ g1, const float* __restrict__ b1,
                          float* __restrict__ o1,
                          const float* __restrict__ g2, const float* __restrict__ b2,
                          float* __restrict__ o2){
    int w = threadIdx.x >> 5, lane = threadIdx.x & 31;
    int row = blockIdx.x*8 + w;
    const float4* in4 = (const float4*)(in + (size_t)row*DM);
    float4 v[4];
    float s = 0.f, q = 0.f;
#pragma unroll
    for (int i = 0; i < 4; i++){
        v[i] = in4[lane + 32*i];
        s += v[i].x + v[i].y + v[i].z + v[i].w;
        q += v[i].x*v[i].x + v[i].y*v[i].y + v[i].z*v[i].z + v[i].w*v[i].w;
    }
#pragma unroll
    for (int o = 16; o; o >>= 1){
        s += __shfl_xor_sync(~0u, s, o);
        q += __shfl_xor_sync(~0u, q, o);
    }
    float mu = s * (1.f/DM);
    float rs = rsqrtf(q*(1.f/DM) - mu*mu + EPSF);
    float4 zz[4];
    float s2 = 0.f, q2 = 0.f;
#pragma unroll
    for (int i = 0; i < 4; i++){
        float4 gg = ((const float4*)g1)[lane + 32*i];
        float4 bb = ((const float4*)b1)[lane + 32*i];
        zz[i].x = (v[i].x - mu)*rs*gg.x + bb.x;
        zz[i].y = (v[i].y - mu)*rs*gg.y + bb.y;
        zz[i].z = (v[i].z - mu)*rs*gg.z + bb.z;
        zz[i].w = (v[i].w - mu)*rs*gg.w + bb.w;
        if (DOUBLE){
            s2 += zz[i].x + zz[i].y + zz[i].z + zz[i].w;
            q2 += zz[i].x*zz[i].x + zz[i].y*zz[i].y + zz[i].z*zz[i].z + zz[i].w*zz[i].w;
        }
        ((float4*)(o1 + (size_t)row*DM))[lane + 32*i] = zz[i];
    }
    if (DOUBLE){
#pragma unroll
        for (int o = 16; o; o >>= 1){
            s2 += __shfl_xor_sync(~0u, s2, o);
            q2 += __shfl_xor_sync(~0u, q2, o);
        }
        float mu2 = s2 * (1.f/DM);
        float rs2 = rsqrtf(q2*(1.f/DM) - mu2*mu2 + EPSF);
#pragma unroll
        for (int i = 0; i < 4; i++){
            float4 gg = ((const float4*)g2)[lane + 32*i];
            float4 bb = ((const float4*)b2)[lane + 32*i];
            float4 o4;
            o4.x = (zz[i].x - mu2)*rs2*gg.x + bb.x;
            o4.y = (zz[i].y - mu2)*rs2*gg.y + bb.y;
            o4.z = (zz[i].z - mu2)*rs2*gg.z + bb.z;
            o4.w = (zz[i].w - mu2)*rs2*gg.w + bb.w;
            ((float4*)(o2 + (size_t)row*DM))[lane + 32*i] = o4;
        }
    }
}

// ---------------- selective scan ----------------
__global__ void scan_kernel(const float* __restrict__ delta,
                            const float* __restrict__ u,
                            const float* __restrict__ zg,
                            const float* __restrict__ xdbl,
                            const float* __restrict__ A_log,
                            const float* __restrict__ Dp,
                            float* __restrict__ y2){
    int blk = blockIdx.x;                    // 128 blocks
    int b = blk >> 3, dblk = blk & 7;
    int t = threadIdx.x;                     // 256
    int half = t & 1;
    int d = dblk*128 + (t >> 1);
    int nb = half * 8;

    float Aa[8];
#pragma unroll
    for (int j = 0; j < 8; j++) Aa[j] = -expf(A_log[d*NST + nb + j]);
    float A0 = Aa[0];
    float stepA = Aa[1] - Aa[0];
    bool prog = true;
#pragma unroll
    for (int j = 0; j < 8; j++){
        float e = A0 + (float)j * stepA;
        if (fabsf(Aa[j] - e) > 1e-5f*fabsf(e) + 1e-7f) prog = false;
    }
    float Dd = Dp[d];

    float h[8];
#pragma unroll
    for (int j = 0; j < 8; j++) h[j] = 0.f;

    size_t base = (size_t)(b*SEQ)*DIN + d;
    const float* xb = xdbl + (size_t)(b*SEQ)*64 + 32 + nb;

    float dv = delta[base], uv = u[base], zv = zg[base];
    float4 B0 = *(const float4*)(xb);
    float4 B1 = *(const float4*)(xb + 4);
    float4 C0 = *(const float4*)(xb + 16);
    float4 C1 = *(const float4*)(xb + 20);

    for (int s = 0; s < SEQ; s++){
        size_t baseN = base + DIN;
        const float* xbN = xb + 64;
        float dvN = delta[baseN], uvN = u[baseN], zvN = zg[baseN];
        float4 B0N = *(const float4*)(xbN);
        float4 B1N = *(const float4*)(xbN + 4);
        float4 C0N = *(const float4*)(xbN + 16);
        float4 C1N = *(const float4*)(xbN + 20);

        float du = dv * uv;
        float y = 0.f;
        if (prog){
            float e = __expf(dv * A0);
            float r = __expf(dv * stepA);
            h[0] = h[0]*e + du*B0.x; y += h[0]*C0.x; e *= r;
            h[1] = h[1]*e + du*B0.y; y += h[1]*C0.y; e *= r;
            h[2] = h[2]*e + du*B0.z; y += h[2]*C0.z; e *= r;
            h[3] = h[3]*e + du*B0.w; y += h[3]*C0.w; e *= r;
            h[4] = h[4]*e + du*B1.x; y += h[4]*C1.x; e *= r;
            h[5] = h[5]*e + du*B1.y; y += h[5]*C1.y; e *= r;
            h[6] = h[6]*e + du*B1.z; y += h[6]*C1.z; e *= r;
            h[7] = h[7]*e + du*B1.w; y += h[7]*C1.w;
        } else {
            float Bv[8] = {B0.x,B0.y,B0.z,B0.w,B1.x,B1.y,B1.z,B1.w};
            float Cv[8] = {C0.x,C0.y,C0.z,C0.w,C1.x,C1.y,C1.z,C1.w};
#pragma unroll
            for (int j = 0; j < 8; j++){
                float e = __expf(dv * Aa[j]);
                h[j] = h[j]*e + du*Bv[j];
                y += h[j]*Cv[j];
            }
        }
        float ysum = y + __shfl_xor_sync(~0u, y, 1);
        if (!half){
            float out = (ysum + uv*Dd) * siluf(zv);
            y2[base] = out;
        }
        base = baseN; xb = xbN;
        dv = dvN; uv = uvN; zv = zvN;
        B0 = B0N; B1 = B1N; C0 = C0N; C1 = C1N;
    }
}

// ---------------- head: partial GEMM per patch index p ----------------
__global__ void head_partial(const float* __restrict__ zf, const float* __restrict__ hw){
    int p = blockIdx.x, mt = blockIdx.y;     // p in [0,63), mt in [0,4)
    __shared__ float As[16][64];
    __shared__ float Ws[16][96];
    int tid = threadIdx.x;                   // 256
    int lm = tid >> 2, lk = (tid & 3) * 4;
    int bkrow = mt*64 + lm;
    int b = bkrow >> 4, kk = bkrow & 15;
    const float* Ag = zf + (size_t)(b*SEQ + p*KVAR + kk)*DM + lk;
    int tx = tid & 15, ty = tid >> 4;
    float acc[4][6];
#pragma unroll
    for (int i = 0; i < 4; i++)
#pragma unroll
        for (int j = 0; j < 6; j++) acc[i][j] = 0.f;

    for (int kt = 0; kt < DM; kt += 16){
        float4 av = *(const float4*)(Ag + kt);
        As[lk+0][lm]=av.x; As[lk+1][lm]=av.y; As[lk+2][lm]=av.z; As[lk+3][lm]=av.w;
#pragma unroll
        for (int i = 0; i < 6; i++){
            int e = tid + i*256;             // 1536 = 96*16 elements
            int n = e >> 4, kq = e & 15;
            Ws[kq][n] = hw[(size_t)n*HWLD + p*DM + kt + kq];
        }
        __syncthreads();
#pragma unroll
        for (int k = 0; k < 16; k++){
            float4 a = *(const float4*)&As[k][ty*4];
            float av4[4] = {a.x, a.y, a.z, a.w};
#pragma unroll
            for (int j = 0; j < 6; j++){
                float wv = Ws[k][tx*6 + j];
#pragma unroll
                for (int i = 0; i < 4; i++) acc[i][j] += av4[i]*wv;
            }
        }
        __syncthreads();
    }
#pragma unroll
    for (int i = 0; i < 4; i++)
#pragma unroll
        for (int j = 0; j < 6; j++)
            g_headp[(size_t)(p*256 + mt*64 + ty*4 + i)*HPRED + tx*6 + j] = acc[i][j];
}

// ---------------- head reduction + de-normalization ----------------
__global__ void head_final(const float* __restrict__ hb, float* __restrict__ out){
    int idx = blockIdx.x*256 + threadIdx.x;  // 24576 = 256*96
    int bk = idx / HPRED, hh = idx % HPRED;
    float s = 0.f;
    for (int p = 0; p < PP; p++) s += g_headp[(size_t)p*(BB*KVAR*HPRED) + idx];
    s += hb[hh];
    int b = bk >> 4, k = bk & 15;
    out[b*(HPRED*KVAR) + hh*KVAR + k] = s * g_std[bk] + g_mean[bk];
}

// ---------------- launch ----------------
#define GT_SMEM (15360*4)   // 61440 bytes dynamic smem for gemm_tc

extern "C" void kernel_launch(void* const* d_in, const int* in_sizes, int n_in,
                              void* d_out, int out_size){
    const float* x        = (const float*)d_in[0];
    const float* patch_w  = (const float*)d_in[1];
    const float* patch_b  = (const float*)d_in[2];
    const float* pos      = (const float*)d_in[3];
    const float* vemb     = (const float*)d_in[4];
    const float* in_w     = (const float*)d_in[5];
    const float* xp_w     = (const float*)d_in[6];
    const float* dt_w     = (const float*)d_in[7];
    const float* dt_b     = (const float*)d_in[8];
    const float* A_log    = (const float*)d_in[9];
    const float* D_par    = (const float*)d_in[10];
    const float* out_w    = (const float*)d_in[11];
    const float* tmb_g    = (const float*)d_in[12];
    const float* tmb_b    = (const float*)d_in[13];
    const float* ffn_g    = (const float*)d_in[14];
    const float* ffn_b    = (const float*)d_in[15];
    const float* ffn_w1   = (const float*)d_in[16];
    const float* ffn_b1   = (const float*)d_in[17];
    const float* ffn_w2   = (const float*)d_in[18];
    const float* ffn_b2   = (const float*)d_in[19];
    const float* norm_g   = (const float*)d_in[20];
    const float* norm_b   = (const float*)d_in[21];
    const float* head_w   = (const float*)d_in[22];
    const float* head_b   = (const float*)d_in[23];
    float* out = (float*)d_out;

    // opt-in >48KB dynamic smem for each gemm_tc instantiation (idempotent)
    cudaFuncSetAttribute(gemm_tc<EP_SPLIT>,    cudaFuncAttributeMaxDynamicSharedMemorySize, GT_SMEM);
    cudaFuncSetAttribute(gemm_tc<EP_SOFTPLUS>, cudaFuncAttributeMaxDynamicSharedMemorySize, GT_SMEM);
    cudaFuncSetAttribute(gemm_tc<EP_RES>,      cudaFuncAttributeMaxDynamicSharedMemorySize, GT_SMEM);
    cudaFuncSetAttribute(gemm_tc<EP_GELU>,     cudaFuncAttributeMaxDynamicSharedMemorySize, GT_SMEM);
    cudaFuncSetAttribute(gemm_tc<EP_BIAS_RES>, cudaFuncAttributeMaxDynamicSharedMemorySize, GT_SMEM);

    float *z, *tmp, *hln, *u, *zgp, *xdbl, *delta, *y2, *hff;
    cudaGetSymbolAddress((void**)&z,    g_z);
    cudaGetSymbolAddress((void**)&tmp,  g_tmp);
    cudaGetSymbolAddress((void**)&hln,  g_hln);
    cudaGetSymbolAddress((void**)&u,    g_u);
    cudaGetSymbolAddress((void**)&zgp,  g_zg);
    cudaGetSymbolAddress((void**)&xdbl, g_xdbl);
    cudaGetSymbolAddress((void**)&delta,g_delta);
    cudaGetSymbolAddress((void**)&y2,   g_y2);
    cudaGetSymbolAddress((void**)&hff,  g_hff);

    stats_kernel<<<BB*KVAR, 256>>>(x);
    embed_kernel<<<TT, 128>>>(x, patch_w, patch_b, pos, vemb);

    const int MT  = TT/128;   // 126 M tiles (128-row)
    const int MT32= TT/32;    // 504 M tiles (32-row)

    for (int l = 0; l < NLAY; l++){
        const float* Wi  = in_w  + (size_t)l*(2*DIN)*DM;
        const float* Wx  = xp_w  + (size_t)l*64*DIN;
        const float* Wdt = dt_w  + (size_t)l*DIN*RNK;
        const float* bdt = dt_b  + (size_t)l*DIN;
        const float* Al  = A_log + (size_t)l*DIN*NST;
        const float* Dl  = D_par + (size_t)l*DIN;
        const float* Wo  = out_w + (size_t)l*DM*DIN;
        const float* W1  = ffn_w1+ (size_t)l*DFF*DM;
        const float* B1  = ffn_b1+ (size_t)l*DFF;
        const float* W2  = ffn_w2+ (size_t)l*DM*DFF;
        const float* B2  = ffn_b2+ (size_t)l*DM;

        // in_proj -> silu(u), zg   (N=2048, K=512)
        gemm_tc<EP_SPLIT><<<dim3(16, MT), 256, GT_SMEM>>>(z, DM, Wi, DM, u, zgp, 0, nullptr, nullptr);
        // x_proj: xdbl = u @ Wx^T   (N=64, K=1024) — streaming 32-row tiles
        gemm_tc32<EP_NONE><<<dim3(1, MT32), 128>>>(u, DIN, Wx, DIN, xdbl, nullptr, 64, nullptr, nullptr);
        // delta = softplus(dt @ Wdt^T + bdt)  (N=1024, K=32)
        gemm_tc<EP_SOFTPLUS><<<dim3(8, MT), 256, GT_SMEM>>>(xdbl, 64, Wdt, RNK, delta, nullptr, DIN, bdt, nullptr);
        // selective scan (fused +u*D, *silu(zg))
        scan_kernel<<<128, 256>>>(delta, u, zgp, xdbl, Al, Dl, y2);
        // out_proj + residual into tmp  (N=512, K=1024)
        gemm_tc<EP_RES><<<dim3(4, MT), 256, GT_SMEM>>>(y2, DIN, Wo, DIN, tmp, nullptr, DM, nullptr, z);
        // LN(tmp)->z ; LN(z)->hln (ffn pre-norm)
        ln_kernel<true><<<TT/8, 256>>>(tmp, tmb_g + l*DM, tmb_b + l*DM, z,
                                       ffn_g + l*DM, ffn_b + l*DM, hln);
        // FFN
        gemm_tc<EP_GELU><<<dim3(16, MT), 256, GT_SMEM>>>(hln, DM, W1, DM, hff, nullptr, DFF, B1, nullptr);
        gemm_tc<EP_BIAS_RES><<<dim3(4, MT), 256, GT_SMEM>>>(hff, DFF, W2, DFF, z, nullptr, DM, B2, z);
    }

    // final LN -> tmp
    ln_kernel<false><<<TT/8, 256>>>(z, norm_g, norm_b, tmp, nullptr, nullptr, nullptr);
    // head
    head_partial<<<dim3(PP, 4), 256>>>(tmp, head_w);
    head_final<<<96, 256>>>(head_b, out);
    (void)in_sizes; (void)n_in; (void)out_size;
}

// round 5
// speedup vs baseline: 1.0041x; 1.0041x over previous
#include <cuda_runtime.h>
#include <math.h>

// ---------------- problem constants ----------------
#define BB     16
#define LCTX   512
#define KVAR   16
#define HPRED  96
#define DM     512
#define NST    16
#define NLAY   3
#define DFF    2048
#define PATCH  16
#define STRIDEP 8
#define PP     63            // (512-16)/8+1
#define DIN    1024          // 2*DM
#define RNK    32            // DT_RANK
#define SEQ    (KVAR*PP)     // 1008 tokens per batch
#define TT     (BB*SEQ)      // 16128 total tokens
#define EPSF   1e-5f
#define HWLD   (PP*DM)       // 32256 head_w row length

// ---------------- scratch (device globals; padded for scan prefetch) ----
__device__ float g_mean[BB*KVAR];
__device__ float g_std[BB*KVAR];
__device__ float g_z   [TT*DM];
__device__ float g_tmp [TT*DM];
__device__ float g_hln [TT*DM];
__device__ float g_u   [TT*DIN + DIN];
__device__ float g_zg  [TT*DIN + DIN];
__device__ float g_xdbl[TT*64 + 64];
__device__ float g_y2  [TT*DIN];
__device__ float g_hff [TT*DFF];
__device__ float g_headp[PP*BB*KVAR*HPRED];

// ---------------- helpers ----------------
__device__ __forceinline__ float siluf(float x){ return x / (1.f + __expf(-x)); }
__device__ __forceinline__ float geluf(float x){
    return 0.5f * x * (1.f + erff(x * 0.70710678118654752f));
}

__device__ __forceinline__ void cp16(void* smem, const void* g){
    unsigned a = (unsigned)__cvta_generic_to_shared(smem);
    asm volatile("cp.async.cg.shared.global [%0], [%1], 16;" :: "r"(a), "l"(g));
}
__device__ __forceinline__ void cp_commit(){ asm volatile("cp.async.commit_group;"); }

__device__ __forceinline__ void mma_tf32(float* c, const unsigned* a, const unsigned* b){
    asm volatile("mma.sync.aligned.m16n8k8.row.col.f32.tf32.tf32.f32 "
        "{%0,%1,%2,%3}, {%4,%5,%6,%7}, {%8,%9}, {%0,%1,%2,%3};"
        : "+f"(c[0]),"+f"(c[1]),"+f"(c[2]),"+f"(c[3])
        : "r"(a[0]),"r"(a[1]),"r"(a[2]),"r"(a[3]), "r"(b[0]),"r"(b[1]));
}

// ---------------- per-(b,k) mean/std over L ----------------
__global__ void stats_kernel(const float* __restrict__ x){
    int bk = blockIdx.x; int b = bk >> 4, k = bk & 15;
    int tid = threadIdx.x;
    float s = 0.f, q = 0.f;
    for (int l = tid; l < LCTX; l += 256){
        float v = x[(b*LCTX + l)*KVAR + k];
        s += v; q += v*v;
    }
    __shared__ float sh[64];
#pragma unroll
    for (int o = 16; o; o >>= 1){
        s += __shfl_xor_sync(~0u, s, o);
        q += __shfl_xor_sync(~0u, q, o);
    }
    int w = tid >> 5;
    if ((tid & 31) == 0){ sh[w] = s; sh[w+32] = q; }
    __syncthreads();
    if (tid == 0){
        float S = 0.f, Q = 0.f;
        for (int i = 0; i < 8; i++){ S += sh[i]; Q += sh[32+i]; }
        float mu  = S * (1.f/LCTX);
        float var = Q * (1.f/LCTX) - mu*mu;
        g_mean[bk] = mu;
        g_std[bk]  = sqrtf(var + EPSF);
    }
}

// ---------------- patch embedding + pos + var embed ----------------
__global__ void embed_kernel(const float* __restrict__ x,
                             const float* __restrict__ pw,
                             const float* __restrict__ pb,
                             const float* __restrict__ pos,
                             const float* __restrict__ vemb){
    int row = blockIdx.x;                    // token row in [0,TT)
    int b = row / SEQ, rem = row % SEQ;
    int p = rem >> 4, k = rem & 15;
    int bk = b*KVAR + k;
    __shared__ float xs[PATCH];
    int tid = threadIdx.x;                   // 128
    if (tid < PATCH){
        float v = x[(b*LCTX + p*STRIDEP + tid)*KVAR + k];
        xs[tid] = (v - g_mean[bk]) / g_std[bk];
    }
    __syncthreads();
#pragma unroll
    for (int j = 0; j < 4; j++){
        int d = tid + j*128;
        float acc = pb[d] + pos[p*DM + d] + vemb[k*DM + d];
        const float4* w4 = (const float4*)(pw + d*PATCH);
#pragma unroll
        for (int t4 = 0; t4 < 4; t4++){
            float4 w = w4[t4];
            acc += xs[t4*4+0]*w.x + xs[t4*4+1]*w.y + xs[t4*4+2]*w.z + xs[t4*4+3]*w.w;
        }
        g_z[row*DM + d] = acc;
    }
}

// ---------------- epilogue modes ----------------
enum { EP_NONE=0, EP_SPLIT=1, EP_GELU=3, EP_BIAS_RES=4, EP_RES=5 };

template<int EP>
__device__ __forceinline__ void ep_store(float* __restrict__ out0, float* __restrict__ out1,
                                         int ldo, const float* __restrict__ bias,
                                         const float* __restrict__ res,
                                         int row, int col, float v0, float v1){
    if (EP == EP_NONE){
        out0[(size_t)row*ldo + col    ] = v0;
        out0[(size_t)row*ldo + col + 1] = v1;
    } else if (EP == EP_SPLIT){
        if (col < DIN){
            out0[(size_t)row*DIN + col    ] = siluf(v0);
            out0[(size_t)row*DIN + col + 1] = siluf(v1);
        } else {
            out1[(size_t)row*DIN + col - DIN    ] = v0;
            out1[(size_t)row*DIN + col - DIN + 1] = v1;
        }
    } else if (EP == EP_GELU){
        out0[(size_t)row*ldo + col    ] = geluf(v0 + bias[col]);
        out0[(size_t)row*ldo + col + 1] = geluf(v1 + bias[col+1]);
    } else if (EP == EP_BIAS_RES){
        out0[(size_t)row*ldo + col    ] = v0 + bias[col]   + res[(size_t)row*ldo + col];
        out0[(size_t)row*ldo + col + 1] = v1 + bias[col+1] + res[(size_t)row*ldo + col + 1];
    } else { // EP_RES
        out0[(size_t)row*ldo + col    ] = v0 + res[(size_t)row*ldo + col];
        out0[(size_t)row*ldo + col + 1] = v1 + res[(size_t)row*ldo + col + 1];
    }
}

// ---------------- tf32 NT GEMM, 128x128 block, 5-stage cp.async ---------
// 8 warps as 2(M) x 4(N), warp tile 64x32. wait_group 3 => 4 stages in flight.
#define GT_ASZ   2560               // 128*20 floats per stage
#define GT_BOFF  12800              // 5 stages of A
#define GT_SMEM  (25600*4)          // 102400 bytes

template<int EP>
__global__ void __launch_bounds__(256) gemm_tc(const float* __restrict__ A, int lda,
                        const float* __restrict__ W, int Kd,
                        float* __restrict__ out0, float* __restrict__ out1, int ldo,
                        const float* __restrict__ bias, const float* __restrict__ res){
    extern __shared__ float sm[];
    int tid = threadIdx.x;
    int nt = blockIdx.x, mt = blockIdx.y;
    int lane = tid & 31, wid = tid >> 5;
    int warpM = wid & 1, warpN = wid >> 1;      // 2 x 4
    int grp = lane >> 2, tig = lane & 3;

    const float* Abase = A + (size_t)(mt*128)*lda;
    const float* Wbase = W + (size_t)(nt*128)*Kd;

    int r  = tid >> 2;              // 0..63
    int kk = (tid & 3) * 4;

    float acc[4][4][4];
#pragma unroll
    for (int i = 0; i < 4; i++)
#pragma unroll
        for (int j = 0; j < 4; j++)
#pragma unroll
            for (int h = 0; h < 4; h++) acc[i][j][h] = 0.f;

    int nK = Kd >> 4;

    auto issue = [&](int stage){
        int buf = stage % 5;
        int ko = stage * 16;
        cp16(&sm[buf*GT_ASZ + r*20 + kk],               Abase + (size_t)r*lda      + ko + kk);
        cp16(&sm[buf*GT_ASZ + (r+64)*20 + kk],          Abase + (size_t)(r+64)*lda + ko + kk);
        cp16(&sm[GT_BOFF + buf*GT_ASZ + r*20 + kk],     Wbase + (size_t)r*Kd       + ko + kk);
        cp16(&sm[GT_BOFF + buf*GT_ASZ + (r+64)*20 + kk],Wbase + (size_t)(r+64)*Kd  + ko + kk);
        cp_commit();
    };

    // pad to exactly 4 outstanding groups (empty commits keep the count)
#pragma unroll
    for (int s = 0; s < 4; s++){
        if (s < nK) issue(s); else cp_commit();
    }

    for (int kt = 0; kt < nK; kt++){
        asm volatile("cp.async.wait_group 3;");
        __syncthreads();                 // stage kt visible; compute kt-1 done everywhere
        if (kt + 4 < nK) issue(kt + 4); else cp_commit();

        const float* Abuf = &sm[(kt % 5)*GT_ASZ];
        const float* Bbuf = &sm[GT_BOFF + (kt % 5)*GT_ASZ];
#pragma unroll
        for (int k0 = 0; k0 < 16; k0 += 8){
            unsigned a[4][4], b[4][2];
#pragma unroll
            for (int i = 0; i < 4; i++){
                int row = warpM*64 + i*16;
                a[i][0] = __float_as_uint(Abuf[(row+grp  )*20 + k0+tig  ]);
                a[i][1] = __float_as_uint(Abuf[(row+grp+8)*20 + k0+tig  ]);
                a[i][2] = __float_as_uint(Abuf[(row+grp  )*20 + k0+tig+4]);
                a[i][3] = __float_as_uint(Abuf[(row+grp+8)*20 + k0+tig+4]);
            }
#pragma unroll
            for (int j = 0; j < 4; j++){
                int n = warpN*32 + j*8;
                b[j][0] = __float_as_uint(Bbuf[(n+grp)*20 + k0+tig  ]);
                b[j][1] = __float_as_uint(Bbuf[(n+grp)*20 + k0+tig+4]);
            }
#pragma unroll
            for (int i = 0; i < 4; i++)
#pragma unroll
                for (int j = 0; j < 4; j++)
                    mma_tf32(acc[i][j], a[i], b[j]);
        }
    }

#pragma unroll
    for (int i = 0; i < 4; i++){
#pragma unroll
        for (int j = 0; j < 4; j++){
            int col = nt*128 + warpN*32 + j*8 + 2*tig;
#pragma unroll
            for (int h = 0; h < 2; h++){
                int row = mt*128 + warpM*64 + i*16 + grp + h*8;
                ep_store<EP>(out0, out1, ldo, bias, res, row, col,
                             acc[i][j][h*2+0], acc[i][j][h*2+1]);
            }
        }
    }
}

// ---------------- tf32 NT GEMM, 32x64 block, 6-stage (streaming x_proj) --
template<int EP>
__global__ void __launch_bounds__(128) gemm_tc32(const float* __restrict__ A, int lda,
                        const float* __restrict__ W, int Kd,
                        float* __restrict__ out0, float* __restrict__ out1, int ldo,
                        const float* __restrict__ bias, const float* __restrict__ res){
    __shared__ float As[6][32][20];
    __shared__ float Bs[6][64][20];
    int tid = threadIdx.x;
    int nt = blockIdx.x, mt = blockIdx.y;
    int lane = tid & 31, wid = tid >> 5;        // wid = warpN (0..3)
    int grp = lane >> 2, tig = lane & 3;

    const float* Abase = A + (size_t)(mt*32)*lda;
    const float* Wbase = W + (size_t)(nt*64)*Kd;

    int r  = tid >> 2;              // 0..31
    int kk = (tid & 3) * 4;

    float acc[2][2][4];
#pragma unroll
    for (int i = 0; i < 2; i++)
#pragma unroll
        for (int j = 0; j < 2; j++)
#pragma unroll
            for (int h = 0; h < 4; h++) acc[i][j][h] = 0.f;

    int nK = Kd >> 4;

    auto issue = [&](int stage){
        int buf = stage % 6;
        int ko = stage * 16;
        cp16(&As[buf][r][kk],      Abase + (size_t)r*lda       + ko + kk);
        cp16(&Bs[buf][r][kk],      Wbase + (size_t)r*Kd        + ko + kk);
        cp16(&Bs[buf][r+32][kk],   Wbase + (size_t)(r+32)*Kd   + ko + kk);
        cp_commit();
    };

#pragma unroll
    for (int s = 0; s < 5; s++){
        if (s < nK) issue(s); else cp_commit();
    }

    for (int kt = 0; kt < nK; kt++){
        asm volatile("cp.async.wait_group 4;");
        __syncthreads();
        if (kt + 5 < nK) issue(kt + 5); else cp_commit();
        int st = kt % 6;
#pragma unroll
        for (int k0 = 0; k0 < 16; k0 += 8){
            unsigned a[2][4], b[2][2];
#pragma unroll
            for (int i = 0; i < 2; i++){
                int row = i*16;
                a[i][0] = __float_as_uint(As[st][row+grp  ][k0+tig  ]);
                a[i][1] = __float_as_uint(As[st][row+grp+8][k0+tig  ]);
                a[i][2] = __float_as_uint(As[st][row+grp  ][k0+tig+4]);
                a[i][3] = __float_as_uint(As[st][row+grp+8][k0+tig+4]);
            }
#pragma unroll
            for (int j = 0; j < 2; j++){
                int n = wid*16 + j*8;
                b[j][0] = __float_as_uint(Bs[st][n+grp][k0+tig  ]);
                b[j][1] = __float_as_uint(Bs[st][n+grp][k0+tig+4]);
            }
#pragma unroll
            for (int i = 0; i < 2; i++)
#pragma unroll
                for (int j = 0; j < 2; j++)
                    mma_tf32(acc[i][j], a[i], b[j]);
        }
    }

#pragma unroll
    for (int i = 0; i < 2; i++){
#pragma unroll
        for (int j = 0; j < 2; j++){
            int col = nt*64 + wid*16 + j*8 + 2*tig;
#pragma unroll
            for (int h = 0; h < 2; h++){
                int row = mt*32 + i*16 + grp + h*8;
                ep_store<EP>(out0, out1, ldo, bias, res, row, col,
                             acc[i][j][h*2+0], acc[i][j][h*2+1]);
            }
        }
    }
}

// ---------------- layer norm (warp per row of 512); optional 2nd LN ----
template<bool DOUBLE>
__global__ void ln_kernel(const float* __restrict__ in,
                          const float* __restrict__ g1, const float* __restrict__ b1,
                          float* __restrict__ o1,
                          const float* __restrict__ g2, const float* __restrict__ b2,
                          float* __restrict__ o2){
    int w = threadIdx.x >> 5, lane = threadIdx.x & 31;
    int row = blockIdx.x*8 + w;
    const float4* in4 = (const float4*)(in + (size_t)row*DM);
    float4 v[4];
    float s = 0.f, q = 0.f;
#pragma unroll
    for (int i = 0; i < 4; i++){
        v[i] = in4[lane + 32*i];
        s += v[i].x + v[i].y + v[i].z + v[i].w;
        q += v[i].x*v[i].x + v[i].y*v[i].y + v[i].z*v[i].z + v[i].w*v[i].w;
    }
#pragma unroll
    for (int o = 16; o; o >>= 1){
        s += __shfl_xor_sync(~0u, s, o);
        q += __shfl_xor_sync(~0u, q, o);
    }
    float mu = s * (1.f/DM);
    float rs = rsqrtf(q*(1.f/DM) - mu*mu + EPSF);
    float4 zz[4];
    float s2 = 0.f, q2 = 0.f;
#pragma unroll
    for (int i = 0; i < 4; i++){
        float4 gg = ((const float4*)g1)[lane + 32*i];
        float4 bb = ((const float4*)b1)[lane + 32*i];
        zz[i].x = (v[i].x - mu)*rs*gg.x + bb.x;
        zz[i].y = (v[i].y - mu)*rs*gg.y + bb.y;
        zz[i].z = (v[i].z - mu)*rs*gg.z + bb.z;
        zz[i].w = (v[i].w - mu)*rs*gg.w + bb.w;
        if (DOUBLE){
            s2 += zz[i].x + zz[i].y + zz[i].z + zz[i].w;
            q2 += zz[i].x*zz[i].x + zz[i].y*zz[i].y + zz[i].z*zz[i].z + zz[i].w*zz[i].w;
        }
        ((float4*)(o1 + (size_t)row*DM))[lane + 32*i] = zz[i];
    }
    if (DOUBLE){
#pragma unroll
        for (int o = 16; o; o >>= 1){
            s2 += __shfl_xor_sync(~0u, s2, o);
            q2 += __shfl_xor_sync(~0u, q2, o);
        }
        float mu2 = s2 * (1.f/DM);
        float rs2 = rsqrtf(q2*(1.f/DM) - mu2*mu2 + EPSF);
#pragma unroll
        for (int i = 0; i < 4; i++){
            float4 gg = ((const float4*)g2)[lane + 32*i];
            float4 bb = ((const float4*)b2)[lane + 32*i];
            float4 o4;
            o4.x = (zz[i].x - mu2)*rs2*gg.x + bb.x;
            o4.y = (zz[i].y - mu2)*rs2*gg.y + bb.y;
            o4.z = (zz[i].z - mu2)*rs2*gg.z + bb.z;
            o4.w = (zz[i].w - mu2)*rs2*gg.w + bb.w;
            ((float4*)(o2 + (size_t)row*DM))[lane + 32*i] = o4;
        }
    }
}

// ---------------- selective scan with fused dt_proj + softplus ----------
// One (b,d) chain split across 2 adjacent lanes (8 states each).
// delta_t = softplus(xdbl[t,0:32] @ Wdt[d]^T + bdt[d]) computed in-kernel.
__global__ void scan_kernel(const float* __restrict__ u,
                            const float* __restrict__ zg,
                            const float* __restrict__ xdbl,
                            const float* __restrict__ Wdt,
                            const float* __restrict__ bdt,
                            const float* __restrict__ A_log,
                            const float* __restrict__ Dp,
                            float* __restrict__ y2){
    int blk = blockIdx.x;                    // 128 blocks
    int b = blk >> 3, dblk = blk & 7;
    int t = threadIdx.x;                     // 256
    int half = t & 1;
    int d = dblk*128 + (t >> 1);
    int nb = half * 8;

    float Aa[8];
#pragma unroll
    for (int j = 0; j < 8; j++) Aa[j] = -expf(A_log[d*NST + nb + j]);
    float A0 = Aa[0];
    float stepA = Aa[1] - Aa[0];
    bool prog = true;
#pragma unroll
    for (int j = 0; j < 8; j++){
        float e = A0 + (float)j * stepA;
        if (fabsf(Aa[j] - e) > 1e-5f*fabsf(e) + 1e-7f) prog = false;
    }
    float Dd = Dp[d];
    float bd = bdt[d];

    float wdt[16];
#pragma unroll
    for (int j = 0; j < 16; j++) wdt[j] = Wdt[d*RNK + half*16 + j];

    float h[8];
#pragma unroll
    for (int j = 0; j < 8; j++) h[j] = 0.f;

    size_t base = (size_t)(b*SEQ)*DIN + d;
    const float* xr = xdbl + (size_t)(b*SEQ)*64;

    // helper: delta from a loaded dt-quarter set (lambda via macro-free inline)
    auto calc_delta = [&](const float4& T0, const float4& T1,
                          const float4& T2, const float4& T3) -> float {
        float a0 = T0.x*wdt[0]  + T0.y*wdt[1]  + T0.z*wdt[2]  + T0.w*wdt[3];
        float a1 = T1.x*wdt[4]  + T1.y*wdt[5]  + T1.z*wdt[6]  + T1.w*wdt[7];
        float a2 = T2.x*wdt[8]  + T2.y*wdt[9]  + T2.z*wdt[10] + T2.w*wdt[11];
        float a3 = T3.x*wdt[12] + T3.y*wdt[13] + T3.z*wdt[14] + T3.w*wdt[15];
        float p = (a0 + a1) + (a2 + a3);
        p += __shfl_xor_sync(~0u, p, 1);
        float xv = p + bd;
        return fmaxf(xv, 0.f) + __logf(1.f + __expf(-fabsf(xv)));
    };

    // step 0 loads
    float uv = u[base], zv = zg[base];
    const float* dtp = xr + half*16;
    float4 T0 = *(const float4*)(dtp), T1 = *(const float4*)(dtp+4);
    float4 T2 = *(const float4*)(dtp+8), T3 = *(const float4*)(dtp+12);
    float4 B0 = *(const float4*)(xr + 32 + nb);
    float4 B1 = *(const float4*)(xr + 36 + nb);
    float4 C0 = *(const float4*)(xr + 48 + nb);
    float4 C1 = *(const float4*)(xr + 52 + nb);
    float dv = calc_delta(T0, T1, T2, T3);

    for (int s = 0; s < SEQ; s++){
        // issue next-step loads early (buffers padded by one row)
        size_t baseN = base + DIN;
        const float* xrN = xr + 64;
        float uvN = u[baseN], zvN = zg[baseN];
        const float* dtpN = xrN + half*16;
        float4 TN0 = *(const float4*)(dtpN),   TN1 = *(const float4*)(dtpN+4);
        float4 TN2 = *(const float4*)(dtpN+8), TN3 = *(const float4*)(dtpN+12);
        float4 B0N = *(const float4*)(xrN + 32 + nb);
        float4 B1N = *(const float4*)(xrN + 36 + nb);
        float4 C0N = *(const float4*)(xrN + 48 + nb);
        float4 C1N = *(const float4*)(xrN + 52 + nb);

        float du = dv * uv;
        float y = 0.f;
        if (prog){
            float e = __expf(dv * A0);
            float r = __expf(dv * stepA);
            h[0] = h[0]*e + du*B0.x; y += h[0]*C0.x; e *= r;
            h[1] = h[1]*e + du*B0.y; y += h[1]*C0.y; e *= r;
            h[2] = h[2]*e + du*B0.z; y += h[2]*C0.z; e *= r;
            h[3] = h[3]*e + du*B0.w; y += h[3]*C0.w; e *= r;
            h[4] = h[4]*e + du*B1.x; y += h[4]*C1.x; e *= r;
            h[5] = h[5]*e + du*B1.y; y += h[5]*C1.y; e *= r;
            h[6] = h[6]*e + du*B1.z; y += h[6]*C1.z; e *= r;
            h[7] = h[7]*e + du*B1.w; y += h[7]*C1.w;
        } else {
            float Bv[8] = {B0.x,B0.y,B0.z,B0.w,B1.x,B1.y,B1.z,B1.w};
            float Cv[8] = {C0.x,C0.y,C0.z,C0.w,C1.x,C1.y,C1.z,C1.w};
#pragma unroll
            for (int j = 0; j < 8; j++){
                float e = __expf(dv * Aa[j]);
                h[j] = h[j]*e + du*Bv[j];
                y += h[j]*Cv[j];
            }
        }
        float ysum = y + __shfl_xor_sync(~0u, y, 1);
        if (!half){
            float out = (ysum + uv*Dd) * siluf(zv);
            y2[base] = out;
        }
        // delta for next step (loads had the whole step to land)
        dv = calc_delta(TN0, TN1, TN2, TN3);
        base = baseN; xr = xrN;
        uv = uvN; zv = zvN;
        B0 = B0N; B1 = B1N; C0 = C0N; C1 = C1N;
    }
}

// ---------------- head: partial GEMM per patch index p ----------------
__global__ void head_partial(const float* __restrict__ zf, const float* __restrict__ hw){
    int p = blockIdx.x, mt = blockIdx.y;     // p in [0,63), mt in [0,4)
    __shared__ float As[16][64];
    __shared__ float Ws[16][96];
    int tid = threadIdx.x;                   // 256
    int lm = tid >> 2, lk = (tid & 3) * 4;
    int bkrow = mt*64 + lm;
    int b = bkrow >> 4, kk = bkrow & 15;
    const float* Ag = zf + (size_t)(b*SEQ + p*KVAR + kk)*DM + lk;
    int tx = tid & 15, ty = tid >> 4;
    float acc[4][6];
#pragma unroll
    for (int i = 0; i < 4; i++)
#pragma unroll
        for (int j = 0; j < 6; j++) acc[i][j] = 0.f;

    for (int kt = 0; kt < DM; kt += 16){
        float4 av = *(const float4*)(Ag + kt);
        As[lk+0][lm]=av.x; As[lk+1][lm]=av.y; As[lk+2][lm]=av.z; As[lk+3][lm]=av.w;
#pragma unroll
        for (int i = 0; i < 6; i++){
            int e = tid + i*256;             // 1536 = 96*16 elements
            int n = e >> 4, kq = e & 15;
            Ws[kq][n] = hw[(size_t)n*HWLD + p*DM + kt + kq];
        }
        __syncthreads();
#pragma unroll
        for (int k = 0; k < 16; k++){
            float4 a = *(const float4*)&As[k][ty*4];
            float av4[4] = {a.x, a.y, a.z, a.w};
#pragma unroll
            for (int j = 0; j < 6; j++){
                float wv = Ws[k][tx*6 + j];
#pragma unroll
                for (int i = 0; i < 4; i++) acc[i][j] += av4[i]*wv;
            }
        }
        __syncthreads();
    }
#pragma unroll
    for (int i = 0; i < 4; i++)
#pragma unroll
        for (int j = 0; j < 6; j++)
            g_headp[(size_t)(p*256 + mt*64 + ty*4 + i)*HPRED + tx*6 + j] = acc[i][j];
}

// ---------------- head reduction + de-normalization ----------------
__global__ void head_final(const float* __restrict__ hb, float* __restrict__ out){
    int idx = blockIdx.x*256 + threadIdx.x;  // 24576 = 256*96
    int bk = idx / HPRED, hh = idx % HPRED;
    float s = 0.f;
    for (int p = 0; p < PP; p++) s += g_headp[(size_t)p*(BB*KVAR*HPRED) + idx];
    s += hb[hh];
    int b = bk >> 4, k = bk & 15;
    out[b*(HPRED*KVAR) + hh*KVAR + k] = s * g_std[bk] + g_mean[bk];
}

// ---------------- launch ----------------
extern "C" void kernel_launch(void* const* d_in, const int* in_sizes, int n_in,
                              void* d_out, int out_size){
    const float* x        = (const float*)d_in[0];
    const float* patch_w  = (const float*)d_in[1];
    const float* patch_b  = (const float*)d_in[2];
    const float* pos      = (const float*)d_in[3];
    const float* vemb     = (const float*)d_in[4];
    const float* in_w     = (const float*)d_in[5];
    const float* xp_w     = (const float*)d_in[6];
    const float* dt_w     = (const float*)d_in[7];
    const float* dt_b     = (const float*)d_in[8];
    const float* A_log    = (const float*)d_in[9];
    const float* D_par    = (const float*)d_in[10];
    const float* out_w    = (const float*)d_in[11];
    const float* tmb_g    = (const float*)d_in[12];
    const float* tmb_b    = (const float*)d_in[13];
    const float* ffn_g    = (const float*)d_in[14];
    const float* ffn_b    = (const float*)d_in[15];
    const float* ffn_w1   = (const float*)d_in[16];
    const float* ffn_b1   = (const float*)d_in[17];
    const float* ffn_w2   = (const float*)d_in[18];
    const float* ffn_b2   = (const float*)d_in[19];
    const float* norm_g   = (const float*)d_in[20];
    const float* norm_b   = (const float*)d_in[21];
    const float* head_w   = (const float*)d_in[22];
    const float* head_b   = (const float*)d_in[23];
    float* out = (float*)d_out;

    // opt-in >48KB dynamic smem (idempotent host calls, capture-legal)
    cudaFuncSetAttribute(gemm_tc<EP_SPLIT>,    cudaFuncAttributeMaxDynamicSharedMemorySize, GT_SMEM);
    cudaFuncSetAttribute(gemm_tc<EP_RES>,      cudaFuncAttributeMaxDynamicSharedMemorySize, GT_SMEM);
    cudaFuncSetAttribute(gemm_tc<EP_GELU>,     cudaFuncAttributeMaxDynamicSharedMemorySize, GT_SMEM);
    cudaFuncSetAttribute(gemm_tc<EP_BIAS_RES>, cudaFuncAttributeMaxDynamicSharedMemorySize, GT_SMEM);

    float *z, *tmp, *hln, *u, *zgp, *xdbl, *y2, *hff;
    cudaGetSymbolAddress((void**)&z,    g_z);
    cudaGetSymbolAddress((void**)&tmp,  g_tmp);
    cudaGetSymbolAddress((void**)&hln,  g_hln);
    cudaGetSymbolAddress((void**)&u,    g_u);
    cudaGetSymbolAddress((void**)&zgp,  g_zg);
    cudaGetSymbolAddress((void**)&xdbl, g_xdbl);
    cudaGetSymbolAddress((void**)&y2,   g_y2);
    cudaGetSymbolAddress((void**)&hff,  g_hff);

    stats_kernel<<<BB*KVAR, 256>>>(x);
    embed_kernel<<<TT, 128>>>(x, patch_w, patch_b, pos, vemb);

    const int MT  = TT/128;   // 126 M tiles (128-row)
    const int MT32= TT/32;    // 504 M tiles (32-row)

    for (int l = 0; l < NLAY; l++){
        const float* Wi  = in_w  + (size_t)l*(2*DIN)*DM;
        const float* Wx  = xp_w  + (size_t)l*64*DIN;
        const float* Wdt = dt_w  + (size_t)l*DIN*RNK;
        const float* bdt = dt_b  + (size_t)l*DIN;
        const float* Al  = A_log + (size_t)l*DIN*NST;
        const float* Dl  = D_par + (size_t)l*DIN;
        const float* Wo  = out_w + (size_t)l*DM*DIN;
        const float* W1  = ffn_w1+ (size_t)l*DFF*DM;
        const float* B1  = ffn_b1+ (size_t)l*DFF;
        const float* W2  = ffn_w2+ (size_t)l*DM*DFF;
        const float* B2  = ffn_b2+ (size_t)l*DM;

        // in_proj -> silu(u), zg   (N=2048, K=512)
        gemm_tc<EP_SPLIT><<<dim3(16, MT), 256, GT_SMEM>>>(z, DM, Wi, DM, u, zgp, 0, nullptr, nullptr);
        // x_proj: xdbl = u @ Wx^T   (N=64, K=1024) — streaming 32-row tiles
        gemm_tc32<EP_NONE><<<dim3(1, MT32), 128>>>(u, DIN, Wx, DIN, xdbl, nullptr, 64, nullptr, nullptr);
        // selective scan (fused dt_proj+softplus, +u*D, *silu(zg))
        scan_kernel<<<128, 256>>>(u, zgp, xdbl, Wdt, bdt, Al, Dl, y2);
        // out_proj + residual into tmp  (N=512, K=1024)
        gemm_tc<EP_RES><<<dim3(4, MT), 256, GT_SMEM>>>(y2, DIN, Wo, DIN, tmp, nullptr, DM, nullptr, z);
        // LN(tmp)->z ; LN(z)->hln (ffn pre-norm)
        ln_kernel<true><<<TT/8, 256>>>(tmp, tmb_g + l*DM, tmb_b + l*DM, z,
                                       ffn_g + l*DM, ffn_b + l*DM, hln);
        // FFN
        gemm_tc<EP_GELU><<<dim3(16, MT), 256, GT_SMEM>>>(hln, DM, W1, DM, hff, nullptr, DFF, B1, nullptr);
        gemm_tc<EP_BIAS_RES><<<dim3(4, MT), 256, GT_SMEM>>>(hff, DFF, W2, DFF, z, nullptr, DM, B2, z);
    }

    // final LN -> tmp
    ln_kernel<false><<<TT/8, 256>>>(z, norm_g, norm_b, tmp, nullptr, nullptr, nullptr);
    // head
    head_partial<<<dim3(PP, 4), 256>>>(tmp, head_w);
    head_final<<<96, 256>>>(head_b, out);
    (void)in_sizes; (void)n_in; (void)out_size;
}

// round 6
// speedup vs baseline: 1.3277x; 1.3223x over previous
#include <cuda_runtime.h>
#include <cuda_fp16.h>
#include <math.h>

// ---------------- problem constants ----------------
#define BB     16
#define LCTX   512
#define KVAR   16
#define HPRED  96
#define DM     512
#define NST    16
#define NLAY   3
#define DFF    2048
#define PATCH  16
#define STRIDEP 8
#define PP     63            // (512-16)/8+1
#define DIN    1024          // 2*DM
#define RNK    32            // DT_RANK
#define SEQ    (KVAR*PP)     // 1008 tokens per batch
#define TT     (BB*SEQ)      // 16128 total tokens
#define EPSF   1e-5f
#define HWLD   (PP*DM)       // 32256 head_w row length

// ---------------- scratch ----------------
__device__ float g_mean[BB*KVAR];
__device__ float g_std[BB*KVAR];
__device__ float g_z   [TT*DM];
__device__ float g_tmp [TT*DM];
__device__ float g_u   [TT*DIN + DIN];
__device__ float g_zg  [TT*DIN + DIN];
__device__ float g_xdbl[TT*64 + 64];
__device__ float g_headp[PP*BB*KVAR*HPRED];
// fp16 activation copies
__device__ __half g_zh  [TT*DM];
__device__ __half g_uh  [TT*DIN];
__device__ __half g_y2h [TT*DIN];
__device__ __half g_hlnh[TT*DM];
__device__ __half g_hffh[TT*DFF];
// fp16 weights (all layers)
__device__ __half h_inw[3*2048*512];
__device__ __half h_xpw[3*64*1024];
__device__ __half h_ow [3*512*1024];
__device__ __half h_w1 [3*2048*512];
__device__ __half h_w2 [3*512*2048];

// ---------------- helpers ----------------
__device__ __forceinline__ float siluf(float x){ return x / (1.f + __expf(-x)); }
__device__ __forceinline__ float geluf(float x){
    return 0.5f * x * (1.f + erff(x * 0.70710678118654752f));
}

__device__ __forceinline__ void cp16(void* smem, const void* g){
    unsigned a = (unsigned)__cvta_generic_to_shared(smem);
    asm volatile("cp.async.cg.shared.global [%0], [%1], 16;" :: "r"(a), "l"(g));
}
__device__ __forceinline__ void cp_commit(){ asm volatile("cp.async.commit_group;"); }

__device__ __forceinline__ void mma_f16(float* c, const unsigned* a, const unsigned* b){
    asm volatile("mma.sync.aligned.m16n8k16.row.col.f32.f16.f16.f32 "
        "{%0,%1,%2,%3}, {%4,%5,%6,%7}, {%8,%9}, {%0,%1,%2,%3};"
        : "+f"(c[0]),"+f"(c[1]),"+f"(c[2]),"+f"(c[3])
        : "r"(a[0]),"r"(a[1]),"r"(a[2]),"r"(a[3]), "r"(b[0]),"r"(b[1]));
}

// ---------------- fp32 -> fp16 conversion ----------------
__global__ void f2h_kernel(const float* __restrict__ in, __half2* __restrict__ out, int n2){
    int i = blockIdx.x*256 + threadIdx.x;
    if (i < n2){
        float2 v = ((const float2*)in)[i];
        out[i] = __floats2half2_rn(v.x, v.y);
    }
}

// ---------------- per-(b,k) mean/std over L ----------------
__global__ void stats_kernel(const float* __restrict__ x){
    int bk = blockIdx.x; int b = bk >> 4, k = bk & 15;
    int tid = threadIdx.x;
    float s = 0.f, q = 0.f;
    for (int l = tid; l < LCTX; l += 256){
        float v = x[(b*LCTX + l)*KVAR + k];
        s += v; q += v*v;
    }
    __shared__ float sh[64];
#pragma unroll
    for (int o = 16; o; o >>= 1){
        s += __shfl_xor_sync(~0u, s, o);
        q += __shfl_xor_sync(~0u, q, o);
    }
    int w = tid >> 5;
    if ((tid & 31) == 0){ sh[w] = s; sh[w+32] = q; }
    __syncthreads();
    if (tid == 0){
        float S = 0.f, Q = 0.f;
        for (int i = 0; i < 8; i++){ S += sh[i]; Q += sh[32+i]; }
        float mu  = S * (1.f/LCTX);
        float var = Q * (1.f/LCTX) - mu*mu;
        g_mean[bk] = mu;
        g_std[bk]  = sqrtf(var + EPSF);
    }
}

// ---------------- patch embedding + pos + var embed ----------------
__global__ void embed_kernel(const float* __restrict__ x,
                             const float* __restrict__ pw,
                             const float* __restrict__ pb,
                             const float* __restrict__ pos,
                             const float* __restrict__ vemb){
    int row = blockIdx.x;                    // token row in [0,TT)
    int b = row / SEQ, rem = row % SEQ;
    int p = rem >> 4, k = rem & 15;
    int bk = b*KVAR + k;
    __shared__ float xs[PATCH];
    int tid = threadIdx.x;                   // 128
    if (tid < PATCH){
        float v = x[(b*LCTX + p*STRIDEP + tid)*KVAR + k];
        xs[tid] = (v - g_mean[bk]) / g_std[bk];
    }
    __syncthreads();
#pragma unroll
    for (int j = 0; j < 4; j++){
        int d = tid + j*128;
        float acc = pb[d] + pos[p*DM + d] + vemb[k*DM + d];
        const float4* w4 = (const float4*)(pw + d*PATCH);
#pragma unroll
        for (int t4 = 0; t4 < 4; t4++){
            float4 w = w4[t4];
            acc += xs[t4*4+0]*w.x + xs[t4*4+1]*w.y + xs[t4*4+2]*w.z + xs[t4*4+3]*w.w;
        }
        g_z[row*DM + d] = acc;
        g_zh[row*DM + d] = __float2half(acc);
    }
}

// ---------------- epilogue modes ----------------
enum { EP_NONE=0, EP_SPLIT=1, EP_GELU=3, EP_BIAS_RES=4, EP_RES=5 };

template<int EP>
__device__ __forceinline__ void ep_store(float* __restrict__ out0, float* __restrict__ out1,
                                         __half* __restrict__ outh, int ldo,
                                         const float* __restrict__ bias,
                                         const float* __restrict__ res,
                                         int row, int col, float v0, float v1){
    if (EP == EP_NONE){
        out0[(size_t)row*ldo + col    ] = v0;
        out0[(size_t)row*ldo + col + 1] = v1;
    } else if (EP == EP_SPLIT){
        if (col < DIN){
            float s0 = siluf(v0), s1 = siluf(v1);
            out0[(size_t)row*DIN + col    ] = s0;
            out0[(size_t)row*DIN + col + 1] = s1;
            *(__half2*)&outh[(size_t)row*DIN + col] = __floats2half2_rn(s0, s1);
        } else {
            out1[(size_t)row*DIN + col - DIN    ] = v0;
            out1[(size_t)row*DIN + col - DIN + 1] = v1;
        }
    } else if (EP == EP_GELU){
        float g0 = geluf(v0 + bias[col]);
        float g1 = geluf(v1 + bias[col+1]);
        *(__half2*)&outh[(size_t)row*ldo + col] = __floats2half2_rn(g0, g1);
    } else if (EP == EP_BIAS_RES){
        float f0 = v0 + bias[col]   + res[(size_t)row*ldo + col];
        float f1 = v1 + bias[col+1] + res[(size_t)row*ldo + col + 1];
        out0[(size_t)row*ldo + col    ] = f0;
        out0[(size_t)row*ldo + col + 1] = f1;
        *(__half2*)&outh[(size_t)row*ldo + col] = __floats2half2_rn(f0, f1);
    } else { // EP_RES
        out0[(size_t)row*ldo + col    ] = v0 + res[(size_t)row*ldo + col];
        out0[(size_t)row*ldo + col + 1] = v1 + res[(size_t)row*ldo + col + 1];
    }
}

// ---------------- fp16 NT GEMM, 128x128 block, BK=32, 5-stage cp.async ---
// 8 warps as 2(M) x 4(N), warp tile 64x32.
#define GH_PITCH 40                  // halfs per smem row (80 B; 16B-aligned, bank-clean)
#define GH_STG   (128*GH_PITCH)      // 5120 halfs per stage per operand
#define GH_BOFF  (5*GH_STG)          // 25600 halfs
#define GH_SMEM  (2*5*GH_STG*2)      // 102400 bytes

template<int EP>
__global__ void __launch_bounds__(256) gemm_h(const __half* __restrict__ A, int lda,
                        const __half* __restrict__ W, int Kd,
                        float* __restrict__ out0, float* __restrict__ out1,
                        __half* __restrict__ outh, int ldo,
                        const float* __restrict__ bias, const float* __restrict__ res){
    extern __shared__ __half smh[];
    int tid = threadIdx.x;
    int nt = blockIdx.x, mt = blockIdx.y;
    int lane = tid & 31, wid = tid >> 5;
    int warpM = wid & 1, warpN = wid >> 1;      // 2 x 4
    int grp = lane >> 2, tig = lane & 3;

    const __half* Abase = A + (size_t)(mt*128)*lda;
    const __half* Wbase = W + (size_t)(nt*128)*Kd;

    int r  = tid >> 2;              // 0..63
    int kk = (tid & 3) * 8;         // half offset, 16B steps

    float acc[4][4][4];
#pragma unroll
    for (int i = 0; i < 4; i++)
#pragma unroll
        for (int j = 0; j < 4; j++)
#pragma unroll
            for (int h = 0; h < 4; h++) acc[i][j][h] = 0.f;

    int nK = Kd >> 5;

    auto issue = [&](int stage){
        int buf = stage % 5;
        int ko = stage * 32;
        cp16(&smh[buf*GH_STG + r*GH_PITCH + kk],               Abase + (size_t)r*lda      + ko + kk);
        cp16(&smh[buf*GH_STG + (r+64)*GH_PITCH + kk],          Abase + (size_t)(r+64)*lda + ko + kk);
        cp16(&smh[GH_BOFF + buf*GH_STG + r*GH_PITCH + kk],     Wbase + (size_t)r*Kd       + ko + kk);
        cp16(&smh[GH_BOFF + buf*GH_STG + (r+64)*GH_PITCH + kk],Wbase + (size_t)(r+64)*Kd  + ko + kk);
        cp_commit();
    };

#pragma unroll
    for (int s = 0; s < 4; s++){
        if (s < nK) issue(s); else cp_commit();
    }

    for (int kt = 0; kt < nK; kt++){
        asm volatile("cp.async.wait_group 3;");
        __syncthreads();
        if (kt + 4 < nK) issue(kt + 4); else cp_commit();

        const __half* Abuf = &smh[(kt % 5)*GH_STG];
        const __half* Bbuf = &smh[GH_BOFF + (kt % 5)*GH_STG];
#pragma unroll
        for (int k0 = 0; k0 < 32; k0 += 16){
            unsigned a[4][4], b[4][2];
#pragma unroll
            for (int i = 0; i < 4; i++){
                int row = warpM*64 + i*16;
                a[i][0] = *(const unsigned*)&Abuf[(row+grp  )*GH_PITCH + k0 +     2*tig];
                a[i][1] = *(const unsigned*)&Abuf[(row+grp+8)*GH_PITCH + k0 +     2*tig];
                a[i][2] = *(const unsigned*)&Abuf[(row+grp  )*GH_PITCH + k0 + 8 + 2*tig];
                a[i][3] = *(const unsigned*)&Abuf[(row+grp+8)*GH_PITCH + k0 + 8 + 2*tig];
            }
#pragma unroll
            for (int j = 0; j < 4; j++){
                int n = warpN*32 + j*8;
                b[j][0] = *(const unsigned*)&Bbuf[(n+grp)*GH_PITCH + k0 +     2*tig];
                b[j][1] = *(const unsigned*)&Bbuf[(n+grp)*GH_PITCH + k0 + 8 + 2*tig];
            }
#pragma unroll
            for (int i = 0; i < 4; i++)
#pragma unroll
                for (int j = 0; j < 4; j++)
                    mma_f16(acc[i][j], a[i], b[j]);
        }
    }

#pragma unroll
    for (int i = 0; i < 4; i++){
#pragma unroll
        for (int j = 0; j < 4; j++){
            int col = nt*128 + warpN*32 + j*8 + 2*tig;
#pragma unroll
            for (int h = 0; h < 2; h++){
                int row = mt*128 + warpM*64 + i*16 + grp + h*8;
                ep_store<EP>(out0, out1, outh, ldo, bias, res, row, col,
                             acc[i][j][h*2+0], acc[i][j][h*2+1]);
            }
        }
    }
}

// ---------------- fp16 NT GEMM, 32x64 block, BK=32, 6-stage (x_proj) -----
template<int EP>
__global__ void __launch_bounds__(128) gemm_h32(const __half* __restrict__ A, int lda,
                        const __half* __restrict__ W, int Kd,
                        float* __restrict__ out0, float* __restrict__ out1,
                        __half* __restrict__ outh, int ldo,
                        const float* __restrict__ bias, const float* __restrict__ res){
    __shared__ __align__(16) __half As[6][32*GH_PITCH];
    __shared__ __align__(16) __half Bs[6][64*GH_PITCH];
    int tid = threadIdx.x;
    int nt = blockIdx.x, mt = blockIdx.y;
    int lane = tid & 31, wid = tid >> 5;        // wid = warpN (0..3)
    int grp = lane >> 2, tig = lane & 3;

    const __half* Abase = A + (size_t)(mt*32)*lda;
    const __half* Wbase = W + (size_t)(nt*64)*Kd;

    int r  = tid >> 2;              // 0..31
    int kk = (tid & 3) * 8;

    float acc[2][2][4];
#pragma unroll
    for (int i = 0; i < 2; i++)
#pragma unroll
        for (int j = 0; j < 2; j++)
#pragma unroll
            for (int h = 0; h < 4; h++) acc[i][j][h] = 0.f;

    int nK = Kd >> 5;

    auto issue = [&](int stage){
        int buf = stage % 6;
        int ko = stage * 32;
        cp16(&As[buf][r*GH_PITCH + kk],        Abase + (size_t)r*lda       + ko + kk);
        cp16(&Bs[buf][r*GH_PITCH + kk],        Wbase + (size_t)r*Kd        + ko + kk);
        cp16(&Bs[buf][(r+32)*GH_PITCH + kk],   Wbase + (size_t)(r+32)*Kd   + ko + kk);
        cp_commit();
    };

#pragma unroll
    for (int s = 0; s < 5; s++){
        if (s < nK) issue(s); else cp_commit();
    }

    for (int kt = 0; kt < nK; kt++){
        asm volatile("cp.async.wait_group 4;");
        __syncthreads();
        if (kt + 5 < nK) issue(kt + 5); else cp_commit();
        const __half* Abuf = As[kt % 6];
        const __half* Bbuf = Bs[kt % 6];
#pragma unroll
        for (int k0 = 0; k0 < 32; k0 += 16){
            unsigned a[2][4], b[2][2];
#pragma unroll
            for (int i = 0; i < 2; i++){
                int row = i*16;
                a[i][0] = *(const unsigned*)&Abuf[(row+grp  )*GH_PITCH + k0 +     2*tig];
                a[i][1] = *(const unsigned*)&Abuf[(row+grp+8)*GH_PITCH + k0 +     2*tig];
                a[i][2] = *(const unsigned*)&Abuf[(row+grp  )*GH_PITCH + k0 + 8 + 2*tig];
                a[i][3] = *(const unsigned*)&Abuf[(row+grp+8)*GH_PITCH + k0 + 8 + 2*tig];
            }
#pragma unroll
            for (int j = 0; j < 2; j++){
                int n = wid*16 + j*8;
                b[j][0] = *(const unsigned*)&Bbuf[(n+grp)*GH_PITCH + k0 +     2*tig];
                b[j][1] = *(const unsigned*)&Bbuf[(n+grp)*GH_PITCH + k0 + 8 + 2*tig];
            }
#pragma unroll
            for (int i = 0; i < 2; i++)
#pragma unroll
                for (int j = 0; j < 2; j++)
                    mma_f16(acc[i][j], a[i], b[j]);
        }
    }

#pragma unroll
    for (int i = 0; i < 2; i++){
#pragma unroll
        for (int j = 0; j < 2; j++){
            int col = nt*64 + wid*16 + j*8 + 2*tig;
#pragma unroll
            for (int h = 0; h < 2; h++){
                int row = mt*32 + i*16 + grp + h*8;
                ep_store<EP>(out0, out1, outh, ldo, bias, res, row, col,
                             acc[i][j][h*2+0], acc[i][j][h*2+1]);
            }
        }
    }
}

// ---------------- layer norm; optional 2nd LN to fp16 ----------------
template<bool DOUBLE>
__global__ void ln_kernel(const float* __restrict__ in,
                          const float* __restrict__ g1, const float* __restrict__ b1,
                          float* __restrict__ o1,
                          const float* __restrict__ g2, const float* __restrict__ b2,
                          __half* __restrict__ o2h){
    int w = threadIdx.x >> 5, lane = threadIdx.x & 31;
    int row = blockIdx.x*8 + w;
    const float4* in4 = (const float4*)(in + (size_t)row*DM);
    float4 v[4];
    float s = 0.f, q = 0.f;
#pragma unroll
    for (int i = 0; i < 4; i++){
        v[i] = in4[lane + 32*i];
        s += v[i].x + v[i].y + v[i].z + v[i].w;
        q += v[i].x*v[i].x + v[i].y*v[i].y + v[i].z*v[i].z + v[i].w*v[i].w;
    }
#pragma unroll
    for (int o = 16; o; o >>= 1){
        s += __shfl_xor_sync(~0u, s, o);
        q += __shfl_xor_sync(~0u, q, o);
    }
    float mu = s * (1.f/DM);
    float rs = rsqrtf(q*(1.f/DM) - mu*mu + EPSF);
    float4 zz[4];
    float s2 = 0.f, q2 = 0.f;
#pragma unroll
    for (int i = 0; i < 4; i++){
        float4 gg = ((const float4*)g1)[lane + 32*i];
        float4 bb = ((const float4*)b1)[lane + 32*i];
        zz[i].x = (v[i].x - mu)*rs*gg.x + bb.x;
        zz[i].y = (v[i].y - mu)*rs*gg.y + bb.y;
        zz[i].z = (v[i].z - mu)*rs*gg.z + bb.z;
        zz[i].w = (v[i].w - mu)*rs*gg.w + bb.w;
        if (DOUBLE){
            s2 += zz[i].x + zz[i].y + zz[i].z + zz[i].w;
            q2 += zz[i].x*zz[i].x + zz[i].y*zz[i].y + zz[i].z*zz[i].z + zz[i].w*zz[i].w;
        }
        ((float4*)(o1 + (size_t)row*DM))[lane + 32*i] = zz[i];
    }
    if (DOUBLE){
#pragma unroll
        for (int o = 16; o; o >>= 1){
            s2 += __shfl_xor_sync(~0u, s2, o);
            q2 += __shfl_xor_sync(~0u, q2, o);
        }
        float mu2 = s2 * (1.f/DM);
        float rs2 = rsqrtf(q2*(1.f/DM) - mu2*mu2 + EPSF);
        __half2* oo = (__half2*)(o2h + (size_t)row*DM);
#pragma unroll
        for (int i = 0; i < 4; i++){
            float4 gg = ((const float4*)g2)[lane + 32*i];
            float4 bb = ((const float4*)b2)[lane + 32*i];
            float o0 = (zz[i].x - mu2)*rs2*gg.x + bb.x;
            float o1v= (zz[i].y - mu2)*rs2*gg.y + bb.y;
            float o2v= (zz[i].z - mu2)*rs2*gg.z + bb.z;
            float o3 = (zz[i].w - mu2)*rs2*gg.w + bb.w;
            oo[2*(lane + 32*i)    ] = __floats2half2_rn(o0, o1v);
            oo[2*(lane + 32*i) + 1] = __floats2half2_rn(o2v, o3);
        }
    }
}

// ---------------- selective scan with fused dt_proj + softplus ----------
__global__ void scan_kernel(const float* __restrict__ u,
                            const float* __restrict__ zg,
                            const float* __restrict__ xdbl,
                            const float* __restrict__ Wdt,
                            const float* __restrict__ bdt,
                            const float* __restrict__ A_log,
                            const float* __restrict__ Dp,
                            __half* __restrict__ y2h){
    int blk = blockIdx.x;                    // 128 blocks
    int b = blk >> 3, dblk = blk & 7;
    int t = threadIdx.x;                     // 256
    int ph = t & 1;
    int d = dblk*128 + (t >> 1);
    int nb = ph * 8;

    float Aa[8];
#pragma unroll
    for (int j = 0; j < 8; j++) Aa[j] = -expf(A_log[d*NST + nb + j]);
    float A0 = Aa[0];
    float stepA = Aa[1] - Aa[0];
    bool prog = true;
#pragma unroll
    for (int j = 0; j < 8; j++){
        float e = A0 + (float)j * stepA;
        if (fabsf(Aa[j] - e) > 1e-5f*fabsf(e) + 1e-7f) prog = false;
    }
    float Dd = Dp[d];
    float bd = bdt[d];

    float wdt[16];
#pragma unroll
    for (int j = 0; j < 16; j++) wdt[j] = Wdt[d*RNK + ph*16 + j];

    float h[8];
#pragma unroll
    for (int j = 0; j < 8; j++) h[j] = 0.f;

    size_t base = (size_t)(b*SEQ)*DIN + d;
    const float* xr = xdbl + (size_t)(b*SEQ)*64;

    auto calc_delta = [&](const float4& T0, const float4& T1,
                          const float4& T2, const float4& T3) -> float {
        float a0 = T0.x*wdt[0]  + T0.y*wdt[1]  + T0.z*wdt[2]  + T0.w*wdt[3];
        float a1 = T1.x*wdt[4]  + T1.y*wdt[5]  + T1.z*wdt[6]  + T1.w*wdt[7];
        float a2 = T2.x*wdt[8]  + T2.y*wdt[9]  + T2.z*wdt[10] + T2.w*wdt[11];
        float a3 = T3.x*wdt[12] + T3.y*wdt[13] + T3.z*wdt[14] + T3.w*wdt[15];
        float p = (a0 + a1) + (a2 + a3);
        p += __shfl_xor_sync(~0u, p, 1);
        float xv = p + bd;
        return fmaxf(xv, 0.f) + __logf(1.f + __expf(-fabsf(xv)));
    };

    float uv = u[base], zv = zg[base];
    const float* dtp = xr + ph*16;
    float4 T0 = *(const float4*)(dtp), T1 = *(const float4*)(dtp+4);
    float4 T2 = *(const float4*)(dtp+8), T3 = *(const float4*)(dtp+12);
    float4 B0 = *(const float4*)(xr + 32 + nb);
    float4 B1 = *(const float4*)(xr + 36 + nb);
    float4 C0 = *(const float4*)(xr + 48 + nb);
    float4 C1 = *(const float4*)(xr + 52 + nb);
    float dv = calc_delta(T0, T1, T2, T3);

    for (int s = 0; s < SEQ; s++){
        size_t baseN = base + DIN;
        const float* xrN = xr + 64;
        float uvN = u[baseN], zvN = zg[baseN];
        const float* dtpN = xrN + ph*16;
        float4 TN0 = *(const float4*)(dtpN),   TN1 = *(const float4*)(dtpN+4);
        float4 TN2 = *(const float4*)(dtpN+8), TN3 = *(const float4*)(dtpN+12);
        float4 B0N = *(const float4*)(xrN + 32 + nb);
        float4 B1N = *(const float4*)(xrN + 36 + nb);
        float4 C0N = *(const float4*)(xrN + 48 + nb);
        float4 C1N = *(const float4*)(xrN + 52 + nb);

        float du = dv * uv;
        float y = 0.f;
        if (prog){
            float e = __expf(dv * A0);
            float rr = __expf(dv * stepA);
            h[0] = h[0]*e + du*B0.x; y += h[0]*C0.x; e *= rr;
            h[1] = h[1]*e + du*B0.y; y += h[1]*C0.y; e *= rr;
            h[2] = h[2]*e + du*B0.z; y += h[2]*C0.z; e *= rr;
            h[3] = h[3]*e + du*B0.w; y += h[3]*C0.w; e *= rr;
            h[4] = h[4]*e + du*B1.x; y += h[4]*C1.x; e *= rr;
            h[5] = h[5]*e + du*B1.y; y += h[5]*C1.y; e *= rr;
            h[6] = h[6]*e + du*B1.z; y += h[6]*C1.z; e *= rr;
            h[7] = h[7]*e + du*B1.w; y += h[7]*C1.w;
        } else {
            float Bv[8] = {B0.x,B0.y,B0.z,B0.w,B1.x,B1.y,B1.z,B1.w};
            float Cv[8] = {C0.x,C0.y,C0.z,C0.w,C1.x,C1.y,C1.z,C1.w};
#pragma unroll
            for (int j = 0; j < 8; j++){
                float e = __expf(dv * Aa[j]);
                h[j] = h[j]*e + du*Bv[j];
                y += h[j]*Cv[j];
            }
        }
        float ysum = y + __shfl_xor_sync(~0u, y, 1);
        if (!ph){
            y2h[base] = __float2half((ysum + uv*Dd) * siluf(zv));
        }
        dv = calc_delta(TN0, TN1, TN2, TN3);
        base = baseN; xr = xrN;
        uv = uvN; zv = zvN;
        B0 = B0N; B1 = B1N; C0 = C0N; C1 = C1N;
    }
}

// ---------------- head: partial GEMM per patch index p ----------------
__global__ void head_partial(const float* __restrict__ zf, const float* __restrict__ hw){
    int p = blockIdx.x, mt = blockIdx.y;     // p in [0,63), mt in [0,4)
    __shared__ float As[16][64];
    __shared__ float Ws[16][96];
    int tid = threadIdx.x;                   // 256
    int lm = tid >> 2, lk = (tid & 3) * 4;
    int bkrow = mt*64 + lm;
    int b = bkrow >> 4, kk = bkrow & 15;
    const float* Ag = zf + (size_t)(b*SEQ + p*KVAR + kk)*DM + lk;
    int tx = tid & 15, ty = tid >> 4;
    float acc[4][6];
#pragma unroll
    for (int i = 0; i < 4; i++)
#pragma unroll
        for (int j = 0; j < 6; j++) acc[i][j] = 0.f;

    for (int kt = 0; kt < DM; kt += 16){
        float4 av = *(const float4*)(Ag + kt);
        As[lk+0][lm]=av.x; As[lk+1][lm]=av.y; As[lk+2][lm]=av.z; As[lk+3][lm]=av.w;
#pragma unroll
        for (int i = 0; i < 6; i++){
            int e = tid + i*256;             // 1536 = 96*16 elements
            int n = e >> 4, kq = e & 15;
            Ws[kq][n] = hw[(size_t)n*HWLD + p*DM + kt + kq];
        }
        __syncthreads();
#pragma unroll
        for (int k = 0; k < 16; k++){
            float4 a = *(const float4*)&As[k][ty*4];
            float av4[4] = {a.x, a.y, a.z, a.w};
#pragma unroll
            for (int j = 0; j < 6; j++){
                float wv = Ws[k][tx*6 + j];
#pragma unroll
                for (int i = 0; i < 4; i++) acc[i][j] += av4[i]*wv;
            }
        }
        __syncthreads();
    }
#pragma unroll
    for (int i = 0; i < 4; i++)
#pragma unroll
        for (int j = 0; j < 6; j++)
            g_headp[(size_t)(p*256 + mt*64 + ty*4 + i)*HPRED + tx*6 + j] = acc[i][j];
}

// ---------------- head reduction + de-normalization ----------------
__global__ void head_final(const float* __restrict__ hb, float* __restrict__ out){
    int idx = blockIdx.x*256 + threadIdx.x;  // 24576 = 256*96
    int bk = idx / HPRED, hh = idx % HPRED;
    float s = 0.f;
    for (int p = 0; p < PP; p++) s += g_headp[(size_t)p*(BB*KVAR*HPRED) + idx];
    s += hb[hh];
    int b = bk >> 4, k = bk & 15;
    out[b*(HPRED*KVAR) + hh*KVAR + k] = s * g_std[bk] + g_mean[bk];
}

// ---------------- launch ----------------
extern "C" void kernel_launch(void* const* d_in, const int* in_sizes, int n_in,
                              void* d_out, int out_size){
    const float* x        = (const float*)d_in[0];
    const float* patch_w  = (const float*)d_in[1];
    const float* patch_b  = (const float*)d_in[2];
    const float* pos      = (const float*)d_in[3];
    const float* vemb     = (const float*)d_in[4];
    const float* in_w     = (const float*)d_in[5];
    const float* xp_w     = (const float*)d_in[6];
    const float* dt_w     = (const float*)d_in[7];
    const float* dt_b     = (const float*)d_in[8];
    const float* A_log    = (const float*)d_in[9];
    const float* D_par    = (const float*)d_in[10];
    const float* out_w    = (const float*)d_in[11];
    const float* tmb_g    = (const float*)d_in[12];
    const float* tmb_b    = (const float*)d_in[13];
    const float* ffn_g    = (const float*)d_in[14];
    const float* ffn_b    = (const float*)d_in[15];
    const float* ffn_w1   = (const float*)d_in[16];
    const float* ffn_b1   = (const float*)d_in[17];
    const float* ffn_w2   = (const float*)d_in[18];
    const float* ffn_b2   = (const float*)d_in[19];
    const float* norm_g   = (const float*)d_in[20];
    const float* norm_b   = (const float*)d_in[21];
    const float* head_w   = (const float*)d_in[22];
    const float* head_b   = (const float*)d_in[23];
    float* out = (float*)d_out;

    cudaFuncSetAttribute(gemm_h<EP_SPLIT>,    cudaFuncAttributeMaxDynamicSharedMemorySize, GH_SMEM);
    cudaFuncSetAttribute(gemm_h<EP_RES>,      cudaFuncAttributeMaxDynamicSharedMemorySize, GH_SMEM);
    cudaFuncSetAttribute(gemm_h<EP_GELU>,     cudaFuncAttributeMaxDynamicSharedMemorySize, GH_SMEM);
    cudaFuncSetAttribute(gemm_h<EP_BIAS_RES>, cudaFuncAttributeMaxDynamicSharedMemorySize, GH_SMEM);

    float *z, *tmp, *u, *zgp, *xdbl;
    __half *zh, *uh, *y2h, *hlnh, *hffh;
    __half *winh, *wxph, *woh, *w1h, *w2h;
    cudaGetSymbolAddress((void**)&z,    g_z);
    cudaGetSymbolAddress((void**)&tmp,  g_tmp);
    cudaGetSymbolAddress((void**)&u,    g_u);
    cudaGetSymbolAddress((void**)&zgp,  g_zg);
    cudaGetSymbolAddress((void**)&xdbl, g_xdbl);
    cudaGetSymbolAddress((void**)&zh,   g_zh);
    cudaGetSymbolAddress((void**)&uh,   g_uh);
    cudaGetSymbolAddress((void**)&y2h,  g_y2h);
    cudaGetSymbolAddress((void**)&hlnh, g_hlnh);
    cudaGetSymbolAddress((void**)&hffh, g_hffh);
    cudaGetSymbolAddress((void**)&winh, h_inw);
    cudaGetSymbolAddress((void**)&wxph, h_xpw);
    cudaGetSymbolAddress((void**)&woh,  h_ow);
    cudaGetSymbolAddress((void**)&w1h,  h_w1);
    cudaGetSymbolAddress((void**)&w2h,  h_w2);

    // weight conversions (fp32 -> fp16), all layers at once
    f2h_kernel<<<(3*2048*512/2 + 255)/256, 256>>>(in_w,  (__half2*)winh, 3*2048*512/2);
    f2h_kernel<<<(3*64*1024/2  + 255)/256, 256>>>(xp_w,  (__half2*)wxph, 3*64*1024/2);
    f2h_kernel<<<(3*512*1024/2 + 255)/256, 256>>>(out_w, (__half2*)woh,  3*512*1024/2);
    f2h_kernel<<<(3*2048*512/2 + 255)/256, 256>>>(ffn_w1,(__half2*)w1h,  3*2048*512/2);
    f2h_kernel<<<(3*512*2048/2 + 255)/256, 256>>>(ffn_w2,(__half2*)w2h,  3*512*2048/2);

    stats_kernel<<<BB*KVAR, 256>>>(x);
    embed_kernel<<<TT, 128>>>(x, patch_w, patch_b, pos, vemb);

    const int MT  = TT/128;   // 126 M tiles (128-row)
    const int MT32= TT/32;    // 504 M tiles (32-row)

    for (int l = 0; l < NLAY; l++){
        const __half* Wi  = winh + (size_t)l*(2*DIN)*DM;
        const __half* Wx  = wxph + (size_t)l*64*DIN;
        const float*  Wdt = dt_w + (size_t)l*DIN*RNK;
        const float*  bdt = dt_b + (size_t)l*DIN;
        const float*  Al  = A_log+ (size_t)l*DIN*NST;
        const float*  Dl  = D_par+ (size_t)l*DIN;
        const __half* Wo  = woh  + (size_t)l*DM*DIN;
        const __half* W1  = w1h  + (size_t)l*DFF*DM;
        const float*  B1  = ffn_b1 + (size_t)l*DFF;
        const __half* W2  = w2h  + (size_t)l*DM*DFF;
        const float*  B2  = ffn_b2 + (size_t)l*DM;

        // in_proj -> silu(u) fp32+fp16, zg fp32   (N=2048, K=512)
        gemm_h<EP_SPLIT><<<dim3(16, MT), 256, GH_SMEM>>>(zh, DM, Wi, DM, u, zgp, uh, 0, nullptr, nullptr);
        // x_proj: xdbl = u @ Wx^T   (N=64, K=1024)
        gemm_h32<EP_NONE><<<dim3(1, MT32), 128>>>(uh, DIN, Wx, DIN, xdbl, nullptr, nullptr, 64, nullptr, nullptr);
        // selective scan (fused dt_proj+softplus, +u*D, *silu(zg)) -> y2h fp16
        scan_kernel<<<128, 256>>>(u, zgp, xdbl, Wdt, bdt, Al, Dl, y2h);
        // out_proj + residual into tmp  (N=512, K=1024)
        gemm_h<EP_RES><<<dim3(4, MT), 256, GH_SMEM>>>(y2h, DIN, Wo, DIN, tmp, nullptr, nullptr, DM, nullptr, z);
        // LN(tmp)->z fp32 ; LN(z)->hln fp16 (ffn pre-norm)
        ln_kernel<true><<<TT/8, 256>>>(tmp, tmb_g + l*DM, tmb_b + l*DM, z,
                                       ffn_g + l*DM, ffn_b + l*DM, hlnh);
        // FFN
        gemm_h<EP_GELU><<<dim3(16, MT), 256, GH_SMEM>>>(hlnh, DM, W1, DM, nullptr, nullptr, hffh, DFF, B1, nullptr);
        gemm_h<EP_BIAS_RES><<<dim3(4, MT), 256, GH_SMEM>>>(hffh, DFF, W2, DFF, z, nullptr, zh, DM, B2, z);
    }

    // final LN -> tmp
    ln_kernel<false><<<TT/8, 256>>>(z, norm_g, norm_b, tmp, nullptr, nullptr, nullptr);
    // head
    head_partial<<<dim3(PP, 4), 256>>>(tmp, head_w);
    head_final<<<96, 256>>>(head_b, out);
    (void)in_sizes; (void)n_in; (void)out_size;
}

// round 8
// speedup vs baseline: 1.3728x; 1.0340x over previous
#include <cuda_runtime.h>
#include <cuda_fp16.h>
#include <math.h>

// ---------------- problem constants ----------------
#define BB     16
#define LCTX   512
#define KVAR   16
#define HPRED  96
#define DM     512
#define NST    16
#define NLAY   3
#define DFF    2048
#define PATCH  16
#define STRIDEP 8
#define PP     63
#define DIN    1024
#define RNK    32
#define SEQ    (KVAR*PP)     // 1008
#define TT     (BB*SEQ)      // 16128
#define EPSF   1e-5f
#define HWLD   (PP*DM)

// ---------------- scratch ----------------
__device__ float g_mean[BB*KVAR];
__device__ float g_std[BB*KVAR];
__device__ float g_z   [TT*DM];
__device__ float g_tmp [TT*DM];
__device__ float g_u   [TT*DIN + DIN];
__device__ float g_zg  [TT*DIN + DIN];
__device__ float g_xdbl[TT*64 + 64];
__device__ float g_headp[PP*BB*KVAR*HPRED];
// fp16 activation copies
__device__ __half g_zh  [TT*DM];
__device__ __half g_uh  [TT*DIN];
__device__ __half g_y2h [TT*DIN];
__device__ __half g_hlnh[TT*DM];
__device__ __half g_hffh[TT*DFF];
// fp16 weights (all layers)
__device__ __half h_inw[3*2048*512];
__device__ __half h_xpw[3*64*1024];
__device__ __half h_ow [3*512*1024];
__device__ __half h_w1 [3*2048*512];
__device__ __half h_w2 [3*512*2048];

// ---------------- helpers ----------------
__device__ __forceinline__ float siluf(float x){ return x / (1.f + __expf(-x)); }
__device__ __forceinline__ float geluf(float x){
    return 0.5f * x * (1.f + erff(x * 0.70710678118654752f));
}

__device__ __forceinline__ void cp16(void* smem, const void* g){
    unsigned a = (unsigned)__cvta_generic_to_shared(smem);
    asm volatile("cp.async.cg.shared.global [%0], [%1], 16;" :: "r"(a), "l"(g));
}
__device__ __forceinline__ void cp_commit(){ asm volatile("cp.async.commit_group;"); }

__device__ __forceinline__ unsigned smem_u32(const void* p){
    unsigned a;
    asm("{ .reg .u64 t; cvta.to.shared.u64 t, %1; cvt.u32.u64 %0, t; }" : "=r"(a) : "l"(p));
    return a;
}

__device__ __forceinline__ void mma_f16(float* c, const unsigned* a, const unsigned* b){
    asm volatile("mma.sync.aligned.m16n8k16.row.col.f32.f16.f16.f32 "
        "{%0,%1,%2,%3}, {%4,%5,%6,%7}, {%8,%9}, {%0,%1,%2,%3};"
        : "+f"(c[0]),"+f"(c[1]),"+f"(c[2]),"+f"(c[3])
        : "r"(a[0]),"r"(a[1]),"r"(a[2]),"r"(a[3]), "r"(b[0]),"r"(b[1]));
}
__device__ __forceinline__ void ldsm4(unsigned &r0, unsigned &r1, unsigned &r2, unsigned &r3,
                                      unsigned addr){
    asm volatile("ldmatrix.sync.aligned.m8n8.x4.shared.b16 {%0,%1,%2,%3}, [%4];"
        : "=r"(r0),"=r"(r1),"=r"(r2),"=r"(r3) : "r"(addr));
}

// ---------------- fp32 -> fp16 conversion ----------------
__global__ void f2h_kernel(const float* __restrict__ in, __half2* __restrict__ out, int n2){
    int i = blockIdx.x*256 + threadIdx.x;
    if (i < n2){
        float2 v = ((const float2*)in)[i];
        out[i] = __floats2half2_rn(v.x, v.y);
    }
}

// ---------------- per-(b,k) mean/std over L ----------------
__global__ void stats_kernel(const float* __restrict__ x){
    int bk = blockIdx.x; int b = bk >> 4, k = bk & 15;
    int tid = threadIdx.x;
    float s = 0.f, q = 0.f;
    for (int l = tid; l < LCTX; l += 256){
        float v = x[(b*LCTX + l)*KVAR + k];
        s += v; q += v*v;
    }
    __shared__ float sh[64];
#pragma unroll
    for (int o = 16; o; o >>= 1){
        s += __shfl_xor_sync(~0u, s, o);
        q += __shfl_xor_sync(~0u, q, o);
    }
    int w = tid >> 5;
    if ((tid & 31) == 0){ sh[w] = s; sh[w+32] = q; }
    __syncthreads();
    if (tid == 0){
        float S = 0.f, Q = 0.f;
        for (int i = 0; i < 8; i++){ S += sh[i]; Q += sh[32+i]; }
        float mu  = S * (1.f/LCTX);
        float var = Q * (1.f/LCTX) - mu*mu;
        g_mean[bk] = mu;
        g_std[bk]  = sqrtf(var + EPSF);
    }
}

// ---------------- patch embedding + pos + var embed ----------------
__global__ void embed_kernel(const float* __restrict__ x,
                             const float* __restrict__ pw,
                             const float* __restrict__ pb,
                             const float* __restrict__ pos,
                             const float* __restrict__ vemb){
    int row = blockIdx.x;
    int b = row / SEQ, rem = row % SEQ;
    int p = rem >> 4, k = rem & 15;
    int bk = b*KVAR + k;
    __shared__ float xs[PATCH];
    int tid = threadIdx.x;                   // 128
    if (tid < PATCH){
        float v = x[(b*LCTX + p*STRIDEP + tid)*KVAR + k];
        xs[tid] = (v - g_mean[bk]) / g_std[bk];
    }
    __syncthreads();
#pragma unroll
    for (int j = 0; j < 4; j++){
        int d = tid + j*128;
        float acc = pb[d] + pos[p*DM + d] + vemb[k*DM + d];
        const float4* w4 = (const float4*)(pw + d*PATCH);
#pragma unroll
        for (int t4 = 0; t4 < 4; t4++){
            float4 w = w4[t4];
            acc += xs[t4*4+0]*w.x + xs[t4*4+1]*w.y + xs[t4*4+2]*w.z + xs[t4*4+3]*w.w;
        }
        g_z[row*DM + d] = acc;
        g_zh[row*DM + d] = __float2half(acc);
    }
}

// ---------------- epilogue modes ----------------
enum { EP_NONE=0, EP_SPLIT=1, EP_GELU=3, EP_BIAS_RES=4, EP_RES=5 };

template<int EP>
__device__ __forceinline__ void ep_store(float* __restrict__ out0, float* __restrict__ out1,
                                         __half* __restrict__ outh, int ldo,
                                         const float* __restrict__ bias,
                                         const float* __restrict__ res,
                                         int row, int col, float v0, float v1){
    if (EP == EP_NONE){
        out0[(size_t)row*ldo + col    ] = v0;
        out0[(size_t)row*ldo + col + 1] = v1;
    } else if (EP == EP_SPLIT){
        if (col < DIN){
            float s0 = siluf(v0), s1 = siluf(v1);
            out0[(size_t)row*DIN + col    ] = s0;
            out0[(size_t)row*DIN + col + 1] = s1;
            *(__half2*)&outh[(size_t)row*DIN + col] = __floats2half2_rn(s0, s1);
        } else {
            out1[(size_t)row*DIN + col - DIN    ] = v0;
            out1[(size_t)row*DIN + col - DIN + 1] = v1;
        }
    } else if (EP == EP_GELU){
        float g0 = geluf(v0 + bias[col]);
        float g1 = geluf(v1 + bias[col+1]);
        *(__half2*)&outh[(size_t)row*ldo + col] = __floats2half2_rn(g0, g1);
    } else if (EP == EP_BIAS_RES){
        float f0 = v0 + bias[col]   + res[(size_t)row*ldo + col];
        float f1 = v1 + bias[col+1] + res[(size_t)row*ldo + col + 1];
        out0[(size_t)row*ldo + col    ] = f0;
        out0[(size_t)row*ldo + col + 1] = f1;
        *(__half2*)&outh[(size_t)row*ldo + col] = __floats2half2_rn(f0, f1);
    } else { // EP_RES
        out0[(size_t)row*ldo + col    ] = v0 + res[(size_t)row*ldo + col];
        out0[(size_t)row*ldo + col + 1] = v1 + res[(size_t)row*ldo + col + 1];
    }
}

// ---------------- fp16 NT GEMM, 128x128 block, BK=32, 5-stage cp.async ---
// 8 warps as 2(M) x 4(N), warp tile 64x32. Fragment loads via ldmatrix.x4.
#define GH_PITCH 40                  // halfs per smem row (80 B)
#define GH_PITCHB 80                 // bytes per row
#define GH_STG   (128*GH_PITCH)      // 5120 halfs per stage per operand
#define GH_BOFF  (5*GH_STG)          // 25600 halfs
#define GH_SMEM  (2*5*GH_STG*2)      // 102400 bytes

template<int EP>
__global__ void __launch_bounds__(256) gemm_h(const __half* __restrict__ A, int lda,
                        const __half* __restrict__ W, int Kd,
                        float* __restrict__ out0, float* __restrict__ out1,
                        __half* __restrict__ outh, int ldo,
                        const float* __restrict__ bias, const float* __restrict__ res){
    extern __shared__ __half smh[];
    int tid = threadIdx.x;
    int nt = blockIdx.x, mt = blockIdx.y;
    int lane = tid & 31, wid = tid >> 5;
    int warpM = wid & 1, warpN = wid >> 1;      // 2 x 4
    int grp = lane >> 2, tig = lane & 3;

    const __half* Abase = A + (size_t)(mt*128)*lda;
    const __half* Wbase = W + (size_t)(nt*128)*Kd;

    int r  = tid >> 2;              // 0..63
    int kk = (tid & 3) * 8;         // half offset, 16B steps

    // ldmatrix lane-derived offsets
    unsigned smBytes = smem_u32(smh);
    int aRow  = lane & 15;
    int aKsel = (lane >> 4) * 8;                 // halfs
    int bRowSel = (lane & 7) + ((lane >> 4) * 8);
    int bKsel = ((lane >> 3) & 1) * 8;           // halfs

    float acc[4][4][4];
#pragma unroll
    for (int i = 0; i < 4; i++)
#pragma unroll
        for (int j = 0; j < 4; j++)
#pragma unroll
            for (int h = 0; h < 4; h++) acc[i][j][h] = 0.f;

    int nK = Kd >> 5;

    auto issue = [&](int stage){
        int buf = stage % 5;
        int ko = stage * 32;
        cp16(&smh[buf*GH_STG + r*GH_PITCH + kk],               Abase + (size_t)r*lda      + ko + kk);
        cp16(&smh[buf*GH_STG + (r+64)*GH_PITCH + kk],          Abase + (size_t)(r+64)*lda + ko + kk);
        cp16(&smh[GH_BOFF + buf*GH_STG + r*GH_PITCH + kk],     Wbase + (size_t)r*Kd       + ko + kk);
        cp16(&smh[GH_BOFF + buf*GH_STG + (r+64)*GH_PITCH + kk],Wbase + (size_t)(r+64)*Kd  + ko + kk);
        cp_commit();
    };

#pragma unroll
    for (int s = 0; s < 4; s++){
        if (s < nK) issue(s); else cp_commit();
    }

    for (int kt = 0; kt < nK; kt++){
        asm volatile("cp.async.wait_group 3;");
        __syncthreads();
        if (kt + 4 < nK) issue(kt + 4); else cp_commit();

        unsigned aSt = smBytes + (unsigned)((kt % 5)*GH_STG*2);
        unsigned bSt = smBytes + (unsigned)((GH_BOFF + (kt % 5)*GH_STG)*2);
#pragma unroll
        for (int k0 = 0; k0 < 32; k0 += 16){
            unsigned a[4][4], b[4][2];
#pragma unroll
            for (int i = 0; i < 4; i++){
                unsigned addr = aSt + (unsigned)((warpM*64 + i*16 + aRow)*GH_PITCHB
                                                 + (k0 + aKsel)*2);
                ldsm4(a[i][0], a[i][1], a[i][2], a[i][3], addr);
            }
#pragma unroll
            for (int j2 = 0; j2 < 2; j2++){
                unsigned addr = bSt + (unsigned)((warpN*32 + j2*16 + bRowSel)*GH_PITCHB
                                                 + (k0 + bKsel)*2);
                ldsm4(b[2*j2][0], b[2*j2][1], b[2*j2+1][0], b[2*j2+1][1], addr);
            }
#pragma unroll
            for (int i = 0; i < 4; i++)
#pragma unroll
                for (int j = 0; j < 4; j++)
                    mma_f16(acc[i][j], a[i], b[j]);
        }
    }

#pragma unroll
    for (int i = 0; i < 4; i++){
#pragma unroll
        for (int j = 0; j < 4; j++){
            int col = nt*128 + warpN*32 + j*8 + 2*tig;
#pragma unroll
            for (int h = 0; h < 2; h++){
                int row = mt*128 + warpM*64 + i*16 + grp + h*8;
                ep_store<EP>(out0, out1, outh, ldo, bias, res, row, col,
                             acc[i][j][h*2+0], acc[i][j][h*2+1]);
            }
        }
    }
}

// ---------------- fp16 NT GEMM, 32x64 block, BK=32, 6-stage (x_proj) -----
template<int EP>
__global__ void __launch_bounds__(128) gemm_h32(const __half* __restrict__ A, int lda,
                        const __half* __restrict__ W, int Kd,
                        float* __restrict__ out0, float* __restrict__ out1,
                        __half* __restrict__ outh, int ldo,
                        const float* __restrict__ bias, const float* __restrict__ res){
    __shared__ __align__(16) __half As[6][32*GH_PITCH];
    __shared__ __align__(16) __half Bs[6][64*GH_PITCH];
    int tid = threadIdx.x;
    int nt = blockIdx.x, mt = blockIdx.y;
    int lane = tid & 31, wid = tid >> 5;        // wid = warpN (0..3)
    int grp = lane >> 2, tig = lane & 3;

    const __half* Abase = A + (size_t)(mt*32)*lda;
    const __half* Wbase = W + (size_t)(nt*64)*Kd;

    int r  = tid >> 2;              // 0..31
    int kk = (tid & 3) * 8;

    unsigned aBase0 = smem_u32(&As[0][0]);
    unsigned bBase0 = smem_u32(&Bs[0][0]);
    int aRow  = lane & 15;
    int aKsel = (lane >> 4) * 8;
    int bRowSel = (lane & 7) + ((lane >> 4) * 8);
    int bKsel = ((lane >> 3) & 1) * 8;

    float acc[2][2][4];
#pragma unroll
    for (int i = 0; i < 2; i++)
#pragma unroll
        for (int j = 0; j < 2; j++)
#pragma unroll
            for (int h = 0; h < 4; h++) acc[i][j][h] = 0.f;

    int nK = Kd >> 5;

    auto issue = [&](int stage){
        int buf = stage % 6;
        int ko = stage * 32;
        cp16(&As[buf][r*GH_PITCH + kk],        Abase + (size_t)r*lda       + ko + kk);
        cp16(&Bs[buf][r*GH_PITCH + kk],        Wbase + (size_t)r*Kd        + ko + kk);
        cp16(&Bs[buf][(r+32)*GH_PITCH + kk],   Wbase + (size_t)(r+32)*Kd   + ko + kk);
        cp_commit();
    };

#pragma unroll
    for (int s = 0; s < 5; s++){
        if (s < nK) issue(s); else cp_commit();
    }

    for (int kt = 0; kt < nK; kt++){
        asm volatile("cp.async.wait_group 4;");
        __syncthreads();
        if (kt + 5 < nK) issue(kt + 5); else cp_commit();
        unsigned aSt = aBase0 + (unsigned)((kt % 6)*32*GH_PITCHB);
        unsigned bSt = bBase0 + (unsigned)((kt % 6)*64*GH_PITCHB);
#pragma unroll
        for (int k0 = 0; k0 < 32; k0 += 16){
            unsigned a[2][4], b[2][2];
#pragma unroll
            for (int i = 0; i < 2; i++){
                unsigned addr = aSt + (unsigned)((i*16 + aRow)*GH_PITCHB + (k0 + aKsel)*2);
                ldsm4(a[i][0], a[i][1], a[i][2], a[i][3], addr);
            }
            {
                unsigned addr = bSt + (unsigned)((wid*16 + bRowSel)*GH_PITCHB + (k0 + bKsel)*2);
                ldsm4(b[0][0], b[0][1], b[1][0], b[1][1], addr);
            }
#pragma unroll
            for (int i = 0; i < 2; i++)
#pragma unroll
                for (int j = 0; j < 2; j++)
                    mma_f16(acc[i][j], a[i], b[j]);
        }
    }

#pragma unroll
    for (int i = 0; i < 2; i++){
#pragma unroll
        for (int j = 0; j < 2; j++){
            int col = nt*64 + wid*16 + j*8 + 2*tig;
#pragma unroll
            for (int h = 0; h < 2; h++){
                int row = mt*32 + i*16 + grp + h*8;
                ep_store<EP>(out0, out1, outh, ldo, bias, res, row, col,
                             acc[i][j][h*2+0], acc[i][j][h*2+1]);
            }
        }
    }
}

// ---------------- layer norm; optional 2nd LN to fp16 ----------------
template<bool DOUBLE>
__global__ void ln_kernel(const float* __restrict__ in,
                          const float* __restrict__ g1, const float* __restrict__ b1,
                          float* __restrict__ o1,
                          const float* __restrict__ g2, const float* __restrict__ b2,
                          __half* __restrict__ o2h){
    int w = threadIdx.x >> 5, lane = threadIdx.x & 31;
    int row = blockIdx.x*8 + w;
    const float4* in4 = (const float4*)(in + (size_t)row*DM);
    float4 v[4];
    float s = 0.f, q = 0.f;
#pragma unroll
    for (int i = 0; i < 4; i++){
        v[i] = in4[lane + 32*i];
        s += v[i].x + v[i].y + v[i].z + v[i].w;
        q += v[i].x*v[i].x + v[i].y*v[i].y + v[i].z*v[i].z + v[i].w*v[i].w;
    }
#pragma unroll
    for (int o = 16; o; o >>= 1){
        s += __shfl_xor_sync(~0u, s, o);
        q += __shfl_xor_sync(~0u, q, o);
    }
    float mu = s * (1.f/DM);
    float rs = rsqrtf(q*(1.f/DM) - mu*mu + EPSF);
    float4 zz[4];
    float s2 = 0.f, q2 = 0.f;
#pragma unroll
    for (int i = 0; i < 4; i++){
        float4 gg = ((const float4*)g1)[lane + 32*i];
        float4 bb = ((const float4*)b1)[lane + 32*i];
        zz[i].x = (v[i].x - mu)*rs*gg.x + bb.x;
        zz[i].y = (v[i].y - mu)*rs*gg.y + bb.y;
        zz[i].z = (v[i].z - mu)*rs*gg.z + bb.z;
        zz[i].w = (v[i].w - mu)*rs*gg.w + bb.w;
        if (DOUBLE){
            s2 += zz[i].x + zz[i].y + zz[i].z + zz[i].w;
            q2 += zz[i].x*zz[i].x + zz[i].y*zz[i].y + zz[i].z*zz[i].z + zz[i].w*zz[i].w;
        }
        ((float4*)(o1 + (size_t)row*DM))[lane + 32*i] = zz[i];
    }
    if (DOUBLE){
#pragma unroll
        for (int o = 16; o; o >>= 1){
            s2 += __shfl_xor_sync(~0u, s2, o);
            q2 += __shfl_xor_sync(~0u, q2, o);
        }
        float mu2 = s2 * (1.f/DM);
        float rs2 = rsqrtf(q2*(1.f/DM) - mu2*mu2 + EPSF);
        __half2* oo = (__half2*)(o2h + (size_t)row*DM);
#pragma unroll
        for (int i = 0; i < 4; i++){
            float4 gg = ((const float4*)g2)[lane + 32*i];
            float4 bb = ((const float4*)b2)[lane + 32*i];
            float o0 = (zz[i].x - mu2)*rs2*gg.x + bb.x;
            float o1v= (zz[i].y - mu2)*rs2*gg.y + bb.y;
            float o2v= (zz[i].z - mu2)*rs2*gg.z + bb.z;
            float o3 = (zz[i].w - mu2)*rs2*gg.w + bb.w;
            oo[2*(lane + 32*i)    ] = __floats2half2_rn(o0, o1v);
            oo[2*(lane + 32*i) + 1] = __floats2half2_rn(o2v, o3);
        }
    }
}

// ---------------- selective scan with fused dt_proj + softplus ----------
__global__ void scan_kernel(const float* __restrict__ u,
                            const float* __restrict__ zg,
                            const float* __restrict__ xdbl,
                            const float* __restrict__ Wdt,
                            const float* __restrict__ bdt,
                            const float* __restrict__ A_log,
                            const float* __restrict__ Dp,
                            __half* __restrict__ y2h){
    int blk = blockIdx.x;                    // 128 blocks
    int b = blk >> 3, dblk = blk & 7;
    int t = threadIdx.x;                     // 256
    int ph = t & 1;
    int d = dblk*128 + (t >> 1);
    int nb = ph * 8;

    float Aa[8];
#pragma unroll
    for (int j = 0; j < 8; j++) Aa[j] = -expf(A_log[d*NST + nb + j]);
    float A0 = Aa[0];
    float stepA = Aa[1] - Aa[0];
    bool prog = true;
#pragma unroll
    for (int j = 0; j < 8; j++){
        float e = A0 + (float)j * stepA;
        if (fabsf(Aa[j] - e) > 1e-5f*fabsf(e) + 1e-7f) prog = false;
    }
    float Dd = Dp[d];
    float bd = bdt[d];

    float wdt[16];
#pragma unroll
    for (int j = 0; j < 16; j++) wdt[j] = Wdt[d*RNK + ph*16 + j];

    float h[8];
#pragma unroll
    for (int j = 0; j < 8; j++) h[j] = 0.f;

    size_t base = (size_t)(b*SEQ)*DIN + d;
    const float* xr = xdbl + (size_t)(b*SEQ)*64;

    auto calc_delta = [&](const float4& T0, const float4& T1,
                          const float4& T2, const float4& T3) -> float {
        float a0 = T0.x*wdt[0]  + T0.y*wdt[1]  + T0.z*wdt[2]  + T0.w*wdt[3];
        float a1 = T1.x*wdt[4]  + T1.y*wdt[5]  + T1.z*wdt[6]  + T1.w*wdt[7];
        float a2 = T2.x*wdt[8]  + T2.y*wdt[9]  + T2.z*wdt[10] + T2.w*wdt[11];
        float a3 = T3.x*wdt[12] + T3.y*wdt[13] + T3.z*wdt[14] + T3.w*wdt[15];
        float p = (a0 + a1) + (a2 + a3);
        p += __shfl_xor_sync(~0u, p, 1);
        float xv = p + bd;
        return fmaxf(xv, 0.f) + __logf(1.f + __expf(-fabsf(xv)));
    };

    float uv = u[base], zv = zg[base];
    const float* dtp = xr + ph*16;
    float4 T0 = *(const float4*)(dtp), T1 = *(const float4*)(dtp+4);
    float4 T2 = *(const float4*)(dtp+8), T3 = *(const float4*)(dtp+12);
    float4 B0 = *(const float4*)(xr + 32 + nb);
    float4 B1 = *(const float4*)(xr + 36 + nb);
    float4 C0 = *(const float4*)(xr + 48 + nb);
    float4 C1 = *(const float4*)(xr + 52 + nb);
    float dv = calc_delta(T0, T1, T2, T3);

    for (int s = 0; s < SEQ; s++){
        size_t baseN = base + DIN;
        const float* xrN = xr + 64;
        float uvN = u[baseN], zvN = zg[baseN];
        const float* dtpN = xrN + ph*16;
        float4 TN0 = *(const float4*)(dtpN),   TN1 = *(const float4*)(dtpN+4);
        float4 TN2 = *(const float4*)(dtpN+8), TN3 = *(const float4*)(dtpN+12);
        float4 B0N = *(const float4*)(xrN + 32 + nb);
        float4 B1N = *(const float4*)(xrN + 36 + nb);
        float4 C0N = *(const float4*)(xrN + 48 + nb);
        float4 C1N = *(const float4*)(xrN + 52 + nb);

        float du = dv * uv;
        float y = 0.f;
        if (prog){
            float e = __expf(dv * A0);
            float rr = __expf(dv * stepA);
            h[0] = h[0]*e + du*B0.x; y += h[0]*C0.x; e *= rr;
            h[1] = h[1]*e + du*B0.y; y += h[1]*C0.y; e *= rr;
            h[2] = h[2]*e + du*B0.z; y += h[2]*C0.z; e *= rr;
            h[3] = h[3]*e + du*B0.w; y += h[3]*C0.w; e *= rr;
            h[4] = h[4]*e + du*B1.x; y += h[4]*C1.x; e *= rr;
            h[5] = h[5]*e + du*B1.y; y += h[5]*C1.y; e *= rr;
            h[6] = h[6]*e + du*B1.z; y += h[6]*C1.z; e *= rr;
            h[7] = h[7]*e + du*B1.w; y += h[7]*C1.w;
        } else {
            float Bv[8] = {B0.x,B0.y,B0.z,B0.w,B1.x,B1.y,B1.z,B1.w};
            float Cv[8] = {C0.x,C0.y,C0.z,C0.w,C1.x,C1.y,C1.z,C1.w};
#pragma unroll
            for (int j = 0; j < 8; j++){
                float e = __expf(dv * Aa[j]);
                h[j] = h[j]*e + du*Bv[j];
                y += h[j]*Cv[j];
            }
        }
        float ysum = y + __shfl_xor_sync(~0u, y, 1);
        if (!ph){
            y2h[base] = __float2half((ysum + uv*Dd) * siluf(zv));
        }
        dv = calc_delta(TN0, TN1, TN2, TN3);
        base = baseN; xr = xrN;
        uv = uvN; zv = zvN;
        B0 = B0N; B1 = B1N; C0 = C0N; C1 = C1N;
    }
}

// ---------------- head: partial GEMM per patch index p ----------------
__global__ void head_partial(const float* __restrict__ zf, const float* __restrict__ hw){
    int p = blockIdx.x, mt = blockIdx.y;
    __shared__ float As[16][64];
    __shared__ float Ws[16][96];
    int tid = threadIdx.x;                   // 256
    int lm = tid >> 2, lk = (tid & 3) * 4;
    int bkrow = mt*64 + lm;
    int b = bkrow >> 4, kk = bkrow & 15;
    const float* Ag = zf + (size_t)(b*SEQ + p*KVAR + kk)*DM + lk;
    int tx = tid & 15, ty = tid >> 4;
    float acc[4][6];
#pragma unroll
    for (int i = 0; i < 4; i++)
#pragma unroll
        for (int j = 0; j < 6; j++) acc[i][j] = 0.f;

    for (int kt = 0; kt < DM; kt += 16){
        float4 av = *(const float4*)(Ag + kt);
        As[lk+0][lm]=av.x; As[lk+1][lm]=av.y; As[lk+2][lm]=av.z; As[lk+3][lm]=av.w;
#pragma unroll
        for (int i = 0; i < 6; i++){
            int e = tid + i*256;
            int n = e >> 4, kq = e & 15;
            Ws[kq][n] = hw[(size_t)n*HWLD + p*DM + kt + kq];
        }
        __syncthreads();
#pragma unroll
        for (int k = 0; k < 16; k++){
            float4 a = *(const float4*)&As[k][ty*4];
            float av4[4] = {a.x, a.y, a.z, a.w};
#pragma unroll
            for (int j = 0; j < 6; j++){
                float wv = Ws[k][tx*6 + j];
#pragma unroll
                for (int i = 0; i < 4; i++) acc[i][j] += av4[i]*wv;
            }
        }
        __syncthreads();
    }
#pragma unroll
    for (int i = 0; i < 4; i++)
#pragma unroll
        for (int j = 0; j < 6; j++)
            g_headp[(size_t)(p*256 + mt*64 + ty*4 + i)*HPRED + tx*6 + j] = acc[i][j];
}

// ---------------- head reduction + de-normalization ----------------
__global__ void head_final(const float* __restrict__ hb, float* __restrict__ out){
    int idx = blockIdx.x*256 + threadIdx.x;
    int bk = idx / HPRED, hh = idx % HPRED;
    float s = 0.f;
    for (int p = 0; p < PP; p++) s += g_headp[(size_t)p*(BB*KVAR*HPRED) + idx];
    s += hb[hh];
    int b = bk >> 4, k = bk & 15;
    out[b*(HPRED*KVAR) + hh*KVAR + k] = s * g_std[bk] + g_mean[bk];
}

// ---------------- launch ----------------
extern "C" void kernel_launch(void* const* d_in, const int* in_sizes, int n_in,
                              void* d_out, int out_size){
    const float* x        = (const float*)d_in[0];
    const float* patch_w  = (const float*)d_in[1];
    const float* patch_b  = (const float*)d_in[2];
    const float* pos      = (const float*)d_in[3];
    const float* vemb     = (const float*)d_in[4];
    const float* in_w     = (const float*)d_in[5];
    const float* xp_w     = (const float*)d_in[6];
    const float* dt_w     = (const float*)d_in[7];
    const float* dt_b     = (const float*)d_in[8];
    const float* A_log    = (const float*)d_in[9];
    const float* D_par    = (const float*)d_in[10];
    const float* out_w    = (const float*)d_in[11];
    const float* tmb_g    = (const float*)d_in[12];
    const float* tmb_b    = (const float*)d_in[13];
    const float* ffn_g    = (const float*)d_in[14];
    const float* ffn_b    = (const float*)d_in[15];
    const float* ffn_w1   = (const float*)d_in[16];
    const float* ffn_b1   = (const float*)d_in[17];
    const float* ffn_w2   = (const float*)d_in[18];
    const float* ffn_b2   = (const float*)d_in[19];
    const float* norm_g   = (const float*)d_in[20];
    const float* norm_b   = (const float*)d_in[21];
    const float* head_w   = (const float*)d_in[22];
    const float* head_b   = (const float*)d_in[23];
    float* out = (float*)d_out;

    cudaFuncSetAttribute(gemm_h<EP_SPLIT>,    cudaFuncAttributeMaxDynamicSharedMemorySize, GH_SMEM);
    cudaFuncSetAttribute(gemm_h<EP_RES>,      cudaFuncAttributeMaxDynamicSharedMemorySize, GH_SMEM);
    cudaFuncSetAttribute(gemm_h<EP_GELU>,     cudaFuncAttributeMaxDynamicSharedMemorySize, GH_SMEM);
    cudaFuncSetAttribute(gemm_h<EP_BIAS_RES>, cudaFuncAttributeMaxDynamicSharedMemorySize, GH_SMEM);

    float *z, *tmp, *u, *zgp, *xdbl;
    __half *zh, *uh, *y2h, *hlnh, *hffh;
    __half *winh, *wxph, *woh, *w1h, *w2h;
    cudaGetSymbolAddress((void**)&z,    g_z);
    cudaGetSymbolAddress((void**)&tmp,  g_tmp);
    cudaGetSymbolAddress((void**)&u,    g_u);
    cudaGetSymbolAddress((void**)&zgp,  g_zg);
    cudaGetSymbolAddress((void**)&xdbl, g_xdbl);
    cudaGetSymbolAddress((void**)&zh,   g_zh);
    cudaGetSymbolAddress((void**)&uh,   g_uh);
    cudaGetSymbolAddress((void**)&y2h,  g_y2h);
    cudaGetSymbolAddress((void**)&hlnh, g_hlnh);
    cudaGetSymbolAddress((void**)&hffh, g_hffh);
    cudaGetSymbolAddress((void**)&winh, h_inw);
    cudaGetSymbolAddress((void**)&wxph, h_xpw);
    cudaGetSymbolAddress((void**)&woh,  h_ow);
    cudaGetSymbolAddress((void**)&w1h,  h_w1);
    cudaGetSymbolAddress((void**)&w2h,  h_w2);

    // weight conversions (fp32 -> fp16), all layers at once
    f2h_kernel<<<(3*2048*512/2 + 255)/256, 256>>>(in_w,  (__half2*)winh, 3*2048*512/2);
    f2h_kernel<<<(3*64*1024/2  + 255)/256, 256>>>(xp_w,  (__half2*)wxph, 3*64*1024/2);
    f2h_kernel<<<(3*512*1024/2 + 255)/256, 256>>>(out_w, (__half2*)woh,  3*512*1024/2);
    f2h_kernel<<<(3*2048*512/2 + 255)/256, 256>>>(ffn_w1,(__half2*)w1h,  3*2048*512/2);
    f2h_kernel<<<(3*512*2048/2 + 255)/256, 256>>>(ffn_w2,(__half2*)w2h,  3*512*2048/2);

    stats_kernel<<<BB*KVAR, 256>>>(x);
    embed_kernel<<<TT, 128>>>(x, patch_w, patch_b, pos, vemb);

    const int MT  = TT/128;   // 126 M tiles (128-row)
    const int MT32= TT/32;    // 504 M tiles (32-row)

    for (int l = 0; l < NLAY; l++){
        const __half* Wi  = winh + (size_t)l*(2*DIN)*DM;
        const __half* Wx  = wxph + (size_t)l*64*DIN;
        const float*  Wdt = dt_w + (size_t)l*DIN*RNK;
        const float*  bdt = dt_b + (size_t)l*DIN;
        const float*  Al  = A_log+ (size_t)l*DIN*NST;
        const float*  Dl  = D_par+ (size_t)l*DIN;
        const __half* Wo  = woh  + (size_t)l*DM*DIN;
        const __half* W1  = w1h  + (size_t)l*DFF*DM;
        const float*  B1  = ffn_b1 + (size_t)l*DFF;
        const __half* W2  = w2h  + (size_t)l*DM*DFF;
        const float*  B2  = ffn_b2 + (size_t)l*DM;

        // in_proj -> silu(u) fp32+fp16, zg fp32   (N=2048, K=512)
        gemm_h<EP_SPLIT><<<dim3(16, MT), 256, GH_SMEM>>>(zh, DM, Wi, DM, u, zgp, uh, 0, nullptr, nullptr);
        // x_proj: xdbl = u @ Wx^T   (N=64, K=1024)
        gemm_h32<EP_NONE><<<dim3(1, MT32), 128>>>(uh, DIN, Wx, DIN, xdbl, nullptr, nullptr, 64, nullptr, nullptr);
        // selective scan (fused dt_proj+softplus, +u*D, *silu(zg)) -> y2h fp16
        scan_kernel<<<128, 256>>>(u, zgp, xdbl, Wdt, bdt, Al, Dl, y2h);
        // out_proj + residual into tmp  (N=512, K=1024)
        gemm_h<EP_RES><<<dim3(4, MT), 256, GH_SMEM>>>(y2h, DIN, Wo, DIN, tmp, nullptr, nullptr, DM, nullptr, z);
        // LN(tmp)->z fp32 ; LN(z)->hln fp16 (ffn pre-norm)
        ln_kernel<true><<<TT/8, 256>>>(tmp, tmb_g + l*DM, tmb_b + l*DM, z,
                                       ffn_g + l*DM, ffn_b + l*DM, hlnh);
        // FFN
        gemm_h<EP_GELU><<<dim3(16, MT), 256, GH_SMEM>>>(hlnh, DM, W1, DM, nullptr, nullptr, hffh, DFF, B1, nullptr);
        gemm_h<EP_BIAS_RES><<<dim3(4, MT), 256, GH_SMEM>>>(hffh, DFF, W2, DFF, z, nullptr, zh, DM, B2, z);
    }

    // final LN -> tmp
    ln_kernel<false><<<TT/8, 256>>>(z, norm_g, norm_b, tmp, nullptr, nullptr, nullptr);
    // head
    head_partial<<<dim3(PP, 4), 256>>>(tmp, head_w);
    head_final<<<96, 256>>>(head_b, out);
    (void)in_sizes; (void)n_in; (void)out_size;
}

// round 9
// speedup vs baseline: 1.3873x; 1.0106x over previous
#include <cuda_runtime.h>
#include <cuda_fp16.h>
#include <math.h>

// ---------------- problem constants ----------------
#define BB     16
#define LCTX   512
#define KVAR   16
#define HPRED  96
#define DM     512
#define NST    16
#define NLAY   3
#define DFF    2048
#define PATCH  16
#define STRIDEP 8
#define PP     63
#define DIN    1024
#define RNK    32
#define SEQ    (KVAR*PP)     // 1008
#define TT     (BB*SEQ)      // 16128
#define EPSF   1e-5f
#define HWLD   (PP*DM)

// ---------------- scratch ----------------
__device__ float g_mean[BB*KVAR];
__device__ float g_std[BB*KVAR];
__device__ float g_z   [TT*DM];
__device__ float g_tmp [TT*DM];
__device__ float g_xdbl[TT*64 + 64];
__device__ float g_headp[PP*BB*KVAR*HPRED];
// fp16 activations (u/zg padded by one row for scan prefetch)
__device__ __half g_zh  [TT*DM];
__device__ __half g_uh  [TT*DIN + DIN];
__device__ __half g_zgh [TT*DIN + DIN];
__device__ __half g_y2h [TT*DIN];
__device__ __half g_hlnh[TT*DM];
__device__ __half g_hffh[TT*DFF];
// fp16 weights (all layers)
__device__ __half h_inw[3*2048*512];
__device__ __half h_xpw[3*64*1024];
__device__ __half h_ow [3*512*1024];
__device__ __half h_w1 [3*2048*512];
__device__ __half h_w2 [3*512*2048];

// ---------------- helpers ----------------
__device__ __forceinline__ float siluf(float x){ return x / (1.f + __expf(-x)); }
__device__ __forceinline__ float geluf(float x){
    return 0.5f * x * (1.f + erff(x * 0.70710678118654752f));
}

__device__ __forceinline__ void cp16(void* smem, const void* g){
    unsigned a = (unsigned)__cvta_generic_to_shared(smem);
    asm volatile("cp.async.cg.shared.global [%0], [%1], 16;" :: "r"(a), "l"(g));
}
__device__ __forceinline__ void cp_commit(){ asm volatile("cp.async.commit_group;"); }

__device__ __forceinline__ unsigned smem_u32(const void* p){
    unsigned a;
    asm("{ .reg .u64 t; cvta.to.shared.u64 t, %1; cvt.u32.u64 %0, t; }" : "=r"(a) : "l"(p));
    return a;
}

__device__ __forceinline__ void mma_f16(float* c, const unsigned* a, const unsigned* b){
    asm volatile("mma.sync.aligned.m16n8k16.row.col.f32.f16.f16.f32 "
        "{%0,%1,%2,%3}, {%4,%5,%6,%7}, {%8,%9}, {%0,%1,%2,%3};"
        : "+f"(c[0]),"+f"(c[1]),"+f"(c[2]),"+f"(c[3])
        : "r"(a[0]),"r"(a[1]),"r"(a[2]),"r"(a[3]), "r"(b[0]),"r"(b[1]));
}
__device__ __forceinline__ void ldsm4(unsigned &r0, unsigned &r1, unsigned &r2, unsigned &r3,
                                      unsigned addr){
    asm volatile("ldmatrix.sync.aligned.m8n8.x4.shared.b16 {%0,%1,%2,%3}, [%4];"
        : "=r"(r0),"=r"(r1),"=r"(r2),"=r"(r3) : "r"(addr));
}

// ---------------- fp32 -> fp16 conversion ----------------
__global__ void f2h_kernel(const float* __restrict__ in, __half2* __restrict__ out, int n2){
    int i = blockIdx.x*256 + threadIdx.x;
    if (i < n2){
        float2 v = ((const float2*)in)[i];
        out[i] = __floats2half2_rn(v.x, v.y);
    }
}

// ---------------- per-(b,k) mean/std over L ----------------
__global__ void stats_kernel(const float* __restrict__ x){
    int bk = blockIdx.x; int b = bk >> 4, k = bk & 15;
    int tid = threadIdx.x;
    float s = 0.f, q = 0.f;
    for (int l = tid; l < LCTX; l += 256){
        float v = x[(b*LCTX + l)*KVAR + k];
        s += v; q += v*v;
    }
    __shared__ float sh[64];
#pragma unroll
    for (int o = 16; o; o >>= 1){
        s += __shfl_xor_sync(~0u, s, o);
        q += __shfl_xor_sync(~0u, q, o);
    }
    int w = tid >> 5;
    if ((tid & 31) == 0){ sh[w] = s; sh[w+32] = q; }
    __syncthreads();
    if (tid == 0){
        float S = 0.f, Q = 0.f;
        for (int i = 0; i < 8; i++){ S += sh[i]; Q += sh[32+i]; }
        float mu  = S * (1.f/LCTX);
        float var = Q * (1.f/LCTX) - mu*mu;
        g_mean[bk] = mu;
        g_std[bk]  = sqrtf(var + EPSF);
    }
}

// ---------------- patch embedding + pos + var embed ----------------
__global__ void embed_kernel(const float* __restrict__ x,
                             const float* __restrict__ pw,
                             const float* __restrict__ pb,
                             const float* __restrict__ pos,
                             const float* __restrict__ vemb){
    int row = blockIdx.x;
    int b = row / SEQ, rem = row % SEQ;
    int p = rem >> 4, k = rem & 15;
    int bk = b*KVAR + k;
    __shared__ float xs[PATCH];
    int tid = threadIdx.x;                   // 128
    if (tid < PATCH){
        float v = x[(b*LCTX + p*STRIDEP + tid)*KVAR + k];
        xs[tid] = (v - g_mean[bk]) / g_std[bk];
    }
    __syncthreads();
#pragma unroll
    for (int j = 0; j < 4; j++){
        int d = tid + j*128;
        float acc = pb[d] + pos[p*DM + d] + vemb[k*DM + d];
        const float4* w4 = (const float4*)(pw + d*PATCH);
#pragma unroll
        for (int t4 = 0; t4 < 4; t4++){
            float4 w = w4[t4];
            acc += xs[t4*4+0]*w.x + xs[t4*4+1]*w.y + xs[t4*4+2]*w.z + xs[t4*4+3]*w.w;
        }
        g_z[row*DM + d] = acc;
        g_zh[row*DM + d] = __float2half(acc);
    }
}

// ---------------- epilogue modes ----------------
enum { EP_NONE=0, EP_SPLIT=1, EP_GELU=3, EP_BIAS_RES=4, EP_RES=5 };

template<int EP>
__device__ __forceinline__ void ep_store(float* __restrict__ out0, float* __restrict__ out1,
                                         __half* __restrict__ outh, int ldo,
                                         const float* __restrict__ bias,
                                         const float* __restrict__ res,
                                         int row, int col, float v0, float v1){
    if (EP == EP_NONE){
        out0[(size_t)row*ldo + col    ] = v0;
        out0[(size_t)row*ldo + col + 1] = v1;
    } else if (EP == EP_SPLIT){
        if (col < DIN){
            // silu(u) -> fp16 (outh)
            float s0 = siluf(v0), s1 = siluf(v1);
            *(__half2*)&outh[(size_t)row*DIN + col] = __floats2half2_rn(s0, s1);
        } else {
            // zg -> fp16 (out1 reinterpreted)
            __half* zgh = (__half*)out1;
            *(__half2*)&zgh[(size_t)row*DIN + col - DIN] = __floats2half2_rn(v0, v1);
        }
    } else if (EP == EP_GELU){
        float g0 = geluf(v0 + bias[col]);
        float g1 = geluf(v1 + bias[col+1]);
        *(__half2*)&outh[(size_t)row*ldo + col] = __floats2half2_rn(g0, g1);
    } else if (EP == EP_BIAS_RES){
        float f0 = v0 + bias[col]   + res[(size_t)row*ldo + col];
        float f1 = v1 + bias[col+1] + res[(size_t)row*ldo + col + 1];
        out0[(size_t)row*ldo + col    ] = f0;
        out0[(size_t)row*ldo + col + 1] = f1;
        *(__half2*)&outh[(size_t)row*ldo + col] = __floats2half2_rn(f0, f1);
    } else { // EP_RES
        out0[(size_t)row*ldo + col    ] = v0 + res[(size_t)row*ldo + col];
        out0[(size_t)row*ldo + col + 1] = v1 + res[(size_t)row*ldo + col + 1];
    }
}

// ---------------- fp16 NT GEMM, 128x128 block, BK=32, 5-stage cp.async ---
// 8 warps as 2(M) x 4(N), warp tile 64x32, ldmatrix fragment loads.
// __launch_bounds__(256,2): 2 CTAs/SM (2*100KB smem fits 228KB).
#define GH_PITCH 40                  // halfs per smem row (80 B)
#define GH_PITCHB 80                 // bytes per row
#define GH_STG   (128*GH_PITCH)      // 5120 halfs per stage per operand
#define GH_BOFF  (5*GH_STG)          // 25600 halfs
#define GH_SMEM  (2*5*GH_STG*2)      // 102400 bytes

template<int EP>
__global__ void __launch_bounds__(256, 2) gemm_h(const __half* __restrict__ A, int lda,
                        const __half* __restrict__ W, int Kd,
                        float* __restrict__ out0, float* __restrict__ out1,
                        __half* __restrict__ outh, int ldo,
                        const float* __restrict__ bias, const float* __restrict__ res){
    extern __shared__ __half smh[];
    int tid = threadIdx.x;
    int nt = blockIdx.x, mt = blockIdx.y;
    int lane = tid & 31, wid = tid >> 5;
    int warpM = wid & 1, warpN = wid >> 1;      // 2 x 4
    int grp = lane >> 2, tig = lane & 3;

    const __half* Abase = A + (size_t)(mt*128)*lda;
    const __half* Wbase = W + (size_t)(nt*128)*Kd;

    int r  = tid >> 2;              // 0..63
    int kk = (tid & 3) * 8;         // half offset, 16B steps

    unsigned smBytes = smem_u32(smh);
    int aRow  = lane & 15;
    int aKsel = (lane >> 4) * 8;
    int bRowSel = (lane & 7) + ((lane >> 4) * 8);
    int bKsel = ((lane >> 3) & 1) * 8;

    float acc[4][4][4];
#pragma unroll
    for (int i = 0; i < 4; i++)
#pragma unroll
        for (int j = 0; j < 4; j++)
#pragma unroll
            for (int h = 0; h < 4; h++) acc[i][j][h] = 0.f;

    int nK = Kd >> 5;

    auto issue = [&](int stage){
        int buf = stage % 5;
        int ko = stage * 32;
        cp16(&smh[buf*GH_STG + r*GH_PITCH + kk],               Abase + (size_t)r*lda      + ko + kk);
        cp16(&smh[buf*GH_STG + (r+64)*GH_PITCH + kk],          Abase + (size_t)(r+64)*lda + ko + kk);
        cp16(&smh[GH_BOFF + buf*GH_STG + r*GH_PITCH + kk],     Wbase + (size_t)r*Kd       + ko + kk);
        cp16(&smh[GH_BOFF + buf*GH_STG + (r+64)*GH_PITCH + kk],Wbase + (size_t)(r+64)*Kd  + ko + kk);
        cp_commit();
    };

#pragma unroll
    for (int s = 0; s < 4; s++){
        if (s < nK) issue(s); else cp_commit();
    }

    for (int kt = 0; kt < nK; kt++){
        asm volatile("cp.async.wait_group 3;");
        __syncthreads();
        if (kt + 4 < nK) issue(kt + 4); else cp_commit();

        unsigned aSt = smBytes + (unsigned)((kt % 5)*GH_STG*2);
        unsigned bSt = smBytes + (unsigned)((GH_BOFF + (kt % 5)*GH_STG)*2);
#pragma unroll
        for (int k0 = 0; k0 < 32; k0 += 16){
            unsigned a[4][4], b[4][2];
#pragma unroll
            for (int i = 0; i < 4; i++){
                unsigned addr = aSt + (unsigned)((warpM*64 + i*16 + aRow)*GH_PITCHB
                                                 + (k0 + aKsel)*2);
                ldsm4(a[i][0], a[i][1], a[i][2], a[i][3], addr);
            }
#pragma unroll
            for (int j2 = 0; j2 < 2; j2++){
                unsigned addr = bSt + (unsigned)((warpN*32 + j2*16 + bRowSel)*GH_PITCHB
                                                 + (k0 + bKsel)*2);
                ldsm4(b[2*j2][0], b[2*j2][1], b[2*j2+1][0], b[2*j2+1][1], addr);
            }
#pragma unroll
            for (int i = 0; i < 4; i++)
#pragma unroll
                for (int j = 0; j < 4; j++)
                    mma_f16(acc[i][j], a[i], b[j]);
        }
    }

#pragma unroll
    for (int i = 0; i < 4; i++){
#pragma unroll
        for (int j = 0; j < 4; j++){
            int col = nt*128 + warpN*32 + j*8 + 2*tig;
#pragma unroll
            for (int h = 0; h < 2; h++){
                int row = mt*128 + warpM*64 + i*16 + grp + h*8;
                ep_store<EP>(out0, out1, outh, ldo, bias, res, row, col,
                             acc[i][j][h*2+0], acc[i][j][h*2+1]);
            }
        }
    }
}

// ---------------- fp16 NT GEMM, 32x64 block, BK=32, 6-stage (x_proj) -----
template<int EP>
__global__ void __launch_bounds__(128, 3) gemm_h32(const __half* __restrict__ A, int lda,
                        const __half* __restrict__ W, int Kd,
                        float* __restrict__ out0, float* __restrict__ out1,
                        __half* __restrict__ outh, int ldo,
                        const float* __restrict__ bias, const float* __restrict__ res){
    __shared__ __align__(16) __half As[6][32*GH_PITCH];
    __shared__ __align__(16) __half Bs[6][64*GH_PITCH];
    int tid = threadIdx.x;
    int nt = blockIdx.x, mt = blockIdx.y;
    int lane = tid & 31, wid = tid >> 5;        // wid = warpN (0..3)
    int grp = lane >> 2, tig = lane & 3;

    const __half* Abase = A + (size_t)(mt*32)*lda;
    const __half* Wbase = W + (size_t)(nt*64)*Kd;

    int r  = tid >> 2;              // 0..31
    int kk = (tid & 3) * 8;

    unsigned aBase0 = smem_u32(&As[0][0]);
    unsigned bBase0 = smem_u32(&Bs[0][0]);
    int aRow  = lane & 15;
    int aKsel = (lane >> 4) * 8;
    int bRowSel = (lane & 7) + ((lane >> 4) * 8);
    int bKsel = ((lane >> 3) & 1) * 8;

    float acc[2][2][4];
#pragma unroll
    for (int i = 0; i < 2; i++)
#pragma unroll
        for (int j = 0; j < 2; j++)
#pragma unroll
            for (int h = 0; h < 4; h++) acc[i][j][h] = 0.f;

    int nK = Kd >> 5;

    auto issue = [&](int stage){
        int buf = stage % 6;
        int ko = stage * 32;
        cp16(&As[buf][r*GH_PITCH + kk],        Abase + (size_t)r*lda       + ko + kk);
        cp16(&Bs[buf][r*GH_PITCH + kk],        Wbase + (size_t)r*Kd        + ko + kk);
        cp16(&Bs[buf][(r+32)*GH_PITCH + kk],   Wbase + (size_t)(r+32)*Kd   + ko + kk);
        cp_commit();
    };

#pragma unroll
    for (int s = 0; s < 5; s++){
        if (s < nK) issue(s); else cp_commit();
    }

    for (int kt = 0; kt < nK; kt++){
        asm volatile("cp.async.wait_group 4;");
        __syncthreads();
        if (kt + 5 < nK) issue(kt + 5); else cp_commit();
        unsigned aSt = aBase0 + (unsigned)((kt % 6)*32*GH_PITCHB);
        unsigned bSt = bBase0 + (unsigned)((kt % 6)*64*GH_PITCHB);
#pragma unroll
        for (int k0 = 0; k0 < 32; k0 += 16){
            unsigned a[2][4], b[2][2];
#pragma unroll
            for (int i = 0; i < 2; i++){
                unsigned addr = aSt + (unsigned)((i*16 + aRow)*GH_PITCHB + (k0 + aKsel)*2);
                ldsm4(a[i][0], a[i][1], a[i][2], a[i][3], addr);
            }
            {
                unsigned addr = bSt + (unsigned)((wid*16 + bRowSel)*GH_PITCHB + (k0 + bKsel)*2);
                ldsm4(b[0][0], b[0][1], b[1][0], b[1][1], addr);
            }
#pragma unroll
            for (int i = 0; i < 2; i++)
#pragma unroll
                for (int j = 0; j < 2; j++)
                    mma_f16(acc[i][j], a[i], b[j]);
        }
    }

#pragma unroll
    for (int i = 0; i < 2; i++){
#pragma unroll
        for (int j = 0; j < 2; j++){
            int col = nt*64 + wid*16 + j*8 + 2*tig;
#pragma unroll
            for (int h = 0; h < 2; h++){
                int row = mt*32 + i*16 + grp + h*8;
                ep_store<EP>(out0, out1, outh, ldo, bias, res, row, col,
                             acc[i][j][h*2+0], acc[i][j][h*2+1]);
            }
        }
    }
}

// ---------------- layer norm; optional 2nd LN to fp16 ----------------
template<bool DOUBLE>
__global__ void ln_kernel(const float* __restrict__ in,
                          const float* __restrict__ g1, const float* __restrict__ b1,
                          float* __restrict__ o1,
                          const float* __restrict__ g2, const float* __restrict__ b2,
                          __half* __restrict__ o2h){
    int w = threadIdx.x >> 5, lane = threadIdx.x & 31;
    int row = blockIdx.x*8 + w;
    const float4* in4 = (const float4*)(in + (size_t)row*DM);
    float4 v[4];
    float s = 0.f, q = 0.f;
#pragma unroll
    for (int i = 0; i < 4; i++){
        v[i] = in4[lane + 32*i];
        s += v[i].x + v[i].y + v[i].z + v[i].w;
        q += v[i].x*v[i].x + v[i].y*v[i].y + v[i].z*v[i].z + v[i].w*v[i].w;
    }
#pragma unroll
    for (int o = 16; o; o >>= 1){
        s += __shfl_xor_sync(~0u, s, o);
        q += __shfl_xor_sync(~0u, q, o);
    }
    float mu = s * (1.f/DM);
    float rs = rsqrtf(q*(1.f/DM) - mu*mu + EPSF);
    float4 zz[4];
    float s2 = 0.f, q2 = 0.f;
#pragma unroll
    for (int i = 0; i < 4; i++){
        float4 gg = ((const float4*)g1)[lane + 32*i];
        float4 bb = ((const float4*)b1)[lane + 32*i];
        zz[i].x = (v[i].x - mu)*rs*gg.x + bb.x;
        zz[i].y = (v[i].y - mu)*rs*gg.y + bb.y;
        zz[i].z = (v[i].z - mu)*rs*gg.z + bb.z;
        zz[i].w = (v[i].w - mu)*rs*gg.w + bb.w;
        if (DOUBLE){
            s2 += zz[i].x + zz[i].y + zz[i].z + zz[i].w;
            q2 += zz[i].x*zz[i].x + zz[i].y*zz[i].y + zz[i].z*zz[i].z + zz[i].w*zz[i].w;
        }
        ((float4*)(o1 + (size_t)row*DM))[lane + 32*i] = zz[i];
    }
    if (DOUBLE){
#pragma unroll
        for (int o = 16; o; o >>= 1){
            s2 += __shfl_xor_sync(~0u, s2, o);
            q2 += __shfl_xor_sync(~0u, q2, o);
        }
        float mu2 = s2 * (1.f/DM);
        float rs2 = rsqrtf(q2*(1.f/DM) - mu2*mu2 + EPSF);
        __half2* oo = (__half2*)(o2h + (size_t)row*DM);
#pragma unroll
        for (int i = 0; i < 4; i++){
            float4 gg = ((const float4*)g2)[lane + 32*i];
            float4 bb = ((const float4*)b2)[lane + 32*i];
            float o0 = (zz[i].x - mu2)*rs2*gg.x + bb.x;
            float o1v= (zz[i].y - mu2)*rs2*gg.y + bb.y;
            float o2v= (zz[i].z - mu2)*rs2*gg.z + bb.z;
            float o3 = (zz[i].w - mu2)*rs2*gg.w + bb.w;
            oo[2*(lane + 32*i)    ] = __floats2half2_rn(o0, o1v);
            oo[2*(lane + 32*i) + 1] = __floats2half2_rn(o2v, o3);
        }
    }
}

// ---------------- selective scan with fused dt_proj + softplus ----------
// u and zg are fp16 now; xdbl fp32.
__global__ void scan_kernel(const __half* __restrict__ u,
                            const __half* __restrict__ zg,
                            const float* __restrict__ xdbl,
                            const float* __restrict__ Wdt,
                            const float* __restrict__ bdt,
                            const float* __restrict__ A_log,
                            const float* __restrict__ Dp,
                            __half* __restrict__ y2h){
    int blk = blockIdx.x;                    // 128 blocks
    int b = blk >> 3, dblk = blk & 7;
    int t = threadIdx.x;                     // 256
    int ph = t & 1;
    int d = dblk*128 + (t >> 1);
    int nb = ph * 8;

    float Aa[8];
#pragma unroll
    for (int j = 0; j < 8; j++) Aa[j] = -expf(A_log[d*NST + nb + j]);
    float A0 = Aa[0];
    float stepA = Aa[1] - Aa[0];
    bool prog = true;
#pragma unroll
    for (int j = 0; j < 8; j++){
        float e = A0 + (float)j * stepA;
        if (fabsf(Aa[j] - e) > 1e-5f*fabsf(e) + 1e-7f) prog = false;
    }
    float Dd = Dp[d];
    float bd = bdt[d];

    float wdt[16];
#pragma unroll
    for (int j = 0; j < 16; j++) wdt[j] = Wdt[d*RNK + ph*16 + j];

    float h[8];
#pragma unroll
    for (int j = 0; j < 8; j++) h[j] = 0.f;

    size_t base = (size_t)(b*SEQ)*DIN + d;
    const float* xr = xdbl + (size_t)(b*SEQ)*64;

    auto calc_delta = [&](const float4& T0, const float4& T1,
                          const float4& T2, const float4& T3) -> float {
        float a0 = T0.x*wdt[0]  + T0.y*wdt[1]  + T0.z*wdt[2]  + T0.w*wdt[3];
        float a1 = T1.x*wdt[4]  + T1.y*wdt[5]  + T1.z*wdt[6]  + T1.w*wdt[7];
        float a2 = T2.x*wdt[8]  + T2.y*wdt[9]  + T2.z*wdt[10] + T2.w*wdt[11];
        float a3 = T3.x*wdt[12] + T3.y*wdt[13] + T3.z*wdt[14] + T3.w*wdt[15];
        float p = (a0 + a1) + (a2 + a3);
        p += __shfl_xor_sync(~0u, p, 1);
        float xv = p + bd;
        return fmaxf(xv, 0.f) + __logf(1.f + __expf(-fabsf(xv)));
    };

    float uv = __half2float(u[base]), zv = __half2float(zg[base]);
    const float* dtp = xr + ph*16;
    float4 T0 = *(const float4*)(dtp), T1 = *(const float4*)(dtp+4);
    float4 T2 = *(const float4*)(dtp+8), T3 = *(const float4*)(dtp+12);
    float4 B0 = *(const float4*)(xr + 32 + nb);
    float4 B1 = *(const float4*)(xr + 36 + nb);
    float4 C0 = *(const float4*)(xr + 48 + nb);
    float4 C1 = *(const float4*)(xr + 52 + nb);
    float dv = calc_delta(T0, T1, T2, T3);

    for (int s = 0; s < SEQ; s++){
        size_t baseN = base + DIN;
        const float* xrN = xr + 64;
        float uvN = __half2float(u[baseN]), zvN = __half2float(zg[baseN]);
        const float* dtpN = xrN + ph*16;
        float4 TN0 = *(const float4*)(dtpN),   TN1 = *(const float4*)(dtpN+4);
        float4 TN2 = *(const float4*)(dtpN+8), TN3 = *(const float4*)(dtpN+12);
        float4 B0N = *(const float4*)(xrN + 32 + nb);
        float4 B1N = *(const float4*)(xrN + 36 + nb);
        float4 C0N = *(const float4*)(xrN + 48 + nb);
        float4 C1N = *(const float4*)(xrN + 52 + nb);

        float du = dv * uv;
        float y = 0.f;
        if (prog){
            float e = __expf(dv * A0);
            float rr = __expf(dv * stepA);
            h[0] = h[0]*e + du*B0.x; y += h[0]*C0.x; e *= rr;
            h[1] = h[1]*e + du*B0.y; y += h[1]*C0.y; e *= rr;
            h[2] = h[2]*e + du*B0.z; y += h[2]*C0.z; e *= rr;
            h[3] = h[3]*e + du*B0.w; y += h[3]*C0.w; e *= rr;
            h[4] = h[4]*e + du*B1.x; y += h[4]*C1.x; e *= rr;
            h[5] = h[5]*e + du*B1.y; y += h[5]*C1.y; e *= rr;
            h[6] = h[6]*e + du*B1.z; y += h[6]*C1.z; e *= rr;
            h[7] = h[7]*e + du*B1.w; y += h[7]*C1.w;
        } else {
            float Bv[8] = {B0.x,B0.y,B0.z,B0.w,B1.x,B1.y,B1.z,B1.w};
            float Cv[8] = {C0.x,C0.y,C0.z,C0.w,C1.x,C1.y,C1.z,C1.w};
#pragma unroll
            for (int j = 0; j < 8; j++){
                float e = __expf(dv * Aa[j]);
                h[j] = h[j]*e + du*Bv[j];
                y += h[j]*Cv[j];
            }
        }
        float ysum = y + __shfl_xor_sync(~0u, y, 1);
        if (!ph){
            y2h[base] = __float2half((ysum + uv*Dd) * siluf(zv));
        }
        dv = calc_delta(TN0, TN1, TN2, TN3);
        base = baseN; xr = xrN;
        uv = uvN; zv = zvN;
        B0 = B0N; B1 = B1N; C0 = C0N; C1 = C1N;
    }
}

// ---------------- head: partial GEMM per patch index p ----------------
__global__ void head_partial(const float* __restrict__ zf, const float* __restrict__ hw){
    int p = blockIdx.x, mt = blockIdx.y;
    __shared__ float As[16][64];
    __shared__ float Ws[16][96];
    int tid = threadIdx.x;                   // 256
    int lm = tid >> 2, lk = (tid & 3) * 4;
    int bkrow = mt*64 + lm;
    int b = bkrow >> 4, kk = bkrow & 15;
    const float* Ag = zf + (size_t)(b*SEQ + p*KVAR + kk)*DM + lk;
    int tx = tid & 15, ty = tid >> 4;
    float acc[4][6];
#pragma unroll
    for (int i = 0; i < 4; i++)
#pragma unroll
        for (int j = 0; j < 6; j++) acc[i][j] = 0.f;

    for (int kt = 0; kt < DM; kt += 16){
        float4 av = *(const float4*)(Ag + kt);
        As[lk+0][lm]=av.x; As[lk+1][lm]=av.y; As[lk+2][lm]=av.z; As[lk+3][lm]=av.w;
#pragma unroll
        for (int i = 0; i < 6; i++){
            int e = tid + i*256;
            int n = e >> 4, kq = e & 15;
            Ws[kq][n] = hw[(size_t)n*HWLD + p*DM + kt + kq];
        }
        __syncthreads();
#pragma unroll
        for (int k = 0; k < 16; k++){
            float4 a = *(const float4*)&As[k][ty*4];
            float av4[4] = {a.x, a.y, a.z, a.w};
#pragma unroll
            for (int j = 0; j < 6; j++){
                float wv = Ws[k][tx*6 + j];
#pragma unroll
                for (int i = 0; i < 4; i++) acc[i][j] += av4[i]*wv;
            }
        }
        __syncthreads();
    }
#pragma unroll
    for (int i = 0; i < 4; i++)
#pragma unroll
        for (int j = 0; j < 6; j++)
            g_headp[(size_t)(p*256 + mt*64 + ty*4 + i)*HPRED + tx*6 + j] = acc[i][j];
}

// ---------------- head reduction + de-normalization ----------------
__global__ void head_final(const float* __restrict__ hb, float* __restrict__ out){
    int idx = blockIdx.x*256 + threadIdx.x;
    int bk = idx / HPRED, hh = idx % HPRED;
    float s = 0.f;
    for (int p = 0; p < PP; p++) s += g_headp[(size_t)p*(BB*KVAR*HPRED) + idx];
    s += hb[hh];
    int b = bk >> 4, k = bk & 15;
    out[b*(HPRED*KVAR) + hh*KVAR + k] = s * g_std[bk] + g_mean[bk];
}

// ---------------- launch ----------------
extern "C" void kernel_launch(void* const* d_in, const int* in_sizes, int n_in,
                              void* d_out, int out_size){
    const float* x        = (const float*)d_in[0];
    const float* patch_w  = (const float*)d_in[1];
    const float* patch_b  = (const float*)d_in[2];
    const float* pos      = (const float*)d_in[3];
    const float* vemb     = (const float*)d_in[4];
    const float* in_w     = (const float*)d_in[5];
    const float* xp_w     = (const float*)d_in[6];
    const float* dt_w     = (const float*)d_in[7];
    const float* dt_b     = (const float*)d_in[8];
    const float* A_log    = (const float*)d_in[9];
    const float* D_par    = (const float*)d_in[10];
    const float* out_w    = (const float*)d_in[11];
    const float* tmb_g    = (const float*)d_in[12];
    const float* tmb_b    = (const float*)d_in[13];
    const float* ffn_g    = (const float*)d_in[14];
    const float* ffn_b    = (const float*)d_in[15];
    const float* ffn_w1   = (const float*)d_in[16];
    const float* ffn_b1   = (const float*)d_in[17];
    const float* ffn_w2   = (const float*)d_in[18];
    const float* ffn_b2   = (const float*)d_in[19];
    const float* norm_g   = (const float*)d_in[20];
    const float* norm_b   = (const float*)d_in[21];
    const float* head_w   = (const float*)d_in[22];
    const float* head_b   = (const float*)d_in[23];
    float* out = (float*)d_out;

    cudaFuncSetAttribute(gemm_h<EP_SPLIT>,    cudaFuncAttributeMaxDynamicSharedMemorySize, GH_SMEM);
    cudaFuncSetAttribute(gemm_h<EP_RES>,      cudaFuncAttributeMaxDynamicSharedMemorySize, GH_SMEM);
    cudaFuncSetAttribute(gemm_h<EP_GELU>,     cudaFuncAttributeMaxDynamicSharedMemorySize, GH_SMEM);
    cudaFuncSetAttribute(gemm_h<EP_BIAS_RES>, cudaFuncAttributeMaxDynamicSharedMemorySize, GH_SMEM);

    float *z, *tmp, *xdbl;
    __half *zh, *uh, *zgh, *y2h, *hlnh, *hffh;
    __half *winh, *wxph, *woh, *w1h, *w2h;
    cudaGetSymbolAddress((void**)&z,    g_z);
    cudaGetSymbolAddress((void**)&tmp,  g_tmp);
    cudaGetSymbolAddress((void**)&xdbl, g_xdbl);
    cudaGetSymbolAddress((void**)&zh,   g_zh);
    cudaGetSymbolAddress((void**)&uh,   g_uh);
    cudaGetSymbolAddress((void**)&zgh,  g_zgh);
    cudaGetSymbolAddress((void**)&y2h,  g_y2h);
    cudaGetSymbolAddress((void**)&hlnh, g_hlnh);
    cudaGetSymbolAddress((void**)&hffh, g_hffh);
    cudaGetSymbolAddress((void**)&winh, h_inw);
    cudaGetSymbolAddress((void**)&wxph, h_xpw);
    cudaGetSymbolAddress((void**)&woh,  h_ow);
    cudaGetSymbolAddress((void**)&w1h,  h_w1);
    cudaGetSymbolAddress((void**)&w2h,  h_w2);

    // weight conversions (fp32 -> fp16), all layers at once
    f2h_kernel<<<(3*2048*512/2 + 255)/256, 256>>>(in_w,  (__half2*)winh, 3*2048*512/2);
    f2h_kernel<<<(3*64*1024/2  + 255)/256, 256>>>(xp_w,  (__half2*)wxph, 3*64*1024/2);
    f2h_kernel<<<(3*512*1024/2 + 255)/256, 256>>>(out_w, (__half2*)woh,  3*512*1024/2);
    f2h_kernel<<<(3*2048*512/2 + 255)/256, 256>>>(ffn_w1,(__half2*)w1h,  3*2048*512/2);
    f2h_kernel<<<(3*512*2048/2 + 255)/256, 256>>>(ffn_w2,(__half2*)w2h,  3*512*2048/2);

    stats_kernel<<<BB*KVAR, 256>>>(x);
    embed_kernel<<<TT, 128>>>(x, patch_w, patch_b, pos, vemb);

    const int MT  = TT/128;   // 126 M tiles (128-row)
    const int MT32= TT/32;    // 504 M tiles (32-row)

    for (int l = 0; l < NLAY; l++){
        const __half* Wi  = winh + (size_t)l*(2*DIN)*DM;
        const __half* Wx  = wxph + (size_t)l*64*DIN;
        const float*  Wdt = dt_w + (size_t)l*DIN*RNK;
        const float*  bdt = dt_b + (size_t)l*DIN;
        const float*  Al  = A_log+ (size_t)l*DIN*NST;
        const float*  Dl  = D_par+ (size_t)l*DIN;
        const __half* Wo  = woh  + (size_t)l*DM*DIN;
        const __half* W1  = w1h  + (size_t)l*DFF*DM;
        const float*  B1  = ffn_b1 + (size_t)l*DFF;
        const __half* W2  = w2h  + (size_t)l*DM*DFF;
        const float*  B2  = ffn_b2 + (size_t)l*DM;

        // in_proj -> silu(u) fp16 (uh), zg fp16 (zgh)   (N=2048, K=512)
        gemm_h<EP_SPLIT><<<dim3(16, MT), 256, GH_SMEM>>>(zh, DM, Wi, DM,
                                                         nullptr, (float*)zgh, uh, 0, nullptr, nullptr);
        // x_proj: xdbl = u @ Wx^T   (N=64, K=1024)
        gemm_h32<EP_NONE><<<dim3(1, MT32), 128>>>(uh, DIN, Wx, DIN, xdbl, nullptr, nullptr, 64, nullptr, nullptr);
        // selective scan (fused dt_proj+softplus, +u*D, *silu(zg)) -> y2h fp16
        scan_kernel<<<128, 256>>>(uh, zgh, xdbl, Wdt, bdt, Al, Dl, y2h);
        // out_proj + residual into tmp  (N=512, K=1024)
        gemm_h<EP_RES><<<dim3(4, MT), 256, GH_SMEM>>>(y2h, DIN, Wo, DIN, tmp, nullptr, nullptr, DM, nullptr, z);
        // LN(tmp)->z fp32 ; LN(z)->hln fp16 (ffn pre-norm)
        ln_kernel<true><<<TT/8, 256>>>(tmp, tmb_g + l*DM, tmb_b + l*DM, z,
                                       ffn_g + l*DM, ffn_b + l*DM, hlnh);
        // FFN
        gemm_h<EP_GELU><<<dim3(16, MT), 256, GH_SMEM>>>(hlnh, DM, W1, DM, nullptr, nullptr, hffh, DFF, B1, nullptr);
        gemm_h<EP_BIAS_RES><<<dim3(4, MT), 256, GH_SMEM>>>(hffh, DFF, W2, DFF, z, nullptr, zh, DM, B2, z);
    }

    // final LN -> tmp
    ln_kernel<false><<<TT/8, 256>>>(z, norm_g, norm_b, tmp, nullptr, nullptr, nullptr);
    // head
    head_partial<<<dim3(PP, 4), 256>>>(tmp, head_w);
    head_final<<<96, 256>>>(head_b, out);
    (void)in_sizes; (void)n_in; (void)out_size;
}

// round 10
// speedup vs baseline: 1.5998x; 1.1532x over previous
#include <cuda_runtime.h>
#include <cuda_fp16.h>
#include <math.h>

// ---------------- problem constants ----------------
#define BB     16
#define LCTX   512
#define KVAR   16
#define HPRED  96
#define DM     512
#define NST    16
#define NLAY   3
#define DFF    2048
#define PATCH  16
#define STRIDEP 8
#define PP     63
#define DIN    1024
#define RNK    32
#define SEQ    (KVAR*PP)     // 1008
#define TT     (BB*SEQ)      // 16128
#define EPSF   1e-5f
#define HWLD   (PP*DM)

// ---------------- scratch ----------------
__device__ float g_mean[BB*KVAR];
__device__ float g_std[BB*KVAR];
__device__ float g_z   [TT*DM];
__device__ float g_tmp [TT*DM];
__device__ float g_xdbl[TT*64 + 64];
__device__ float g_headp[PP*BB*KVAR*HPRED];
// fp16 activations
__device__ __half g_zh  [TT*DM];
__device__ __half g_uh  [TT*DIN + DIN];
__device__ __half g_zgh [TT*DIN + DIN];
__device__ __half g_y2h [TT*DIN];
__device__ __half g_hlnh[TT*DM];
__device__ __half g_hffh[TT*DFF];
// fp16 weights (all layers)
__device__ __half h_inw[3*2048*512];
__device__ __half h_xpw[3*64*1024];
__device__ __half h_ow [3*512*1024];
__device__ __half h_w1 [3*2048*512];
__device__ __half h_w2 [3*512*2048];

// ---------------- helpers ----------------
__device__ __forceinline__ float siluf(float x){ return x / (1.f + __expf(-x)); }
__device__ __forceinline__ float geluf(float x){
    return 0.5f * x * (1.f + erff(x * 0.70710678118654752f));
}

__device__ __forceinline__ void cp16(void* smem, const void* g){
    unsigned a = (unsigned)__cvta_generic_to_shared(smem);
    asm volatile("cp.async.cg.shared.global [%0], [%1], 16;" :: "r"(a), "l"(g));
}
__device__ __forceinline__ void cp16s(unsigned saddr, const void* g){
    asm volatile("cp.async.cg.shared.global [%0], [%1], 16;" :: "r"(saddr), "l"(g));
}
__device__ __forceinline__ void cp_commit(){ asm volatile("cp.async.commit_group;"); }

__device__ __forceinline__ unsigned smem_u32(const void* p){
    unsigned a;
    asm("{ .reg .u64 t; cvta.to.shared.u64 t, %1; cvt.u32.u64 %0, t; }" : "=r"(a) : "l"(p));
    return a;
}

__device__ __forceinline__ void mma_f16(float* c, const unsigned* a, const unsigned* b){
    asm volatile("mma.sync.aligned.m16n8k16.row.col.f32.f16.f16.f32 "
        "{%0,%1,%2,%3}, {%4,%5,%6,%7}, {%8,%9}, {%0,%1,%2,%3};"
        : "+f"(c[0]),"+f"(c[1]),"+f"(c[2]),"+f"(c[3])
        : "r"(a[0]),"r"(a[1]),"r"(a[2]),"r"(a[3]), "r"(b[0]),"r"(b[1]));
}
__device__ __forceinline__ void ldsm4(unsigned &r0, unsigned &r1, unsigned &r2, unsigned &r3,
                                      unsigned addr){
    asm volatile("ldmatrix.sync.aligned.m8n8.x4.shared.b16 {%0,%1,%2,%3}, [%4];"
        : "=r"(r0),"=r"(r1),"=r"(r2),"=r"(r3) : "r"(addr));
}

// ---------------- fp32 -> fp16 conversion ----------------
__global__ void f2h_kernel(const float* __restrict__ in, __half2* __restrict__ out, int n2){
    int i = blockIdx.x*256 + threadIdx.x;
    if (i < n2){
        float2 v = ((const float2*)in)[i];
        out[i] = __floats2half2_rn(v.x, v.y);
    }
}

// ---------------- per-(b,k) mean/std over L ----------------
__global__ void stats_kernel(const float* __restrict__ x){
    int bk = blockIdx.x; int b = bk >> 4, k = bk & 15;
    int tid = threadIdx.x;
    float s = 0.f, q = 0.f;
    for (int l = tid; l < LCTX; l += 256){
        float v = x[(b*LCTX + l)*KVAR + k];
        s += v; q += v*v;
    }
    __shared__ float sh[64];
#pragma unroll
    for (int o = 16; o; o >>= 1){
        s += __shfl_xor_sync(~0u, s, o);
        q += __shfl_xor_sync(~0u, q, o);
    }
    int w = tid >> 5;
    if ((tid & 31) == 0){ sh[w] = s; sh[w+32] = q; }
    __syncthreads();
    if (tid == 0){
        float S = 0.f, Q = 0.f;
        for (int i = 0; i < 8; i++){ S += sh[i]; Q += sh[32+i]; }
        float mu  = S * (1.f/LCTX);
        float var = Q * (1.f/LCTX) - mu*mu;
        g_mean[bk] = mu;
        g_std[bk]  = sqrtf(var + EPSF);
    }
}

// ---------------- patch embedding + pos + var embed ----------------
__global__ void embed_kernel(const float* __restrict__ x,
                             const float* __restrict__ pw,
                             const float* __restrict__ pb,
                             const float* __restrict__ pos,
                             const float* __restrict__ vemb){
    int row = blockIdx.x;
    int b = row / SEQ, rem = row % SEQ;
    int p = rem >> 4, k = rem & 15;
    int bk = b*KVAR + k;
    __shared__ float xs[PATCH];
    int tid = threadIdx.x;                   // 128
    if (tid < PATCH){
        float v = x[(b*LCTX + p*STRIDEP + tid)*KVAR + k];
        xs[tid] = (v - g_mean[bk]) / g_std[bk];
    }
    __syncthreads();
#pragma unroll
    for (int j = 0; j < 4; j++){
        int d = tid + j*128;
        float acc = pb[d] + pos[p*DM + d] + vemb[k*DM + d];
        const float4* w4 = (const float4*)(pw + d*PATCH);
#pragma unroll
        for (int t4 = 0; t4 < 4; t4++){
            float4 w = w4[t4];
            acc += xs[t4*4+0]*w.x + xs[t4*4+1]*w.y + xs[t4*4+2]*w.z + xs[t4*4+3]*w.w;
        }
        g_z[row*DM + d] = acc;
        g_zh[row*DM + d] = __float2half(acc);
    }
}

// ---------------- epilogue modes ----------------
enum { EP_NONE=0, EP_SPLIT=1, EP_GELU=3, EP_BIAS_RES=4, EP_RES=5 };

template<int EP>
__device__ __forceinline__ void ep_store(float* __restrict__ out0, float* __restrict__ out1,
                                         __half* __restrict__ outh, int ldo,
                                         const float* __restrict__ bias,
                                         const float* __restrict__ res,
                                         int row, int col, float v0, float v1){
    if (EP == EP_NONE){
        out0[(size_t)row*ldo + col    ] = v0;
        out0[(size_t)row*ldo + col + 1] = v1;
    } else if (EP == EP_SPLIT){
        if (col < DIN){
            float s0 = siluf(v0), s1 = siluf(v1);
            *(__half2*)&outh[(size_t)row*DIN + col] = __floats2half2_rn(s0, s1);
        } else {
            __half* zgh = (__half*)out1;
            *(__half2*)&zgh[(size_t)row*DIN + col - DIN] = __floats2half2_rn(v0, v1);
        }
    } else if (EP == EP_GELU){
        float g0 = geluf(v0 + bias[col]);
        float g1 = geluf(v1 + bias[col+1]);
        *(__half2*)&outh[(size_t)row*ldo + col] = __floats2half2_rn(g0, g1);
    } else if (EP == EP_BIAS_RES){
        float f0 = v0 + bias[col]   + res[(size_t)row*ldo + col];
        float f1 = v1 + bias[col+1] + res[(size_t)row*ldo + col + 1];
        out0[(size_t)row*ldo + col    ] = f0;
        out0[(size_t)row*ldo + col + 1] = f1;
        *(__half2*)&outh[(size_t)row*ldo + col] = __floats2half2_rn(f0, f1);
    } else { // EP_RES
        out0[(size_t)row*ldo + col    ] = v0 + res[(size_t)row*ldo + col];
        out0[(size_t)row*ldo + col + 1] = v1 + res[(size_t)row*ldo + col + 1];
    }
}

// ---------------- fp16 NT GEMM, 128x128 block, BK=32, 5-stage cp.async ---
#define GH_PITCH 40
#define GH_PITCHB 80
#define GH_STG   (128*GH_PITCH)
#define GH_BOFF  (5*GH_STG)
#define GH_SMEM  (2*5*GH_STG*2)      // 102400 bytes

template<int EP>
__global__ void __launch_bounds__(256, 2) gemm_h(const __half* __restrict__ A, int lda,
                        const __half* __restrict__ W, int Kd,
                        float* __restrict__ out0, float* __restrict__ out1,
                        __half* __restrict__ outh, int ldo,
                        const float* __restrict__ bias, const float* __restrict__ res){
    extern __shared__ __half smh[];
    int tid = threadIdx.x;
    int nt = blockIdx.x, mt = blockIdx.y;
    int lane = tid & 31, wid = tid >> 5;
    int warpM = wid & 1, warpN = wid >> 1;      // 2 x 4
    int grp = lane >> 2, tig = lane & 3;

    const __half* Abase = A + (size_t)(mt*128)*lda;
    const __half* Wbase = W + (size_t)(nt*128)*Kd;

    int r  = tid >> 2;
    int kk = (tid & 3) * 8;

    unsigned smBytes = smem_u32(smh);
    int aRow  = lane & 15;
    int aKsel = (lane >> 4) * 8;
    int bRowSel = (lane & 7) + ((lane >> 4) * 8);
    int bKsel = ((lane >> 3) & 1) * 8;

    float acc[4][4][4];
#pragma unroll
    for (int i = 0; i < 4; i++)
#pragma unroll
        for (int j = 0; j < 4; j++)
#pragma unroll
            for (int h = 0; h < 4; h++) acc[i][j][h] = 0.f;

    int nK = Kd >> 5;

    auto issue = [&](int stage){
        int buf = stage % 5;
        int ko = stage * 32;
        cp16(&smh[buf*GH_STG + r*GH_PITCH + kk],               Abase + (size_t)r*lda      + ko + kk);
        cp16(&smh[buf*GH_STG + (r+64)*GH_PITCH + kk],          Abase + (size_t)(r+64)*lda + ko + kk);
        cp16(&smh[GH_BOFF + buf*GH_STG + r*GH_PITCH + kk],     Wbase + (size_t)r*Kd       + ko + kk);
        cp16(&smh[GH_BOFF + buf*GH_STG + (r+64)*GH_PITCH + kk],Wbase + (size_t)(r+64)*Kd  + ko + kk);
        cp_commit();
    };

#pragma unroll
    for (int s = 0; s < 4; s++){
        if (s < nK) issue(s); else cp_commit();
    }

    for (int kt = 0; kt < nK; kt++){
        asm volatile("cp.async.wait_group 3;");
        __syncthreads();
        if (kt + 4 < nK) issue(kt + 4); else cp_commit();

        unsigned aSt = smBytes + (unsigned)((kt % 5)*GH_STG*2);
        unsigned bSt = smBytes + (unsigned)((GH_BOFF + (kt % 5)*GH_STG)*2);
#pragma unroll
        for (int k0 = 0; k0 < 32; k0 += 16){
            unsigned a[4][4], b[4][2];
#pragma unroll
            for (int i = 0; i < 4; i++){
                unsigned addr = aSt + (unsigned)((warpM*64 + i*16 + aRow)*GH_PITCHB
                                                 + (k0 + aKsel)*2);
                ldsm4(a[i][0], a[i][1], a[i][2], a[i][3], addr);
            }
#pragma unroll
            for (int j2 = 0; j2 < 2; j2++){
                unsigned addr = bSt + (unsigned)((warpN*32 + j2*16 + bRowSel)*GH_PITCHB
                                                 + (k0 + bKsel)*2);
                ldsm4(b[2*j2][0], b[2*j2][1], b[2*j2+1][0], b[2*j2+1][1], addr);
            }
#pragma unroll
            for (int i = 0; i < 4; i++)
#pragma unroll
                for (int j = 0; j < 4; j++)
                    mma_f16(acc[i][j], a[i], b[j]);
        }
    }

#pragma unroll
    for (int i = 0; i < 4; i++){
#pragma unroll
        for (int j = 0; j < 4; j++){
            int col = nt*128 + warpN*32 + j*8 + 2*tig;
#pragma unroll
            for (int h = 0; h < 2; h++){
                int row = mt*128 + warpM*64 + i*16 + grp + h*8;
                ep_store<EP>(out0, out1, outh, ldo, bias, res, row, col,
                             acc[i][j][h*2+0], acc[i][j][h*2+1]);
            }
        }
    }
}

// ---------------- fp16 NT GEMM, 32x64 block, BK=32, 6-stage (x_proj) -----
template<int EP>
__global__ void __launch_bounds__(128, 3) gemm_h32(const __half* __restrict__ A, int lda,
                        const __half* __restrict__ W, int Kd,
                        float* __restrict__ out0, float* __restrict__ out1,
                        __half* __restrict__ outh, int ldo,
                        const float* __restrict__ bias, const float* __restrict__ res){
    __shared__ __align__(16) __half As[6][32*GH_PITCH];
    __shared__ __align__(16) __half Bs[6][64*GH_PITCH];
    int tid = threadIdx.x;
    int nt = blockIdx.x, mt = blockIdx.y;
    int lane = tid & 31, wid = tid >> 5;
    int grp = lane >> 2, tig = lane & 3;

    const __half* Abase = A + (size_t)(mt*32)*lda;
    const __half* Wbase = W + (size_t)(nt*64)*Kd;

    int r  = tid >> 2;
    int kk = (tid & 3) * 8;

    unsigned aBase0 = smem_u32(&As[0][0]);
    unsigned bBase0 = smem_u32(&Bs[0][0]);
    int aRow  = lane & 15;
    int aKsel = (lane >> 4) * 8;
    int bRowSel = (lane & 7) + ((lane >> 4) * 8);
    int bKsel = ((lane >> 3) & 1) * 8;

    float acc[2][2][4];
#pragma unroll
    for (int i = 0; i < 2; i++)
#pragma unroll
        for (int j = 0; j < 2; j++)
#pragma unroll
            for (int h = 0; h < 4; h++) acc[i][j][h] = 0.f;

    int nK = Kd >> 5;

    auto issue = [&](int stage){
        int buf = stage % 6;
        int ko = stage * 32;
        cp16(&As[buf][r*GH_PITCH + kk],        Abase + (size_t)r*lda       + ko + kk);
        cp16(&Bs[buf][r*GH_PITCH + kk],        Wbase + (size_t)r*Kd        + ko + kk);
        cp16(&Bs[buf][(r+32)*GH_PITCH + kk],   Wbase + (size_t)(r+32)*Kd   + ko + kk);
        cp_commit();
    };

#pragma unroll
    for (int s = 0; s < 5; s++){
        if (s < nK) issue(s); else cp_commit();
    }

    for (int kt = 0; kt < nK; kt++){
        asm volatile("cp.async.wait_group 4;");
        __syncthreads();
        if (kt + 5 < nK) issue(kt + 5); else cp_commit();
        unsigned aSt = aBase0 + (unsigned)((kt % 6)*32*GH_PITCHB);
        unsigned bSt = bBase0 + (unsigned)((kt % 6)*64*GH_PITCHB);
#pragma unroll
        for (int k0 = 0; k0 < 32; k0 += 16){
            unsigned a[2][4], b[2][2];
#pragma unroll
            for (int i = 0; i < 2; i++){
                unsigned addr = aSt + (unsigned)((i*16 + aRow)*GH_PITCHB + (k0 + aKsel)*2);
                ldsm4(a[i][0], a[i][1], a[i][2], a[i][3], addr);
            }
            {
                unsigned addr = bSt + (unsigned)((wid*16 + bRowSel)*GH_PITCHB + (k0 + bKsel)*2);
                ldsm4(b[0][0], b[0][1], b[1][0], b[1][1], addr);
            }
#pragma unroll
            for (int i = 0; i < 2; i++)
#pragma unroll
                for (int j = 0; j < 2; j++)
                    mma_f16(acc[i][j], a[i], b[j]);
        }
    }

#pragma unroll
    for (int i = 0; i < 2; i++){
#pragma unroll
        for (int j = 0; j < 2; j++){
            int col = nt*64 + wid*16 + j*8 + 2*tig;
#pragma unroll
            for (int h = 0; h < 2; h++){
                int row = mt*32 + i*16 + grp + h*8;
                ep_store<EP>(out0, out1, outh, ldo, bias, res, row, col,
                             acc[i][j][h*2+0], acc[i][j][h*2+1]);
            }
        }
    }
}

// ---------------- layer norm; optional 2nd LN to fp16 ----------------
template<bool DOUBLE>
__global__ void ln_kernel(const float* __restrict__ in,
                          const float* __restrict__ g1, const float* __restrict__ b1,
                          float* __restrict__ o1,
                          const float* __restrict__ g2, const float* __restrict__ b2,
                          __half* __restrict__ o2h){
    int w = threadIdx.x >> 5, lane = threadIdx.x & 31;
    int row = blockIdx.x*8 + w;
    const float4* in4 = (const float4*)(in + (size_t)row*DM);
    float4 v[4];
    float s = 0.f, q = 0.f;
#pragma unroll
    for (int i = 0; i < 4; i++){
        v[i] = in4[lane + 32*i];
        s += v[i].x + v[i].y + v[i].z + v[i].w;
        q += v[i].x*v[i].x + v[i].y*v[i].y + v[i].z*v[i].z + v[i].w*v[i].w;
    }
#pragma unroll
    for (int o = 16; o; o >>= 1){
        s += __shfl_xor_sync(~0u, s, o);
        q += __shfl_xor_sync(~0u, q, o);
    }
    float mu = s * (1.f/DM);
    float rs = rsqrtf(q*(1.f/DM) - mu*mu + EPSF);
    float4 zz[4];
    float s2 = 0.f, q2 = 0.f;
#pragma unroll
    for (int i = 0; i < 4; i++){
        float4 gg = ((const float4*)g1)[lane + 32*i];
        float4 bb = ((const float4*)b1)[lane + 32*i];
        zz[i].x = (v[i].x - mu)*rs*gg.x + bb.x;
        zz[i].y = (v[i].y - mu)*rs*gg.y + bb.y;
        zz[i].z = (v[i].z - mu)*rs*gg.z + bb.z;
        zz[i].w = (v[i].w - mu)*rs*gg.w + bb.w;
        if (DOUBLE){
            s2 += zz[i].x + zz[i].y + zz[i].z + zz[i].w;
            q2 += zz[i].x*zz[i].x + zz[i].y*zz[i].y + zz[i].z*zz[i].z + zz[i].w*zz[i].w;
        }
        ((float4*)(o1 + (size_t)row*DM))[lane + 32*i] = zz[i];
    }
    if (DOUBLE){
#pragma unroll
        for (int o = 16; o; o >>= 1){
            s2 += __shfl_xor_sync(~0u, s2, o);
            q2 += __shfl_xor_sync(~0u, q2, o);
        }
        float mu2 = s2 * (1.f/DM);
        float rs2 = rsqrtf(q2*(1.f/DM) - mu2*mu2 + EPSF);
        __half2* oo = (__half2*)(o2h + (size_t)row*DM);
#pragma unroll
        for (int i = 0; i < 4; i++){
            float4 gg = ((const float4*)g2)[lane + 32*i];
            float4 bb = ((const float4*)b2)[lane + 32*i];
            float o0 = (zz[i].x - mu2)*rs2*gg.x + bb.x;
            float o1v= (zz[i].y - mu2)*rs2*gg.y + bb.y;
            float o2v= (zz[i].z - mu2)*rs2*gg.z + bb.z;
            float o3 = (zz[i].w - mu2)*rs2*gg.w + bb.w;
            oo[2*(lane + 32*i)    ] = __floats2half2_rn(o0, o1v);
            oo[2*(lane + 32*i) + 1] = __floats2half2_rn(o2v, o3);
        }
    }
}

// ---------------- selective scan with per-warp cp.async ring ----------
// Block = (b, dblk); warp w owns d in [dblk*128 + w*16, +16), 2 lanes per d.
// Ring stage (320 B/warp): [0:32) u fp16x16, [32:64) zg fp16x16, [64:320) xdbl row (64 fp32).
// 16 stages deep; dv for step t+1 computed at step t from stage t+1.
#define SC_DEPTH 16
__global__ void __launch_bounds__(256) scan_kernel(
                            const __half* __restrict__ u,
                            const __half* __restrict__ zg,
                            const float* __restrict__ xdbl,
                            const float* __restrict__ Wdt,
                            const float* __restrict__ bdt,
                            const float* __restrict__ A_log,
                            const float* __restrict__ Dp,
                            __half* __restrict__ y2h){
    __shared__ __align__(16) char ring[8][SC_DEPTH][320];
    int blk = blockIdx.x;                    // 128 blocks
    int b = blk >> 3, dblk = blk & 7;
    int tid = threadIdx.x;
    int w = tid >> 5, lane = tid & 31;
    int ph = lane & 1;
    int d = dblk*128 + w*16 + (lane >> 1);
    int nb = ph * 8;

    float Aa[8];
#pragma unroll
    for (int j = 0; j < 8; j++) Aa[j] = -expf(A_log[d*NST + nb + j]);
    float A0 = Aa[0];
    float stepA = Aa[1] - Aa[0];
    bool prog = true;
#pragma unroll
    for (int j = 0; j < 8; j++){
        float e = A0 + (float)j * stepA;
        if (fabsf(Aa[j] - e) > 1e-5f*fabsf(e) + 1e-7f) prog = false;
    }
    float Dd = Dp[d];
    float bd = bdt[d];
    float wdt[16];
#pragma unroll
    for (int j = 0; j < 16; j++) wdt[j] = Wdt[d*RNK + ph*16 + j];

    float h[8];
#pragma unroll
    for (int j = 0; j < 8; j++) h[j] = 0.f;

    // global bases
    size_t uvbase = (size_t)(b*SEQ)*DIN + dblk*128 + w*16;   // half index of warp chunk at t=0
    const float* xrow = xdbl + (size_t)(b*SEQ)*64;
    size_t ybase = (size_t)(b*SEQ)*DIN + d;

    unsigned ring0 = smem_u32(&ring[w][0][0]);

    auto issue = [&](int t){
        unsigned sa = ring0 + (unsigned)((t % SC_DEPTH) * 320);
        if (lane < 20){
            if (lane < 2)
                cp16s(sa + lane*16, (const char*)u + (uvbase + (size_t)t*DIN)*2 + lane*16);
            else if (lane < 4)
                cp16s(sa + 32 + (lane-2)*16, (const char*)zg + (uvbase + (size_t)t*DIN)*2 + (lane-2)*16);
            else
                cp16s(sa + 64 + (lane-4)*16, (const char*)(xrow + (size_t)t*64) + (lane-4)*16);
        }
        cp_commit();
    };

    auto calc_delta = [&](const float* xd) -> float {
        const float4 T0 = *(const float4*)(xd + ph*16);
        const float4 T1 = *(const float4*)(xd + ph*16 + 4);
        const float4 T2 = *(const float4*)(xd + ph*16 + 8);
        const float4 T3 = *(const float4*)(xd + ph*16 + 12);
        float a0 = T0.x*wdt[0]  + T0.y*wdt[1]  + T0.z*wdt[2]  + T0.w*wdt[3];
        float a1 = T1.x*wdt[4]  + T1.y*wdt[5]  + T1.z*wdt[6]  + T1.w*wdt[7];
        float a2 = T2.x*wdt[8]  + T2.y*wdt[9]  + T2.z*wdt[10] + T2.w*wdt[11];
        float a3 = T3.x*wdt[12] + T3.y*wdt[13] + T3.z*wdt[14] + T3.w*wdt[15];
        float p = (a0 + a1) + (a2 + a3);
        p += __shfl_xor_sync(~0u, p, 1);
        float xv = p + bd;
        return fmaxf(xv, 0.f) + __logf(1.f + __expf(-fabsf(xv)));
    };

    // prefill 15 stages
#pragma unroll
    for (int t0 = 0; t0 < SC_DEPTH-1; t0++) issue(t0);

    // dv for t=0 from stage 0
    asm volatile("cp.async.wait_group %0;" :: "n"(SC_DEPTH-2));
    __syncwarp();
    float dv = calc_delta((const float*)(ring[w][0] + 64));

    for (int t = 0; t < SEQ; t++){
        asm volatile("cp.async.wait_group %0;" :: "n"(SC_DEPTH-3));  // stages t, t+1 done
        __syncwarp();
        // keep group count invariant: issue stage t+15 or empty commit
        if (t + SC_DEPTH-1 < SEQ) issue(t + SC_DEPTH-1);
        else cp_commit();

        const char* sp = ring[w][t % SC_DEPTH];
        float uv = __half2float(((const __half*)sp)[lane >> 1]);
        float zv = __half2float(((const __half*)(sp + 32))[lane >> 1]);
        const float* xd = (const float*)(sp + 64);
        float4 B0 = *(const float4*)(xd + 32 + nb);
        float4 B1 = *(const float4*)(xd + 36 + nb);
        float4 C0 = *(const float4*)(xd + 48 + nb);
        float4 C1 = *(const float4*)(xd + 52 + nb);

        float du = dv * uv;
        float y = 0.f;
        if (prog){
            float e = __expf(dv * A0);
            float rr = __expf(dv * stepA);
            h[0] = h[0]*e + du*B0.x; y += h[0]*C0.x; e *= rr;
            h[1] = h[1]*e + du*B0.y; y += h[1]*C0.y; e *= rr;
            h[2] = h[2]*e + du*B0.z; y += h[2]*C0.z; e *= rr;
            h[3] = h[3]*e + du*B0.w; y += h[3]*C0.w; e *= rr;
            h[4] = h[4]*e + du*B1.x; y += h[4]*C1.x; e *= rr;
            h[5] = h[5]*e + du*B1.y; y += h[5]*C1.y; e *= rr;
            h[6] = h[6]*e + du*B1.z; y += h[6]*C1.z; e *= rr;
            h[7] = h[7]*e + du*B1.w; y += h[7]*C1.w;
        } else {
            float Bv[8] = {B0.x,B0.y,B0.z,B0.w,B1.x,B1.y,B1.z,B1.w};
            float Cv[8] = {C0.x,C0.y,C0.z,C0.w,C1.x,C1.y,C1.z,C1.w};
#pragma unroll
            for (int j = 0; j < 8; j++){
                float e = __expf(dv * Aa[j]);
                h[j] = h[j]*e + du*Bv[j];
                y += h[j]*Cv[j];
            }
        }
        float ysum = y + __shfl_xor_sync(~0u, y, 1);
        if (!ph){
            y2h[ybase + (size_t)t*DIN] = __float2half((ysum + uv*Dd) * siluf(zv));
        }
        // dv for next step from stage t+1 (already waited)
        if (t + 1 < SEQ)
            dv = calc_delta((const float*)(ring[w][(t+1) % SC_DEPTH] + 64));
    }
}

// ---------------- head: partial GEMM per patch index p ----------------
__global__ void head_partial(const float* __restrict__ zf, const float* __restrict__ hw){
    int p = blockIdx.x, mt = blockIdx.y;
    __shared__ float As[16][64];
    __shared__ float Ws[16][96];
    int tid = threadIdx.x;                   // 256
    int lm = tid >> 2, lk = (tid & 3) * 4;
    int bkrow = mt*64 + lm;
    int b = bkrow >> 4, kk = bkrow & 15;
    const float* Ag = zf + (size_t)(b*SEQ + p*KVAR + kk)*DM + lk;
    int tx = tid & 15, ty = tid >> 4;
    float acc[4][6];
#pragma unroll
    for (int i = 0; i < 4; i++)
#pragma unroll
        for (int j = 0; j < 6; j++) acc[i][j] = 0.f;

    for (int kt = 0; kt < DM; kt += 16){
        float4 av = *(const float4*)(Ag + kt);
        As[lk+0][lm]=av.x; As[lk+1][lm]=av.y; As[lk+2][lm]=av.z; As[lk+3][lm]=av.w;
#pragma unroll
        for (int i = 0; i < 6; i++){
            int e = tid + i*256;
            int n = e >> 4, kq = e & 15;
            Ws[kq][n] = hw[(size_t)n*HWLD + p*DM + kt + kq];
        }
        __syncthreads();
#pragma unroll
        for (int k = 0; k < 16; k++){
            float4 a = *(const float4*)&As[k][ty*4];
            float av4[4] = {a.x, a.y, a.z, a.w};
#pragma unroll
            for (int j = 0; j < 6; j++){
                float wv = Ws[k][tx*6 + j];
#pragma unroll
                for (int i = 0; i < 4; i++) acc[i][j] += av4[i]*wv;
            }
        }
        __syncthreads();
    }
#pragma unroll
    for (int i = 0; i < 4; i++)
#pragma unroll
        for (int j = 0; j < 6; j++)
            g_headp[(size_t)(p*256 + mt*64 + ty*4 + i)*HPRED + tx*6 + j] = acc[i][j];
}

// ---------------- head reduction + de-normalization ----------------
__global__ void head_final(const float* __restrict__ hb, float* __restrict__ out){
    int idx = blockIdx.x*256 + threadIdx.x;
    int bk = idx / HPRED, hh = idx % HPRED;
    float s = 0.f;
    for (int p = 0; p < PP; p++) s += g_headp[(size_t)p*(BB*KVAR*HPRED) + idx];
    s += hb[hh];
    int b = bk >> 4, k = bk & 15;
    out[b*(HPRED*KVAR) + hh*KVAR + k] = s * g_std[bk] + g_mean[bk];
}

// ---------------- launch ----------------
extern "C" void kernel_launch(void* const* d_in, const int* in_sizes, int n_in,
                              void* d_out, int out_size){
    const float* x        = (const float*)d_in[0];
    const float* patch_w  = (const float*)d_in[1];
    const float* patch_b  = (const float*)d_in[2];
    const float* pos      = (const float*)d_in[3];
    const float* vemb     = (const float*)d_in[4];
    const float* in_w     = (const float*)d_in[5];
    const float* xp_w     = (const float*)d_in[6];
    const float* dt_w     = (const float*)d_in[7];
    const float* dt_b     = (const float*)d_in[8];
    const float* A_log    = (const float*)d_in[9];
    const float* D_par    = (const float*)d_in[10];
    const float* out_w    = (const float*)d_in[11];
    const float* tmb_g    = (const float*)d_in[12];
    const float* tmb_b    = (const float*)d_in[13];
    const float* ffn_g    = (const float*)d_in[14];
    const float* ffn_b    = (const float*)d_in[15];
    const float* ffn_w1   = (const float*)d_in[16];
    const float* ffn_b1   = (const float*)d_in[17];
    const float* ffn_w2   = (const float*)d_in[18];
    const float* ffn_b2   = (const float*)d_in[19];
    const float* norm_g   = (const float*)d_in[20];
    const float* norm_b   = (const float*)d_in[21];
    const float* head_w   = (const float*)d_in[22];
    const float* head_b   = (const float*)d_in[23];
    float* out = (float*)d_out;

    cudaFuncSetAttribute(gemm_h<EP_SPLIT>,    cudaFuncAttributeMaxDynamicSharedMemorySize, GH_SMEM);
    cudaFuncSetAttribute(gemm_h<EP_RES>,      cudaFuncAttributeMaxDynamicSharedMemorySize, GH_SMEM);
    cudaFuncSetAttribute(gemm_h<EP_GELU>,     cudaFuncAttributeMaxDynamicSharedMemorySize, GH_SMEM);
    cudaFuncSetAttribute(gemm_h<EP_BIAS_RES>, cudaFuncAttributeMaxDynamicSharedMemorySize, GH_SMEM);

    float *z, *tmp, *xdbl;
    __half *zh, *uh, *zgh, *y2h, *hlnh, *hffh;
    __half *winh, *wxph, *woh, *w1h, *w2h;
    cudaGetSymbolAddress((void**)&z,    g_z);
    cudaGetSymbolAddress((void**)&tmp,  g_tmp);
    cudaGetSymbolAddress((void**)&xdbl, g_xdbl);
    cudaGetSymbolAddress((void**)&zh,   g_zh);
    cudaGetSymbolAddress((void**)&uh,   g_uh);
    cudaGetSymbolAddress((void**)&zgh,  g_zgh);
    cudaGetSymbolAddress((void**)&y2h,  g_y2h);
    cudaGetSymbolAddress((void**)&hlnh, g_hlnh);
    cudaGetSymbolAddress((void**)&hffh, g_hffh);
    cudaGetSymbolAddress((void**)&winh, h_inw);
    cudaGetSymbolAddress((void**)&wxph, h_xpw);
    cudaGetSymbolAddress((void**)&woh,  h_ow);
    cudaGetSymbolAddress((void**)&w1h,  h_w1);
    cudaGetSymbolAddress((void**)&w2h,  h_w2);

    // weight conversions (fp32 -> fp16), all layers at once
    f2h_kernel<<<(3*2048*512/2 + 255)/256, 256>>>(in_w,  (__half2*)winh, 3*2048*512/2);
    f2h_kernel<<<(3*64*1024/2  + 255)/256, 256>>>(xp_w,  (__half2*)wxph, 3*64*1024/2);
    f2h_kernel<<<(3*512*1024/2 + 255)/256, 256>>>(out_w, (__half2*)woh,  3*512*1024/2);
    f2h_kernel<<<(3*2048*512/2 + 255)/256, 256>>>(ffn_w1,(__half2*)w1h,  3*2048*512/2);
    f2h_kernel<<<(3*512*2048/2 + 255)/256, 256>>>(ffn_w2,(__half2*)w2h,  3*512*2048/2);

    stats_kernel<<<BB*KVAR, 256>>>(x);
    embed_kernel<<<TT, 128>>>(x, patch_w, patch_b, pos, vemb);

    const int MT  = TT/128;   // 126 M tiles (128-row)
    const int MT32= TT/32;    // 504 M tiles (32-row)

    for (int l = 0; l < NLAY; l++){
        const __half* Wi  = winh + (size_t)l*(2*DIN)*DM;
        const __half* Wx  = wxph + (size_t)l*64*DIN;
        const float*  Wdt = dt_w + (size_t)l*DIN*RNK;
        const float*  bdt = dt_b + (size_t)l*DIN;
        const float*  Al  = A_log+ (size_t)l*DIN*NST;
        const float*  Dl  = D_par+ (size_t)l*DIN;
        const __half* Wo  = woh  + (size_t)l*DM*DIN;
        const __half* W1  = w1h  + (size_t)l*DFF*DM;
        const float*  B1  = ffn_b1 + (size_t)l*DFF;
        const __half* W2  = w2h  + (size_t)l*DM*DFF;
        const float*  B2  = ffn_b2 + (size_t)l*DM;

        // in_proj -> silu(u) fp16 (uh), zg fp16 (zgh)   (N=2048, K=512)
        gemm_h<EP_SPLIT><<<dim3(16, MT), 256, GH_SMEM>>>(zh, DM, Wi, DM,
                                                         nullptr, (float*)zgh, uh, 0, nullptr, nullptr);
        // x_proj: xdbl = u @ Wx^T   (N=64, K=1024)
        gemm_h32<EP_NONE><<<dim3(1, MT32), 128>>>(uh, DIN, Wx, DIN, xdbl, nullptr, nullptr, 64, nullptr, nullptr);
        // selective scan (fused dt_proj+softplus, +u*D, *silu(zg)) -> y2h fp16
        scan_kernel<<<128, 256>>>(uh, zgh, xdbl, Wdt, bdt, Al, Dl, y2h);
        // out_proj + residual into tmp  (N=512, K=1024)
        gemm_h<EP_RES><<<dim3(4, MT), 256, GH_SMEM>>>(y2h, DIN, Wo, DIN, tmp, nullptr, nullptr, DM, nullptr, z);
        // LN(tmp)->z fp32 ; LN(z)->hln fp16 (ffn pre-norm)
        ln_kernel<true><<<TT/8, 256>>>(tmp, tmb_g + l*DM, tmb_b + l*DM, z,
                                       ffn_g + l*DM, ffn_b + l*DM, hlnh);
        // FFN
        gemm_h<EP_GELU><<<dim3(16, MT), 256, GH_SMEM>>>(hlnh, DM, W1, DM, nullptr, nullptr, hffh, DFF, B1, nullptr);
        gemm_h<EP_BIAS_RES><<<dim3(4, MT), 256, GH_SMEM>>>(hffh, DFF, W2, DFF, z, nullptr, zh, DM, B2, z);
    }

    // final LN -> tmp
    ln_kernel<false><<<TT/8, 256>>>(z, norm_g, norm_b, tmp, nullptr, nullptr, nullptr);
    // head
    head_partial<<<dim3(PP, 4), 256>>>(tmp, head_w);
    head_final<<<96, 256>>>(head_b, out);
    (void)in_sizes; (void)n_in; (void)out_size;
}

// round 13
// speedup vs baseline: 1.6290x; 1.0183x over previous
#include <cuda_runtime.h>
#include <cuda_fp16.h>
#include <math.h>

// ---------------- problem constants ----------------
#define BB     16
#define LCTX   512
#define KVAR   16
#define HPRED  96
#define DM     512
#define NST    16
#define NLAY   3
#define DFF    2048
#define PATCH  16
#define STRIDEP 8
#define PP     63
#define DIN    1024
#define RNK    32
#define SEQ    (KVAR*PP)     // 1008
#define TT     (BB*SEQ)      // 16128
#define EPSF   1e-5f
#define HWLD   (PP*DM)       // 32256

// ---------------- scratch ----------------
__device__ float g_mean[BB*KVAR];
__device__ float g_std[BB*KVAR];
__device__ float g_z   [TT*DM];
__device__ float g_tmp [TT*DM];
__device__ float g_xdbl[TT*64 + 64];
__device__ float g_headp[PP*BB*KVAR*HPRED];
// fp16 activations
__device__ __half g_zh  [TT*DM];
__device__ __half g_uh  [TT*DIN + DIN];
__device__ __half g_zgh [TT*DIN + DIN];
__device__ __half g_y2h [TT*DIN];
__device__ __half g_hlnh[TT*DM];
__device__ __half g_hffh[TT*DFF];
// fp16 weights
__device__ __half h_inw[3*2048*512];
__device__ __half h_xpw[3*64*1024];
__device__ __half h_ow [3*512*1024];
__device__ __half h_w1 [3*2048*512];
__device__ __half h_w2 [3*512*2048];
__device__ __half h_hww[HPRED*HWLD];

// ---------------- helpers ----------------
__device__ __forceinline__ float siluf(float x){ return x / (1.f + __expf(-x)); }
__device__ __forceinline__ float geluf(float x){
    return 0.5f * x * (1.f + erff(x * 0.70710678118654752f));
}

__device__ __forceinline__ void cp16(void* smem, const void* g){
    unsigned a = (unsigned)__cvta_generic_to_shared(smem);
    asm volatile("cp.async.cg.shared.global [%0], [%1], 16;" :: "r"(a), "l"(g));
}
__device__ __forceinline__ void cp16s(unsigned saddr, const void* g){
    asm volatile("cp.async.cg.shared.global [%0], [%1], 16;" :: "r"(saddr), "l"(g));
}
__device__ __forceinline__ void cp_commit(){ asm volatile("cp.async.commit_group;"); }

__device__ __forceinline__ unsigned smem_u32(const void* p){
    unsigned a;
    asm("{ .reg .u64 t; cvta.to.shared.u64 t, %1; cvt.u32.u64 %0, t; }" : "=r"(a) : "l"(p));
    return a;
}

__device__ __forceinline__ void mma_f16(float* c, const unsigned* a, const unsigned* b){
    asm volatile("mma.sync.aligned.m16n8k16.row.col.f32.f16.f16.f32 "
        "{%0,%1,%2,%3}, {%4,%5,%6,%7}, {%8,%9}, {%0,%1,%2,%3};"
        : "+f"(c[0]),"+f"(c[1]),"+f"(c[2]),"+f"(c[3])
        : "r"(a[0]),"r"(a[1]),"r"(a[2]),"r"(a[3]), "r"(b[0]),"r"(b[1]));
}
__device__ __forceinline__ void ldsm4(unsigned &r0, unsigned &r1, unsigned &r2, unsigned &r3,
                                      unsigned addr){
    asm volatile("ldmatrix.sync.aligned.m8n8.x4.shared.b16 {%0,%1,%2,%3}, [%4];"
        : "=r"(r0),"=r"(r1),"=r"(r2),"=r"(r3) : "r"(addr));
}

// ---------------- fp32 -> fp16 conversion ----------------
__global__ void f2h_kernel(const float* __restrict__ in, __half2* __restrict__ out, int n2){
    int i = blockIdx.x*256 + threadIdx.x;
    if (i < n2){
        float2 v = ((const float2*)in)[i];
        out[i] = __floats2half2_rn(v.x, v.y);
    }
}

// ---------------- per-(b,k) mean/std over L ----------------
__global__ void stats_kernel(const float* __restrict__ x){
    int bk = blockIdx.x; int b = bk >> 4, k = bk & 15;
    int tid = threadIdx.x;
    float s = 0.f, q = 0.f;
    for (int l = tid; l < LCTX; l += 256){
        float v = x[(b*LCTX + l)*KVAR + k];
        s += v; q += v*v;
    }
    __shared__ float sh[64];
#pragma unroll
    for (int o = 16; o; o >>= 1){
        s += __shfl_xor_sync(~0u, s, o);
        q += __shfl_xor_sync(~0u, q, o);
    }
    int w = tid >> 5;
    if ((tid & 31) == 0){ sh[w] = s; sh[w+32] = q; }
    __syncthreads();
    if (tid == 0){
        float S = 0.f, Q = 0.f;
        for (int i = 0; i < 8; i++){ S += sh[i]; Q += sh[32+i]; }
        float mu  = S * (1.f/LCTX);
        float var = Q * (1.f/LCTX) - mu*mu;
        g_mean[bk] = mu;
        g_std[bk]  = sqrtf(var + EPSF);
    }
}

// ---------------- patch embedding + pos + var embed ----------------
__global__ void embed_kernel(const float* __restrict__ x,
                             const float* __restrict__ pw,
                             const float* __restrict__ pb,
                             const float* __restrict__ pos,
                             const float* __restrict__ vemb){
    int row = blockIdx.x;
    int b = row / SEQ, rem = row % SEQ;
    int p = rem >> 4, k = rem & 15;
    int bk = b*KVAR + k;
    __shared__ float xs[PATCH];
    int tid = threadIdx.x;                   // 128
    if (tid < PATCH){
        float v = x[(b*LCTX + p*STRIDEP + tid)*KVAR + k];
        xs[tid] = (v - g_mean[bk]) / g_std[bk];
    }
    __syncthreads();
#pragma unroll
    for (int j = 0; j < 4; j++){
        int d = tid + j*128;
        float acc = pb[d] + pos[p*DM + d] + vemb[k*DM + d];
        const float4* w4 = (const float4*)(pw + d*PATCH);
#pragma unroll
        for (int t4 = 0; t4 < 4; t4++){
            float4 w = w4[t4];
            acc += xs[t4*4+0]*w.x + xs[t4*4+1]*w.y + xs[t4*4+2]*w.z + xs[t4*4+3]*w.w;
        }
        g_z[row*DM + d] = acc;
        g_zh[row*DM + d] = __float2half(acc);
    }
}

// ---------------- epilogue modes ----------------
enum { EP_NONE=0, EP_SPLIT=1, EP_GELU=3, EP_BIAS_RES=4, EP_RES=5 };

template<int EP>
__device__ __forceinline__ void ep_store(float* __restrict__ out0, float* __restrict__ out1,
                                         __half* __restrict__ outh, int ldo,
                                         const float* __restrict__ bias,
                                         const float* __restrict__ res,
                                         int row, int col, float v0, float v1){
    if (EP == EP_NONE){
        out0[(size_t)row*ldo + col    ] = v0;
        out0[(size_t)row*ldo + col + 1] = v1;
    } else if (EP == EP_SPLIT){
        if (col < DIN){
            float s0 = siluf(v0), s1 = siluf(v1);
            *(__half2*)&outh[(size_t)row*DIN + col] = __floats2half2_rn(s0, s1);
        } else {
            __half* zgh = (__half*)out1;
            *(__half2*)&zgh[(size_t)row*DIN + col - DIN] = __floats2half2_rn(v0, v1);
        }
    } else if (EP == EP_GELU){
        float g0 = geluf(v0 + bias[col]);
        float g1 = geluf(v1 + bias[col+1]);
        *(__half2*)&outh[(size_t)row*ldo + col] = __floats2half2_rn(g0, g1);
    } else if (EP == EP_BIAS_RES){
        float f0 = v0 + bias[col]   + res[(size_t)row*ldo + col];
        float f1 = v1 + bias[col+1] + res[(size_t)row*ldo + col + 1];
        out0[(size_t)row*ldo + col    ] = f0;
        out0[(size_t)row*ldo + col + 1] = f1;
        *(__half2*)&outh[(size_t)row*ldo + col] = __floats2half2_rn(f0, f1);
    } else { // EP_RES
        out0[(size_t)row*ldo + col    ] = v0 + res[(size_t)row*ldo + col];
        out0[(size_t)row*ldo + col + 1] = v1 + res[(size_t)row*ldo + col + 1];
    }
}

// ---------------- fp16 NT GEMM, 128x128 block, BK=32, 5-stage cp.async ---
#define GH_PITCH 40
#define GH_PITCHB 80
#define GH_STG   (128*GH_PITCH)
#define GH_BOFF  (5*GH_STG)
#define GH_SMEM  (2*5*GH_STG*2)      // 102400 bytes

template<int EP>
__global__ void __launch_bounds__(256, 2) gemm_h(const __half* __restrict__ A, int lda,
                        const __half* __restrict__ W, int Kd,
                        float* __restrict__ out0, float* __restrict__ out1,
                        __half* __restrict__ outh, int ldo,
                        const float* __restrict__ bias, const float* __restrict__ res){
    extern __shared__ __half smh[];
    int tid = threadIdx.x;
    int nt = blockIdx.x, mt = blockIdx.y;
    int lane = tid & 31, wid = tid >> 5;
    int warpM = wid & 1, warpN = wid >> 1;      // 2 x 4
    int grp = lane >> 2, tig = lane & 3;

    const __half* Abase = A + (size_t)(mt*128)*lda;
    const __half* Wbase = W + (size_t)(nt*128)*Kd;

    int r  = tid >> 2;
    int kk = (tid & 3) * 8;

    unsigned smBytes = smem_u32(smh);
    int aRow  = lane & 15;
    int aKsel = (lane >> 4) * 8;
    int bRowSel = (lane & 7) + ((lane >> 4) * 8);
    int bKsel = ((lane >> 3) & 1) * 8;

    float acc[4][4][4];
#pragma unroll
    for (int i = 0; i < 4; i++)
#pragma unroll
        for (int j = 0; j < 4; j++)
#pragma unroll
            for (int h = 0; h < 4; h++) acc[i][j][h] = 0.f;

    int nK = Kd >> 5;

    auto issue = [&](int stage){
        int buf = stage % 5;
        int ko = stage * 32;
        cp16(&smh[buf*GH_STG + r*GH_PITCH + kk],               Abase + (size_t)r*lda      + ko + kk);
        cp16(&smh[buf*GH_STG + (r+64)*GH_PITCH + kk],          Abase + (size_t)(r+64)*lda + ko + kk);
        cp16(&smh[GH_BOFF + buf*GH_STG + r*GH_PITCH + kk],     Wbase + (size_t)r*Kd       + ko + kk);
        cp16(&smh[GH_BOFF + buf*GH_STG + (r+64)*GH_PITCH + kk],Wbase + (size_t)(r+64)*Kd  + ko + kk);
        cp_commit();
    };

#pragma unroll
    for (int s = 0; s < 4; s++){
        if (s < nK) issue(s); else cp_commit();
    }

    for (int kt = 0; kt < nK; kt++){
        asm volatile("cp.async.wait_group 3;");
        __syncthreads();
        if (kt + 4 < nK) issue(kt + 4); else cp_commit();

        unsigned aSt = smBytes + (unsigned)((kt % 5)*GH_STG*2);
        unsigned bSt = smBytes + (unsigned)((GH_BOFF + (kt % 5)*GH_STG)*2);
#pragma unroll
        for (int k0 = 0; k0 < 32; k0 += 16){
            unsigned a[4][4], b[4][2];
#pragma unroll
            for (int i = 0; i < 4; i++){
                unsigned addr = aSt + (unsigned)((warpM*64 + i*16 + aRow)*GH_PITCHB
                                                 + (k0 + aKsel)*2);
                ldsm4(a[i][0], a[i][1], a[i][2], a[i][3], addr);
            }
#pragma unroll
            for (int j2 = 0; j2 < 2; j2++){
                unsigned addr = bSt + (unsigned)((warpN*32 + j2*16 + bRowSel)*GH_PITCHB
                                                 + (k0 + bKsel)*2);
                ldsm4(b[2*j2][0], b[2*j2][1], b[2*j2+1][0], b[2*j2+1][1], addr);
            }
#pragma unroll
            for (int i = 0; i < 4; i++)
#pragma unroll
                for (int j = 0; j < 4; j++)
                    mma_f16(acc[i][j], a[i], b[j]);
        }
    }

#pragma unroll
    for (int i = 0; i < 4; i++){
#pragma unroll
        for (int j = 0; j < 4; j++){
            int col = nt*128 + warpN*32 + j*8 + 2*tig;
#pragma unroll
            for (int h = 0; h < 2; h++){
                int row = mt*128 + warpM*64 + i*16 + grp + h*8;
                ep_store<EP>(out0, out1, outh, ldo, bias, res, row, col,
                             acc[i][j][h*2+0], acc[i][j][h*2+1]);
            }
        }
    }
}

// ---------------- fp16 NT GEMM, 32x64 block, BK=32, 6-stage (x_proj) -----
template<int EP>
__global__ void __launch_bounds__(128, 3) gemm_h32(const __half* __restrict__ A, int lda,
                        const __half* __restrict__ W, int Kd,
                        float* __restrict__ out0, float* __restrict__ out1,
                        __half* __restrict__ outh, int ldo,
                        const float* __restrict__ bias, const float* __restrict__ res){
    __shared__ __align__(16) __half As[6][32*GH_PITCH];
    __shared__ __align__(16) __half Bs[6][64*GH_PITCH];
    int tid = threadIdx.x;
    int nt = blockIdx.x, mt = blockIdx.y;
    int lane = tid & 31, wid = tid >> 5;
    int grp = lane >> 2, tig = lane & 3;

    const __half* Abase = A + (size_t)(mt*32)*lda;
    const __half* Wbase = W + (size_t)(nt*64)*Kd;

    int r  = tid >> 2;
    int kk = (tid & 3) * 8;

    unsigned aBase0 = smem_u32(&As[0][0]);
    unsigned bBase0 = smem_u32(&Bs[0][0]);
    int aRow  = lane & 15;
    int aKsel = (lane >> 4) * 8;
    int bRowSel = (lane & 7) + ((lane >> 4) * 8);
    int bKsel = ((lane >> 3) & 1) * 8;

    float acc[2][2][4];
#pragma unroll
    for (int i = 0; i < 2; i++)
#pragma unroll
        for (int j = 0; j < 2; j++)
#pragma unroll
            for (int h = 0; h < 4; h++) acc[i][j][h] = 0.f;

    int nK = Kd >> 5;

    auto issue = [&](int stage){
        int buf = stage % 6;
        int ko = stage * 32;
        cp16(&As[buf][r*GH_PITCH + kk],        Abase + (size_t)r*lda       + ko + kk);
        cp16(&Bs[buf][r*GH_PITCH + kk],        Wbase + (size_t)r*Kd        + ko + kk);
        cp16(&Bs[buf][(r+32)*GH_PITCH + kk],   Wbase + (size_t)(r+32)*Kd   + ko + kk);
        cp_commit();
    };

#pragma unroll
    for (int s = 0; s < 5; s++){
        if (s < nK) issue(s); else cp_commit();
    }

    for (int kt = 0; kt < nK; kt++){
        asm volatile("cp.async.wait_group 4;");
        __syncthreads();
        if (kt + 5 < nK) issue(kt + 5); else cp_commit();
        unsigned aSt = aBase0 + (unsigned)((kt % 6)*32*GH_PITCHB);
        unsigned bSt = bBase0 + (unsigned)((kt % 6)*64*GH_PITCHB);
#pragma unroll
        for (int k0 = 0; k0 < 32; k0 += 16){
            unsigned a[2][4], b[2][2];
#pragma unroll
            for (int i = 0; i < 2; i++){
                unsigned addr = aSt + (unsigned)((i*16 + aRow)*GH_PITCHB + (k0 + aKsel)*2);
                ldsm4(a[i][0], a[i][1], a[i][2], a[i][3], addr);
            }
            {
                unsigned addr = bSt + (unsigned)((wid*16 + bRowSel)*GH_PITCHB + (k0 + bKsel)*2);
                ldsm4(b[0][0], b[0][1], b[1][0], b[1][1], addr);
            }
#pragma unroll
            for (int i = 0; i < 2; i++)
#pragma unroll
                for (int j = 0; j < 2; j++)
                    mma_f16(acc[i][j], a[i], b[j]);
        }
    }

#pragma unroll
    for (int i = 0; i < 2; i++){
#pragma unroll
        for (int j = 0; j < 2; j++){
            int col = nt*64 + wid*16 + j*8 + 2*tig;
#pragma unroll
            for (int h = 0; h < 2; h++){
                int row = mt*32 + i*16 + grp + h*8;
                ep_store<EP>(out0, out1, outh, ldo, bias, res, row, col,
                             acc[i][j][h*2+0], acc[i][j][h*2+1]);
            }
        }
    }
}

// ---------------- layer norm; 2nd LN / fp16 copy ----------------
template<bool DOUBLE>
__global__ void ln_kernel(const float* __restrict__ in,
                          const float* __restrict__ g1, const float* __restrict__ b1,
                          float* __restrict__ o1,
                          const float* __restrict__ g2, const float* __restrict__ b2,
                          __half* __restrict__ o2h){
    int w = threadIdx.x >> 5, lane = threadIdx.x & 31;
    int row = blockIdx.x*8 + w;
    const float4* in4 = (const float4*)(in + (size_t)row*DM);
    float4 v[4];
    float s = 0.f, q = 0.f;
#pragma unroll
    for (int i = 0; i < 4; i++){
        v[i] = in4[lane + 32*i];
        s += v[i].x + v[i].y + v[i].z + v[i].w;
        q += v[i].x*v[i].x + v[i].y*v[i].y + v[i].z*v[i].z + v[i].w*v[i].w;
    }
#pragma unroll
    for (int o = 16; o; o >>= 1){
        s += __shfl_xor_sync(~0u, s, o);
        q += __shfl_xor_sync(~0u, q, o);
    }
    float mu = s * (1.f/DM);
    float rs = rsqrtf(q*(1.f/DM) - mu*mu + EPSF);
    float4 zz[4];
    float s2 = 0.f, q2 = 0.f;
#pragma unroll
    for (int i = 0; i < 4; i++){
        float4 gg = ((const float4*)g1)[lane + 32*i];
        float4 bb = ((const float4*)b1)[lane + 32*i];
        zz[i].x = (v[i].x - mu)*rs*gg.x + bb.x;
        zz[i].y = (v[i].y - mu)*rs*gg.y + bb.y;
        zz[i].z = (v[i].z - mu)*rs*gg.z + bb.z;
        zz[i].w = (v[i].w - mu)*rs*gg.w + bb.w;
        if (DOUBLE){
            s2 += zz[i].x + zz[i].y + zz[i].z + zz[i].w;
            q2 += zz[i].x*zz[i].x + zz[i].y*zz[i].y + zz[i].z*zz[i].z + zz[i].w*zz[i].w;
        }
        ((float4*)(o1 + (size_t)row*DM))[lane + 32*i] = zz[i];
    }
    if (DOUBLE){
#pragma unroll
        for (int o = 16; o; o >>= 1){
            s2 += __shfl_xor_sync(~0u, s2, o);
            q2 += __shfl_xor_sync(~0u, q2, o);
        }
        float mu2 = s2 * (1.f/DM);
        float rs2 = rsqrtf(q2*(1.f/DM) - mu2*mu2 + EPSF);
        __half2* oo = (__half2*)(o2h + (size_t)row*DM);
#pragma unroll
        for (int i = 0; i < 4; i++){
            float4 gg = ((const float4*)g2)[lane + 32*i];
            float4 bb = ((const float4*)b2)[lane + 32*i];
            float o0 = (zz[i].x - mu2)*rs2*gg.x + bb.x;
            float o1v= (zz[i].y - mu2)*rs2*gg.y + bb.y;
            float o2v= (zz[i].z - mu2)*rs2*gg.z + bb.z;
            float o3 = (zz[i].w - mu2)*rs2*gg.w + bb.w;
            oo[2*(lane + 32*i)    ] = __floats2half2_rn(o0, o1v);
            oo[2*(lane + 32*i) + 1] = __floats2half2_rn(o2v, o3);
        }
    } else if (o2h){
        __half2* oo = (__half2*)(o2h + (size_t)row*DM);
#pragma unroll
        for (int i = 0; i < 4; i++){
            oo[2*(lane + 32*i)    ] = __floats2half2_rn(zz[i].x, zz[i].y);
            oo[2*(lane + 32*i) + 1] = __floats2half2_rn(zz[i].z, zz[i].w);
        }
    }
}

// ---------------- selective scan with per-warp cp.async ring (round 10) --
#define SC_DEPTH 16
__global__ void __launch_bounds__(256) scan_kernel(
                            const __half* __restrict__ u,
                            const __half* __restrict__ zg,
                            const float* __restrict__ xdbl,
                            const float* __restrict__ Wdt,
                            const float* __restrict__ bdt,
                            const float* __restrict__ A_log,
                            const float* __restrict__ Dp,
                            __half* __restrict__ y2h){
    __shared__ __align__(16) char ring[8][SC_DEPTH][320];
    int blk = blockIdx.x;                    // 128 blocks
    int b = blk >> 3, dblk = blk & 7;
    int tid = threadIdx.x;
    int w = tid >> 5, lane = tid & 31;
    int ph = lane & 1;
    int d = dblk*128 + w*16 + (lane >> 1);
    int nb = ph * 8;

    float Aa[8];
#pragma unroll
    for (int j = 0; j < 8; j++) Aa[j] = -expf(A_log[d*NST + nb + j]);
    float A0 = Aa[0];
    float stepA = Aa[1] - Aa[0];
    bool prog = true;
#pragma unroll
    for (int j = 0; j < 8; j++){
        float e = A0 + (float)j * stepA;
        if (fabsf(Aa[j] - e) > 1e-5f*fabsf(e) + 1e-7f) prog = false;
    }
    float Dd = Dp[d];
    float bd = bdt[d];
    float wdt[16];
#pragma unroll
    for (int j = 0; j < 16; j++) wdt[j] = Wdt[d*RNK + ph*16 + j];

    float h[8];
#pragma unroll
    for (int j = 0; j < 8; j++) h[j] = 0.f;

    size_t uvbase = (size_t)(b*SEQ)*DIN + dblk*128 + w*16;
    const float* xrow = xdbl + (size_t)(b*SEQ)*64;
    size_t ybase = (size_t)(b*SEQ)*DIN + d;

    unsigned ring0 = smem_u32(&ring[w][0][0]);

    auto issue = [&](int t){
        unsigned sa = ring0 + (unsigned)((t % SC_DEPTH) * 320);
        if (lane < 20){
            if (lane < 2)
                cp16s(sa + lane*16, (const char*)u + (uvbase + (size_t)t*DIN)*2 + lane*16);
            else if (lane < 4)
                cp16s(sa + 32 + (lane-2)*16, (const char*)zg + (uvbase + (size_t)t*DIN)*2 + (lane-2)*16);
            else
                cp16s(sa + 64 + (lane-4)*16, (const char*)(xrow + (size_t)t*64) + (lane-4)*16);
        }
        cp_commit();
    };

    auto calc_delta = [&](const float* xd) -> float {
        const float4 T0 = *(const float4*)(xd + ph*16);
        const float4 T1 = *(const float4*)(xd + ph*16 + 4);
        const float4 T2 = *(const float4*)(xd + ph*16 + 8);
        const float4 T3 = *(const float4*)(xd + ph*16 + 12);
        float a0 = T0.x*wdt[0]  + T0.y*wdt[1]  + T0.z*wdt[2]  + T0.w*wdt[3];
        float a1 = T1.x*wdt[4]  + T1.y*wdt[5]  + T1.z*wdt[6]  + T1.w*wdt[7];
        float a2 = T2.x*wdt[8]  + T2.y*wdt[9]  + T2.z*wdt[10] + T2.w*wdt[11];
        float a3 = T3.x*wdt[12] + T3.y*wdt[13] + T3.z*wdt[14] + T3.w*wdt[15];
        float p = (a0 + a1) + (a2 + a3);
        p += __shfl_xor_sync(~0u, p, 1);
        float xv = p + bd;
        return fmaxf(xv, 0.f) + __logf(1.f + __expf(-fabsf(xv)));
    };

#pragma unroll
    for (int t0 = 0; t0 < SC_DEPTH-1; t0++) issue(t0);

    asm volatile("cp.async.wait_group %0;" :: "n"(SC_DEPTH-2));
    __syncwarp();
    float dv = calc_delta((const float*)(ring[w][0] + 64));

    for (int t = 0; t < SEQ; t++){
        asm volatile("cp.async.wait_group %0;" :: "n"(SC_DEPTH-3));
        __syncwarp();
        if (t + SC_DEPTH-1 < SEQ) issue(t + SC_DEPTH-1);
        else cp_commit();

        const char* sp = ring[w][t % SC_DEPTH];
        float uv = __half2float(((const __half*)sp)[lane >> 1]);
        float zv = __half2float(((const __half*)(sp + 32))[lane >> 1]);
        const float* xd = (const float*)(sp + 64);
        float4 B0 = *(const float4*)(xd + 32 + nb);
        float4 B1 = *(const float4*)(xd + 36 + nb);
        float4 C0 = *(const float4*)(xd + 48 + nb);
        float4 C1 = *(const float4*)(xd + 52 + nb);

        float du = dv * uv;
        float y = 0.f;
        if (prog){
            float e = __expf(dv * A0);
            float rr = __expf(dv * stepA);
            h[0] = h[0]*e + du*B0.x; y += h[0]*C0.x; e *= rr;
            h[1] = h[1]*e + du*B0.y; y += h[1]*C0.y; e *= rr;
            h[2] = h[2]*e + du*B0.z; y += h[2]*C0.z; e *= rr;
            h[3] = h[3]*e + du*B0.w; y += h[3]*C0.w; e *= rr;
            h[4] = h[4]*e + du*B1.x; y += h[4]*C1.x; e *= rr;
            h[5] = h[5]*e + du*B1.y; y += h[5]*C1.y; e *= rr;
            h[6] = h[6]*e + du*B1.z; y += h[6]*C1.z; e *= rr;
            h[7] = h[7]*e + du*B1.w; y += h[7]*C1.w;
        } else {
            float Bv[8] = {B0.x,B0.y,B0.z,B0.w,B1.x,B1.y,B1.z,B1.w};
            float Cv[8] = {C0.x,C0.y,C0.z,C0.w,C1.x,C1.y,C1.z,C1.w};
#pragma unroll
            for (int j = 0; j < 8; j++){
                float e = __expf(dv * Aa[j]);
                h[j] = h[j]*e + du*Bv[j];
                y += h[j]*Cv[j];
            }
        }
        float ysum = y + __shfl_xor_sync(~0u, y, 1);
        if (!ph){
            y2h[ybase + (size_t)t*DIN] = __float2half((ysum + uv*Dd) * siluf(zv));
        }
        if (t + 1 < SEQ)
            dv = calc_delta((const float*)(ring[w][(t+1) % SC_DEPTH] + 64));
    }
}

// ---------------- head: fp16 MMA partial GEMM per patch index p ----------
// grid (PP, 2): block does 128 rows (b,k) x 96 cols for one p (K=512).
#define HB_PITCH  72
#define HB_PITCHB 144
#define HM_ASTG   (128*HB_PITCH)
#define HM_BSTG   (112*HB_PITCH)
#define HM_SMEM   (2*(HM_ASTG + HM_BSTG)*2)   // 69120 bytes

__global__ void __launch_bounds__(256) head_mma(const __half* __restrict__ zf,
                                                const __half* __restrict__ hw){
    extern __shared__ __half hsm[];
    __half* As = hsm;
    __half* Bs = hsm + 2*HM_ASTG;
    int p = blockIdx.x, mt = blockIdx.y;
    int tid = threadIdx.x, lane = tid & 31, wid = tid >> 5;
    int warpM = wid & 1, warpN = wid >> 1;     // 2 x 4; warp tile 64 x 24
    int grp = lane >> 2, tig = lane & 3;
    unsigned aB = smem_u32(As), bB = smem_u32(Bs);
    int aRow  = lane & 15;
    int aKsel = (lane >> 4) * 8;
    int bRowSel = (lane & 7) + ((lane >> 4) * 8);
    int bKsel = ((lane >> 3) & 1) * 8;

    // zero B pad rows [96,112) in both buffers: no uninitialized ldmatrix reads
    for (int idx = tid; idx < 2*16*HB_PITCH; idx += 256){
        int buf = idx / (16*HB_PITCH);
        int rem = idx - buf*(16*HB_PITCH);
        Bs[buf*HM_BSTG + 96*HB_PITCH + rem] = __float2half(0.f);
    }
    __syncthreads();

    float acc[4][3][4];
#pragma unroll
    for (int i = 0; i < 4; i++)
#pragma unroll
        for (int j = 0; j < 3; j++)
#pragma unroll
            for (int h = 0; h < 4; h++) acc[i][j][h] = 0.f;

    // each row = 64 halfs = 8 cp16 chunks of 8 halfs
    auto issue = [&](int kt){
        int buf = kt & 1;
#pragma unroll
        for (int i2 = 0; i2 < 4; i2++){        // A: 128 rows x 8 chunks = 1024
            int ca = tid + i2*256;
            int r = ca >> 3, cc = (ca & 7)*8;
            int R = mt*128 + r, bb = R >> 4, k2 = R & 15;
            cp16(&As[buf*HM_ASTG + r*HB_PITCH + cc],
                 zf + ((size_t)(bb*SEQ + p*KVAR + k2))*DM + kt*64 + cc);
        }
#pragma unroll
        for (int i2 = 0; i2 < 3; i2++){        // B: 96 rows x 8 chunks = 768
            int cb = tid + i2*256;
            int rn = cb >> 3, cc = (cb & 7)*8;
            cp16(&Bs[buf*HM_BSTG + rn*HB_PITCH + cc],
                 hw + (size_t)rn*HWLD + p*DM + kt*64 + cc);
        }
        cp_commit();
    };

    issue(0);
    for (int kt = 0; kt < 8; kt++){
        __syncthreads();                        // reads of previous buf done
        if (kt + 1 < 8) issue(kt + 1); else cp_commit();
        asm volatile("cp.async.wait_group 1;");
        __syncthreads();
        int buf = kt & 1;
        unsigned aSt = aB + (unsigned)(buf*HM_ASTG*2);
        unsigned bSt = bB + (unsigned)(buf*HM_BSTG*2);
#pragma unroll
        for (int k0 = 0; k0 < 64; k0 += 16){
            unsigned a[4][4], b[3][2], dump0, dump1;
#pragma unroll
            for (int i = 0; i < 4; i++){
                unsigned addr = aSt + (unsigned)((warpM*64 + i*16 + aRow)*HB_PITCHB
                                                 + (k0 + aKsel)*2);
                ldsm4(a[i][0], a[i][1], a[i][2], a[i][3], addr);
            }
            {
                unsigned addr = bSt + (unsigned)((warpN*24 + bRowSel)*HB_PITCHB + (k0 + bKsel)*2);
                ldsm4(b[0][0], b[0][1], b[1][0], b[1][1], addr);
                unsigned addr2 = bSt + (unsigned)((warpN*24 + 16 + bRowSel)*HB_PITCHB + (k0 + bKsel)*2);
                ldsm4(b[2][0], b[2][1], dump0, dump1, addr2);
            }
#pragma unroll
            for (int i = 0; i < 4; i++)
#pragma unroll
                for (int j = 0; j < 3; j++)
                    mma_f16(acc[i][j], a[i], b[j]);
        }
    }

#pragma unroll
    for (int i = 0; i < 4; i++){
#pragma unroll
        for (int j = 0; j < 3; j++){
            int col = warpN*24 + j*8 + 2*tig;
#pragma unroll
            for (int h = 0; h < 2; h++){
                int R = mt*128 + warpM*64 + i*16 + grp + h*8;
                g_headp[(size_t)(p*256 + R)*HPRED + col    ] = acc[i][j][h*2+0];
                g_headp[(size_t)(p*256 + R)*HPRED + col + 1] = acc[i][j][h*2+1];
            }
        }
    }
}

// ---------------- head reduction + de-normalization ----------------
__global__ void head_final(const float* __restrict__ hb, float* __restrict__ out){
    int idx = blockIdx.x*256 + threadIdx.x;
    int bk = idx / HPRED, hh = idx % HPRED;
    float s = 0.f;
    for (int p = 0; p < PP; p++) s += g_headp[(size_t)p*(BB*KVAR*HPRED) + idx];
    s += hb[hh];
    int b = bk >> 4, k = bk & 15;
    out[b*(HPRED*KVAR) + hh*KVAR + k] = s * g_std[bk] + g_mean[bk];
}

// ---------------- launch ----------------
extern "C" void kernel_launch(void* const* d_in, const int* in_sizes, int n_in,
                              void* d_out, int out_size){
    const float* x        = (const float*)d_in[0];
    const float* patch_w  = (const float*)d_in[1];
    const float* patch_b  = (const float*)d_in[2];
    const float* pos      = (const float*)d_in[3];
    const float* vemb     = (const float*)d_in[4];
    const float* in_w     = (const float*)d_in[5];
    const float* xp_w     = (const float*)d_in[6];
    const float* dt_w     = (const float*)d_in[7];
    const float* dt_b     = (const float*)d_in[8];
    const float* A_log    = (const float*)d_in[9];
    const float* D_par    = (const float*)d_in[10];
    const float* out_w    = (const float*)d_in[11];
    const float* tmb_g    = (const float*)d_in[12];
    const float* tmb_b    = (const float*)d_in[13];
    const float* ffn_g    = (const float*)d_in[14];
    const float* ffn_b    = (const float*)d_in[15];
    const float* ffn_w1   = (const float*)d_in[16];
    const float* ffn_b1   = (const float*)d_in[17];
    const float* ffn_w2   = (const float*)d_in[18];
    const float* ffn_b2   = (const float*)d_in[19];
    const float* norm_g   = (const float*)d_in[20];
    const float* norm_b   = (const float*)d_in[21];
    const float* head_w   = (const float*)d_in[22];
    const float* head_b   = (const float*)d_in[23];
    float* out = (float*)d_out;

    cudaFuncSetAttribute(gemm_h<EP_SPLIT>,    cudaFuncAttributeMaxDynamicSharedMemorySize, GH_SMEM);
    cudaFuncSetAttribute(gemm_h<EP_RES>,      cudaFuncAttributeMaxDynamicSharedMemorySize, GH_SMEM);
    cudaFuncSetAttribute(gemm_h<EP_GELU>,     cudaFuncAttributeMaxDynamicSharedMemorySize, GH_SMEM);
    cudaFuncSetAttribute(gemm_h<EP_BIAS_RES>, cudaFuncAttributeMaxDynamicSharedMemorySize, GH_SMEM);
    cudaFuncSetAttribute(head_mma,            cudaFuncAttributeMaxDynamicSharedMemorySize, HM_SMEM);

    float *z, *tmp, *xdbl;
    __half *zh, *uh, *zgh, *y2h, *hlnh, *hffh;
    __half *winh, *wxph, *woh, *w1h, *w2h, *hwwh;
    cudaGetSymbolAddress((void**)&z,    g_z);
    cudaGetSymbolAddress((void**)&tmp,  g_tmp);
    cudaGetSymbolAddress((void**)&xdbl, g_xdbl);
    cudaGetSymbolAddress((void**)&zh,   g_zh);
    cudaGetSymbolAddress((void**)&uh,   g_uh);
    cudaGetSymbolAddress((void**)&zgh,  g_zgh);
    cudaGetSymbolAddress((void**)&y2h,  g_y2h);
    cudaGetSymbolAddress((void**)&hlnh, g_hlnh);
    cudaGetSymbolAddress((void**)&hffh, g_hffh);
    cudaGetSymbolAddress((void**)&winh, h_inw);
    cudaGetSymbolAddress((void**)&wxph, h_xpw);
    cudaGetSymbolAddress((void**)&woh,  h_ow);
    cudaGetSymbolAddress((void**)&w1h,  h_w1);
    cudaGetSymbolAddress((void**)&w2h,  h_w2);
    cudaGetSymbolAddress((void**)&hwwh, h_hww);

    // weight conversions (fp32 -> fp16)
    f2h_kernel<<<(3*2048*512/2 + 255)/256, 256>>>(in_w,  (__half2*)winh, 3*2048*512/2);
    f2h_kernel<<<(3*64*1024/2  + 255)/256, 256>>>(xp_w,  (__half2*)wxph, 3*64*1024/2);
    f2h_kernel<<<(3*512*1024/2 + 255)/256, 256>>>(out_w, (__half2*)woh,  3*512*1024/2);
    f2h_kernel<<<(3*2048*512/2 + 255)/256, 256>>>(ffn_w1,(__half2*)w1h,  3*2048*512/2);
    f2h_kernel<<<(3*512*2048/2 + 255)/256, 256>>>(ffn_w2,(__half2*)w2h,  3*512*2048/2);
    f2h_kernel<<<(HPRED*HWLD/2 + 255)/256, 256>>>(head_w,(__half2*)hwwh, HPRED*HWLD/2);

    stats_kernel<<<BB*KVAR, 256>>>(x);
    embed_kernel<<<TT, 128>>>(x, patch_w, patch_b, pos, vemb);

    const int MT  = TT/128;
    const int MT32= TT/32;

    for (int l = 0; l < NLAY; l++){
        const __half* Wi  = winh + (size_t)l*(2*DIN)*DM;
        const __half* Wx  = wxph + (size_t)l*64*DIN;
        const float*  Wdt = dt_w + (size_t)l*DIN*RNK;
        const float*  bdt = dt_b + (size_t)l*DIN;
        const float*  Al  = A_log+ (size_t)l*DIN*NST;
        const float*  Dl  = D_par+ (size_t)l*DIN;
        const __half* Wo  = woh  + (size_t)l*DM*DIN;
        const __half* W1  = w1h  + (size_t)l*DFF*DM;
        const float*  B1  = ffn_b1 + (size_t)l*DFF;
        const __half* W2  = w2h  + (size_t)l*DM*DFF;
        const float*  B2  = ffn_b2 + (size_t)l*DM;

        gemm_h<EP_SPLIT><<<dim3(16, MT), 256, GH_SMEM>>>(zh, DM, Wi, DM,
                                                         nullptr, (float*)zgh, uh, 0, nullptr, nullptr);
        gemm_h32<EP_NONE><<<dim3(1, MT32), 128>>>(uh, DIN, Wx, DIN, xdbl, nullptr, nullptr, 64, nullptr, nullptr);
        scan_kernel<<<128, 256>>>(uh, zgh, xdbl, Wdt, bdt, Al, Dl, y2h);
        gemm_h<EP_RES><<<dim3(4, MT), 256, GH_SMEM>>>(y2h, DIN, Wo, DIN, tmp, nullptr, nullptr, DM, nullptr, z);
        ln_kernel<true><<<TT/8, 256>>>(tmp, tmb_g + l*DM, tmb_b + l*DM, z,
                                       ffn_g + l*DM, ffn_b + l*DM, hlnh);
        gemm_h<EP_GELU><<<dim3(16, MT), 256, GH_SMEM>>>(hlnh, DM, W1, DM, nullptr, nullptr, hffh, DFF, B1, nullptr);
        gemm_h<EP_BIAS_RES><<<dim3(4, MT), 256, GH_SMEM>>>(hffh, DFF, W2, DFF, z, nullptr, zh, DM, B2, z);
    }

    // final LN -> tmp (fp32) + hlnh (fp16 for head)
    ln_kernel<false><<<TT/8, 256>>>(z, norm_g, norm_b, tmp, nullptr, nullptr, hlnh);
    // head (fp16 MMA partials per p) + reduction
    head_mma<<<dim3(PP, 2), 256, HM_SMEM>>>(hlnh, hwwh);
    head_final<<<96, 256>>>(head_b, out);
    (void)in_sizes; (void)n_in; (void)out_size;
}

// round 14
// speedup vs baseline: 1.8405x; 1.1298x over previous
#include <cuda_runtime.h>
#include <cuda_fp16.h>
#include <math.h>

// ---------------- problem constants ----------------
#define BB     16
#define LCTX   512
#define KVAR   16
#define HPRED  96
#define DM     512
#define NST    16
#define NLAY   3
#define DFF    2048
#define PATCH  16
#define STRIDEP 8
#define PP     63
#define DIN    1024
#define RNK    32
#define SEQ    (KVAR*PP)     // 1008
#define TT     (BB*SEQ)      // 16128
#define EPSF   1e-5f
#define HWLD   (PP*DM)       // 32256
#define NCH    8             // scan chunks
#define CHL    (SEQ/NCH)     // 126 steps per chunk

// ---------------- scratch ----------------
__device__ float g_mean[BB*KVAR];
__device__ float g_std[BB*KVAR];
__device__ float g_z   [TT*DM];
__device__ float g_tmp [TT*DM];
__device__ float g_xdbl[TT*64 + 64];
__device__ float g_headp[PP*BB*KVAR*HPRED];
// chunked-scan state
__device__ float g_hch [NCH*BB*DIN*NST];
__device__ float g_hin [NCH*BB*DIN*NST];
__device__ float g_sumd[NCH*BB*DIN];
// fp16 activations
__device__ __half g_zh  [TT*DM];
__device__ __half g_uh  [TT*DIN + DIN];
__device__ __half g_zgh [TT*DIN + DIN];
__device__ __half g_y2h [TT*DIN];
__device__ __half g_hlnh[TT*DM];
__device__ __half g_hffh[TT*DFF];
// fp16 weights
__device__ __half h_inw[3*2048*512];
__device__ __half h_xpw[3*64*1024];
__device__ __half h_ow [3*512*1024];
__device__ __half h_w1 [3*2048*512];
__device__ __half h_w2 [3*512*2048];
__device__ __half h_hww[HPRED*HWLD];

// ---------------- helpers ----------------
__device__ __forceinline__ float siluf(float x){ return x / (1.f + __expf(-x)); }
__device__ __forceinline__ float geluf(float x){
    return 0.5f * x * (1.f + erff(x * 0.70710678118654752f));
}

__device__ __forceinline__ void cp16(void* smem, const void* g){
    unsigned a = (unsigned)__cvta_generic_to_shared(smem);
    asm volatile("cp.async.cg.shared.global [%0], [%1], 16;" :: "r"(a), "l"(g));
}
__device__ __forceinline__ void cp16s(unsigned saddr, const void* g){
    asm volatile("cp.async.cg.shared.global [%0], [%1], 16;" :: "r"(saddr), "l"(g));
}
__device__ __forceinline__ void cp_commit(){ asm volatile("cp.async.commit_group;"); }

__device__ __forceinline__ unsigned smem_u32(const void* p){
    unsigned a;
    asm("{ .reg .u64 t; cvta.to.shared.u64 t, %1; cvt.u32.u64 %0, t; }" : "=r"(a) : "l"(p));
    return a;
}

__device__ __forceinline__ void mma_f16(float* c, const unsigned* a, const unsigned* b){
    asm volatile("mma.sync.aligned.m16n8k16.row.col.f32.f16.f16.f32 "
        "{%0,%1,%2,%3}, {%4,%5,%6,%7}, {%8,%9}, {%0,%1,%2,%3};"
        : "+f"(c[0]),"+f"(c[1]),"+f"(c[2]),"+f"(c[3])
        : "r"(a[0]),"r"(a[1]),"r"(a[2]),"r"(a[3]), "r"(b[0]),"r"(b[1]));
}
__device__ __forceinline__ void ldsm4(unsigned &r0, unsigned &r1, unsigned &r2, unsigned &r3,
                                      unsigned addr){
    asm volatile("ldmatrix.sync.aligned.m8n8.x4.shared.b16 {%0,%1,%2,%3}, [%4];"
        : "=r"(r0),"=r"(r1),"=r"(r2),"=r"(r3) : "r"(addr));
}

// ---------------- fp32 -> fp16 conversion ----------------
__global__ void f2h_kernel(const float* __restrict__ in, __half2* __restrict__ out, int n2){
    int i = blockIdx.x*256 + threadIdx.x;
    if (i < n2){
        float2 v = ((const float2*)in)[i];
        out[i] = __floats2half2_rn(v.x, v.y);
    }
}

// ---------------- per-(b,k) mean/std over L ----------------
__global__ void stats_kernel(const float* __restrict__ x){
    int bk = blockIdx.x; int b = bk >> 4, k = bk & 15;
    int tid = threadIdx.x;
    float s = 0.f, q = 0.f;
    for (int l = tid; l < LCTX; l += 256){
        float v = x[(b*LCTX + l)*KVAR + k];
        s += v; q += v*v;
    }
    __shared__ float sh[64];
#pragma unroll
    for (int o = 16; o; o >>= 1){
        s += __shfl_xor_sync(~0u, s, o);
        q += __shfl_xor_sync(~0u, q, o);
    }
    int w = tid >> 5;
    if ((tid & 31) == 0){ sh[w] = s; sh[w+32] = q; }
    __syncthreads();
    if (tid == 0){
        float S = 0.f, Q = 0.f;
        for (int i = 0; i < 8; i++){ S += sh[i]; Q += sh[32+i]; }
        float mu  = S * (1.f/LCTX);
        float var = Q * (1.f/LCTX) - mu*mu;
        g_mean[bk] = mu;
        g_std[bk]  = sqrtf(var + EPSF);
    }
}

// ---------------- patch embedding + pos + var embed ----------------
__global__ void embed_kernel(const float* __restrict__ x,
                             const float* __restrict__ pw,
                             const float* __restrict__ pb,
                             const float* __restrict__ pos,
                             const float* __restrict__ vemb){
    int row = blockIdx.x;
    int b = row / SEQ, rem = row % SEQ;
    int p = rem >> 4, k = rem & 15;
    int bk = b*KVAR + k;
    __shared__ float xs[PATCH];
    int tid = threadIdx.x;                   // 128
    if (tid < PATCH){
        float v = x[(b*LCTX + p*STRIDEP + tid)*KVAR + k];
        xs[tid] = (v - g_mean[bk]) / g_std[bk];
    }
    __syncthreads();
#pragma unroll
    for (int j = 0; j < 4; j++){
        int d = tid + j*128;
        float acc = pb[d] + pos[p*DM + d] + vemb[k*DM + d];
        const float4* w4 = (const float4*)(pw + d*PATCH);
#pragma unroll
        for (int t4 = 0; t4 < 4; t4++){
            float4 w = w4[t4];
            acc += xs[t4*4+0]*w.x + xs[t4*4+1]*w.y + xs[t4*4+2]*w.z + xs[t4*4+3]*w.w;
        }
        g_z[row*DM + d] = acc;
        g_zh[row*DM + d] = __float2half(acc);
    }
}

// ---------------- epilogue modes ----------------
enum { EP_NONE=0, EP_SPLIT=1, EP_GELU=3, EP_BIAS_RES=4, EP_RES=5 };

template<int EP>
__device__ __forceinline__ void ep_store(float* __restrict__ out0, float* __restrict__ out1,
                                         __half* __restrict__ outh, int ldo,
                                         const float* __restrict__ bias,
                                         const float* __restrict__ res,
                                         int row, int col, float v0, float v1){
    if (EP == EP_NONE){
        out0[(size_t)row*ldo + col    ] = v0;
        out0[(size_t)row*ldo + col + 1] = v1;
    } else if (EP == EP_SPLIT){
        if (col < DIN){
            float s0 = siluf(v0), s1 = siluf(v1);
            *(__half2*)&outh[(size_t)row*DIN + col] = __floats2half2_rn(s0, s1);
        } else {
            __half* zgh = (__half*)out1;
            *(__half2*)&zgh[(size_t)row*DIN + col - DIN] = __floats2half2_rn(v0, v1);
        }
    } else if (EP == EP_GELU){
        float g0 = geluf(v0 + bias[col]);
        float g1 = geluf(v1 + bias[col+1]);
        *(__half2*)&outh[(size_t)row*ldo + col] = __floats2half2_rn(g0, g1);
    } else if (EP == EP_BIAS_RES){
        float f0 = v0 + bias[col]   + res[(size_t)row*ldo + col];
        float f1 = v1 + bias[col+1] + res[(size_t)row*ldo + col + 1];
        out0[(size_t)row*ldo + col    ] = f0;
        out0[(size_t)row*ldo + col + 1] = f1;
        *(__half2*)&outh[(size_t)row*ldo + col] = __floats2half2_rn(f0, f1);
    } else { // EP_RES
        out0[(size_t)row*ldo + col    ] = v0 + res[(size_t)row*ldo + col];
        out0[(size_t)row*ldo + col + 1] = v1 + res[(size_t)row*ldo + col + 1];
    }
}

// ---------------- fp16 NT GEMM, 128x128 block, BK=32, 5-stage cp.async ---
#define GH_PITCH 40
#define GH_PITCHB 80
#define GH_STG   (128*GH_PITCH)
#define GH_BOFF  (5*GH_STG)
#define GH_SMEM  (2*5*GH_STG*2)      // 102400 bytes

template<int EP>
__global__ void __launch_bounds__(256, 2) gemm_h(const __half* __restrict__ A, int lda,
                        const __half* __restrict__ W, int Kd,
                        float* __restrict__ out0, float* __restrict__ out1,
                        __half* __restrict__ outh, int ldo,
                        const float* __restrict__ bias, const float* __restrict__ res){
    extern __shared__ __half smh[];
    int tid = threadIdx.x;
    int nt = blockIdx.x, mt = blockIdx.y;
    int lane = tid & 31, wid = tid >> 5;
    int warpM = wid & 1, warpN = wid >> 1;      // 2 x 4
    int grp = lane >> 2, tig = lane & 3;

    const __half* Abase = A + (size_t)(mt*128)*lda;
    const __half* Wbase = W + (size_t)(nt*128)*Kd;

    int r  = tid >> 2;
    int kk = (tid & 3) * 8;

    unsigned smBytes = smem_u32(smh);
    int aRow  = lane & 15;
    int aKsel = (lane >> 4) * 8;
    int bRowSel = (lane & 7) + ((lane >> 4) * 8);
    int bKsel = ((lane >> 3) & 1) * 8;

    float acc[4][4][4];
#pragma unroll
    for (int i = 0; i < 4; i++)
#pragma unroll
        for (int j = 0; j < 4; j++)
#pragma unroll
            for (int h = 0; h < 4; h++) acc[i][j][h] = 0.f;

    int nK = Kd >> 5;

    auto issue = [&](int stage){
        int buf = stage % 5;
        int ko = stage * 32;
        cp16(&smh[buf*GH_STG + r*GH_PITCH + kk],               Abase + (size_t)r*lda      + ko + kk);
        cp16(&smh[buf*GH_STG + (r+64)*GH_PITCH + kk],          Abase + (size_t)(r+64)*lda + ko + kk);
        cp16(&smh[GH_BOFF + buf*GH_STG + r*GH_PITCH + kk],     Wbase + (size_t)r*Kd       + ko + kk);
        cp16(&smh[GH_BOFF + buf*GH_STG + (r+64)*GH_PITCH + kk],Wbase + (size_t)(r+64)*Kd  + ko + kk);
        cp_commit();
    };

#pragma unroll
    for (int s = 0; s < 4; s++){
        if (s < nK) issue(s); else cp_commit();
    }

    for (int kt = 0; kt < nK; kt++){
        asm volatile("cp.async.wait_group 3;");
        __syncthreads();
        if (kt + 4 < nK) issue(kt + 4); else cp_commit();

        unsigned aSt = smBytes + (unsigned)((kt % 5)*GH_STG*2);
        unsigned bSt = smBytes + (unsigned)((GH_BOFF + (kt % 5)*GH_STG)*2);
#pragma unroll
        for (int k0 = 0; k0 < 32; k0 += 16){
            unsigned a[4][4], b[4][2];
#pragma unroll
            for (int i = 0; i < 4; i++){
                unsigned addr = aSt + (unsigned)((warpM*64 + i*16 + aRow)*GH_PITCHB
                                                 + (k0 + aKsel)*2);
                ldsm4(a[i][0], a[i][1], a[i][2], a[i][3], addr);
            }
#pragma unroll
            for (int j2 = 0; j2 < 2; j2++){
                unsigned addr = bSt + (unsigned)((warpN*32 + j2*16 + bRowSel)*GH_PITCHB
                                                 + (k0 + bKsel)*2);
                ldsm4(b[2*j2][0], b[2*j2][1], b[2*j2+1][0], b[2*j2+1][1], addr);
            }
#pragma unroll
            for (int i = 0; i < 4; i++)
#pragma unroll
                for (int j = 0; j < 4; j++)
                    mma_f16(acc[i][j], a[i], b[j]);
        }
    }

#pragma unroll
    for (int i = 0; i < 4; i++){
#pragma unroll
        for (int j = 0; j < 4; j++){
            int col = nt*128 + warpN*32 + j*8 + 2*tig;
#pragma unroll
            for (int h = 0; h < 2; h++){
                int row = mt*128 + warpM*64 + i*16 + grp + h*8;
                ep_store<EP>(out0, out1, outh, ldo, bias, res, row, col,
                             acc[i][j][h*2+0], acc[i][j][h*2+1]);
            }
        }
    }
}

// ---------------- fp16 NT GEMM, 32x64 block, BK=32, 6-stage (x_proj) -----
template<int EP>
__global__ void __launch_bounds__(128, 3) gemm_h32(const __half* __restrict__ A, int lda,
                        const __half* __restrict__ W, int Kd,
                        float* __restrict__ out0, float* __restrict__ out1,
                        __half* __restrict__ outh, int ldo,
                        const float* __restrict__ bias, const float* __restrict__ res){
    __shared__ __align__(16) __half As[6][32*GH_PITCH];
    __shared__ __align__(16) __half Bs[6][64*GH_PITCH];
    int tid = threadIdx.x;
    int nt = blockIdx.x, mt = blockIdx.y;
    int lane = tid & 31, wid = tid >> 5;
    int grp = lane >> 2, tig = lane & 3;

    const __half* Abase = A + (size_t)(mt*32)*lda;
    const __half* Wbase = W + (size_t)(nt*64)*Kd;

    int r  = tid >> 2;
    int kk = (tid & 3) * 8;

    unsigned aBase0 = smem_u32(&As[0][0]);
    unsigned bBase0 = smem_u32(&Bs[0][0]);
    int aRow  = lane & 15;
    int aKsel = (lane >> 4) * 8;
    int bRowSel = (lane & 7) + ((lane >> 4) * 8);
    int bKsel = ((lane >> 3) & 1) * 8;

    float acc[2][2][4];
#pragma unroll
    for (int i = 0; i < 2; i++)
#pragma unroll
        for (int j = 0; j < 2; j++)
#pragma unroll
            for (int h = 0; h < 4; h++) acc[i][j][h] = 0.f;

    int nK = Kd >> 5;

    auto issue = [&](int stage){
        int buf = stage % 6;
        int ko = stage * 32;
        cp16(&As[buf][r*GH_PITCH + kk],        Abase + (size_t)r*lda       + ko + kk);
        cp16(&Bs[buf][r*GH_PITCH + kk],        Wbase + (size_t)r*Kd        + ko + kk);
        cp16(&Bs[buf][(r+32)*GH_PITCH + kk],   Wbase + (size_t)(r+32)*Kd   + ko + kk);
        cp_commit();
    };

#pragma unroll
    for (int s = 0; s < 5; s++){
        if (s < nK) issue(s); else cp_commit();
    }

    for (int kt = 0; kt < nK; kt++){
        asm volatile("cp.async.wait_group 4;");
        __syncthreads();
        if (kt + 5 < nK) issue(kt + 5); else cp_commit();
        unsigned aSt = aBase0 + (unsigned)((kt % 6)*32*GH_PITCHB);
        unsigned bSt = bBase0 + (unsigned)((kt % 6)*64*GH_PITCHB);
#pragma unroll
        for (int k0 = 0; k0 < 32; k0 += 16){
            unsigned a[2][4], b[2][2];
#pragma unroll
            for (int i = 0; i < 2; i++){
                unsigned addr = aSt + (unsigned)((i*16 + aRow)*GH_PITCHB + (k0 + aKsel)*2);
                ldsm4(a[i][0], a[i][1], a[i][2], a[i][3], addr);
            }
            {
                unsigned addr = bSt + (unsigned)((wid*16 + bRowSel)*GH_PITCHB + (k0 + bKsel)*2);
                ldsm4(b[0][0], b[0][1], b[1][0], b[1][1], addr);
            }
#pragma unroll
            for (int i = 0; i < 2; i++)
#pragma unroll
                for (int j = 0; j < 2; j++)
                    mma_f16(acc[i][j], a[i], b[j]);
        }
    }

#pragma unroll
    for (int i = 0; i < 2; i++){
#pragma unroll
        for (int j = 0; j < 2; j++){
            int col = nt*64 + wid*16 + j*8 + 2*tig;
#pragma unroll
            for (int h = 0; h < 2; h++){
                int row = mt*32 + i*16 + grp + h*8;
                ep_store<EP>(out0, out1, outh, ldo, bias, res, row, col,
                             acc[i][j][h*2+0], acc[i][j][h*2+1]);
            }
        }
    }
}

// ---------------- layer norm; 2nd LN / fp16 copy ----------------
template<bool DOUBLE>
__global__ void ln_kernel(const float* __restrict__ in,
                          const float* __restrict__ g1, const float* __restrict__ b1,
                          float* __restrict__ o1,
                          const float* __restrict__ g2, const float* __restrict__ b2,
                          __half* __restrict__ o2h){
    int w = threadIdx.x >> 5, lane = threadIdx.x & 31;
    int row = blockIdx.x*8 + w;
    const float4* in4 = (const float4*)(in + (size_t)row*DM);
    float4 v[4];
    float s = 0.f, q = 0.f;
#pragma unroll
    for (int i = 0; i < 4; i++){
        v[i] = in4[lane + 32*i];
        s += v[i].x + v[i].y + v[i].z + v[i].w;
        q += v[i].x*v[i].x + v[i].y*v[i].y + v[i].z*v[i].z + v[i].w*v[i].w;
    }
#pragma unroll
    for (int o = 16; o; o >>= 1){
        s += __shfl_xor_sync(~0u, s, o);
        q += __shfl_xor_sync(~0u, q, o);
    }
    float mu = s * (1.f/DM);
    float rs = rsqrtf(q*(1.f/DM) - mu*mu + EPSF);
    float4 zz[4];
    float s2 = 0.f, q2 = 0.f;
#pragma unroll
    for (int i = 0; i < 4; i++){
        float4 gg = ((const float4*)g1)[lane + 32*i];
        float4 bb = ((const float4*)b1)[lane + 32*i];
        zz[i].x = (v[i].x - mu)*rs*gg.x + bb.x;
        zz[i].y = (v[i].y - mu)*rs*gg.y + bb.y;
        zz[i].z = (v[i].z - mu)*rs*gg.z + bb.z;
        zz[i].w = (v[i].w - mu)*rs*gg.w + bb.w;
        if (DOUBLE){
            s2 += zz[i].x + zz[i].y + zz[i].z + zz[i].w;
            q2 += zz[i].x*zz[i].x + zz[i].y*zz[i].y + zz[i].z*zz[i].z + zz[i].w*zz[i].w;
        }
        ((float4*)(o1 + (size_t)row*DM))[lane + 32*i] = zz[i];
    }
    if (DOUBLE){
#pragma unroll
        for (int o = 16; o; o >>= 1){
            s2 += __shfl_xor_sync(~0u, s2, o);
            q2 += __shfl_xor_sync(~0u, q2, o);
        }
        float mu2 = s2 * (1.f/DM);
        float rs2 = rsqrtf(q2*(1.f/DM) - mu2*mu2 + EPSF);
        __half2* oo = (__half2*)(o2h + (size_t)row*DM);
#pragma unroll
        for (int i = 0; i < 4; i++){
            float4 gg = ((const float4*)g2)[lane + 32*i];
            float4 bb = ((const float4*)b2)[lane + 32*i];
            float o0 = (zz[i].x - mu2)*rs2*gg.x + bb.x;
            float o1v= (zz[i].y - mu2)*rs2*gg.y + bb.y;
            float o2v= (zz[i].z - mu2)*rs2*gg.z + bb.z;
            float o3 = (zz[i].w - mu2)*rs2*gg.w + bb.w;
            oo[2*(lane + 32*i)    ] = __floats2half2_rn(o0, o1v);
            oo[2*(lane + 32*i) + 1] = __floats2half2_rn(o2v, o3);
        }
    } else if (o2h){
        __half2* oo = (__half2*)(o2h + (size_t)row*DM);
#pragma unroll
        for (int i = 0; i < 4; i++){
            oo[2*(lane + 32*i)    ] = __floats2half2_rn(zz[i].x, zz[i].y);
            oo[2*(lane + 32*i) + 1] = __floats2half2_rn(zz[i].z, zz[i].w);
        }
    }
}

// ---------------- chunked selective scan ----------------
// Block = (b,dblk) x chunk; warp w owns 16 d's, 2 lanes per d (8 states each).
// Ring stage (320 B/warp): [0:32) u fp16x16, [32:64) zg fp16x16, [64:320) xdbl row.
#define SC_DEPTH 8

// Phase 1: local scan from h=0, output final h + sum(delta); no y.
__global__ void __launch_bounds__(256) scan_part1(
                            const __half* __restrict__ u,
                            const float* __restrict__ xdbl,
                            const float* __restrict__ Wdt,
                            const float* __restrict__ bdt,
                            const float* __restrict__ A_log){
    __shared__ __align__(16) char ring[8][SC_DEPTH][320];
    int blk = blockIdx.x;
    int b = blk >> 3, dblk = blk & 7;
    int chunk = blockIdx.y;
    int tid = threadIdx.x;
    int w = tid >> 5, lane = tid & 31;
    int ph = lane & 1;
    int d = dblk*128 + w*16 + (lane >> 1);
    int nb = ph * 8;
    int tbeg = chunk*CHL, tend = tbeg + CHL;

    float Aa[8];
#pragma unroll
    for (int j = 0; j < 8; j++) Aa[j] = -expf(A_log[d*NST + nb + j]);
    float A0 = Aa[0];
    float stepA = Aa[1] - Aa[0];
    bool prog = true;
#pragma unroll
    for (int j = 0; j < 8; j++){
        float e = A0 + (float)j * stepA;
        if (fabsf(Aa[j] - e) > 1e-5f*fabsf(e) + 1e-7f) prog = false;
    }
    float bd = bdt[d];
    float wdt[16];
#pragma unroll
    for (int j = 0; j < 16; j++) wdt[j] = Wdt[d*RNK + ph*16 + j];

    float h[8];
#pragma unroll
    for (int j = 0; j < 8; j++) h[j] = 0.f;
    float sumd = 0.f;

    size_t uvbase = (size_t)(b*SEQ)*DIN + dblk*128 + w*16;
    const float* xrow = xdbl + (size_t)(b*SEQ)*64;
    unsigned ring0 = smem_u32(&ring[w][0][0]);

    auto issue = [&](int t){
        unsigned sa = ring0 + (unsigned)((t % SC_DEPTH) * 320);
        if (lane < 2)
            cp16s(sa + lane*16, (const char*)u + (uvbase + (size_t)t*DIN)*2 + lane*16);
        else if (lane >= 4 && lane < 20)
            cp16s(sa + 64 + (lane-4)*16, (const char*)(xrow + (size_t)t*64) + (lane-4)*16);
        cp_commit();
    };

    auto calc_delta = [&](const float* xd) -> float {
        const float4 T0 = *(const float4*)(xd + ph*16);
        const float4 T1 = *(const float4*)(xd + ph*16 + 4);
        const float4 T2 = *(const float4*)(xd + ph*16 + 8);
        const float4 T3 = *(const float4*)(xd + ph*16 + 12);
        float a0 = T0.x*wdt[0]  + T0.y*wdt[1]  + T0.z*wdt[2]  + T0.w*wdt[3];
        float a1 = T1.x*wdt[4]  + T1.y*wdt[5]  + T1.z*wdt[6]  + T1.w*wdt[7];
        float a2 = T2.x*wdt[8]  + T2.y*wdt[9]  + T2.z*wdt[10] + T2.w*wdt[11];
        float a3 = T3.x*wdt[12] + T3.y*wdt[13] + T3.z*wdt[14] + T3.w*wdt[15];
        float p = (a0 + a1) + (a2 + a3);
        p += __shfl_xor_sync(~0u, p, 1);
        float xv = p + bd;
        return fmaxf(xv, 0.f) + __logf(1.f + __expf(-fabsf(xv)));
    };

#pragma unroll
    for (int t0 = 0; t0 < SC_DEPTH-1; t0++) issue(tbeg + t0);

    asm volatile("cp.async.wait_group %0;" :: "n"(SC_DEPTH-2));
    __syncwarp();
    float dv = calc_delta((const float*)(ring[w][tbeg % SC_DEPTH] + 64));

    for (int t = tbeg; t < tend; t++){
        asm volatile("cp.async.wait_group %0;" :: "n"(SC_DEPTH-3));
        __syncwarp();
        if (t + SC_DEPTH-1 < tend) issue(t + SC_DEPTH-1);
        else cp_commit();

        const char* sp = ring[w][t % SC_DEPTH];
        float uv = __half2float(((const __half*)sp)[lane >> 1]);
        const float* xd = (const float*)(sp + 64);
        float4 B0 = *(const float4*)(xd + 32 + nb);
        float4 B1 = *(const float4*)(xd + 36 + nb);

        sumd += dv;
        float du = dv * uv;
        if (prog){
            float e = __expf(dv * A0);
            float rr = __expf(dv * stepA);
            h[0] = h[0]*e + du*B0.x; e *= rr;
            h[1] = h[1]*e + du*B0.y; e *= rr;
            h[2] = h[2]*e + du*B0.z; e *= rr;
            h[3] = h[3]*e + du*B0.w; e *= rr;
            h[4] = h[4]*e + du*B1.x; e *= rr;
            h[5] = h[5]*e + du*B1.y; e *= rr;
            h[6] = h[6]*e + du*B1.z; e *= rr;
            h[7] = h[7]*e + du*B1.w;
        } else {
            float Bv[8] = {B0.x,B0.y,B0.z,B0.w,B1.x,B1.y,B1.z,B1.w};
#pragma unroll
            for (int j = 0; j < 8; j++){
                float e = __expf(dv * Aa[j]);
                h[j] = h[j]*e + du*Bv[j];
            }
        }
        if (t + 1 < tend)
            dv = calc_delta((const float*)(ring[w][(t+1) % SC_DEPTH] + 64));
    }

    size_t obase = (((size_t)(chunk*BB + b)*DIN + d))*NST + nb;
    *(float4*)&g_hch[obase]   = make_float4(h[0], h[1], h[2], h[3]);
    *(float4*)&g_hch[obase+4] = make_float4(h[4], h[5], h[6], h[7]);
    if (!ph) g_sumd[(size_t)(chunk*BB + b)*DIN + d] = sumd;
}

// Combine: sequential over 8 chunk states per (b,d,n); writes h_in per chunk.
__global__ void scan_combine(const float* __restrict__ A_log){
    int idx = blockIdx.x*256 + threadIdx.x;     // 262144 threads
    int n = idx & 15;
    int d = (idx >> 4) & 1023;
    int b = idx >> 14;
    float An = -expf(A_log[d*NST + n]);
    float h = 0.f;
#pragma unroll
    for (int c = 0; c < NCH; c++){
        size_t base = (size_t)(c*BB + b)*DIN + d;
        g_hin[base*NST + n] = h;
        h = __expf(An * g_sumd[base]) * h + g_hch[base*NST + n];
    }
}

// Phase 2: scan with true h_in, produce y.
__global__ void __launch_bounds__(256) scan_part2(
                            const __half* __restrict__ u,
                            const __half* __restrict__ zg,
                            const float* __restrict__ xdbl,
                            const float* __restrict__ Wdt,
                            const float* __restrict__ bdt,
                            const float* __restrict__ A_log,
                            const float* __restrict__ Dp,
                            __half* __restrict__ y2h){
    __shared__ __align__(16) char ring[8][SC_DEPTH][320];
    int blk = blockIdx.x;
    int b = blk >> 3, dblk = blk & 7;
    int chunk = blockIdx.y;
    int tid = threadIdx.x;
    int w = tid >> 5, lane = tid & 31;
    int ph = lane & 1;
    int d = dblk*128 + w*16 + (lane >> 1);
    int nb = ph * 8;
    int tbeg = chunk*CHL, tend = tbeg + CHL;

    float Aa[8];
#pragma unroll
    for (int j = 0; j < 8; j++) Aa[j] = -expf(A_log[d*NST + nb + j]);
    float A0 = Aa[0];
    float stepA = Aa[1] - Aa[0];
    bool prog = true;
#pragma unroll
    for (int j = 0; j < 8; j++){
        float e = A0 + (float)j * stepA;
        if (fabsf(Aa[j] - e) > 1e-5f*fabsf(e) + 1e-7f) prog = false;
    }
    float Dd = Dp[d];
    float bd = bdt[d];
    float wdt[16];
#pragma unroll
    for (int j = 0; j < 16; j++) wdt[j] = Wdt[d*RNK + ph*16 + j];

    float h[8];
    {
        size_t ibase = (((size_t)(chunk*BB + b)*DIN + d))*NST + nb;
        float4 h0 = *(const float4*)&g_hin[ibase];
        float4 h1 = *(const float4*)&g_hin[ibase+4];
        h[0]=h0.x; h[1]=h0.y; h[2]=h0.z; h[3]=h0.w;
        h[4]=h1.x; h[5]=h1.y; h[6]=h1.z; h[7]=h1.w;
    }

    size_t uvbase = (size_t)(b*SEQ)*DIN + dblk*128 + w*16;
    const float* xrow = xdbl + (size_t)(b*SEQ)*64;
    size_t ybase = (size_t)(b*SEQ)*DIN + d;
    unsigned ring0 = smem_u32(&ring[w][0][0]);

    auto issue = [&](int t){
        unsigned sa = ring0 + (unsigned)((t % SC_DEPTH) * 320);
        if (lane < 20){
            if (lane < 2)
                cp16s(sa + lane*16, (const char*)u + (uvbase + (size_t)t*DIN)*2 + lane*16);
            else if (lane < 4)
                cp16s(sa + 32 + (lane-2)*16, (const char*)zg + (uvbase + (size_t)t*DIN)*2 + (lane-2)*16);
            else
                cp16s(sa + 64 + (lane-4)*16, (const char*)(xrow + (size_t)t*64) + (lane-4)*16);
        }
        cp_commit();
    };

    auto calc_delta = [&](const float* xd) -> float {
        const float4 T0 = *(const float4*)(xd + ph*16);
        const float4 T1 = *(const float4*)(xd + ph*16 + 4);
        const float4 T2 = *(const float4*)(xd + ph*16 + 8);
        const float4 T3 = *(const float4*)(xd + ph*16 + 12);
        float a0 = T0.x*wdt[0]  + T0.y*wdt[1]  + T0.z*wdt[2]  + T0.w*wdt[3];
        float a1 = T1.x*wdt[4]  + T1.y*wdt[5]  + T1.z*wdt[6]  + T1.w*wdt[7];
        float a2 = T2.x*wdt[8]  + T2.y*wdt[9]  + T2.z*wdt[10] + T2.w*wdt[11];
        float a3 = T3.x*wdt[12] + T3.y*wdt[13] + T3.z*wdt[14] + T3.w*wdt[15];
        float p = (a0 + a1) + (a2 + a3);
        p += __shfl_xor_sync(~0u, p, 1);
        float xv = p + bd;
        return fmaxf(xv, 0.f) + __logf(1.f + __expf(-fabsf(xv)));
    };

#pragma unroll
    for (int t0 = 0; t0 < SC_DEPTH-1; t0++) issue(tbeg + t0);

    asm volatile("cp.async.wait_group %0;" :: "n"(SC_DEPTH-2));
    __syncwarp();
    float dv = calc_delta((const float*)(ring[w][tbeg % SC_DEPTH] + 64));

    for (int t = tbeg; t < tend; t++){
        asm volatile("cp.async.wait_group %0;" :: "n"(SC_DEPTH-3));
        __syncwarp();
        if (t + SC_DEPTH-1 < tend) issue(t + SC_DEPTH-1);
        else cp_commit();

        const char* sp = ring[w][t % SC_DEPTH];
        float uv = __half2float(((const __half*)sp)[lane >> 1]);
        float zv = __half2float(((const __half*)(sp + 32))[lane >> 1]);
        const float* xd = (const float*)(sp + 64);
        float4 B0 = *(const float4*)(xd + 32 + nb);
        float4 B1 = *(const float4*)(xd + 36 + nb);
        float4 C0 = *(const float4*)(xd + 48 + nb);
        float4 C1 = *(const float4*)(xd + 52 + nb);

        float du = dv * uv;
        float y = 0.f;
        if (prog){
            float e = __expf(dv * A0);
            float rr = __expf(dv * stepA);
            h[0] = h[0]*e + du*B0.x; y += h[0]*C0.x; e *= rr;
            h[1] = h[1]*e + du*B0.y; y += h[1]*C0.y; e *= rr;
            h[2] = h[2]*e + du*B0.z; y += h[2]*C0.z; e *= rr;
            h[3] = h[3]*e + du*B0.w; y += h[3]*C0.w; e *= rr;
            h[4] = h[4]*e + du*B1.x; y += h[4]*C1.x; e *= rr;
            h[5] = h[5]*e + du*B1.y; y += h[5]*C1.y; e *= rr;
            h[6] = h[6]*e + du*B1.z; y += h[6]*C1.z; e *= rr;
            h[7] = h[7]*e + du*B1.w; y += h[7]*C1.w;
        } else {
            float Bv[8] = {B0.x,B0.y,B0.z,B0.w,B1.x,B1.y,B1.z,B1.w};
            float Cv[8] = {C0.x,C0.y,C0.z,C0.w,C1.x,C1.y,C1.z,C1.w};
#pragma unroll
            for (int j = 0; j < 8; j++){
                float e = __expf(dv * Aa[j]);
                h[j] = h[j]*e + du*Bv[j];
                y += h[j]*Cv[j];
            }
        }
        float ysum = y + __shfl_xor_sync(~0u, y, 1);
        if (!ph){
            y2h[ybase + (size_t)t*DIN] = __float2half((ysum + uv*Dd) * siluf(zv));
        }
        if (t + 1 < tend)
            dv = calc_delta((const float*)(ring[w][(t+1) % SC_DEPTH] + 64));
    }
}

// ---------------- head: fp16 MMA partial GEMM per patch index p ----------
// grid (PP, 2): block does 128 rows (b,k) x 96 cols for one p (K=512).
#define HB_PITCH  72
#define HB_PITCHB 144
#define HM_ASTG   (128*HB_PITCH)
#define HM_BSTG   (112*HB_PITCH)
#define HM_SMEM   (2*(HM_ASTG + HM_BSTG)*2)   // 69120 bytes

__global__ void __launch_bounds__(256) head_mma(const __half* __restrict__ zf,
                                                const __half* __restrict__ hw){
    extern __shared__ __half hsm[];
    __half* As = hsm;
    __half* Bs = hsm + 2*HM_ASTG;
    int p = blockIdx.x, mt = blockIdx.y;
    int tid = threadIdx.x, lane = tid & 31, wid = tid >> 5;
    int warpM = wid & 1, warpN = wid >> 1;     // 2 x 4; warp tile 64 x 24
    int grp = lane >> 2, tig = lane & 3;
    unsigned aB = smem_u32(As), bB = smem_u32(Bs);
    int aRow  = lane & 15;
    int aKsel = (lane >> 4) * 8;
    int bRowSel = (lane & 7) + ((lane >> 4) * 8);
    int bKsel = ((lane >> 3) & 1) * 8;

    // zero B pad rows [96,112) in both buffers
    for (int idx = tid; idx < 2*16*HB_PITCH; idx += 256){
        int buf = idx / (16*HB_PITCH);
        int rem = idx - buf*(16*HB_PITCH);
        Bs[buf*HM_BSTG + 96*HB_PITCH + rem] = __float2half(0.f);
    }
    __syncthreads();

    float acc[4][3][4];
#pragma unroll
    for (int i = 0; i < 4; i++)
#pragma unroll
        for (int j = 0; j < 3; j++)
#pragma unroll
            for (int h = 0; h < 4; h++) acc[i][j][h] = 0.f;

    // each row = 64 halfs = 8 cp16 chunks of 8 halfs
    auto issue = [&](int kt){
        int buf = kt & 1;
#pragma unroll
        for (int i2 = 0; i2 < 4; i2++){        // A: 128 rows x 8 chunks = 1024
            int ca = tid + i2*256;
            int r = ca >> 3, cc = (ca & 7)*8;
            int R = mt*128 + r, bb = R >> 4, k2 = R & 15;
            cp16(&As[buf*HM_ASTG + r*HB_PITCH + cc],
                 zf + ((size_t)(bb*SEQ + p*KVAR + k2))*DM + kt*64 + cc);
        }
#pragma unroll
        for (int i2 = 0; i2 < 3; i2++){        // B: 96 rows x 8 chunks = 768
            int cb = tid + i2*256;
            int rn = cb >> 3, cc = (cb & 7)*8;
            cp16(&Bs[buf*HM_BSTG + rn*HB_PITCH + cc],
                 hw + (size_t)rn*HWLD + p*DM + kt*64 + cc);
        }
        cp_commit();
    };

    issue(0);
    for (int kt = 0; kt < 8; kt++){
        __syncthreads();
        if (kt + 1 < 8) issue(kt + 1); else cp_commit();
        asm volatile("cp.async.wait_group 1;");
        __syncthreads();
        int buf = kt & 1;
        unsigned aSt = aB + (unsigned)(buf*HM_ASTG*2);
        unsigned bSt = bB + (unsigned)(buf*HM_BSTG*2);
#pragma unroll
        for (int k0 = 0; k0 < 64; k0 += 16){
            unsigned a[4][4], b[3][2], dump0, dump1;
#pragma unroll
            for (int i = 0; i < 4; i++){
                unsigned addr = aSt + (unsigned)((warpM*64 + i*16 + aRow)*HB_PITCHB
                                                 + (k0 + aKsel)*2);
                ldsm4(a[i][0], a[i][1], a[i][2], a[i][3], addr);
            }
            {
                unsigned addr = bSt + (unsigned)((warpN*24 + bRowSel)*HB_PITCHB + (k0 + bKsel)*2);
                ldsm4(b[0][0], b[0][1], b[1][0], b[1][1], addr);
                unsigned addr2 = bSt + (unsigned)((warpN*24 + 16 + bRowSel)*HB_PITCHB + (k0 + bKsel)*2);
                ldsm4(b[2][0], b[2][1], dump0, dump1, addr2);
            }
#pragma unroll
            for (int i = 0; i < 4; i++)
#pragma unroll
                for (int j = 0; j < 3; j++)
                    mma_f16(acc[i][j], a[i], b[j]);
        }
    }

#pragma unroll
    for (int i = 0; i < 4; i++){
#pragma unroll
        for (int j = 0; j < 3; j++){
            int col = warpN*24 + j*8 + 2*tig;
#pragma unroll
            for (int h = 0; h < 2; h++){
                int R = mt*128 + warpM*64 + i*16 + grp + h*8;
                g_headp[(size_t)(p*256 + R)*HPRED + col    ] = acc[i][j][h*2+0];
                g_headp[(size_t)(p*256 + R)*HPRED + col + 1] = acc[i][j][h*2+1];
            }
        }
    }
}

// ---------------- head reduction + de-normalization ----------------
__global__ void head_final(const float* __restrict__ hb, float* __restrict__ out){
    int idx = blockIdx.x*256 + threadIdx.x;
    int bk = idx / HPRED, hh = idx % HPRED;
    float s = 0.f;
    for (int p = 0; p < PP; p++) s += g_headp[(size_t)p*(BB*KVAR*HPRED) + idx];
    s += hb[hh];
    int b = bk >> 4, k = bk & 15;
    out[b*(HPRED*KVAR) + hh*KVAR + k] = s * g_std[bk] + g_mean[bk];
}

// ---------------- launch ----------------
extern "C" void kernel_launch(void* const* d_in, const int* in_sizes, int n_in,
                              void* d_out, int out_size){
    const float* x        = (const float*)d_in[0];
    const float* patch_w  = (const float*)d_in[1];
    const float* patch_b  = (const float*)d_in[2];
    const float* pos      = (const float*)d_in[3];
    const float* vemb     = (const float*)d_in[4];
    const float* in_w     = (const float*)d_in[5];
    const float* xp_w     = (const float*)d_in[6];
    const float* dt_w     = (const float*)d_in[7];
    const float* dt_b     = (const float*)d_in[8];
    const float* A_log    = (const float*)d_in[9];
    const float* D_par    = (const float*)d_in[10];
    const float* out_w    = (const float*)d_in[11];
    const float* tmb_g    = (const float*)d_in[12];
    const float* tmb_b    = (const float*)d_in[13];
    const float* ffn_g    = (const float*)d_in[14];
    const float* ffn_b    = (const float*)d_in[15];
    const float* ffn_w1   = (const float*)d_in[16];
    const float* ffn_b1   = (const float*)d_in[17];
    const float* ffn_w2   = (const float*)d_in[18];
    const float* ffn_b2   = (const float*)d_in[19];
    const float* norm_g   = (const float*)d_in[20];
    const float* norm_b   = (const float*)d_in[21];
    const float* head_w   = (const float*)d_in[22];
    const float* head_b   = (const float*)d_in[23];
    float* out = (float*)d_out;

    cudaFuncSetAttribute(gemm_h<EP_SPLIT>,    cudaFuncAttributeMaxDynamicSharedMemorySize, GH_SMEM);
    cudaFuncSetAttribute(gemm_h<EP_RES>,      cudaFuncAttributeMaxDynamicSharedMemorySize, GH_SMEM);
    cudaFuncSetAttribute(gemm_h<EP_GELU>,     cudaFuncAttributeMaxDynamicSharedMemorySize, GH_SMEM);
    cudaFuncSetAttribute(gemm_h<EP_BIAS_RES>, cudaFuncAttributeMaxDynamicSharedMemorySize, GH_SMEM);
    cudaFuncSetAttribute(head_mma,            cudaFuncAttributeMaxDynamicSharedMemorySize, HM_SMEM);

    float *z, *tmp, *xdbl;
    __half *zh, *uh, *zgh, *y2h, *hlnh, *hffh;
    __half *winh, *wxph, *woh, *w1h, *w2h, *hwwh;
    cudaGetSymbolAddress((void**)&z,    g_z);
    cudaGetSymbolAddress((void**)&tmp,  g_tmp);
    cudaGetSymbolAddress((void**)&xdbl, g_xdbl);
    cudaGetSymbolAddress((void**)&zh,   g_zh);
    cudaGetSymbolAddress((void**)&uh,   g_uh);
    cudaGetSymbolAddress((void**)&zgh,  g_zgh);
    cudaGetSymbolAddress((void**)&y2h,  g_y2h);
    cudaGetSymbolAddress((void**)&hlnh, g_hlnh);
    cudaGetSymbolAddress((void**)&hffh, g_hffh);
    cudaGetSymbolAddress((void**)&winh, h_inw);
    cudaGetSymbolAddress((void**)&wxph, h_xpw);
    cudaGetSymbolAddress((void**)&woh,  h_ow);
    cudaGetSymbolAddress((void**)&w1h,  h_w1);
    cudaGetSymbolAddress((void**)&w2h,  h_w2);
    cudaGetSymbolAddress((void**)&hwwh, h_hww);

    // weight conversions (fp32 -> fp16)
    f2h_kernel<<<(3*2048*512/2 + 255)/256, 256>>>(in_w,  (__half2*)winh, 3*2048*512/2);
    f2h_kernel<<<(3*64*1024/2  + 255)/256, 256>>>(xp_w,  (__half2*)wxph, 3*64*1024/2);
    f2h_kernel<<<(3*512*1024/2 + 255)/256, 256>>>(out_w, (__half2*)woh,  3*512*1024/2);
    f2h_kernel<<<(3*2048*512/2 + 255)/256, 256>>>(ffn_w1,(__half2*)w1h,  3*2048*512/2);
    f2h_kernel<<<(3*512*2048/2 + 255)/256, 256>>>(ffn_w2,(__half2*)w2h,  3*512*2048/2);
    f2h_kernel<<<(HPRED*HWLD/2 + 255)/256, 256>>>(head_w,(__half2*)hwwh, HPRED*HWLD/2);

    stats_kernel<<<BB*KVAR, 256>>>(x);
    embed_kernel<<<TT, 128>>>(x, patch_w, patch_b, pos, vemb);

    const int MT  = TT/128;
    const int MT32= TT/32;

    for (int l = 0; l < NLAY; l++){
        const __half* Wi  = winh + (size_t)l*(2*DIN)*DM;
        const __half* Wx  = wxph + (size_t)l*64*DIN;
        const float*  Wdt = dt_w + (size_t)l*DIN*RNK;
        const float*  bdt = dt_b + (size_t)l*DIN;
        const float*  Al  = A_log+ (size_t)l*DIN*NST;
        const float*  Dl  = D_par+ (size_t)l*DIN;
        const __half* Wo  = woh  + (size_t)l*DM*DIN;
        const __half* W1  = w1h  + (size_t)l*DFF*DM;
        const float*  B1  = ffn_b1 + (size_t)l*DFF;
        const __half* W2  = w2h  + (size_t)l*DM*DFF;
        const float*  B2  = ffn_b2 + (size_t)l*DM;

        gemm_h<EP_SPLIT><<<dim3(16, MT), 256, GH_SMEM>>>(zh, DM, Wi, DM,
                                                         nullptr, (float*)zgh, uh, 0, nullptr, nullptr);
        gemm_h32<EP_NONE><<<dim3(1, MT32), 128>>>(uh, DIN, Wx, DIN, xdbl, nullptr, nullptr, 64, nullptr, nullptr);
        // chunked selective scan (exact combine)
        scan_part1<<<dim3(128, NCH), 256>>>(uh, xdbl, Wdt, bdt, Al);
        scan_combine<<<1024, 256>>>(Al);
        scan_part2<<<dim3(128, NCH), 256>>>(uh, zgh, xdbl, Wdt, bdt, Al, Dl, y2h);
        gemm_h<EP_RES><<<dim3(4, MT), 256, GH_SMEM>>>(y2h, DIN, Wo, DIN, tmp, nullptr, nullptr, DM, nullptr, z);
        ln_kernel<true><<<TT/8, 256>>>(tmp, tmb_g + l*DM, tmb_b + l*DM, z,
                                       ffn_g + l*DM, ffn_b + l*DM, hlnh);
        gemm_h<EP_GELU><<<dim3(16, MT), 256, GH_SMEM>>>(hlnh, DM, W1, DM, nullptr, nullptr, hffh, DFF, B1, nullptr);
        gemm_h<EP_BIAS_RES><<<dim3(4, MT), 256, GH_SMEM>>>(hffh, DFF, W2, DFF, z, nullptr, zh, DM, B2, z);
    }

    // final LN -> tmp (fp32) + hlnh (fp16 for head)
    ln_kernel<false><<<TT/8, 256>>>(z, norm_g, norm_b, tmp, nullptr, nullptr, hlnh);
    // head (fp16 MMA partials per p) + reduction
    head_mma<<<dim3(PP, 2), 256, HM_SMEM>>>(hlnh, hwwh);
    head_final<<<96, 256>>>(head_b, out);
    (void)in_sizes; (void)n_in; (void)out_size;
}

// round 15
// speedup vs baseline: 1.8507x; 1.0055x over previous
#include <cuda_runtime.h>
#include <cuda_fp16.h>
#include <math.h>

// ---------------- problem constants ----------------
#define BB     16
#define LCTX   512
#define KVAR   16
#define HPRED  96
#define DM     512
#define NST    16
#define NLAY   3
#define DFF    2048
#define PATCH  16
#define STRIDEP 8
#define PP     63
#define DIN    1024
#define RNK    32
#define SEQ    (KVAR*PP)     // 1008
#define TT     (BB*SEQ)      // 16128
#define EPSF   1e-5f
#define HWLD   (PP*DM)       // 32256
#define NCH    16            // scan chunks
#define CHL    (SEQ/NCH)     // 63 steps per chunk

// ---------------- scratch ----------------
__device__ float g_mean[BB*KVAR];
__device__ float g_std[BB*KVAR];
__device__ float g_z   [TT*DM];
__device__ float g_tmp [TT*DM];
__device__ float g_xdbl[TT*64 + 64];
__device__ float g_headp[PP*BB*KVAR*HPRED];
// chunked-scan state
__device__ float g_hch [NCH*BB*DIN*NST];
__device__ float g_hin [NCH*BB*DIN*NST];
__device__ float g_sumd[NCH*BB*DIN];
// fp16 activations
__device__ __half g_zh  [TT*DM];
__device__ __half g_uh  [TT*DIN + DIN];
__device__ __half g_zgh [TT*DIN + DIN];
__device__ __half g_y2h [TT*DIN];
__device__ __half g_hlnh[TT*DM];
__device__ __half g_hffh[TT*DFF];
// fp16 weights
__device__ __half h_inw[3*2048*512];
__device__ __half h_xpw[3*64*1024];
__device__ __half h_ow [3*512*1024];
__device__ __half h_w1 [3*2048*512];
__device__ __half h_w2 [3*512*2048];
__device__ __half h_hww[HPRED*HWLD];

// ---------------- helpers ----------------
__device__ __forceinline__ float siluf(float x){ return x / (1.f + __expf(-x)); }
__device__ __forceinline__ float geluf(float x){
    return 0.5f * x * (1.f + erff(x * 0.70710678118654752f));
}

__device__ __forceinline__ void cp16(void* smem, const void* g){
    unsigned a = (unsigned)__cvta_generic_to_shared(smem);
    asm volatile("cp.async.cg.shared.global [%0], [%1], 16;" :: "r"(a), "l"(g));
}
__device__ __forceinline__ void cp16s(unsigned saddr, const void* g){
    asm volatile("cp.async.cg.shared.global [%0], [%1], 16;" :: "r"(saddr), "l"(g));
}
__device__ __forceinline__ void cp_commit(){ asm volatile("cp.async.commit_group;"); }

__device__ __forceinline__ unsigned smem_u32(const void* p){
    unsigned a;
    asm("{ .reg .u64 t; cvta.to.shared.u64 t, %1; cvt.u32.u64 %0, t; }" : "=r"(a) : "l"(p));
    return a;
}

__device__ __forceinline__ void mma_f16(float* c, const unsigned* a, const unsigned* b){
    asm volatile("mma.sync.aligned.m16n8k16.row.col.f32.f16.f16.f32 "
        "{%0,%1,%2,%3}, {%4,%5,%6,%7}, {%8,%9}, {%0,%1,%2,%3};"
        : "+f"(c[0]),"+f"(c[1]),"+f"(c[2]),"+f"(c[3])
        : "r"(a[0]),"r"(a[1]),"r"(a[2]),"r"(a[3]), "r"(b[0]),"r"(b[1]));
}
__device__ __forceinline__ void ldsm4(unsigned &r0, unsigned &r1, unsigned &r2, unsigned &r3,
                                      unsigned addr){
    asm volatile("ldmatrix.sync.aligned.m8n8.x4.shared.b16 {%0,%1,%2,%3}, [%4];"
        : "=r"(r0),"=r"(r1),"=r"(r2),"=r"(r3) : "r"(addr));
}

// ---------------- merged fp32 -> fp16 conversion (all weights, 1 launch) --
#define F2H_N0 1572864   // in_w
#define F2H_N1 98304     // xp_w
#define F2H_N2 786432    // out_w
#define F2H_N3 1572864   // ffn_w1
#define F2H_N4 1572864   // ffn_w2
#define F2H_N5 1548288   // head_w
#define F2H_TOT (F2H_N0+F2H_N1+F2H_N2+F2H_N3+F2H_N4+F2H_N5)

__global__ void f2h_all(const float* __restrict__ p0, const float* __restrict__ p1,
                        const float* __restrict__ p2, const float* __restrict__ p3,
                        const float* __restrict__ p4, const float* __restrict__ p5,
                        __half2* q0, __half2* q1, __half2* q2,
                        __half2* q3, __half2* q4, __half2* q5){
    int i = blockIdx.x*256 + threadIdx.x;
    if (i >= F2H_TOT) return;
    const float* in; __half2* out; int off = i;
    if (off < F2H_N0){ in = p0; out = q0; }
    else if ((off -= F2H_N0) < F2H_N1){ in = p1; out = q1; }
    else if ((off -= F2H_N1) < F2H_N2){ in = p2; out = q2; }
    else if ((off -= F2H_N2) < F2H_N3){ in = p3; out = q3; }
    else if ((off -= F2H_N3) < F2H_N4){ in = p4; out = q4; }
    else { off -= F2H_N4; in = p5; out = q5; }
    float2 v = ((const float2*)in)[off];
    out[off] = __floats2half2_rn(v.x, v.y);
}

// ---------------- per-(b,k) mean/std over L ----------------
__global__ void stats_kernel(const float* __restrict__ x){
    int bk = blockIdx.x; int b = bk >> 4, k = bk & 15;
    int tid = threadIdx.x;
    float s = 0.f, q = 0.f;
    for (int l = tid; l < LCTX; l += 256){
        float v = x[(b*LCTX + l)*KVAR + k];
        s += v; q += v*v;
    }
    __shared__ float sh[64];
#pragma unroll
    for (int o = 16; o; o >>= 1){
        s += __shfl_xor_sync(~0u, s, o);
        q += __shfl_xor_sync(~0u, q, o);
    }
    int w = tid >> 5;
    if ((tid & 31) == 0){ sh[w] = s; sh[w+32] = q; }
    __syncthreads();
    if (tid == 0){
        float S = 0.f, Q = 0.f;
        for (int i = 0; i < 8; i++){ S += sh[i]; Q += sh[32+i]; }
        float mu  = S * (1.f/LCTX);
        float var = Q * (1.f/LCTX) - mu*mu;
        g_mean[bk] = mu;
        g_std[bk]  = sqrtf(var + EPSF);
    }
}

// ---------------- patch embedding + pos + var embed ----------------
__global__ void embed_kernel(const float* __restrict__ x,
                             const float* __restrict__ pw,
                             const float* __restrict__ pb,
                             const float* __restrict__ pos,
                             const float* __restrict__ vemb){
    int row = blockIdx.x;
    int b = row / SEQ, rem = row % SEQ;
    int p = rem >> 4, k = rem & 15;
    int bk = b*KVAR + k;
    __shared__ float xs[PATCH];
    int tid = threadIdx.x;                   // 128
    if (tid < PATCH){
        float v = x[(b*LCTX + p*STRIDEP + tid)*KVAR + k];
        xs[tid] = (v - g_mean[bk]) / g_std[bk];
    }
    __syncthreads();
#pragma unroll
    for (int j = 0; j < 4; j++){
        int d = tid + j*128;
        float acc = pb[d] + pos[p*DM + d] + vemb[k*DM + d];
        const float4* w4 = (const float4*)(pw + d*PATCH);
#pragma unroll
        for (int t4 = 0; t4 < 4; t4++){
            float4 w = w4[t4];
            acc += xs[t4*4+0]*w.x + xs[t4*4+1]*w.y + xs[t4*4+2]*w.z + xs[t4*4+3]*w.w;
        }
        g_z[row*DM + d] = acc;
        g_zh[row*DM + d] = __float2half(acc);
    }
}

// ---------------- epilogue modes ----------------
enum { EP_NONE=0, EP_SPLIT=1, EP_GELU=3, EP_BIAS_RES=4, EP_RES=5 };

template<int EP>
__device__ __forceinline__ void ep_store(float* __restrict__ out0, float* __restrict__ out1,
                                         __half* __restrict__ outh, int ldo,
                                         const float* __restrict__ bias,
                                         const float* __restrict__ res,
                                         int row, int col, float v0, float v1){
    if (EP == EP_NONE){
        out0[(size_t)row*ldo + col    ] = v0;
        out0[(size_t)row*ldo + col + 1] = v1;
    } else if (EP == EP_SPLIT){
        if (col < DIN){
            float s0 = siluf(v0), s1 = siluf(v1);
            *(__half2*)&outh[(size_t)row*DIN + col] = __floats2half2_rn(s0, s1);
        } else {
            __half* zgh = (__half*)out1;
            *(__half2*)&zgh[(size_t)row*DIN + col - DIN] = __floats2half2_rn(v0, v1);
        }
    } else if (EP == EP_GELU){
        float g0 = geluf(v0 + bias[col]);
        float g1 = geluf(v1 + bias[col+1]);
        *(__half2*)&outh[(size_t)row*ldo + col] = __floats2half2_rn(g0, g1);
    } else if (EP == EP_BIAS_RES){
        float f0 = v0 + bias[col]   + res[(size_t)row*ldo + col];
        float f1 = v1 + bias[col+1] + res[(size_t)row*ldo + col + 1];
        out0[(size_t)row*ldo + col    ] = f0;
        out0[(size_t)row*ldo + col + 1] = f1;
        *(__half2*)&outh[(size_t)row*ldo + col] = __floats2half2_rn(f0, f1);
    } else { // EP_RES
        out0[(size_t)row*ldo + col    ] = v0 + res[(size_t)row*ldo + col];
        out0[(size_t)row*ldo + col + 1] = v1 + res[(size_t)row*ldo + col + 1];
    }
}

// ---------------- fp16 NT GEMM, 128x128 block, BK=32, 5-stage cp.async ---
#define GH_PITCH 40
#define GH_PITCHB 80
#define GH_STG   (128*GH_PITCH)
#define GH_BOFF  (5*GH_STG)
#define GH_SMEM  (2*5*GH_STG*2)      // 102400 bytes

template<int EP>
__global__ void __launch_bounds__(256, 2) gemm_h(const __half* __restrict__ A, int lda,
                        const __half* __restrict__ W, int Kd,
                        float* __restrict__ out0, float* __restrict__ out1,
                        __half* __restrict__ outh, int ldo,
                        const float* __restrict__ bias, const float* __restrict__ res){
    extern __shared__ __half smh[];
    int tid = threadIdx.x;
    int nt = blockIdx.x, mt = blockIdx.y;
    int lane = tid & 31, wid = tid >> 5;
    int warpM = wid & 1, warpN = wid >> 1;      // 2 x 4
    int grp = lane >> 2, tig = lane & 3;

    const __half* Abase = A + (size_t)(mt*128)*lda;
    const __half* Wbase = W + (size_t)(nt*128)*Kd;

    int r  = tid >> 2;
    int kk = (tid & 3) * 8;

    unsigned smBytes = smem_u32(smh);
    int aRow  = lane & 15;
    int aKsel = (lane >> 4) * 8;
    int bRowSel = (lane & 7) + ((lane >> 4) * 8);
    int bKsel = ((lane >> 3) & 1) * 8;

    float acc[4][4][4];
#pragma unroll
    for (int i = 0; i < 4; i++)
#pragma unroll
        for (int j = 0; j < 4; j++)
#pragma unroll
            for (int h = 0; h < 4; h++) acc[i][j][h] = 0.f;

    int nK = Kd >> 5;

    auto issue = [&](int stage){
        int buf = stage % 5;
        int ko = stage * 32;
        cp16(&smh[buf*GH_STG + r*GH_PITCH + kk],               Abase + (size_t)r*lda      + ko + kk);
        cp16(&smh[buf*GH_STG + (r+64)*GH_PITCH + kk],          Abase + (size_t)(r+64)*lda + ko + kk);
        cp16(&smh[GH_BOFF + buf*GH_STG + r*GH_PITCH + kk],     Wbase + (size_t)r*Kd       + ko + kk);
        cp16(&smh[GH_BOFF + buf*GH_STG + (r+64)*GH_PITCH + kk],Wbase + (size_t)(r+64)*Kd  + ko + kk);
        cp_commit();
    };

#pragma unroll
    for (int s = 0; s < 4; s++){
        if (s < nK) issue(s); else cp_commit();
    }

    for (int kt = 0; kt < nK; kt++){
        asm volatile("cp.async.wait_group 3;");
        __syncthreads();
        if (kt + 4 < nK) issue(kt + 4); else cp_commit();

        unsigned aSt = smBytes + (unsigned)((kt % 5)*GH_STG*2);
        unsigned bSt = smBytes + (unsigned)((GH_BOFF + (kt % 5)*GH_STG)*2);
#pragma unroll
        for (int k0 = 0; k0 < 32; k0 += 16){
            unsigned a[4][4], b[4][2];
#pragma unroll
            for (int i = 0; i < 4; i++){
                unsigned addr = aSt + (unsigned)((warpM*64 + i*16 + aRow)*GH_PITCHB
                                                 + (k0 + aKsel)*2);
                ldsm4(a[i][0], a[i][1], a[i][2], a[i][3], addr);
            }
#pragma unroll
            for (int j2 = 0; j2 < 2; j2++){
                unsigned addr = bSt + (unsigned)((warpN*32 + j2*16 + bRowSel)*GH_PITCHB
                                                 + (k0 + bKsel)*2);
                ldsm4(b[2*j2][0], b[2*j2][1], b[2*j2+1][0], b[2*j2+1][1], addr);
            }
#pragma unroll
            for (int i = 0; i < 4; i++)
#pragma unroll
                for (int j = 0; j < 4; j++)
                    mma_f16(acc[i][j], a[i], b[j]);
        }
    }

#pragma unroll
    for (int i = 0; i < 4; i++){
#pragma unroll
        for (int j = 0; j < 4; j++){
            int col = nt*128 + warpN*32 + j*8 + 2*tig;
#pragma unroll
            for (int h = 0; h < 2; h++){
                int row = mt*128 + warpM*64 + i*16 + grp + h*8;
                ep_store<EP>(out0, out1, outh, ldo, bias, res, row, col,
                             acc[i][j][h*2+0], acc[i][j][h*2+1]);
            }
        }
    }
}

// ---------------- fp16 NT GEMM, 32x64 block, BK=32, 6-stage (x_proj) -----
template<int EP>
__global__ void __launch_bounds__(128, 3) gemm_h32(const __half* __restrict__ A, int lda,
                        const __half* __restrict__ W, int Kd,
                        float* __restrict__ out0, float* __restrict__ out1,
                        __half* __restrict__ outh, int ldo,
                        const float* __restrict__ bias, const float* __restrict__ res){
    __shared__ __align__(16) __half As[6][32*GH_PITCH];
    __shared__ __align__(16) __half Bs[6][64*GH_PITCH];
    int tid = threadIdx.x;
    int nt = blockIdx.x, mt = blockIdx.y;
    int lane = tid & 31, wid = tid >> 5;
    int grp = lane >> 2, tig = lane & 3;

    const __half* Abase = A + (size_t)(mt*32)*lda;
    const __half* Wbase = W + (size_t)(nt*64)*Kd;

    int r  = tid >> 2;
    int kk = (tid & 3) * 8;

    unsigned aBase0 = smem_u32(&As[0][0]);
    unsigned bBase0 = smem_u32(&Bs[0][0]);
    int aRow  = lane & 15;
    int aKsel = (lane >> 4) * 8;
    int bRowSel = (lane & 7) + ((lane >> 4) * 8);
    int bKsel = ((lane >> 3) & 1) * 8;

    float acc[2][2][4];
#pragma unroll
    for (int i = 0; i < 2; i++)
#pragma unroll
        for (int j = 0; j < 2; j++)
#pragma unroll
            for (int h = 0; h < 4; h++) acc[i][j][h] = 0.f;

    int nK = Kd >> 5;

    auto issue = [&](int stage){
        int buf = stage % 6;
        int ko = stage * 32;
        cp16(&As[buf][r*GH_PITCH + kk],        Abase + (size_t)r*lda       + ko + kk);
        cp16(&Bs[buf][r*GH_PITCH + kk],        Wbase + (size_t)r*Kd        + ko + kk);
        cp16(&Bs[buf][(r+32)*GH_PITCH + kk],   Wbase + (size_t)(r+32)*Kd   + ko + kk);
        cp_commit();
    };

#pragma unroll
    for (int s = 0; s < 5; s++){
        if (s < nK) issue(s); else cp_commit();
    }

    for (int kt = 0; kt < nK; kt++){
        asm volatile("cp.async.wait_group 4;");
        __syncthreads();
        if (kt + 5 < nK) issue(kt + 5); else cp_commit();
        unsigned aSt = aBase0 + (unsigned)((kt % 6)*32*GH_PITCHB);
        unsigned bSt = bBase0 + (unsigned)((kt % 6)*64*GH_PITCHB);
#pragma unroll
        for (int k0 = 0; k0 < 32; k0 += 16){
            unsigned a[2][4], b[2][2];
#pragma unroll
            for (int i = 0; i < 2; i++){
                unsigned addr = aSt + (unsigned)((i*16 + aRow)*GH_PITCHB + (k0 + aKsel)*2);
                ldsm4(a[i][0], a[i][1], a[i][2], a[i][3], addr);
            }
            {
                unsigned addr = bSt + (unsigned)((wid*16 + bRowSel)*GH_PITCHB + (k0 + bKsel)*2);
                ldsm4(b[0][0], b[0][1], b[1][0], b[1][1], addr);
            }
#pragma unroll
            for (int i = 0; i < 2; i++)
#pragma unroll
                for (int j = 0; j < 2; j++)
                    mma_f16(acc[i][j], a[i], b[j]);
        }
    }

#pragma unroll
    for (int i = 0; i < 2; i++){
#pragma unroll
        for (int j = 0; j < 2; j++){
            int col = nt*64 + wid*16 + j*8 + 2*tig;
#pragma unroll
            for (int h = 0; h < 2; h++){
                int row = mt*32 + i*16 + grp + h*8;
                ep_store<EP>(out0, out1, outh, ldo, bias, res, row, col,
                             acc[i][j][h*2+0], acc[i][j][h*2+1]);
            }
        }
    }
}

// ---------------- layer norm; 2nd LN / fp16 copy ----------------
template<bool DOUBLE>
__global__ void ln_kernel(const float* __restrict__ in,
                          const float* __restrict__ g1, const float* __restrict__ b1,
                          float* __restrict__ o1,
                          const float* __restrict__ g2, const float* __restrict__ b2,
                          __half* __restrict__ o2h){
    int w = threadIdx.x >> 5, lane = threadIdx.x & 31;
    int row = blockIdx.x*8 + w;
    const float4* in4 = (const float4*)(in + (size_t)row*DM);
    float4 v[4];
    float s = 0.f, q = 0.f;
#pragma unroll
    for (int i = 0; i < 4; i++){
        v[i] = in4[lane + 32*i];
        s += v[i].x + v[i].y + v[i].z + v[i].w;
        q += v[i].x*v[i].x + v[i].y*v[i].y + v[i].z*v[i].z + v[i].w*v[i].w;
    }
#pragma unroll
    for (int o = 16; o; o >>= 1){
        s += __shfl_xor_sync(~0u, s, o);
        q += __shfl_xor_sync(~0u, q, o);
    }
    float mu = s * (1.f/DM);
    float rs = rsqrtf(q*(1.f/DM) - mu*mu + EPSF);
    float4 zz[4];
    float s2 = 0.f, q2 = 0.f;
#pragma unroll
    for (int i = 0; i < 4; i++){
        float4 gg = ((const float4*)g1)[lane + 32*i];
        float4 bb = ((const float4*)b1)[lane + 32*i];
        zz[i].x = (v[i].x - mu)*rs*gg.x + bb.x;
        zz[i].y = (v[i].y - mu)*rs*gg.y + bb.y;
        zz[i].z = (v[i].z - mu)*rs*gg.z + bb.z;
        zz[i].w = (v[i].w - mu)*rs*gg.w + bb.w;
        if (DOUBLE){
            s2 += zz[i].x + zz[i].y + zz[i].z + zz[i].w;
            q2 += zz[i].x*zz[i].x + zz[i].y*zz[i].y + zz[i].z*zz[i].z + zz[i].w*zz[i].w;
        }
        ((float4*)(o1 + (size_t)row*DM))[lane + 32*i] = zz[i];
    }
    if (DOUBLE){
#pragma unroll
        for (int o = 16; o; o >>= 1){
            s2 += __shfl_xor_sync(~0u, s2, o);
            q2 += __shfl_xor_sync(~0u, q2, o);
        }
        float mu2 = s2 * (1.f/DM);
        float rs2 = rsqrtf(q2*(1.f/DM) - mu2*mu2 + EPSF);
        __half2* oo = (__half2*)(o2h + (size_t)row*DM);
#pragma unroll
        for (int i = 0; i < 4; i++){
            float4 gg = ((const float4*)g2)[lane + 32*i];
            float4 bb = ((const float4*)b2)[lane + 32*i];
            float o0 = (zz[i].x - mu2)*rs2*gg.x + bb.x;
            float o1v= (zz[i].y - mu2)*rs2*gg.y + bb.y;
            float o2v= (zz[i].z - mu2)*rs2*gg.z + bb.z;
            float o3 = (zz[i].w - mu2)*rs2*gg.w + bb.w;
            oo[2*(lane + 32*i)    ] = __floats2half2_rn(o0, o1v);
            oo[2*(lane + 32*i) + 1] = __floats2half2_rn(o2v, o3);
        }
    } else if (o2h){
        __half2* oo = (__half2*)(o2h + (size_t)row*DM);
#pragma unroll
        for (int i = 0; i < 4; i++){
            oo[2*(lane + 32*i)    ] = __floats2half2_rn(zz[i].x, zz[i].y);
            oo[2*(lane + 32*i) + 1] = __floats2half2_rn(zz[i].z, zz[i].w);
        }
    }
}

// ---------------- chunked selective scan ----------------
#define SC_DEPTH 8

// Phase 1: local scan from h=0, output final h + sum(delta); no y.
__global__ void __launch_bounds__(256) scan_part1(
                            const __half* __restrict__ u,
                            const float* __restrict__ xdbl,
                            const float* __restrict__ Wdt,
                            const float* __restrict__ bdt,
                            const float* __restrict__ A_log){
    __shared__ __align__(16) char ring[8][SC_DEPTH][320];
    int blk = blockIdx.x;
    int b = blk >> 3, dblk = blk & 7;
    int chunk = blockIdx.y;
    int tid = threadIdx.x;
    int w = tid >> 5, lane = tid & 31;
    int ph = lane & 1;
    int d = dblk*128 + w*16 + (lane >> 1);
    int nb = ph * 8;
    int tbeg = chunk*CHL, tend = tbeg + CHL;

    float Aa[8];
#pragma unroll
    for (int j = 0; j < 8; j++) Aa[j] = -expf(A_log[d*NST + nb + j]);
    float A0 = Aa[0];
    float stepA = Aa[1] - Aa[0];
    bool prog = true;
#pragma unroll
    for (int j = 0; j < 8; j++){
        float e = A0 + (float)j * stepA;
        if (fabsf(Aa[j] - e) > 1e-5f*fabsf(e) + 1e-7f) prog = false;
    }
    float bd = bdt[d];
    float wdt[16];
#pragma unroll
    for (int j = 0; j < 16; j++) wdt[j] = Wdt[d*RNK + ph*16 + j];

    float h[8];
#pragma unroll
    for (int j = 0; j < 8; j++) h[j] = 0.f;
    float sumd = 0.f;

    size_t uvbase = (size_t)(b*SEQ)*DIN + dblk*128 + w*16;
    const float* xrow = xdbl + (size_t)(b*SEQ)*64;
    unsigned ring0 = smem_u32(&ring[w][0][0]);

    auto issue = [&](int t){
        unsigned sa = ring0 + (unsigned)((t % SC_DEPTH) * 320);
        if (lane < 2)
            cp16s(sa + lane*16, (const char*)u + (uvbase + (size_t)t*DIN)*2 + lane*16);
        else if (lane >= 4 && lane < 20)
            cp16s(sa + 64 + (lane-4)*16, (const char*)(xrow + (size_t)t*64) + (lane-4)*16);
        cp_commit();
    };

    auto calc_delta = [&](const float* xd) -> float {
        const float4 T0 = *(const float4*)(xd + ph*16);
        const float4 T1 = *(const float4*)(xd + ph*16 + 4);
        const float4 T2 = *(const float4*)(xd + ph*16 + 8);
        const float4 T3 = *(const float4*)(xd + ph*16 + 12);
        float a0 = T0.x*wdt[0]  + T0.y*wdt[1]  + T0.z*wdt[2]  + T0.w*wdt[3];
        float a1 = T1.x*wdt[4]  + T1.y*wdt[5]  + T1.z*wdt[6]  + T1.w*wdt[7];
        float a2 = T2.x*wdt[8]  + T2.y*wdt[9]  + T2.z*wdt[10] + T2.w*wdt[11];
        float a3 = T3.x*wdt[12] + T3.y*wdt[13] + T3.z*wdt[14] + T3.w*wdt[15];
        float p = (a0 + a1) + (a2 + a3);
        p += __shfl_xor_sync(~0u, p, 1);
        float xv = p + bd;
        return fmaxf(xv, 0.f) + __logf(1.f + __expf(-fabsf(xv)));
    };

#pragma unroll
    for (int t0 = 0; t0 < SC_DEPTH-1; t0++) issue(tbeg + t0);

    asm volatile("cp.async.wait_group %0;" :: "n"(SC_DEPTH-2));
    __syncwarp();
    float dv = calc_delta((const float*)(ring[w][tbeg % SC_DEPTH] + 64));

    for (int t = tbeg; t < tend; t++){
        asm volatile("cp.async.wait_group %0;" :: "n"(SC_DEPTH-3));
        __syncwarp();
        if (t + SC_DEPTH-1 < tend) issue(t + SC_DEPTH-1);
        else cp_commit();

        const char* sp = ring[w][t % SC_DEPTH];
        float uv = __half2float(((const __half*)sp)[lane >> 1]);
        const float* xd = (const float*)(sp + 64);
        float4 B0 = *(const float4*)(xd + 32 + nb);
        float4 B1 = *(const float4*)(xd + 36 + nb);

        sumd += dv;
        float du = dv * uv;
        if (prog){
            float e = __expf(dv * A0);
            float rr = __expf(dv * stepA);
            h[0] = h[0]*e + du*B0.x; e *= rr;
            h[1] = h[1]*e + du*B0.y; e *= rr;
            h[2] = h[2]*e + du*B0.z; e *= rr;
            h[3] = h[3]*e + du*B0.w; e *= rr;
            h[4] = h[4]*e + du*B1.x; e *= rr;
            h[5] = h[5]*e + du*B1.y; e *= rr;
            h[6] = h[6]*e + du*B1.z; e *= rr;
            h[7] = h[7]*e + du*B1.w;
        } else {
            float Bv[8] = {B0.x,B0.y,B0.z,B0.w,B1.x,B1.y,B1.z,B1.w};
#pragma unroll
            for (int j = 0; j < 8; j++){
                float e = __expf(dv * Aa[j]);
                h[j] = h[j]*e + du*Bv[j];
            }
        }
        if (t + 1 < tend)
            dv = calc_delta((const float*)(ring[w][(t+1) % SC_DEPTH] + 64));
    }

    size_t obase = (((size_t)(chunk*BB + b)*DIN + d))*NST + nb;
    *(float4*)&g_hch[obase]   = make_float4(h[0], h[1], h[2], h[3]);
    *(float4*)&g_hch[obase+4] = make_float4(h[4], h[5], h[6], h[7]);
    if (!ph) g_sumd[(size_t)(chunk*BB + b)*DIN + d] = sumd;
}

// Combine: sequential over chunk states per (b,d,n); writes h_in per chunk.
__global__ void scan_combine(const float* __restrict__ A_log){
    int idx = blockIdx.x*256 + threadIdx.x;     // 262144 threads
    int n = idx & 15;
    int d = (idx >> 4) & 1023;
    int b = idx >> 14;
    float An = -expf(A_log[d*NST + n]);
    float h = 0.f;
#pragma unroll
    for (int c = 0; c < NCH; c++){
        size_t base = (size_t)(c*BB + b)*DIN + d;
        g_hin[base*NST + n] = h;
        h = __expf(An * g_sumd[base]) * h + g_hch[base*NST + n];
    }
}

// Phase 2: scan with true h_in, produce y.
__global__ void __launch_bounds__(256) scan_part2(
                            const __half* __restrict__ u,
                            const __half* __restrict__ zg,
                            const float* __restrict__ xdbl,
                            const float* __restrict__ Wdt,
                            const float* __restrict__ bdt,
                            const float* __restrict__ A_log,
                            const float* __restrict__ Dp,
                            __half* __restrict__ y2h){
    __shared__ __align__(16) char ring[8][SC_DEPTH][320];
    int blk = blockIdx.x;
    int b = blk >> 3, dblk = blk & 7;
    int chunk = blockIdx.y;
    int tid = threadIdx.x;
    int w = tid >> 5, lane = tid & 31;
    int ph = lane & 1;
    int d = dblk*128 + w*16 + (lane >> 1);
    int nb = ph * 8;
    int tbeg = chunk*CHL, tend = tbeg + CHL;

    float Aa[8];
#pragma unroll
    for (int j = 0; j < 8; j++) Aa[j] = -expf(A_log[d*NST + nb + j]);
    float A0 = Aa[0];
    float stepA = Aa[1] - Aa[0];
    bool prog = true;
#pragma unroll
    for (int j = 0; j < 8; j++){
        float e = A0 + (float)j * stepA;
        if (fabsf(Aa[j] - e) > 1e-5f*fabsf(e) + 1e-7f) prog = false;
    }
    float Dd = Dp[d];
    float bd = bdt[d];
    float wdt[16];
#pragma unroll
    for (int j = 0; j < 16; j++) wdt[j] = Wdt[d*RNK + ph*16 + j];

    float h[8];
    {
        size_t ibase = (((size_t)(chunk*BB + b)*DIN + d))*NST + nb;
        float4 h0 = *(const float4*)&g_hin[ibase];
        float4 h1 = *(const float4*)&g_hin[ibase+4];
        h[0]=h0.x; h[1]=h0.y; h[2]=h0.z; h[3]=h0.w;
        h[4]=h1.x; h[5]=h1.y; h[6]=h1.z; h[7]=h1.w;
    }

    size_t uvbase = (size_t)(b*SEQ)*DIN + dblk*128 + w*16;
    const float* xrow = xdbl + (size_t)(b*SEQ)*64;
    size_t ybase = (size_t)(b*SEQ)*DIN + d;
    unsigned ring0 = smem_u32(&ring[w][0][0]);

    auto issue = [&](int t){
        unsigned sa = ring0 + (unsigned)((t % SC_DEPTH) * 320);
        if (lane < 20){
            if (lane < 2)
                cp16s(sa + lane*16, (const char*)u + (uvbase + (size_t)t*DIN)*2 + lane*16);
            else if (lane < 4)
                cp16s(sa + 32 + (lane-2)*16, (const char*)zg + (uvbase + (size_t)t*DIN)*2 + (lane-2)*16);
            else
                cp16s(sa + 64 + (lane-4)*16, (const char*)(xrow + (size_t)t*64) + (lane-4)*16);
        }
        cp_commit();
    };

    auto calc_delta = [&](const float* xd) -> float {
        const float4 T0 = *(const float4*)(xd + ph*16);
        const float4 T1 = *(const float4*)(xd + ph*16 + 4);
        const float4 T2 = *(const float4*)(xd + ph*16 + 8);
        const float4 T3 = *(const float4*)(xd + ph*16 + 12);
        float a0 = T0.x*wdt[0]  + T0.y*wdt[1]  + T0.z*wdt[2]  + T0.w*wdt[3];
        float a1 = T1.x*wdt[4]  + T1.y*wdt[5]  + T1.z*wdt[6]  + T1.w*wdt[7];
        float a2 = T2.x*wdt[8]  + T2.y*wdt[9]  + T2.z*wdt[10] + T2.w*wdt[11];
        float a3 = T3.x*wdt[12] + T3.y*wdt[13] + T3.z*wdt[14] + T3.w*wdt[15];
        float p = (a0 + a1) + (a2 + a3);
        p += __shfl_xor_sync(~0u, p, 1);
        float xv = p + bd;
        return fmaxf(xv, 0.f) + __logf(1.f + __expf(-fabsf(xv)));
    };

#pragma unroll
    for (int t0 = 0; t0 < SC_DEPTH-1; t0++) issue(tbeg + t0);

    asm volatile("cp.async.wait_group %0;" :: "n"(SC_DEPTH-2));
    __syncwarp();
    float dv = calc_delta((const float*)(ring[w][tbeg % SC_DEPTH] + 64));

    for (int t = tbeg; t < tend; t++){
        asm volatile("cp.async.wait_group %0;" :: "n"(SC_DEPTH-3));
        __syncwarp();
        if (t + SC_DEPTH-1 < tend) issue(t + SC_DEPTH-1);
        else cp_commit();

        const char* sp = ring[w][t % SC_DEPTH];
        float uv = __half2float(((const __half*)sp)[lane >> 1]);
        float zv = __half2float(((const __half*)(sp + 32))[lane >> 1]);
        const float* xd = (const float*)(sp + 64);
        float4 B0 = *(const float4*)(xd + 32 + nb);
        float4 B1 = *(const float4*)(xd + 36 + nb);
        float4 C0 = *(const float4*)(xd + 48 + nb);
        float4 C1 = *(const float4*)(xd + 52 + nb);

        float du = dv * uv;
        float y = 0.f;
        if (prog){
            float e = __expf(dv * A0);
            float rr = __expf(dv * stepA);
            h[0] = h[0]*e + du*B0.x; y += h[0]*C0.x; e *= rr;
            h[1] = h[1]*e + du*B0.y; y += h[1]*C0.y; e *= rr;
            h[2] = h[2]*e + du*B0.z; y += h[2]*C0.z; e *= rr;
            h[3] = h[3]*e + du*B0.w; y += h[3]*C0.w; e *= rr;
            h[4] = h[4]*e + du*B1.x; y += h[4]*C1.x; e *= rr;
            h[5] = h[5]*e + du*B1.y; y += h[5]*C1.y; e *= rr;
            h[6] = h[6]*e + du*B1.z; y += h[6]*C1.z; e *= rr;
            h[7] = h[7]*e + du*B1.w; y += h[7]*C1.w;
        } else {
            float Bv[8] = {B0.x,B0.y,B0.z,B0.w,B1.x,B1.y,B1.z,B1.w};
            float Cv[8] = {C0.x,C0.y,C0.z,C0.w,C1.x,C1.y,C1.z,C1.w};
#pragma unroll
            for (int j = 0; j < 8; j++){
                float e = __expf(dv * Aa[j]);
                h[j] = h[j]*e + du*Bv[j];
                y += h[j]*Cv[j];
            }
        }
        float ysum = y + __shfl_xor_sync(~0u, y, 1);
        if (!ph){
            y2h[ybase + (size_t)t*DIN] = __float2half((ysum + uv*Dd) * siluf(zv));
        }
        if (t + 1 < tend)
            dv = calc_delta((const float*)(ring[w][(t+1) % SC_DEPTH] + 64));
    }
}

// ---------------- head: fp16 MMA partial GEMM per patch index p ----------
#define HB_PITCH  72
#define HB_PITCHB 144
#define HM_ASTG   (128*HB_PITCH)
#define HM_BSTG   (112*HB_PITCH)
#define HM_SMEM   (2*(HM_ASTG + HM_BSTG)*2)   // 69120 bytes

__global__ void __launch_bounds__(256) head_mma(const __half* __restrict__ zf,
                                                const __half* __restrict__ hw){
    extern __shared__ __half hsm[];
    __half* As = hsm;
    __half* Bs = hsm + 2*HM_ASTG;
    int p = blockIdx.x, mt = blockIdx.y;
    int tid = threadIdx.x, lane = tid & 31, wid = tid >> 5;
    int warpM = wid & 1, warpN = wid >> 1;     // 2 x 4; warp tile 64 x 24
    int grp = lane >> 2, tig = lane & 3;
    unsigned aB = smem_u32(As), bB = smem_u32(Bs);
    int aRow  = lane & 15;
    int aKsel = (lane >> 4) * 8;
    int bRowSel = (lane & 7) + ((lane >> 4) * 8);
    int bKsel = ((lane >> 3) & 1) * 8;

    // zero B pad rows [96,112) in both buffers
    for (int idx = tid; idx < 2*16*HB_PITCH; idx += 256){
        int buf = idx / (16*HB_PITCH);
        int rem = idx - buf*(16*HB_PITCH);
        Bs[buf*HM_BSTG + 96*HB_PITCH + rem] = __float2half(0.f);
    }
    __syncthreads();

    float acc[4][3][4];
#pragma unroll
    for (int i = 0; i < 4; i++)
#pragma unroll
        for (int j = 0; j < 3; j++)
#pragma unroll
            for (int h = 0; h < 4; h++) acc[i][j][h] = 0.f;

    auto issue = [&](int kt){
        int buf = kt & 1;
#pragma unroll
        for (int i2 = 0; i2 < 4; i2++){        // A: 128 rows x 8 chunks = 1024
            int ca = tid + i2*256;
            int r = ca >> 3, cc = (ca & 7)*8;
            int R = mt*128 + r, bb = R >> 4, k2 = R & 15;
            cp16(&As[buf*HM_ASTG + r*HB_PITCH + cc],
                 zf + ((size_t)(bb*SEQ + p*KVAR + k2))*DM + kt*64 + cc);
        }
#pragma unroll
        for (int i2 = 0; i2 < 3; i2++){        // B: 96 rows x 8 chunks = 768
            int cb = tid + i2*256;
            int rn = cb >> 3, cc = (cb & 7)*8;
            cp16(&Bs[buf*HM_BSTG + rn*HB_PITCH + cc],
                 hw + (size_t)rn*HWLD + p*DM + kt*64 + cc);
        }
        cp_commit();
    };

    issue(0);
    for (int kt = 0; kt < 8; kt++){
        __syncthreads();
        if (kt + 1 < 8) issue(kt + 1); else cp_commit();
        asm volatile("cp.async.wait_group 1;");
        __syncthreads();
        int buf = kt & 1;
        unsigned aSt = aB + (unsigned)(buf*HM_ASTG*2);
        unsigned bSt = bB + (unsigned)(buf*HM_BSTG*2);
#pragma unroll
        for (int k0 = 0; k0 < 64; k0 += 16){
            unsigned a[4][4], b[3][2], dump0, dump1;
#pragma unroll
            for (int i = 0; i < 4; i++){
                unsigned addr = aSt + (unsigned)((warpM*64 + i*16 + aRow)*HB_PITCHB
                                                 + (k0 + aKsel)*2);
                ldsm4(a[i][0], a[i][1], a[i][2], a[i][3], addr);
            }
            {
                unsigned addr = bSt + (unsigned)((warpN*24 + bRowSel)*HB_PITCHB + (k0 + bKsel)*2);
                ldsm4(b[0][0], b[0][1], b[1][0], b[1][1], addr);
                unsigned addr2 = bSt + (unsigned)((warpN*24 + 16 + bRowSel)*HB_PITCHB + (k0 + bKsel)*2);
                ldsm4(b[2][0], b[2][1], dump0, dump1, addr2);
            }
#pragma unroll
            for (int i = 0; i < 4; i++)
#pragma unroll
                for (int j = 0; j < 3; j++)
                    mma_f16(acc[i][j], a[i], b[j]);
        }
    }

#pragma unroll
    for (int i = 0; i < 4; i++){
#pragma unroll
        for (int j = 0; j < 3; j++){
            int col = warpN*24 + j*8 + 2*tig;
#pragma unroll
            for (int h = 0; h < 2; h++){
                int R = mt*128 + warpM*64 + i*16 + grp + h*8;
                g_headp[(size_t)(p*256 + R)*HPRED + col    ] = acc[i][j][h*2+0];
                g_headp[(size_t)(p*256 + R)*HPRED + col + 1] = acc[i][j][h*2+1];
            }
        }
    }
}

// ---------------- head reduction + de-normalization ----------------
__global__ void head_final(const float* __restrict__ hb, float* __restrict__ out){
    int idx = blockIdx.x*256 + threadIdx.x;
    int bk = idx / HPRED, hh = idx % HPRED;
    float s = 0.f;
    for (int p = 0; p < PP; p++) s += g_headp[(size_t)p*(BB*KVAR*HPRED) + idx];
    s += hb[hh];
    int b = bk >> 4, k = bk & 15;
    out[b*(HPRED*KVAR) + hh*KVAR + k] = s * g_std[bk] + g_mean[bk];
}

// ---------------- launch ----------------
extern "C" void kernel_launch(void* const* d_in, const int* in_sizes, int n_in,
                              void* d_out, int out_size){
    const float* x        = (const float*)d_in[0];
    const float* patch_w  = (const float*)d_in[1];
    const float* patch_b  = (const float*)d_in[2];
    const float* pos      = (const float*)d_in[3];
    const float* vemb     = (const float*)d_in[4];
    const float* in_w     = (const float*)d_in[5];
    const float* xp_w     = (const float*)d_in[6];
    const float* dt_w     = (const float*)d_in[7];
    const float* dt_b     = (const float*)d_in[8];
    const float* A_log    = (const float*)d_in[9];
    const float* D_par    = (const float*)d_in[10];
    const float* out_w    = (const float*)d_in[11];
    const float* tmb_g    = (const float*)d_in[12];
    const float* tmb_b    = (const float*)d_in[13];
    const float* ffn_g    = (const float*)d_in[14];
    const float* ffn_b    = (const float*)d_in[15];
    const float* ffn_w1   = (const float*)d_in[16];
    const float* ffn_b1   = (const float*)d_in[17];
    const float* ffn_w2   = (const float*)d_in[18];
    const float* ffn_b2   = (const float*)d_in[19];
    const float* norm_g   = (const float*)d_in[20];
    const float* norm_b   = (const float*)d_in[21];
    const float* head_w   = (const float*)d_in[22];
    const float* head_b   = (const float*)d_in[23];
    float* out = (float*)d_out;

    cudaFuncSetAttribute(gemm_h<EP_SPLIT>,    cudaFuncAttributeMaxDynamicSharedMemorySize, GH_SMEM);
    cudaFuncSetAttribute(gemm_h<EP_RES>,      cudaFuncAttributeMaxDynamicSharedMemorySize, GH_SMEM);
    cudaFuncSetAttribute(gemm_h<EP_GELU>,     cudaFuncAttributeMaxDynamicSharedMemorySize, GH_SMEM);
    cudaFuncSetAttribute(gemm_h<EP_BIAS_RES>, cudaFuncAttributeMaxDynamicSharedMemorySize, GH_SMEM);
    cudaFuncSetAttribute(head_mma,            cudaFuncAttributeMaxDynamicSharedMemorySize, HM_SMEM);

    float *z, *tmp, *xdbl;
    __half *zh, *uh, *zgh, *y2h, *hlnh, *hffh;
    __half *winh, *wxph, *woh, *w1h, *w2h, *hwwh;
    cudaGetSymbolAddress((void**)&z,    g_z);
    cudaGetSymbolAddress((void**)&tmp,  g_tmp);
    cudaGetSymbolAddress((void**)&xdbl, g_xdbl);
    cudaGetSymbolAddress((void**)&zh,   g_zh);
    cudaGetSymbolAddress((void**)&uh,   g_uh);
    cudaGetSymbolAddress((void**)&zgh,  g_zgh);
    cudaGetSymbolAddress((void**)&y2h,  g_y2h);
    cudaGetSymbolAddress((void**)&hlnh, g_hlnh);
    cudaGetSymbolAddress((void**)&hffh, g_hffh);
    cudaGetSymbolAddress((void**)&winh, h_inw);
    cudaGetSymbolAddress((void**)&wxph, h_xpw);
    cudaGetSymbolAddress((void**)&woh,  h_ow);
    cudaGetSymbolAddress((void**)&w1h,  h_w1);
    cudaGetSymbolAddress((void**)&w2h,  h_w2);
    cudaGetSymbolAddress((void**)&hwwh, h_hww);

    // merged weight conversion (fp32 -> fp16), single launch
    f2h_all<<<(F2H_TOT + 255)/256, 256>>>(in_w, xp_w, out_w, ffn_w1, ffn_w2, head_w,
                                          (__half2*)winh, (__half2*)wxph, (__half2*)woh,
                                          (__half2*)w1h, (__half2*)w2h, (__half2*)hwwh);

    stats_kernel<<<BB*KVAR, 256>>>(x);
    embed_kernel<<<TT, 128>>>(x, patch_w, patch_b, pos, vemb);

    const int MT  = TT/128;
    const int MT32= TT/32;

    for (int l = 0; l < NLAY; l++){
        const __half* Wi  = winh + (size_t)l*(2*DIN)*DM;
        const __half* Wx  = wxph + (size_t)l*64*DIN;
        const float*  Wdt = dt_w + (size_t)l*DIN*RNK;
        const float*  bdt = dt_b + (size_t)l*DIN;
        const float*  Al  = A_log+ (size_t)l*DIN*NST;
        const float*  Dl  = D_par+ (size_t)l*DIN;
        const __half* Wo  = woh  + (size_t)l*DM*DIN;
        const __half* W1  = w1h  + (size_t)l*DFF*DM;
        const float*  B1  = ffn_b1 + (size_t)l*DFF;
        const __half* W2  = w2h  + (size_t)l*DM*DFF;
        const float*  B2  = ffn_b2 + (size_t)l*DM;

        gemm_h<EP_SPLIT><<<dim3(16, MT), 256, GH_SMEM>>>(zh, DM, Wi, DM,
                                                         nullptr, (float*)zgh, uh, 0, nullptr, nullptr);
        gemm_h32<EP_NONE><<<dim3(1, MT32), 128>>>(uh, DIN, Wx, DIN, xdbl, nullptr, nullptr, 64, nullptr, nullptr);
        // chunked selective scan (exact combine)
        scan_part1<<<dim3(128, NCH), 256>>>(uh, xdbl, Wdt, bdt, Al);
        scan_combine<<<1024, 256>>>(Al);
        scan_part2<<<dim3(128, NCH), 256>>>(uh, zgh, xdbl, Wdt, bdt, Al, Dl, y2h);
        gemm_h<EP_RES><<<dim3(4, MT), 256, GH_SMEM>>>(y2h, DIN, Wo, DIN, tmp, nullptr, nullptr, DM, nullptr, z);
        ln_kernel<true><<<TT/8, 256>>>(tmp, tmb_g + l*DM, tmb_b + l*DM, z,
                                       ffn_g + l*DM, ffn_b + l*DM, hlnh);
        gemm_h<EP_GELU><<<dim3(16, MT), 256, GH_SMEM>>>(hlnh, DM, W1, DM, nullptr, nullptr, hffh, DFF, B1, nullptr);
        gemm_h<EP_BIAS_RES><<<dim3(4, MT), 256, GH_SMEM>>>(hffh, DFF, W2, DFF, z, nullptr, zh, DM, B2, z);
    }

    // final LN -> tmp (fp32) + hlnh (fp16 for head)
    ln_kernel<false><<<TT/8, 256>>>(z, norm_g, norm_b, tmp, nullptr, nullptr, hlnh);
    // head (fp16 MMA partials per p) + reduction
    head_mma<<<dim3(PP, 2), 256, HM_SMEM>>>(hlnh, hwwh);
    head_final<<<96, 256>>>(head_b, out);
    (void)in_sizes; (void)n_in; (void)out_size;
}

// round 16
// speedup vs baseline: 1.9377x; 1.0470x over previous
#include <cuda_runtime.h>
#include <cuda_fp16.h>
#include <math.h>

// ---------------- problem constants ----------------
#define BB     16
#define LCTX   512
#define KVAR   16
#define HPRED  96
#define DM     512
#define NST    16
#define NLAY   3
#define DFF    2048
#define PATCH  16
#define STRIDEP 8
#define PP     63
#define DIN    1024
#define RNK    32
#define SEQ    (KVAR*PP)     // 1008
#define TT     (BB*SEQ)      // 16128
#define EPSF   1e-5f
#define HWLD   (PP*DM)       // 32256
#define NCH    16            // scan chunks
#define CHL    (SEQ/NCH)     // 63 steps per chunk

// ---------------- scratch ----------------
__device__ float g_mean[BB*KVAR];
__device__ float g_std[BB*KVAR];
__device__ float g_z   [TT*DM];
__device__ float g_tmp [TT*DM];
__device__ float g_xdbl[TT*64 + 64];
__device__ float g_headp[PP*BB*KVAR*HPRED];
// chunked-scan state
__device__ float g_hch [NCH*BB*DIN*NST];
__device__ float g_hin [NCH*BB*DIN*NST];
__device__ float g_sumd[NCH*BB*DIN];
// fp16 activations
__device__ __half g_zh  [TT*DM];
__device__ __half g_uh  [TT*DIN + DIN];
__device__ __half g_zgh [TT*DIN + DIN];
__device__ __half g_y2h [TT*DIN];
__device__ __half g_hlnh[TT*DM];
__device__ __half g_hffh[TT*DFF];
// fp16 weights
__device__ __half h_inw[3*2048*512];
__device__ __half h_xpw[3*64*1024];
__device__ __half h_ow [3*512*1024];
__device__ __half h_w1 [3*2048*512];
__device__ __half h_w2 [3*512*2048];
__device__ __half h_hww[HPRED*HWLD];

// ---------------- helpers ----------------
__device__ __forceinline__ float siluf(float x){ return x / (1.f + __expf(-x)); }
__device__ __forceinline__ float geluf(float x){
    return 0.5f * x * (1.f + erff(x * 0.70710678118654752f));
}

__device__ __forceinline__ void cp16(void* smem, const void* g){
    unsigned a = (unsigned)__cvta_generic_to_shared(smem);
    asm volatile("cp.async.cg.shared.global [%0], [%1], 16;" :: "r"(a), "l"(g));
}
__device__ __forceinline__ void cp16s(unsigned saddr, const void* g){
    asm volatile("cp.async.cg.shared.global [%0], [%1], 16;" :: "r"(saddr), "l"(g));
}
__device__ __forceinline__ void cp_commit(){ asm volatile("cp.async.commit_group;"); }

__device__ __forceinline__ unsigned smem_u32(const void* p){
    unsigned a;
    asm("{ .reg .u64 t; cvta.to.shared.u64 t, %1; cvt.u32.u64 %0, t; }" : "=r"(a) : "l"(p));
    return a;
}

__device__ __forceinline__ void mma_f16(float* c, const unsigned* a, const unsigned* b){
    asm volatile("mma.sync.aligned.m16n8k16.row.col.f32.f16.f16.f32 "
        "{%0,%1,%2,%3}, {%4,%5,%6,%7}, {%8,%9}, {%0,%1,%2,%3};"
        : "+f"(c[0]),"+f"(c[1]),"+f"(c[2]),"+f"(c[3])
        : "r"(a[0]),"r"(a[1]),"r"(a[2]),"r"(a[3]), "r"(b[0]),"r"(b[1]));
}
__device__ __forceinline__ void ldsm4(unsigned &r0, unsigned &r1, unsigned &r2, unsigned &r3,
                                      unsigned addr){
    asm volatile("ldmatrix.sync.aligned.m8n8.x4.shared.b16 {%0,%1,%2,%3}, [%4];"
        : "=r"(r0),"=r"(r1),"=r"(r2),"=r"(r3) : "r"(addr));
}

// ---------------- merged fp32 -> fp16 conversion (all weights, 1 launch) --
#define F2H_N0 1572864   // in_w
#define F2H_N1 98304     // xp_w
#define F2H_N2 786432    // out_w
#define F2H_N3 1572864   // ffn_w1
#define F2H_N4 1572864   // ffn_w2
#define F2H_N5 1548288   // head_w
#define F2H_TOT (F2H_N0+F2H_N1+F2H_N2+F2H_N3+F2H_N4+F2H_N5)

__global__ void f2h_all(const float* __restrict__ p0, const float* __restrict__ p1,
                        const float* __restrict__ p2, const float* __restrict__ p3,
                        const float* __restrict__ p4, const float* __restrict__ p5,
                        __half2* q0, __half2* q1, __half2* q2,
                        __half2* q3, __half2* q4, __half2* q5){
    int i = blockIdx.x*256 + threadIdx.x;
    if (i >= F2H_TOT) return;
    const float* in; __half2* out; int off = i;
    if (off < F2H_N0){ in = p0; out = q0; }
    else if ((off -= F2H_N0) < F2H_N1){ in = p1; out = q1; }
    else if ((off -= F2H_N1) < F2H_N2){ in = p2; out = q2; }
    else if ((off -= F2H_N2) < F2H_N3){ in = p3; out = q3; }
    else if ((off -= F2H_N3) < F2H_N4){ in = p4; out = q4; }
    else { off -= F2H_N4; in = p5; out = q5; }
    float2 v = ((const float2*)in)[off];
    out[off] = __floats2half2_rn(v.x, v.y);
}

// ---------------- per-(b,k) mean/std over L ----------------
__global__ void stats_kernel(const float* __restrict__ x){
    int bk = blockIdx.x; int b = bk >> 4, k = bk & 15;
    int tid = threadIdx.x;
    float s = 0.f, q = 0.f;
    for (int l = tid; l < LCTX; l += 256){
        float v = x[(b*LCTX + l)*KVAR + k];
        s += v; q += v*v;
    }
    __shared__ float sh[64];
#pragma unroll
    for (int o = 16; o; o >>= 1){
        s += __shfl_xor_sync(~0u, s, o);
        q += __shfl_xor_sync(~0u, q, o);
    }
    int w = tid >> 5;
    if ((tid & 31) == 0){ sh[w] = s; sh[w+32] = q; }
    __syncthreads();
    if (tid == 0){
        float S = 0.f, Q = 0.f;
        for (int i = 0; i < 8; i++){ S += sh[i]; Q += sh[32+i]; }
        float mu  = S * (1.f/LCTX);
        float var = Q * (1.f/LCTX) - mu*mu;
        g_mean[bk] = mu;
        g_std[bk]  = sqrtf(var + EPSF);
    }
}

// ---------------- patch embedding + pos + var embed ----------------
__global__ void embed_kernel(const float* __restrict__ x,
                             const float* __restrict__ pw,
                             const float* __restrict__ pb,
                             const float* __restrict__ pos,
                             const float* __restrict__ vemb){
    int row = blockIdx.x;
    int b = row / SEQ, rem = row % SEQ;
    int p = rem >> 4, k = rem & 15;
    int bk = b*KVAR + k;
    __shared__ float xs[PATCH];
    int tid = threadIdx.x;                   // 128
    if (tid < PATCH){
        float v = x[(b*LCTX + p*STRIDEP + tid)*KVAR + k];
        xs[tid] = (v - g_mean[bk]) / g_std[bk];
    }
    __syncthreads();
#pragma unroll
    for (int j = 0; j < 4; j++){
        int d = tid + j*128;
        float acc = pb[d] + pos[p*DM + d] + vemb[k*DM + d];
        const float4* w4 = (const float4*)(pw + d*PATCH);
#pragma unroll
        for (int t4 = 0; t4 < 4; t4++){
            float4 w = w4[t4];
            acc += xs[t4*4+0]*w.x + xs[t4*4+1]*w.y + xs[t4*4+2]*w.z + xs[t4*4+3]*w.w;
        }
        g_z[row*DM + d] = acc;
        g_zh[row*DM + d] = __float2half(acc);
    }
}

// ---------------- epilogue modes ----------------
enum { EP_NONE=0, EP_SPLIT=1, EP_GELU=3, EP_BIAS_RES=4, EP_RES=5 };

template<int EP>
__device__ __forceinline__ void ep_store(float* __restrict__ out0, float* __restrict__ out1,
                                         __half* __restrict__ outh, int ldo,
                                         const float* __restrict__ bias,
                                         const float* __restrict__ res,
                                         int row, int col, float v0, float v1){
    if (EP == EP_NONE){
        out0[(size_t)row*ldo + col    ] = v0;
        out0[(size_t)row*ldo + col + 1] = v1;
    } else if (EP == EP_SPLIT){
        if (col < DIN){
            float s0 = siluf(v0), s1 = siluf(v1);
            *(__half2*)&outh[(size_t)row*DIN + col] = __floats2half2_rn(s0, s1);
        } else {
            __half* zgh = (__half*)out1;
            *(__half2*)&zgh[(size_t)row*DIN + col - DIN] = __floats2half2_rn(v0, v1);
        }
    } else if (EP == EP_GELU){
        float g0 = geluf(v0 + bias[col]);
        float g1 = geluf(v1 + bias[col+1]);
        *(__half2*)&outh[(size_t)row*ldo + col] = __floats2half2_rn(g0, g1);
    } else if (EP == EP_BIAS_RES){
        float f0 = v0 + bias[col]   + res[(size_t)row*ldo + col];
        float f1 = v1 + bias[col+1] + res[(size_t)row*ldo + col + 1];
        out0[(size_t)row*ldo + col    ] = f0;
        out0[(size_t)row*ldo + col + 1] = f1;
        *(__half2*)&outh[(size_t)row*ldo + col] = __floats2half2_rn(f0, f1);
    } else { // EP_RES
        out0[(size_t)row*ldo + col    ] = v0 + res[(size_t)row*ldo + col];
        out0[(size_t)row*ldo + col + 1] = v1 + res[(size_t)row*ldo + col + 1];
    }
}

// ---------------- fp16 NT GEMM, 128x128 block, BK=64, 3-stage cp.async ---
// 8 warps as 2(M) x 4(N), warp tile 64x32. Half the barriers vs BK=32.
#define G2_PITCH  72                 // halfs per smem row (144 B; conflict-free)
#define G2_PITCHB 144
#define G2_STG    (128*G2_PITCH)     // 9216 halfs per stage per operand
#define G2_BOFF   (3*G2_STG)
#define G2_SMEM   (2*3*G2_STG*2)     // 110592 bytes

template<int EP>
__global__ void __launch_bounds__(256, 2) gemm_h(const __half* __restrict__ A, int lda,
                        const __half* __restrict__ W, int Kd,
                        float* __restrict__ out0, float* __restrict__ out1,
                        __half* __restrict__ outh, int ldo,
                        const float* __restrict__ bias, const float* __restrict__ res){
    extern __shared__ __half smh[];
    int tid = threadIdx.x;
    int nt = blockIdx.x, mt = blockIdx.y;
    int lane = tid & 31, wid = tid >> 5;
    int warpM = wid & 1, warpN = wid >> 1;      // 2 x 4
    int grp = lane >> 2, tig = lane & 3;

    const __half* Abase = A + (size_t)(mt*128)*lda;
    const __half* Wbase = W + (size_t)(nt*128)*Kd;

    unsigned smBytes = smem_u32(smh);
    int aRow  = lane & 15;
    int aKsel = (lane >> 4) * 8;
    int bRowSel = (lane & 7) + ((lane >> 4) * 8);
    int bKsel = ((lane >> 3) & 1) * 8;

    float acc[4][4][4];
#pragma unroll
    for (int i = 0; i < 4; i++)
#pragma unroll
        for (int j = 0; j < 4; j++)
#pragma unroll
            for (int h = 0; h < 4; h++) acc[i][j][h] = 0.f;

    int nK = Kd >> 6;                // 64-wide K slabs

    // each stage: A 128 rows x 8 chunks, B 128 rows x 8 chunks (8 halfs each)
    auto issue = [&](int stage){
        int buf = stage % 3;
        int ko = stage * 64;
#pragma unroll
        for (int i2 = 0; i2 < 4; i2++){
            int ca = tid + i2*256;
            int r2 = ca >> 3, cc = (ca & 7)*8;
            cp16(&smh[buf*G2_STG + r2*G2_PITCH + cc],           Abase + (size_t)r2*lda + ko + cc);
            cp16(&smh[G2_BOFF + buf*G2_STG + r2*G2_PITCH + cc], Wbase + (size_t)r2*Kd  + ko + cc);
        }
        cp_commit();
    };

    issue(0);
    if (nK > 1) issue(1);
    else cp_commit();

    for (int kt = 0; kt < nK; kt++){
        asm volatile("cp.async.wait_group 1;");
        __syncthreads();                 // stage kt visible; compute kt-1 done
        if (kt + 2 < nK) issue(kt + 2);  // overwrites buffer (kt-1)%3 — safe
        else cp_commit();

        unsigned aSt = smBytes + (unsigned)((kt % 3)*G2_STG*2);
        unsigned bSt = smBytes + (unsigned)((G2_BOFF + (kt % 3)*G2_STG)*2);
#pragma unroll
        for (int k0 = 0; k0 < 64; k0 += 16){
            unsigned a[4][4], b[4][2];
#pragma unroll
            for (int i = 0; i < 4; i++){
                unsigned addr = aSt + (unsigned)((warpM*64 + i*16 + aRow)*G2_PITCHB
                                                 + (k0 + aKsel)*2);
                ldsm4(a[i][0], a[i][1], a[i][2], a[i][3], addr);
            }
#pragma unroll
            for (int j2 = 0; j2 < 2; j2++){
                unsigned addr = bSt + (unsigned)((warpN*32 + j2*16 + bRowSel)*G2_PITCHB
                                                 + (k0 + bKsel)*2);
                ldsm4(b[2*j2][0], b[2*j2][1], b[2*j2+1][0], b[2*j2+1][1], addr);
            }
#pragma unroll
            for (int i = 0; i < 4; i++)
#pragma unroll
                for (int j = 0; j < 4; j++)
                    mma_f16(acc[i][j], a[i], b[j]);
        }
    }

#pragma unroll
    for (int i = 0; i < 4; i++){
#pragma unroll
        for (int j = 0; j < 4; j++){
            int col = nt*128 + warpN*32 + j*8 + 2*tig;
#pragma unroll
            for (int h = 0; h < 2; h++){
                int row = mt*128 + warpM*64 + i*16 + grp + h*8;
                ep_store<EP>(out0, out1, outh, ldo, bias, res, row, col,
                             acc[i][j][h*2+0], acc[i][j][h*2+1]);
            }
        }
    }
}

// ---------------- fp16 NT GEMM, 32x64 block, BK=32, 6-stage (x_proj) -----
#define GH_PITCH 40
#define GH_PITCHB 80
template<int EP>
__global__ void __launch_bounds__(128, 3) gemm_h32(const __half* __restrict__ A, int lda,
                        const __half* __restrict__ W, int Kd,
                        float* __restrict__ out0, float* __restrict__ out1,
                        __half* __restrict__ outh, int ldo,
                        const float* __restrict__ bias, const float* __restrict__ res){
    __shared__ __align__(16) __half As[6][32*GH_PITCH];
    __shared__ __align__(16) __half Bs[6][64*GH_PITCH];
    int tid = threadIdx.x;
    int nt = blockIdx.x, mt = blockIdx.y;
    int lane = tid & 31, wid = tid >> 5;
    int grp = lane >> 2, tig = lane & 3;

    const __half* Abase = A + (size_t)(mt*32)*lda;
    const __half* Wbase = W + (size_t)(nt*64)*Kd;

    int r  = tid >> 2;
    int kk = (tid & 3) * 8;

    unsigned aBase0 = smem_u32(&As[0][0]);
    unsigned bBase0 = smem_u32(&Bs[0][0]);
    int aRow  = lane & 15;
    int aKsel = (lane >> 4) * 8;
    int bRowSel = (lane & 7) + ((lane >> 4) * 8);
    int bKsel = ((lane >> 3) & 1) * 8;

    float acc[2][2][4];
#pragma unroll
    for (int i = 0; i < 2; i++)
#pragma unroll
        for (int j = 0; j < 2; j++)
#pragma unroll
            for (int h = 0; h < 4; h++) acc[i][j][h] = 0.f;

    int nK = Kd >> 5;

    auto issue = [&](int stage){
        int buf = stage % 6;
        int ko = stage * 32;
        cp16(&As[buf][r*GH_PITCH + kk],        Abase + (size_t)r*lda       + ko + kk);
        cp16(&Bs[buf][r*GH_PITCH + kk],        Wbase + (size_t)r*Kd        + ko + kk);
        cp16(&Bs[buf][(r+32)*GH_PITCH + kk],   Wbase + (size_t)(r+32)*Kd   + ko + kk);
        cp_commit();
    };

#pragma unroll
    for (int s = 0; s < 5; s++){
        if (s < nK) issue(s); else cp_commit();
    }

    for (int kt = 0; kt < nK; kt++){
        asm volatile("cp.async.wait_group 4;");
        __syncthreads();
        if (kt + 5 < nK) issue(kt + 5); else cp_commit();
        unsigned aSt = aBase0 + (unsigned)((kt % 6)*32*GH_PITCHB);
        unsigned bSt = bBase0 + (unsigned)((kt % 6)*64*GH_PITCHB);
#pragma unroll
        for (int k0 = 0; k0 < 32; k0 += 16){
            unsigned a[2][4], b[2][2];
#pragma unroll
            for (int i = 0; i < 2; i++){
                unsigned addr = aSt + (unsigned)((i*16 + aRow)*GH_PITCHB + (k0 + aKsel)*2);
                ldsm4(a[i][0], a[i][1], a[i][2], a[i][3], addr);
            }
            {
                unsigned addr = bSt + (unsigned)((wid*16 + bRowSel)*GH_PITCHB + (k0 + bKsel)*2);
                ldsm4(b[0][0], b[0][1], b[1][0], b[1][1], addr);
            }
#pragma unroll
            for (int i = 0; i < 2; i++)
#pragma unroll
                for (int j = 0; j < 2; j++)
                    mma_f16(acc[i][j], a[i], b[j]);
        }
    }

#pragma unroll
    for (int i = 0; i < 2; i++){
#pragma unroll
        for (int j = 0; j < 2; j++){
            int col = nt*64 + wid*16 + j*8 + 2*tig;
#pragma unroll
            for (int h = 0; h < 2; h++){
                int row = mt*32 + i*16 + grp + h*8;
                ep_store<EP>(out0, out1, outh, ldo, bias, res, row, col,
                             acc[i][j][h*2+0], acc[i][j][h*2+1]);
            }
        }
    }
}

// ---------------- layer norm; 2nd LN / fp16 copy ----------------
template<bool DOUBLE>
__global__ void ln_kernel(const float* __restrict__ in,
                          const float* __restrict__ g1, const float* __restrict__ b1,
                          float* __restrict__ o1,
                          const float* __restrict__ g2, const float* __restrict__ b2,
                          __half* __restrict__ o2h){
    int w = threadIdx.x >> 5, lane = threadIdx.x & 31;
    int row = blockIdx.x*8 + w;
    const float4* in4 = (const float4*)(in + (size_t)row*DM);
    float4 v[4];
    float s = 0.f, q = 0.f;
#pragma unroll
    for (int i = 0; i < 4; i++){
        v[i] = in4[lane + 32*i];
        s += v[i].x + v[i].y + v[i].z + v[i].w;
        q += v[i].x*v[i].x + v[i].y*v[i].y + v[i].z*v[i].z + v[i].w*v[i].w;
    }
#pragma unroll
    for (int o = 16; o; o >>= 1){
        s += __shfl_xor_sync(~0u, s, o);
        q += __shfl_xor_sync(~0u, q, o);
    }
    float mu = s * (1.f/DM);
    float rs = rsqrtf(q*(1.f/DM) - mu*mu + EPSF);
    float4 zz[4];
    float s2 = 0.f, q2 = 0.f;
#pragma unroll
    for (int i = 0; i < 4; i++){
        float4 gg = ((const float4*)g1)[lane + 32*i];
        float4 bb = ((const float4*)b1)[lane + 32*i];
        zz[i].x = (v[i].x - mu)*rs*gg.x + bb.x;
        zz[i].y = (v[i].y - mu)*rs*gg.y + bb.y;
        zz[i].z = (v[i].z - mu)*rs*gg.z + bb.z;
        zz[i].w = (v[i].w - mu)*rs*gg.w + bb.w;
        if (DOUBLE){
            s2 += zz[i].x + zz[i].y + zz[i].z + zz[i].w;
            q2 += zz[i].x*zz[i].x + zz[i].y*zz[i].y + zz[i].z*zz[i].z + zz[i].w*zz[i].w;
        }
        ((float4*)(o1 + (size_t)row*DM))[lane + 32*i] = zz[i];
    }
    if (DOUBLE){
#pragma unroll
        for (int o = 16; o; o >>= 1){
            s2 += __shfl_xor_sync(~0u, s2, o);
            q2 += __shfl_xor_sync(~0u, q2, o);
        }
        float mu2 = s2 * (1.f/DM);
        float rs2 = rsqrtf(q2*(1.f/DM) - mu2*mu2 + EPSF);
        __half2* oo = (__half2*)(o2h + (size_t)row*DM);
#pragma unroll
        for (int i = 0; i < 4; i++){
            float4 gg = ((const float4*)g2)[lane + 32*i];
            float4 bb = ((const float4*)b2)[lane + 32*i];
            float o0 = (zz[i].x - mu2)*rs2*gg.x + bb.x;
            float o1v= (zz[i].y - mu2)*rs2*gg.y + bb.y;
            float o2v= (zz[i].z - mu2)*rs2*gg.z + bb.z;
            float o3 = (zz[i].w - mu2)*rs2*gg.w + bb.w;
            oo[2*(lane + 32*i)    ] = __floats2half2_rn(o0, o1v);
            oo[2*(lane + 32*i) + 1] = __floats2half2_rn(o2v, o3);
        }
    } else if (o2h){
        __half2* oo = (__half2*)(o2h + (size_t)row*DM);
#pragma unroll
        for (int i = 0; i < 4; i++){
            oo[2*(lane + 32*i)    ] = __floats2half2_rn(zz[i].x, zz[i].y);
            oo[2*(lane + 32*i) + 1] = __floats2half2_rn(zz[i].z, zz[i].w);
        }
    }
}

// ---------------- chunked selective scan ----------------
#define SC_DEPTH 8

// Phase 1: local scan from h=0, output final h + sum(delta); no y.
__global__ void __launch_bounds__(256) scan_part1(
                            const __half* __restrict__ u,
                            const float* __restrict__ xdbl,
                            const float* __restrict__ Wdt,
                            const float* __restrict__ bdt,
                            const float* __restrict__ A_log){
    __shared__ __align__(16) char ring[8][SC_DEPTH][320];
    int blk = blockIdx.x;
    int b = blk >> 3, dblk = blk & 7;
    int chunk = blockIdx.y;
    int tid = threadIdx.x;
    int w = tid >> 5, lane = tid & 31;
    int ph = lane & 1;
    int d = dblk*128 + w*16 + (lane >> 1);
    int nb = ph * 8;
    int tbeg = chunk*CHL, tend = tbeg + CHL;

    float Aa[8];
#pragma unroll
    for (int j = 0; j < 8; j++) Aa[j] = -expf(A_log[d*NST + nb + j]);
    float A0 = Aa[0];
    float stepA = Aa[1] - Aa[0];
    bool prog = true;
#pragma unroll
    for (int j = 0; j < 8; j++){
        float e = A0 + (float)j * stepA;
        if (fabsf(Aa[j] - e) > 1e-5f*fabsf(e) + 1e-7f) prog = false;
    }
    float bd = bdt[d];
    float wdt[16];
#pragma unroll
    for (int j = 0; j < 16; j++) wdt[j] = Wdt[d*RNK + ph*16 + j];

    float h[8];
#pragma unroll
    for (int j = 0; j < 8; j++) h[j] = 0.f;
    float sumd = 0.f;

    size_t uvbase = (size_t)(b*SEQ)*DIN + dblk*128 + w*16;
    const float* xrow = xdbl + (size_t)(b*SEQ)*64;
    unsigned ring0 = smem_u32(&ring[w][0][0]);

    auto issue = [&](int t){
        unsigned sa = ring0 + (unsigned)((t % SC_DEPTH) * 320);
        if (lane < 2)
            cp16s(sa + lane*16, (const char*)u + (uvbase + (size_t)t*DIN)*2 + lane*16);
        else if (lane >= 4 && lane < 20)
            cp16s(sa + 64 + (lane-4)*16, (const char*)(xrow + (size_t)t*64) + (lane-4)*16);
        cp_commit();
    };

    auto calc_delta = [&](const float* xd) -> float {
        const float4 T0 = *(const float4*)(xd + ph*16);
        const float4 T1 = *(const float4*)(xd + ph*16 + 4);
        const float4 T2 = *(const float4*)(xd + ph*16 + 8);
        const float4 T3 = *(const float4*)(xd + ph*16 + 12);
        float a0 = T0.x*wdt[0]  + T0.y*wdt[1]  + T0.z*wdt[2]  + T0.w*wdt[3];
        float a1 = T1.x*wdt[4]  + T1.y*wdt[5]  + T1.z*wdt[6]  + T1.w*wdt[7];
        float a2 = T2.x*wdt[8]  + T2.y*wdt[9]  + T2.z*wdt[10] + T2.w*wdt[11];
        float a3 = T3.x*wdt[12] + T3.y*wdt[13] + T3.z*wdt[14] + T3.w*wdt[15];
        float p = (a0 + a1) + (a2 + a3);
        p += __shfl_xor_sync(~0u, p, 1);
        float xv = p + bd;
        return fmaxf(xv, 0.f) + __logf(1.f + __expf(-fabsf(xv)));
    };

#pragma unroll
    for (int t0 = 0; t0 < SC_DEPTH-1; t0++) issue(tbeg + t0);

    asm volatile("cp.async.wait_group %0;" :: "n"(SC_DEPTH-2));
    __syncwarp();
    float dv = calc_delta((const float*)(ring[w][tbeg % SC_DEPTH] + 64));

    for (int t = tbeg; t < tend; t++){
        asm volatile("cp.async.wait_group %0;" :: "n"(SC_DEPTH-3));
        __syncwarp();
        if (t + SC_DEPTH-1 < tend) issue(t + SC_DEPTH-1);
        else cp_commit();

        const char* sp = ring[w][t % SC_DEPTH];
        float uv = __half2float(((const __half*)sp)[lane >> 1]);
        const float* xd = (const float*)(sp + 64);
        float4 B0 = *(const float4*)(xd + 32 + nb);
        float4 B1 = *(const float4*)(xd + 36 + nb);

        sumd += dv;
        float du = dv * uv;
        if (prog){
            float e = __expf(dv * A0);
            float rr = __expf(dv * stepA);
            h[0] = h[0]*e + du*B0.x; e *= rr;
            h[1] = h[1]*e + du*B0.y; e *= rr;
            h[2] = h[2]*e + du*B0.z; e *= rr;
            h[3] = h[3]*e + du*B0.w; e *= rr;
            h[4] = h[4]*e + du*B1.x; e *= rr;
            h[5] = h[5]*e + du*B1.y; e *= rr;
            h[6] = h[6]*e + du*B1.z; e *= rr;
            h[7] = h[7]*e + du*B1.w;
        } else {
            float Bv[8] = {B0.x,B0.y,B0.z,B0.w,B1.x,B1.y,B1.z,B1.w};
#pragma unroll
            for (int j = 0; j < 8; j++){
                float e = __expf(dv * Aa[j]);
                h[j] = h[j]*e + du*Bv[j];
            }
        }
        if (t + 1 < tend)
            dv = calc_delta((const float*)(ring[w][(t+1) % SC_DEPTH] + 64));
    }

    size_t obase = (((size_t)(chunk*BB + b)*DIN + d))*NST + nb;
    *(float4*)&g_hch[obase]   = make_float4(h[0], h[1], h[2], h[3]);
    *(float4*)&g_hch[obase+4] = make_float4(h[4], h[5], h[6], h[7]);
    if (!ph) g_sumd[(size_t)(chunk*BB + b)*DIN + d] = sumd;
}

// Combine: sequential over chunk states per (b,d,n); writes h_in per chunk.
__global__ void scan_combine(const float* __restrict__ A_log){
    int idx = blockIdx.x*256 + threadIdx.x;     // 262144 threads
    int n = idx & 15;
    int d = (idx >> 4) & 1023;
    int b = idx >> 14;
    float An = -expf(A_log[d*NST + n]);
    float h = 0.f;
#pragma unroll
    for (int c = 0; c < NCH; c++){
        size_t base = (size_t)(c*BB + b)*DIN + d;
        g_hin[base*NST + n] = h;
        h = __expf(An * g_sumd[base]) * h + g_hch[base*NST + n];
    }
}

// Phase 2: scan with true h_in, produce y.
__global__ void __launch_bounds__(256) scan_part2(
                            const __half* __restrict__ u,
                            const __half* __restrict__ zg,
                            const float* __restrict__ xdbl,
                            const float* __restrict__ Wdt,
                            const float* __restrict__ bdt,
                            const float* __restrict__ A_log,
                            const float* __restrict__ Dp,
                            __half* __restrict__ y2h){
    __shared__ __align__(16) char ring[8][SC_DEPTH][320];
    int blk = blockIdx.x;
    int b = blk >> 3, dblk = blk & 7;
    int chunk = blockIdx.y;
    int tid = threadIdx.x;
    int w = tid >> 5, lane = tid & 31;
    int ph = lane & 1;
    int d = dblk*128 + w*16 + (lane >> 1);
    int nb = ph * 8;
    int tbeg = chunk*CHL, tend = tbeg + CHL;

    float Aa[8];
#pragma unroll
    for (int j = 0; j < 8; j++) Aa[j] = -expf(A_log[d*NST + nb + j]);
    float A0 = Aa[0];
    float stepA = Aa[1] - Aa[0];
    bool prog = true;
#pragma unroll
    for (int j = 0; j < 8; j++){
        float e = A0 + (float)j * stepA;
        if (fabsf(Aa[j] - e) > 1e-5f*fabsf(e) + 1e-7f) prog = false;
    }
    float Dd = Dp[d];
    float bd = bdt[d];
    float wdt[16];
#pragma unroll
    for (int j = 0; j < 16; j++) wdt[j] = Wdt[d*RNK + ph*16 + j];

    float h[8];
    {
        size_t ibase = (((size_t)(chunk*BB + b)*DIN + d))*NST + nb;
        float4 h0 = *(const float4*)&g_hin[ibase];
        float4 h1 = *(const float4*)&g_hin[ibase+4];
        h[0]=h0.x; h[1]=h0.y; h[2]=h0.z; h[3]=h0.w;
        h[4]=h1.x; h[5]=h1.y; h[6]=h1.z; h[7]=h1.w;
    }

    size_t uvbase = (size_t)(b*SEQ)*DIN + dblk*128 + w*16;
    const float* xrow = xdbl + (size_t)(b*SEQ)*64;
    size_t ybase = (size_t)(b*SEQ)*DIN + d;
    unsigned ring0 = smem_u32(&ring[w][0][0]);

    auto issue = [&](int t){
        unsigned sa = ring0 + (unsigned)((t % SC_DEPTH) * 320);
        if (lane < 20){
            if (lane < 2)
                cp16s(sa + lane*16, (const char*)u + (uvbase + (size_t)t*DIN)*2 + lane*16);
            else if (lane < 4)
                cp16s(sa + 32 + (lane-2)*16, (const char*)zg + (uvbase + (size_t)t*DIN)*2 + (lane-2)*16);
            else
                cp16s(sa + 64 + (lane-4)*16, (const char*)(xrow + (size_t)t*64) + (lane-4)*16);
        }
        cp_commit();
    };

    auto calc_delta = [&](const float* xd) -> float {
        const float4 T0 = *(const float4*)(xd + ph*16);
        const float4 T1 = *(const float4*)(xd + ph*16 + 4);
        const float4 T2 = *(const float4*)(xd + ph*16 + 8);
        const float4 T3 = *(const float4*)(xd + ph*16 + 12);
        float a0 = T0.x*wdt[0]  + T0.y*wdt[1]  + T0.z*wdt[2]  + T0.w*wdt[3];
        float a1 = T1.x*wdt[4]  + T1.y*wdt[5]  + T1.z*wdt[6]  + T1.w*wdt[7];
        float a2 = T2.x*wdt[8]  + T2.y*wdt[9]  + T2.z*wdt[10] + T2.w*wdt[11];
        float a3 = T3.x*wdt[12] + T3.y*wdt[13] + T3.z*wdt[14] + T3.w*wdt[15];
        float p = (a0 + a1) + (a2 + a3);
        p += __shfl_xor_sync(~0u, p, 1);
        float xv = p + bd;
        return fmaxf(xv, 0.f) + __logf(1.f + __expf(-fabsf(xv)));
    };

#pragma unroll
    for (int t0 = 0; t0 < SC_DEPTH-1; t0++) issue(tbeg + t0);

    asm volatile("cp.async.wait_group %0;" :: "n"(SC_DEPTH-2));
    __syncwarp();
    float dv = calc_delta((const float*)(ring[w][tbeg % SC_DEPTH] + 64));

    for (int t = tbeg; t < tend; t++){
        asm volatile("cp.async.wait_group %0;" :: "n"(SC_DEPTH-3));
        __syncwarp();
        if (t + SC_DEPTH-1 < tend) issue(t + SC_DEPTH-1);
        else cp_commit();

        const char* sp = ring[w][t % SC_DEPTH];
        float uv = __half2float(((const __half*)sp)[lane >> 1]);
        float zv = __half2float(((const __half*)(sp + 32))[lane >> 1]);
        const float* xd = (const float*)(sp + 64);
        float4 B0 = *(const float4*)(xd + 32 + nb);
        float4 B1 = *(const float4*)(xd + 36 + nb);
        float4 C0 = *(const float4*)(xd + 48 + nb);
        float4 C1 = *(const float4*)(xd + 52 + nb);

        float du = dv * uv;
        float y = 0.f;
        if (prog){
            float e = __expf(dv * A0);
            float rr = __expf(dv * stepA);
            h[0] = h[0]*e + du*B0.x; y += h[0]*C0.x; e *= rr;
            h[1] = h[1]*e + du*B0.y; y += h[1]*C0.y; e *= rr;
            h[2] = h[2]*e + du*B0.z; y += h[2]*C0.z; e *= rr;
            h[3] = h[3]*e + du*B0.w; y += h[3]*C0.w; e *= rr;
            h[4] = h[4]*e + du*B1.x; y += h[4]*C1.x; e *= rr;
            h[5] = h[5]*e + du*B1.y; y += h[5]*C1.y; e *= rr;
            h[6] = h[6]*e + du*B1.z; y += h[6]*C1.z; e *= rr;
            h[7] = h[7]*e + du*B1.w; y += h[7]*C1.w;
        } else {
            float Bv[8] = {B0.x,B0.y,B0.z,B0.w,B1.x,B1.y,B1.z,B1.w};
            float Cv[8] = {C0.x,C0.y,C0.z,C0.w,C1.x,C1.y,C1.z,C1.w};
#pragma unroll
            for (int j = 0; j < 8; j++){
                float e = __expf(dv * Aa[j]);
                h[j] = h[j]*e + du*Bv[j];
                y += h[j]*Cv[j];
            }
        }
        float ysum = y + __shfl_xor_sync(~0u, y, 1);
        if (!ph){
            y2h[ybase + (size_t)t*DIN] = __float2half((ysum + uv*Dd) * siluf(zv));
        }
        if (t + 1 < tend)
            dv = calc_delta((const float*)(ring[w][(t+1) % SC_DEPTH] + 64));
    }
}

// ---------------- head: fp16 MMA partial GEMM per patch index p ----------
#define HB_PITCH  72
#define HB_PITCHB 144
#define HM_ASTG   (128*HB_PITCH)
#define HM_BSTG   (112*HB_PITCH)
#define HM_SMEM   (2*(HM_ASTG + HM_BSTG)*2)   // 69120 bytes

__global__ void __launch_bounds__(256) head_mma(const __half* __restrict__ zf,
                                                const __half* __restrict__ hw){
    extern __shared__ __half hsm[];
    __half* As = hsm;
    __half* Bs = hsm + 2*HM_ASTG;
    int p = blockIdx.x, mt = blockIdx.y;
    int tid = threadIdx.x, lane = tid & 31, wid = tid >> 5;
    int warpM = wid & 1, warpN = wid >> 1;     // 2 x 4; warp tile 64 x 24
    int grp = lane >> 2, tig = lane & 3;
    unsigned aB = smem_u32(As), bB = smem_u32(Bs);
    int aRow  = lane & 15;
    int aKsel = (lane >> 4) * 8;
    int bRowSel = (lane & 7) + ((lane >> 4) * 8);
    int bKsel = ((lane >> 3) & 1) * 8;

    // zero B pad rows [96,112) in both buffers
    for (int idx = tid; idx < 2*16*HB_PITCH; idx += 256){
        int buf = idx / (16*HB_PITCH);
        int rem = idx - buf*(16*HB_PITCH);
        Bs[buf*HM_BSTG + 96*HB_PITCH + rem] = __float2half(0.f);
    }
    __syncthreads();

    float acc[4][3][4];
#pragma unroll
    for (int i = 0; i < 4; i++)
#pragma unroll
        for (int j = 0; j < 3; j++)
#pragma unroll
            for (int h = 0; h < 4; h++) acc[i][j][h] = 0.f;

    auto issue = [&](int kt){
        int buf = kt & 1;
#pragma unroll
        for (int i2 = 0; i2 < 4; i2++){        // A: 128 rows x 8 chunks = 1024
            int ca = tid + i2*256;
            int r = ca >> 3, cc = (ca & 7)*8;
            int R = mt*128 + r, bb = R >> 4, k2 = R & 15;
            cp16(&As[buf*HM_ASTG + r*HB_PITCH + cc],
                 zf + ((size_t)(bb*SEQ + p*KVAR + k2))*DM + kt*64 + cc);
        }
#pragma unroll
        for (int i2 = 0; i2 < 3; i2++){        // B: 96 rows x 8 chunks = 768
            int cb = tid + i2*256;
            int rn = cb >> 3, cc = (cb & 7)*8;
            cp16(&Bs[buf*HM_BSTG + rn*HB_PITCH + cc],
                 hw + (size_t)rn*HWLD + p*DM + kt*64 + cc);
        }
        cp_commit();
    };

    issue(0);
    for (int kt = 0; kt < 8; kt++){
        __syncthreads();
        if (kt + 1 < 8) issue(kt + 1); else cp_commit();
        asm volatile("cp.async.wait_group 1;");
        __syncthreads();
        int buf = kt & 1;
        unsigned aSt = aB + (unsigned)(buf*HM_ASTG*2);
        unsigned bSt = bB + (unsigned)(buf*HM_BSTG*2);
#pragma unroll
        for (int k0 = 0; k0 < 64; k0 += 16){
            unsigned a[4][4], b[3][2], dump0, dump1;
#pragma unroll
            for (int i = 0; i < 4; i++){
                unsigned addr = aSt + (unsigned)((warpM*64 + i*16 + aRow)*HB_PITCHB
                                                 + (k0 + aKsel)*2);
                ldsm4(a[i][0], a[i][1], a[i][2], a[i][3], addr);
            }
            {
                unsigned addr = bSt + (unsigned)((warpN*24 + bRowSel)*HB_PITCHB + (k0 + bKsel)*2);
                ldsm4(b[0][0], b[0][1], b[1][0], b[1][1], addr);
                unsigned addr2 = bSt + (unsigned)((warpN*24 + 16 + bRowSel)*HB_PITCHB + (k0 + bKsel)*2);
                ldsm4(b[2][0], b[2][1], dump0, dump1, addr2);
            }
#pragma unroll
            for (int i = 0; i < 4; i++)
#pragma unroll
                for (int j = 0; j < 3; j++)
                    mma_f16(acc[i][j], a[i], b[j]);
        }
    }

#pragma unroll
    for (int i = 0; i < 4; i++){
#pragma unroll
        for (int j = 0; j < 3; j++){
            int col = warpN*24 + j*8 + 2*tig;
#pragma unroll
            for (int h = 0; h < 2; h++){
                int R = mt*128 + warpM*64 + i*16 + grp + h*8;
                g_headp[(size_t)(p*256 + R)*HPRED + col    ] = acc[i][j][h*2+0];
                g_headp[(size_t)(p*256 + R)*HPRED + col + 1] = acc[i][j][h*2+1];
            }
        }
    }
}

// ---------------- head reduction + de-normalization ----------------
__global__ void head_final(const float* __restrict__ hb, float* __restrict__ out){
    int idx = blockIdx.x*256 + threadIdx.x;
    int bk = idx / HPRED, hh = idx % HPRED;
    float s = 0.f;
    for (int p = 0; p < PP; p++) s += g_headp[(size_t)p*(BB*KVAR*HPRED) + idx];
    s += hb[hh];
    int b = bk >> 4, k = bk & 15;
    out[b*(HPRED*KVAR) + hh*KVAR + k] = s * g_std[bk] + g_mean[bk];
}

// ---------------- launch ----------------
extern "C" void kernel_launch(void* const* d_in, const int* in_sizes, int n_in,
                              void* d_out, int out_size){
    const float* x        = (const float*)d_in[0];
    const float* patch_w  = (const float*)d_in[1];
    const float* patch_b  = (const float*)d_in[2];
    const float* pos      = (const float*)d_in[3];
    const float* vemb     = (const float*)d_in[4];
    const float* in_w     = (const float*)d_in[5];
    const float* xp_w     = (const float*)d_in[6];
    const float* dt_w     = (const float*)d_in[7];
    const float* dt_b     = (const float*)d_in[8];
    const float* A_log    = (const float*)d_in[9];
    const float* D_par    = (const float*)d_in[10];
    const float* out_w    = (const float*)d_in[11];
    const float* tmb_g    = (const float*)d_in[12];
    const float* tmb_b    = (const float*)d_in[13];
    const float* ffn_g    = (const float*)d_in[14];
    const float* ffn_b    = (const float*)d_in[15];
    const float* ffn_w1   = (const float*)d_in[16];
    const float* ffn_b1   = (const float*)d_in[17];
    const float* ffn_w2   = (const float*)d_in[18];
    const float* ffn_b2   = (const float*)d_in[19];
    const float* norm_g   = (const float*)d_in[20];
    const float* norm_b   = (const float*)d_in[21];
    const float* head_w   = (const float*)d_in[22];
    const float* head_b   = (const float*)d_in[23];
    float* out = (float*)d_out;

    cudaFuncSetAttribute(gemm_h<EP_SPLIT>,    cudaFuncAttributeMaxDynamicSharedMemorySize, G2_SMEM);
    cudaFuncSetAttribute(gemm_h<EP_RES>,      cudaFuncAttributeMaxDynamicSharedMemorySize, G2_SMEM);
    cudaFuncSetAttribute(gemm_h<EP_GELU>,     cudaFuncAttributeMaxDynamicSharedMemorySize, G2_SMEM);
    cudaFuncSetAttribute(gemm_h<EP_BIAS_RES>, cudaFuncAttributeMaxDynamicSharedMemorySize, G2_SMEM);
    cudaFuncSetAttribute(head_mma,            cudaFuncAttributeMaxDynamicSharedMemorySize, HM_SMEM);

    float *z, *tmp, *xdbl;
    __half *zh, *uh, *zgh, *y2h, *hlnh, *hffh;
    __half *winh, *wxph, *woh, *w1h, *w2h, *hwwh;
    cudaGetSymbolAddress((void**)&z,    g_z);
    cudaGetSymbolAddress((void**)&tmp,  g_tmp);
    cudaGetSymbolAddress((void**)&xdbl, g_xdbl);
    cudaGetSymbolAddress((void**)&zh,   g_zh);
    cudaGetSymbolAddress((void**)&uh,   g_uh);
    cudaGetSymbolAddress((void**)&zgh,  g_zgh);
    cudaGetSymbolAddress((void**)&y2h,  g_y2h);
    cudaGetSymbolAddress((void**)&hlnh, g_hlnh);
    cudaGetSymbolAddress((void**)&hffh, g_hffh);
    cudaGetSymbolAddress((void**)&winh, h_inw);
    cudaGetSymbolAddress((void**)&wxph, h_xpw);
    cudaGetSymbolAddress((void**)&woh,  h_ow);
    cudaGetSymbolAddress((void**)&w1h,  h_w1);
    cudaGetSymbolAddress((void**)&w2h,  h_w2);
    cudaGetSymbolAddress((void**)&hwwh, h_hww);

    // merged weight conversion (fp32 -> fp16), single launch
    f2h_all<<<(F2H_TOT + 255)/256, 256>>>(in_w, xp_w, out_w, ffn_w1, ffn_w2, head_w,
                                          (__half2*)winh, (__half2*)wxph, (__half2*)woh,
                                          (__half2*)w1h, (__half2*)w2h, (__half2*)hwwh);

    stats_kernel<<<BB*KVAR, 256>>>(x);
    embed_kernel<<<TT, 128>>>(x, patch_w, patch_b, pos, vemb);

    const int MT  = TT/128;
    const int MT32= TT/32;

    for (int l = 0; l < NLAY; l++){
        const __half* Wi  = winh + (size_t)l*(2*DIN)*DM;
        const __half* Wx  = wxph + (size_t)l*64*DIN;
        const float*  Wdt = dt_w + (size_t)l*DIN*RNK;
        const float*  bdt = dt_b + (size_t)l*DIN;
        const float*  Al  = A_log+ (size_t)l*DIN*NST;
        const float*  Dl  = D_par+ (size_t)l*DIN;
        const __half* Wo  = woh  + (size_t)l*DM*DIN;
        const __half* W1  = w1h  + (size_t)l*DFF*DM;
        const float*  B1  = ffn_b1 + (size_t)l*DFF;
        const __half* W2  = w2h  + (size_t)l*DM*DFF;
        const float*  B2  = ffn_b2 + (size_t)l*DM;

        gemm_h<EP_SPLIT><<<dim3(16, MT), 256, G2_SMEM>>>(zh, DM, Wi, DM,
                                                         nullptr, (float*)zgh, uh, 0, nullptr, nullptr);
        gemm_h32<EP_NONE><<<dim3(1, MT32), 128>>>(uh, DIN, Wx, DIN, xdbl, nullptr, nullptr, 64, nullptr, nullptr);
        // chunked selective scan (exact combine)
        scan_part1<<<dim3(128, NCH), 256>>>(uh, xdbl, Wdt, bdt, Al);
        scan_combine<<<1024, 256>>>(Al);
        scan_part2<<<dim3(128, NCH), 256>>>(uh, zgh, xdbl, Wdt, bdt, Al, Dl, y2h);
        gemm_h<EP_RES><<<dim3(4, MT), 256, G2_SMEM>>>(y2h, DIN, Wo, DIN, tmp, nullptr, nullptr, DM, nullptr, z);
        ln_kernel<true><<<TT/8, 256>>>(tmp, tmb_g + l*DM, tmb_b + l*DM, z,
                                       ffn_g + l*DM, ffn_b + l*DM, hlnh);
        gemm_h<EP_GELU><<<dim3(16, MT), 256, G2_SMEM>>>(hlnh, DM, W1, DM, nullptr, nullptr, hffh, DFF, B1, nullptr);
        gemm_h<EP_BIAS_RES><<<dim3(4, MT), 256, G2_SMEM>>>(hffh, DFF, W2, DFF, z, nullptr, zh, DM, B2, z);
    }

    // final LN -> tmp (fp32) + hlnh (fp16 for head)
    ln_kernel<false><<<TT/8, 256>>>(z, norm_g, norm_b, tmp, nullptr, nullptr, hlnh);
    // head (fp16 MMA partials per p) + reduction
    head_mma<<<dim3(PP, 2), 256, HM_SMEM>>>(hlnh, hwwh);
    head_final<<<96, 256>>>(head_b, out);
    (void)in_sizes; (void)n_in; (void)out_size;
}

// round 17
// speedup vs baseline: 1.9480x; 1.0053x over previous
#include <cuda_runtime.h>
#include <cuda_fp16.h>
#include <math.h>

// ---------------- problem constants ----------------
#define BB     16
#define LCTX   512
#define KVAR   16
#define HPRED  96
#define DM     512
#define NST    16
#define NLAY   3
#define DFF    2048
#define PATCH  16
#define STRIDEP 8
#define PP     63
#define DIN    1024
#define RNK    32
#define SEQ    (KVAR*PP)     // 1008
#define TT     (BB*SEQ)      // 16128
#define EPSF   1e-5f
#define HWLD   (PP*DM)       // 32256
#define NCH    16            // scan chunks
#define CHL    (SEQ/NCH)     // 63 steps per chunk

// ---------------- scratch ----------------
__device__ float g_mean[BB*KVAR];
__device__ float g_std[BB*KVAR];
__device__ float g_z   [TT*DM];
__device__ float g_tmp [TT*DM];
__device__ float g_xdbl[TT*64 + 64];
__device__ float g_headp[PP*BB*KVAR*HPRED];
// chunked-scan state
__device__ float g_hch [NCH*BB*DIN*NST];
__device__ float g_hin [NCH*BB*DIN*NST];
__device__ float g_sumd[NCH*BB*DIN];
// fp16 activations
__device__ __half g_zh  [TT*DM];
__device__ __half g_uh  [TT*DIN + DIN];
__device__ __half g_zgh [TT*DIN + DIN];
__device__ __half g_y2h [TT*DIN];
__device__ __half g_hlnh[TT*DM];
__device__ __half g_hffh[TT*DFF];
// fp16 weights
__device__ __half h_inw[3*2048*512];
__device__ __half h_xpw[3*64*1024];
__device__ __half h_ow [3*512*1024];
__device__ __half h_w1 [3*2048*512];
__device__ __half h_w2 [3*512*2048];
__device__ __half h_hww[HPRED*HWLD];

// ---------------- helpers ----------------
__device__ __forceinline__ float siluf(float x){ return x / (1.f + __expf(-x)); }
__device__ __forceinline__ float geluf(float x){
    return 0.5f * x * (1.f + erff(x * 0.70710678118654752f));
}

__device__ __forceinline__ void cp16(void* smem, const void* g){
    unsigned a = (unsigned)__cvta_generic_to_shared(smem);
    asm volatile("cp.async.cg.shared.global [%0], [%1], 16;" :: "r"(a), "l"(g));
}
__device__ __forceinline__ void cp16s(unsigned saddr, const void* g){
    asm volatile("cp.async.cg.shared.global [%0], [%1], 16;" :: "r"(saddr), "l"(g));
}
__device__ __forceinline__ void cp_commit(){ asm volatile("cp.async.commit_group;"); }

__device__ __forceinline__ unsigned smem_u32(const void* p){
    unsigned a;
    asm("{ .reg .u64 t; cvta.to.shared.u64 t, %1; cvt.u32.u64 %0, t; }" : "=r"(a) : "l"(p));
    return a;
}

__device__ __forceinline__ void mma_f16(float* c, const unsigned* a, const unsigned* b){
    asm volatile("mma.sync.aligned.m16n8k16.row.col.f32.f16.f16.f32 "
        "{%0,%1,%2,%3}, {%4,%5,%6,%7}, {%8,%9}, {%0,%1,%2,%3};"
        : "+f"(c[0]),"+f"(c[1]),"+f"(c[2]),"+f"(c[3])
        : "r"(a[0]),"r"(a[1]),"r"(a[2]),"r"(a[3]), "r"(b[0]),"r"(b[1]));
}
__device__ __forceinline__ void ldsm4(unsigned &r0, unsigned &r1, unsigned &r2, unsigned &r3,
                                      unsigned addr){
    asm volatile("ldmatrix.sync.aligned.m8n8.x4.shared.b16 {%0,%1,%2,%3}, [%4];"
        : "=r"(r0),"=r"(r1),"=r"(r2),"=r"(r3) : "r"(addr));
}

// ---------------- merged fp32 -> fp16 conversion (all weights, 1 launch) --
#define F2H_N0 1572864   // in_w
#define F2H_N1 98304     // xp_w
#define F2H_N2 786432    // out_w
#define F2H_N3 1572864   // ffn_w1
#define F2H_N4 1572864   // ffn_w2
#define F2H_N5 1548288   // head_w
#define F2H_TOT (F2H_N0+F2H_N1+F2H_N2+F2H_N3+F2H_N4+F2H_N5)

__global__ void f2h_all(const float* __restrict__ p0, const float* __restrict__ p1,
                        const float* __restrict__ p2, const float* __restrict__ p3,
                        const float* __restrict__ p4, const float* __restrict__ p5,
                        __half2* q0, __half2* q1, __half2* q2,
                        __half2* q3, __half2* q4, __half2* q5){
    int i = blockIdx.x*256 + threadIdx.x;
    if (i >= F2H_TOT) return;
    const float* in; __half2* out; int off = i;
    if (off < F2H_N0){ in = p0; out = q0; }
    else if ((off -= F2H_N0) < F2H_N1){ in = p1; out = q1; }
    else if ((off -= F2H_N1) < F2H_N2){ in = p2; out = q2; }
    else if ((off -= F2H_N2) < F2H_N3){ in = p3; out = q3; }
    else if ((off -= F2H_N3) < F2H_N4){ in = p4; out = q4; }
    else { off -= F2H_N4; in = p5; out = q5; }
    float2 v = ((const float2*)in)[off];
    out[off] = __floats2half2_rn(v.x, v.y);
}

// ---------------- per-(b,k) mean/std over L ----------------
__global__ void stats_kernel(const float* __restrict__ x){
    int bk = blockIdx.x; int b = bk >> 4, k = bk & 15;
    int tid = threadIdx.x;
    float s = 0.f, q = 0.f;
    for (int l = tid; l < LCTX; l += 256){
        float v = x[(b*LCTX + l)*KVAR + k];
        s += v; q += v*v;
    }
    __shared__ float sh[64];
#pragma unroll
    for (int o = 16; o; o >>= 1){
        s += __shfl_xor_sync(~0u, s, o);
        q += __shfl_xor_sync(~0u, q, o);
    }
    int w = tid >> 5;
    if ((tid & 31) == 0){ sh[w] = s; sh[w+32] = q; }
    __syncthreads();
    if (tid == 0){
        float S = 0.f, Q = 0.f;
        for (int i = 0; i < 8; i++){ S += sh[i]; Q += sh[32+i]; }
        float mu  = S * (1.f/LCTX);
        float var = Q * (1.f/LCTX) - mu*mu;
        g_mean[bk] = mu;
        g_std[bk]  = sqrtf(var + EPSF);
    }
}

// ---------------- patch embedding + pos + var embed ----------------
__global__ void embed_kernel(const float* __restrict__ x,
                             const float* __restrict__ pw,
                             const float* __restrict__ pb,
                             const float* __restrict__ pos,
                             const float* __restrict__ vemb){
    int row = blockIdx.x;
    int b = row / SEQ, rem = row % SEQ;
    int p = rem >> 4, k = rem & 15;
    int bk = b*KVAR + k;
    __shared__ float xs[PATCH];
    int tid = threadIdx.x;                   // 128
    if (tid < PATCH){
        float v = x[(b*LCTX + p*STRIDEP + tid)*KVAR + k];
        xs[tid] = (v - g_mean[bk]) / g_std[bk];
    }
    __syncthreads();
#pragma unroll
    for (int j = 0; j < 4; j++){
        int d = tid + j*128;
        float acc = pb[d] + pos[p*DM + d] + vemb[k*DM + d];
        const float4* w4 = (const float4*)(pw + d*PATCH);
#pragma unroll
        for (int t4 = 0; t4 < 4; t4++){
            float4 w = w4[t4];
            acc += xs[t4*4+0]*w.x + xs[t4*4+1]*w.y + xs[t4*4+2]*w.z + xs[t4*4+3]*w.w;
        }
        g_z[row*DM + d] = acc;
        g_zh[row*DM + d] = __float2half(acc);
    }
}

// ---------------- epilogue modes ----------------
enum { EP_NONE=0, EP_SPLIT=1, EP_GELU=3, EP_BIAS_RES=4, EP_RES=5 };

template<int EP>
__device__ __forceinline__ void ep_store(float* __restrict__ out0, float* __restrict__ out1,
                                         __half* __restrict__ outh, int ldo,
                                         const float* __restrict__ bias,
                                         const float* __restrict__ res,
                                         int row, int col, float v0, float v1){
    if (EP == EP_NONE){
        out0[(size_t)row*ldo + col    ] = v0;
        out0[(size_t)row*ldo + col + 1] = v1;
    } else if (EP == EP_SPLIT){
        if (col < DIN){
            float s0 = siluf(v0), s1 = siluf(v1);
            *(__half2*)&outh[(size_t)row*DIN + col] = __floats2half2_rn(s0, s1);
        } else {
            __half* zgh = (__half*)out1;
            *(__half2*)&zgh[(size_t)row*DIN + col - DIN] = __floats2half2_rn(v0, v1);
        }
    } else if (EP == EP_GELU){
        float g0 = geluf(v0 + bias[col]);
        float g1 = geluf(v1 + bias[col+1]);
        *(__half2*)&outh[(size_t)row*ldo + col] = __floats2half2_rn(g0, g1);
    } else if (EP == EP_BIAS_RES){
        float f0 = v0 + bias[col]   + res[(size_t)row*ldo + col];
        float f1 = v1 + bias[col+1] + res[(size_t)row*ldo + col + 1];
        out0[(size_t)row*ldo + col    ] = f0;
        out0[(size_t)row*ldo + col + 1] = f1;
        *(__half2*)&outh[(size_t)row*ldo + col] = __floats2half2_rn(f0, f1);
    } else { // EP_RES
        out0[(size_t)row*ldo + col    ] = v0 + res[(size_t)row*ldo + col];
        out0[(size_t)row*ldo + col + 1] = v1 + res[(size_t)row*ldo + col + 1];
    }
}

// ---------------- fp16 NT GEMM, 128x128 block, BK=64, 3-stage cp.async ---
#define G2_PITCH  72
#define G2_PITCHB 144
#define G2_STG    (128*G2_PITCH)
#define G2_BOFF   (3*G2_STG)
#define G2_SMEM   (2*3*G2_STG*2)     // 110592 bytes

template<int EP>
__global__ void __launch_bounds__(256, 2) gemm_h(const __half* __restrict__ A, int lda,
                        const __half* __restrict__ W, int Kd,
                        float* __restrict__ out0, float* __restrict__ out1,
                        __half* __restrict__ outh, int ldo,
                        const float* __restrict__ bias, const float* __restrict__ res){
    extern __shared__ __half smh[];
    int tid = threadIdx.x;
    int nt = blockIdx.x, mt = blockIdx.y;
    int lane = tid & 31, wid = tid >> 5;
    int warpM = wid & 1, warpN = wid >> 1;      // 2 x 4
    int grp = lane >> 2, tig = lane & 3;

    const __half* Abase = A + (size_t)(mt*128)*lda;
    const __half* Wbase = W + (size_t)(nt*128)*Kd;

    unsigned smBytes = smem_u32(smh);
    int aRow  = lane & 15;
    int aKsel = (lane >> 4) * 8;
    int bRowSel = (lane & 7) + ((lane >> 4) * 8);
    int bKsel = ((lane >> 3) & 1) * 8;

    float acc[4][4][4];
#pragma unroll
    for (int i = 0; i < 4; i++)
#pragma unroll
        for (int j = 0; j < 4; j++)
#pragma unroll
            for (int h = 0; h < 4; h++) acc[i][j][h] = 0.f;

    int nK = Kd >> 6;

    auto issue = [&](int stage){
        int buf = stage % 3;
        int ko = stage * 64;
#pragma unroll
        for (int i2 = 0; i2 < 4; i2++){
            int ca = tid + i2*256;
            int r2 = ca >> 3, cc = (ca & 7)*8;
            cp16(&smh[buf*G2_STG + r2*G2_PITCH + cc],           Abase + (size_t)r2*lda + ko + cc);
            cp16(&smh[G2_BOFF + buf*G2_STG + r2*G2_PITCH + cc], Wbase + (size_t)r2*Kd  + ko + cc);
        }
        cp_commit();
    };

    issue(0);
    if (nK > 1) issue(1);
    else cp_commit();

    for (int kt = 0; kt < nK; kt++){
        asm volatile("cp.async.wait_group 1;");
        __syncthreads();
        if (kt + 2 < nK) issue(kt + 2);
        else cp_commit();

        unsigned aSt = smBytes + (unsigned)((kt % 3)*G2_STG*2);
        unsigned bSt = smBytes + (unsigned)((G2_BOFF + (kt % 3)*G2_STG)*2);
#pragma unroll
        for (int k0 = 0; k0 < 64; k0 += 16){
            unsigned a[4][4], b[4][2];
#pragma unroll
            for (int i = 0; i < 4; i++){
                unsigned addr = aSt + (unsigned)((warpM*64 + i*16 + aRow)*G2_PITCHB
                                                 + (k0 + aKsel)*2);
                ldsm4(a[i][0], a[i][1], a[i][2], a[i][3], addr);
            }
#pragma unroll
            for (int j2 = 0; j2 < 2; j2++){
                unsigned addr = bSt + (unsigned)((warpN*32 + j2*16 + bRowSel)*G2_PITCHB
                                                 + (k0 + bKsel)*2);
                ldsm4(b[2*j2][0], b[2*j2][1], b[2*j2+1][0], b[2*j2+1][1], addr);
            }
#pragma unroll
            for (int i = 0; i < 4; i++)
#pragma unroll
                for (int j = 0; j < 4; j++)
                    mma_f16(acc[i][j], a[i], b[j]);
        }
    }

#pragma unroll
    for (int i = 0; i < 4; i++){
#pragma unroll
        for (int j = 0; j < 4; j++){
            int col = nt*128 + warpN*32 + j*8 + 2*tig;
#pragma unroll
            for (int h = 0; h < 2; h++){
                int row = mt*128 + warpM*64 + i*16 + grp + h*8;
                ep_store<EP>(out0, out1, outh, ldo, bias, res, row, col,
                             acc[i][j][h*2+0], acc[i][j][h*2+1]);
            }
        }
    }
}

// ---------------- fp16 NT GEMM, 32x64 block, BK=64, 3-stage (x_proj) -----
#define X2_ASTG (32*G2_PITCH)
#define X2_BSTG (64*G2_PITCH)
template<int EP>
__global__ void __launch_bounds__(128, 3) gemm_h32(const __half* __restrict__ A, int lda,
                        const __half* __restrict__ W, int Kd,
                        float* __restrict__ out0, float* __restrict__ out1,
                        __half* __restrict__ outh, int ldo,
                        const float* __restrict__ bias, const float* __restrict__ res){
    __shared__ __align__(16) __half As[3][X2_ASTG];
    __shared__ __align__(16) __half Bs[3][X2_BSTG];
    int tid = threadIdx.x;
    int nt = blockIdx.x, mt = blockIdx.y;
    int lane = tid & 31, wid = tid >> 5;        // wid = warpN (0..3)
    int grp = lane >> 2, tig = lane & 3;

    const __half* Abase = A + (size_t)(mt*32)*lda;
    const __half* Wbase = W + (size_t)(nt*64)*Kd;

    unsigned aBase0 = smem_u32(&As[0][0]);
    unsigned bBase0 = smem_u32(&Bs[0][0]);
    int aRow  = lane & 15;
    int aKsel = (lane >> 4) * 8;
    int bRowSel = (lane & 7) + ((lane >> 4) * 8);
    int bKsel = ((lane >> 3) & 1) * 8;

    float acc[2][2][4];
#pragma unroll
    for (int i = 0; i < 2; i++)
#pragma unroll
        for (int j = 0; j < 2; j++)
#pragma unroll
            for (int h = 0; h < 4; h++) acc[i][j][h] = 0.f;

    int nK = Kd >> 6;                 // 16 slabs for K=1024

    auto issue = [&](int stage){
        int buf = stage % 3;
        int ko = stage * 64;
#pragma unroll
        for (int i2 = 0; i2 < 2; i2++){          // A: 32 rows x 8 chunks = 256
            int ca = tid + i2*128;
            int r2 = ca >> 3, cc = (ca & 7)*8;
            cp16(&As[buf][r2*G2_PITCH + cc], Abase + (size_t)r2*lda + ko + cc);
        }
#pragma unroll
        for (int i2 = 0; i2 < 4; i2++){          // B: 64 rows x 8 chunks = 512
            int cb = tid + i2*128;
            int rn = cb >> 3, cc = (cb & 7)*8;
            cp16(&Bs[buf][rn*G2_PITCH + cc], Wbase + (size_t)rn*Kd + ko + cc);
        }
        cp_commit();
    };

    issue(0);
    issue(1);                          // nK >= 2 always (K=1024)

    for (int kt = 0; kt < nK; kt++){
        asm volatile("cp.async.wait_group 1;");
        __syncthreads();
        if (kt + 2 < nK) issue(kt + 2);
        else cp_commit();
        unsigned aSt = aBase0 + (unsigned)((kt % 3)*X2_ASTG*2);
        unsigned bSt = bBase0 + (unsigned)((kt % 3)*X2_BSTG*2);
#pragma unroll
        for (int k0 = 0; k0 < 64; k0 += 16){
            unsigned a[2][4], b[2][2];
#pragma unroll
            for (int i = 0; i < 2; i++){
                unsigned addr = aSt + (unsigned)((i*16 + aRow)*G2_PITCHB + (k0 + aKsel)*2);
                ldsm4(a[i][0], a[i][1], a[i][2], a[i][3], addr);
            }
            {
                unsigned addr = bSt + (unsigned)((wid*16 + bRowSel)*G2_PITCHB + (k0 + bKsel)*2);
                ldsm4(b[0][0], b[0][1], b[1][0], b[1][1], addr);
            }
#pragma unroll
            for (int i = 0; i < 2; i++)
#pragma unroll
                for (int j = 0; j < 2; j++)
                    mma_f16(acc[i][j], a[i], b[j]);
        }
    }

#pragma unroll
    for (int i = 0; i < 2; i++){
#pragma unroll
        for (int j = 0; j < 2; j++){
            int col = nt*64 + wid*16 + j*8 + 2*tig;
#pragma unroll
            for (int h = 0; h < 2; h++){
                int row = mt*32 + i*16 + grp + h*8;
                ep_store<EP>(out0, out1, outh, ldo, bias, res, row, col,
                             acc[i][j][h*2+0], acc[i][j][h*2+1]);
            }
        }
    }
}

// ---------------- layer norm; 2nd LN / fp16 copy; o1 nullable ----------
template<bool DOUBLE>
__global__ void ln_kernel(const float* __restrict__ in,
                          const float* __restrict__ g1, const float* __restrict__ b1,
                          float* __restrict__ o1,
                          const float* __restrict__ g2, const float* __restrict__ b2,
                          __half* __restrict__ o2h){
    int w = threadIdx.x >> 5, lane = threadIdx.x & 31;
    int row = blockIdx.x*8 + w;
    const float4* in4 = (const float4*)(in + (size_t)row*DM);
    float4 v[4];
    float s = 0.f, q = 0.f;
#pragma unroll
    for (int i = 0; i < 4; i++){
        v[i] = in4[lane + 32*i];
        s += v[i].x + v[i].y + v[i].z + v[i].w;
        q += v[i].x*v[i].x + v[i].y*v[i].y + v[i].z*v[i].z + v[i].w*v[i].w;
    }
#pragma unroll
    for (int o = 16; o; o >>= 1){
        s += __shfl_xor_sync(~0u, s, o);
        q += __shfl_xor_sync(~0u, q, o);
    }
    float mu = s * (1.f/DM);
    float rs = rsqrtf(q*(1.f/DM) - mu*mu + EPSF);
    float4 zz[4];
    float s2 = 0.f, q2 = 0.f;
#pragma unroll
    for (int i = 0; i < 4; i++){
        float4 gg = ((const float4*)g1)[lane + 32*i];
        float4 bb = ((const float4*)b1)[lane + 32*i];
        zz[i].x = (v[i].x - mu)*rs*gg.x + bb.x;
        zz[i].y = (v[i].y - mu)*rs*gg.y + bb.y;
        zz[i].z = (v[i].z - mu)*rs*gg.z + bb.z;
        zz[i].w = (v[i].w - mu)*rs*gg.w + bb.w;
        if (DOUBLE){
            s2 += zz[i].x + zz[i].y + zz[i].z + zz[i].w;
            q2 += zz[i].x*zz[i].x + zz[i].y*zz[i].y + zz[i].z*zz[i].z + zz[i].w*zz[i].w;
        }
        if (o1) ((float4*)(o1 + (size_t)row*DM))[lane + 32*i] = zz[i];
    }
    if (DOUBLE){
#pragma unroll
        for (int o = 16; o; o >>= 1){
            s2 += __shfl_xor_sync(~0u, s2, o);
            q2 += __shfl_xor_sync(~0u, q2, o);
        }
        float mu2 = s2 * (1.f/DM);
        float rs2 = rsqrtf(q2*(1.f/DM) - mu2*mu2 + EPSF);
        __half2* oo = (__half2*)(o2h + (size_t)row*DM);
#pragma unroll
        for (int i = 0; i < 4; i++){
            float4 gg = ((const float4*)g2)[lane + 32*i];
            float4 bb = ((const float4*)b2)[lane + 32*i];
            float o0 = (zz[i].x - mu2)*rs2*gg.x + bb.x;
            float o1v= (zz[i].y - mu2)*rs2*gg.y + bb.y;
            float o2v= (zz[i].z - mu2)*rs2*gg.z + bb.z;
            float o3 = (zz[i].w - mu2)*rs2*gg.w + bb.w;
            oo[2*(lane + 32*i)    ] = __floats2half2_rn(o0, o1v);
            oo[2*(lane + 32*i) + 1] = __floats2half2_rn(o2v, o3);
        }
    } else if (o2h){
        __half2* oo = (__half2*)(o2h + (size_t)row*DM);
#pragma unroll
        for (int i = 0; i < 4; i++){
            oo[2*(lane + 32*i)    ] = __floats2half2_rn(zz[i].x, zz[i].y);
            oo[2*(lane + 32*i) + 1] = __floats2half2_rn(zz[i].z, zz[i].w);
        }
    }
}

// ---------------- chunked selective scan ----------------
#define SC_DEPTH 8

// Phase 1: local scan from h=0, output final h + sum(delta); no y.
__global__ void __launch_bounds__(256) scan_part1(
                            const __half* __restrict__ u,
                            const float* __restrict__ xdbl,
                            const float* __restrict__ Wdt,
                            const float* __restrict__ bdt,
                            const float* __restrict__ A_log){
    __shared__ __align__(16) char ring[8][SC_DEPTH][320];
    int blk = blockIdx.x;
    int b = blk >> 3, dblk = blk & 7;
    int chunk = blockIdx.y;
    int tid = threadIdx.x;
    int w = tid >> 5, lane = tid & 31;
    int ph = lane & 1;
    int d = dblk*128 + w*16 + (lane >> 1);
    int nb = ph * 8;
    int tbeg = chunk*CHL, tend = tbeg + CHL;

    float Aa[8];
#pragma unroll
    for (int j = 0; j < 8; j++) Aa[j] = -expf(A_log[d*NST + nb + j]);
    float A0 = Aa[0];
    float stepA = Aa[1] - Aa[0];
    bool prog = true;
#pragma unroll
    for (int j = 0; j < 8; j++){
        float e = A0 + (float)j * stepA;
        if (fabsf(Aa[j] - e) > 1e-5f*fabsf(e) + 1e-7f) prog = false;
    }
    float bd = bdt[d];
    float wdt[16];
#pragma unroll
    for (int j = 0; j < 16; j++) wdt[j] = Wdt[d*RNK + ph*16 + j];

    float h[8];
#pragma unroll
    for (int j = 0; j < 8; j++) h[j] = 0.f;
    float sumd = 0.f;

    size_t uvbase = (size_t)(b*SEQ)*DIN + dblk*128 + w*16;
    const float* xrow = xdbl + (size_t)(b*SEQ)*64;
    unsigned ring0 = smem_u32(&ring[w][0][0]);

    auto issue = [&](int t){
        unsigned sa = ring0 + (unsigned)((t % SC_DEPTH) * 320);
        if (lane < 2)
            cp16s(sa + lane*16, (const char*)u + (uvbase + (size_t)t*DIN)*2 + lane*16);
        else if (lane >= 4 && lane < 20)
            cp16s(sa + 64 + (lane-4)*16, (const char*)(xrow + (size_t)t*64) + (lane-4)*16);
        cp_commit();
    };

    auto calc_delta = [&](const float* xd) -> float {
        const float4 T0 = *(const float4*)(xd + ph*16);
        const float4 T1 = *(const float4*)(xd + ph*16 + 4);
        const float4 T2 = *(const float4*)(xd + ph*16 + 8);
        const float4 T3 = *(const float4*)(xd + ph*16 + 12);
        float a0 = T0.x*wdt[0]  + T0.y*wdt[1]  + T0.z*wdt[2]  + T0.w*wdt[3];
        float a1 = T1.x*wdt[4]  + T1.y*wdt[5]  + T1.z*wdt[6]  + T1.w*wdt[7];
        float a2 = T2.x*wdt[8]  + T2.y*wdt[9]  + T2.z*wdt[10] + T2.w*wdt[11];
        float a3 = T3.x*wdt[12] + T3.y*wdt[13] + T3.z*wdt[14] + T3.w*wdt[15];
        float p = (a0 + a1) + (a2 + a3);
        p += __shfl_xor_sync(~0u, p, 1);
        float xv = p + bd;
        return fmaxf(xv, 0.f) + __logf(1.f + __expf(-fabsf(xv)));
    };

#pragma unroll
    for (int t0 = 0; t0 < SC_DEPTH-1; t0++) issue(tbeg + t0);

    asm volatile("cp.async.wait_group %0;" :: "n"(SC_DEPTH-2));
    __syncwarp();
    float dv = calc_delta((const float*)(ring[w][tbeg % SC_DEPTH] + 64));

    for (int t = tbeg; t < tend; t++){
        asm volatile("cp.async.wait_group %0;" :: "n"(SC_DEPTH-3));
        __syncwarp();
        if (t + SC_DEPTH-1 < tend) issue(t + SC_DEPTH-1);
        else cp_commit();

        const char* sp = ring[w][t % SC_DEPTH];
        float uv = __half2float(((const __half*)sp)[lane >> 1]);
        const float* xd = (const float*)(sp + 64);
        float4 B0 = *(const float4*)(xd + 32 + nb);
        float4 B1 = *(const float4*)(xd + 36 + nb);

        sumd += dv;
        float du = dv * uv;
        if (prog){
            float e = __expf(dv * A0);
            float rr = __expf(dv * stepA);
            h[0] = h[0]*e + du*B0.x; e *= rr;
            h[1] = h[1]*e + du*B0.y; e *= rr;
            h[2] = h[2]*e + du*B0.z; e *= rr;
            h[3] = h[3]*e + du*B0.w; e *= rr;
            h[4] = h[4]*e + du*B1.x; e *= rr;
            h[5] = h[5]*e + du*B1.y; e *= rr;
            h[6] = h[6]*e + du*B1.z; e *= rr;
            h[7] = h[7]*e + du*B1.w;
        } else {
            float Bv[8] = {B0.x,B0.y,B0.z,B0.w,B1.x,B1.y,B1.z,B1.w};
#pragma unroll
            for (int j = 0; j < 8; j++){
                float e = __expf(dv * Aa[j]);
                h[j] = h[j]*e + du*Bv[j];
            }
        }
        if (t + 1 < tend)
            dv = calc_delta((const float*)(ring[w][(t+1) % SC_DEPTH] + 64));
    }

    size_t obase = (((size_t)(chunk*BB + b)*DIN + d))*NST + nb;
    *(float4*)&g_hch[obase]   = make_float4(h[0], h[1], h[2], h[3]);
    *(float4*)&g_hch[obase+4] = make_float4(h[4], h[5], h[6], h[7]);
    if (!ph) g_sumd[(size_t)(chunk*BB + b)*DIN + d] = sumd;
}

// Combine: sequential over chunk states per (b,d,n); writes h_in per chunk.
__global__ void scan_combine(const float* __restrict__ A_log){
    int idx = blockIdx.x*256 + threadIdx.x;     // 262144 threads
    int n = idx & 15;
    int d = (idx >> 4) & 1023;
    int b = idx >> 14;
    float An = -expf(A_log[d*NST + n]);
    float h = 0.f;
#pragma unroll
    for (int c = 0; c < NCH; c++){
        size_t base = (size_t)(c*BB + b)*DIN + d;
        g_hin[base*NST + n] = h;
        h = __expf(An * g_sumd[base]) * h + g_hch[base*NST + n];
    }
}

// Phase 2: scan with true h_in, produce y.
__global__ void __launch_bounds__(256) scan_part2(
                            const __half* __restrict__ u,
                            const __half* __restrict__ zg,
                            const float* __restrict__ xdbl,
                            const float* __restrict__ Wdt,
                            const float* __restrict__ bdt,
                            const float* __restrict__ A_log,
                            const float* __restrict__ Dp,
                            __half* __restrict__ y2h){
    __shared__ __align__(16) char ring[8][SC_DEPTH][320];
    int blk = blockIdx.x;
    int b = blk >> 3, dblk = blk & 7;
    int chunk = blockIdx.y;
    int tid = threadIdx.x;
    int w = tid >> 5, lane = tid & 31;
    int ph = lane & 1;
    int d = dblk*128 + w*16 + (lane >> 1);
    int nb = ph * 8;
    int tbeg = chunk*CHL, tend = tbeg + CHL;

    float Aa[8];
#pragma unroll
    for (int j = 0; j < 8; j++) Aa[j] = -expf(A_log[d*NST + nb + j]);
    float A0 = Aa[0];
    float stepA = Aa[1] - Aa[0];
    bool prog = true;
#pragma unroll
    for (int j = 0; j < 8; j++){
        float e = A0 + (float)j * stepA;
        if (fabsf(Aa[j] - e) > 1e-5f*fabsf(e) + 1e-7f) prog = false;
    }
    float Dd = Dp[d];
    float bd = bdt[d];
    float wdt[16];
#pragma unroll
    for (int j = 0; j < 16; j++) wdt[j] = Wdt[d*RNK + ph*16 + j];

    float h[8];
    {
        size_t ibase = (((size_t)(chunk*BB + b)*DIN + d))*NST + nb;
        float4 h0 = *(const float4*)&g_hin[ibase];
        float4 h1 = *(const float4*)&g_hin[ibase+4];
        h[0]=h0.x; h[1]=h0.y; h[2]=h0.z; h[3]=h0.w;
        h[4]=h1.x; h[5]=h1.y; h[6]=h1.z; h[7]=h1.w;
    }

    size_t uvbase = (size_t)(b*SEQ)*DIN + dblk*128 + w*16;
    const float* xrow = xdbl + (size_t)(b*SEQ)*64;
    size_t ybase = (size_t)(b*SEQ)*DIN + d;
    unsigned ring0 = smem_u32(&ring[w][0][0]);

    auto issue = [&](int t){
        unsigned sa = ring0 + (unsigned)((t % SC_DEPTH) * 320);
        if (lane < 20){
            if (lane < 2)
                cp16s(sa + lane*16, (const char*)u + (uvbase + (size_t)t*DIN)*2 + lane*16);
            else if (lane < 4)
                cp16s(sa + 32 + (lane-2)*16, (const char*)zg + (uvbase + (size_t)t*DIN)*2 + (lane-2)*16);
            else
                cp16s(sa + 64 + (lane-4)*16, (const char*)(xrow + (size_t)t*64) + (lane-4)*16);
        }
        cp_commit();
    };

    auto calc_delta = [&](const float* xd) -> float {
        const float4 T0 = *(const float4*)(xd + ph*16);
        const float4 T1 = *(const float4*)(xd + ph*16 + 4);
        const float4 T2 = *(const float4*)(xd + ph*16 + 8);
        const float4 T3 = *(const float4*)(xd + ph*16 + 12);
        float a0 = T0.x*wdt[0]  + T0.y*wdt[1]  + T0.z*wdt[2]  + T0.w*wdt[3];
        float a1 = T1.x*wdt[4]  + T1.y*wdt[5]  + T1.z*wdt[6]  + T1.w*wdt[7];
        float a2 = T2.x*wdt[8]  + T2.y*wdt[9]  + T2.z*wdt[10] + T2.w*wdt[11];
        float a3 = T3.x*wdt[12] + T3.y*wdt[13] + T3.z*wdt[14] + T3.w*wdt[15];
        float p = (a0 + a1) + (a2 + a3);
        p += __shfl_xor_sync(~0u, p, 1);
        float xv = p + bd;
        return fmaxf(xv, 0.f) + __logf(1.f + __expf(-fabsf(xv)));
    };

#pragma unroll
    for (int t0 = 0; t0 < SC_DEPTH-1; t0++) issue(tbeg + t0);

    asm volatile("cp.async.wait_group %0;" :: "n"(SC_DEPTH-2));
    __syncwarp();
    float dv = calc_delta((const float*)(ring[w][tbeg % SC_DEPTH] + 64));

    for (int t = tbeg; t < tend; t++){
        asm volatile("cp.async.wait_group %0;" :: "n"(SC_DEPTH-3));
        __syncwarp();
        if (t + SC_DEPTH-1 < tend) issue(t + SC_DEPTH-1);
        else cp_commit();

        const char* sp = ring[w][t % SC_DEPTH];
        float uv = __half2float(((const __half*)sp)[lane >> 1]);
        float zv = __half2float(((const __half*)(sp + 32))[lane >> 1]);
        const float* xd = (const float*)(sp + 64);
        float4 B0 = *(const float4*)(xd + 32 + nb);
        float4 B1 = *(const float4*)(xd + 36 + nb);
        float4 C0 = *(const float4*)(xd + 48 + nb);
        float4 C1 = *(const float4*)(xd + 52 + nb);

        float du = dv * uv;
        float y = 0.f;
        if (prog){
            float e = __expf(dv * A0);
            float rr = __expf(dv * stepA);
            h[0] = h[0]*e + du*B0.x; y += h[0]*C0.x; e *= rr;
            h[1] = h[1]*e + du*B0.y; y += h[1]*C0.y; e *= rr;
            h[2] = h[2]*e + du*B0.z; y += h[2]*C0.z; e *= rr;
            h[3] = h[3]*e + du*B0.w; y += h[3]*C0.w; e *= rr;
            h[4] = h[4]*e + du*B1.x; y += h[4]*C1.x; e *= rr;
            h[5] = h[5]*e + du*B1.y; y += h[5]*C1.y; e *= rr;
            h[6] = h[6]*e + du*B1.z; y += h[6]*C1.z; e *= rr;
            h[7] = h[7]*e + du*B1.w; y += h[7]*C1.w;
        } else {
            float Bv[8] = {B0.x,B0.y,B0.z,B0.w,B1.x,B1.y,B1.z,B1.w};
            float Cv[8] = {C0.x,C0.y,C0.z,C0.w,C1.x,C1.y,C1.z,C1.w};
#pragma unroll
            for (int j = 0; j < 8; j++){
                float e = __expf(dv * Aa[j]);
                h[j] = h[j]*e + du*Bv[j];
                y += h[j]*Cv[j];
            }
        }
        float ysum = y + __shfl_xor_sync(~0u, y, 1);
        if (!ph){
            y2h[ybase + (size_t)t*DIN] = __float2half((ysum + uv*Dd) * siluf(zv));
        }
        if (t + 1 < tend)
            dv = calc_delta((const float*)(ring[w][(t+1) % SC_DEPTH] + 64));
    }
}

// ---------------- head: fp16 MMA partial GEMM per patch index p ----------
#define HB_PITCH  72
#define HB_PITCHB 144
#define HM_ASTG   (128*HB_PITCH)
#define HM_BSTG   (112*HB_PITCH)
#define HM_SMEM   (2*(HM_ASTG + HM_BSTG)*2)   // 69120 bytes

__global__ void __launch_bounds__(256) head_mma(const __half* __restrict__ zf,
                                                const __half* __restrict__ hw){
    extern __shared__ __half hsm[];
    __half* As = hsm;
    __half* Bs = hsm + 2*HM_ASTG;
    int p = blockIdx.x, mt = blockIdx.y;
    int tid = threadIdx.x, lane = tid & 31, wid = tid >> 5;
    int warpM = wid & 1, warpN = wid >> 1;     // 2 x 4; warp tile 64 x 24
    int grp = lane >> 2, tig = lane & 3;
    unsigned aB = smem_u32(As), bB = smem_u32(Bs);
    int aRow  = lane & 15;
    int aKsel = (lane >> 4) * 8;
    int bRowSel = (lane & 7) + ((lane >> 4) * 8);
    int bKsel = ((lane >> 3) & 1) * 8;

    // zero B pad rows [96,112) in both buffers
    for (int idx = tid; idx < 2*16*HB_PITCH; idx += 256){
        int buf = idx / (16*HB_PITCH);
        int rem = idx - buf*(16*HB_PITCH);
        Bs[buf*HM_BSTG + 96*HB_PITCH + rem] = __float2half(0.f);
    }
    __syncthreads();

    float acc[4][3][4];
#pragma unroll
    for (int i = 0; i < 4; i++)
#pragma unroll
        for (int j = 0; j < 3; j++)
#pragma unroll
            for (int h = 0; h < 4; h++) acc[i][j][h] = 0.f;

    auto issue = [&](int kt){
        int buf = kt & 1;
#pragma unroll
        for (int i2 = 0; i2 < 4; i2++){        // A: 128 rows x 8 chunks = 1024
            int ca = tid + i2*256;
            int r = ca >> 3, cc = (ca & 7)*8;
            int R = mt*128 + r, bb = R >> 4, k2 = R & 15;
            cp16(&As[buf*HM_ASTG + r*HB_PITCH + cc],
                 zf + ((size_t)(bb*SEQ + p*KVAR + k2))*DM + kt*64 + cc);
        }
#pragma unroll
        for (int i2 = 0; i2 < 3; i2++){        // B: 96 rows x 8 chunks = 768
            int cb = tid + i2*256;
            int rn = cb >> 3, cc = (cb & 7)*8;
            cp16(&Bs[buf*HM_BSTG + rn*HB_PITCH + cc],
                 hw + (size_t)rn*HWLD + p*DM + kt*64 + cc);
        }
        cp_commit();
    };

    issue(0);
    for (int kt = 0; kt < 8; kt++){
        __syncthreads();
        if (kt + 1 < 8) issue(kt + 1); else cp_commit();
        asm volatile("cp.async.wait_group 1;");
        __syncthreads();
        int buf = kt & 1;
        unsigned aSt = aB + (unsigned)(buf*HM_ASTG*2);
        unsigned bSt = bB + (unsigned)(buf*HM_BSTG*2);
#pragma unroll
        for (int k0 = 0; k0 < 64; k0 += 16){
            unsigned a[4][4], b[3][2], dump0, dump1;
#pragma unroll
            for (int i = 0; i < 4; i++){
                unsigned addr = aSt + (unsigned)((warpM*64 + i*16 + aRow)*HB_PITCHB
                                                 + (k0 + aKsel)*2);
                ldsm4(a[i][0], a[i][1], a[i][2], a[i][3], addr);
            }
            {
                unsigned addr = bSt + (unsigned)((warpN*24 + bRowSel)*HB_PITCHB + (k0 + bKsel)*2);
                ldsm4(b[0][0], b[0][1], b[1][0], b[1][1], addr);
                unsigned addr2 = bSt + (unsigned)((warpN*24 + 16 + bRowSel)*HB_PITCHB + (k0 + bKsel)*2);
                ldsm4(b[2][0], b[2][1], dump0, dump1, addr2);
            }
#pragma unroll
            for (int i = 0; i < 4; i++)
#pragma unroll
                for (int j = 0; j < 3; j++)
                    mma_f16(acc[i][j], a[i], b[j]);
        }
    }

#pragma unroll
    for (int i = 0; i < 4; i++){
#pragma unroll
        for (int j = 0; j < 3; j++){
            int col = warpN*24 + j*8 + 2*tig;
#pragma unroll
            for (int h = 0; h < 2; h++){
                int R = mt*128 + warpM*64 + i*16 + grp + h*8;
                g_headp[(size_t)(p*256 + R)*HPRED + col    ] = acc[i][j][h*2+0];
                g_headp[(size_t)(p*256 + R)*HPRED + col + 1] = acc[i][j][h*2+1];
            }
        }
    }
}

// ---------------- head reduction + de-normalization ----------------
__global__ void head_final(const float* __restrict__ hb, float* __restrict__ out){
    int idx = blockIdx.x*256 + threadIdx.x;
    int bk = idx / HPRED, hh = idx % HPRED;
    float s = 0.f;
    for (int p = 0; p < PP; p++) s += g_headp[(size_t)p*(BB*KVAR*HPRED) + idx];
    s += hb[hh];
    int b = bk >> 4, k = bk & 15;
    out[b*(HPRED*KVAR) + hh*KVAR + k] = s * g_std[bk] + g_mean[bk];
}

// ---------------- launch ----------------
extern "C" void kernel_launch(void* const* d_in, const int* in_sizes, int n_in,
                              void* d_out, int out_size){
    const float* x        = (const float*)d_in[0];
    const float* patch_w  = (const float*)d_in[1];
    const float* patch_b  = (const float*)d_in[2];
    const float* pos      = (const float*)d_in[3];
    const float* vemb     = (const float*)d_in[4];
    const float* in_w     = (const float*)d_in[5];
    const float* xp_w     = (const float*)d_in[6];
    const float* dt_w     = (const float*)d_in[7];
    const float* dt_b     = (const float*)d_in[8];
    const float* A_log    = (const float*)d_in[9];
    const float* D_par    = (const float*)d_in[10];
    const float* out_w    = (const float*)d_in[11];
    const float* tmb_g    = (const float*)d_in[12];
    const float* tmb_b    = (const float*)d_in[13];
    const float* ffn_g    = (const float*)d_in[14];
    const float* ffn_b    = (const float*)d_in[15];
    const float* ffn_w1   = (const float*)d_in[16];
    const float* ffn_b1   = (const float*)d_in[17];
    const float* ffn_w2   = (const float*)d_in[18];
    const float* ffn_b2   = (const float*)d_in[19];
    const float* norm_g   = (const float*)d_in[20];
    const float* norm_b   = (const float*)d_in[21];
    const float* head_w   = (const float*)d_in[22];
    const float* head_b   = (const float*)d_in[23];
    float* out = (float*)d_out;

    cudaFuncSetAttribute(gemm_h<EP_SPLIT>,    cudaFuncAttributeMaxDynamicSharedMemorySize, G2_SMEM);
    cudaFuncSetAttribute(gemm_h<EP_RES>,      cudaFuncAttributeMaxDynamicSharedMemorySize, G2_SMEM);
    cudaFuncSetAttribute(gemm_h<EP_GELU>,     cudaFuncAttributeMaxDynamicSharedMemorySize, G2_SMEM);
    cudaFuncSetAttribute(gemm_h<EP_BIAS_RES>, cudaFuncAttributeMaxDynamicSharedMemorySize, G2_SMEM);
    cudaFuncSetAttribute(head_mma,            cudaFuncAttributeMaxDynamicSharedMemorySize, HM_SMEM);

    float *z, *tmp, *xdbl;
    __half *zh, *uh, *zgh, *y2h, *hlnh, *hffh;
    __half *winh, *wxph, *woh, *w1h, *w2h, *hwwh;
    cudaGetSymbolAddress((void**)&z,    g_z);
    cudaGetSymbolAddress((void**)&tmp,  g_tmp);
    cudaGetSymbolAddress((void**)&xdbl, g_xdbl);
    cudaGetSymbolAddress((void**)&zh,   g_zh);
    cudaGetSymbolAddress((void**)&uh,   g_uh);
    cudaGetSymbolAddress((void**)&zgh,  g_zgh);
    cudaGetSymbolAddress((void**)&y2h,  g_y2h);
    cudaGetSymbolAddress((void**)&hlnh, g_hlnh);
    cudaGetSymbolAddress((void**)&hffh, g_hffh);
    cudaGetSymbolAddress((void**)&winh, h_inw);
    cudaGetSymbolAddress((void**)&wxph, h_xpw);
    cudaGetSymbolAddress((void**)&woh,  h_ow);
    cudaGetSymbolAddress((void**)&w1h,  h_w1);
    cudaGetSymbolAddress((void**)&w2h,  h_w2);
    cudaGetSymbolAddress((void**)&hwwh, h_hww);

    // merged weight conversion (fp32 -> fp16), single launch
    f2h_all<<<(F2H_TOT + 255)/256, 256>>>(in_w, xp_w, out_w, ffn_w1, ffn_w2, head_w,
                                          (__half2*)winh, (__half2*)wxph, (__half2*)woh,
                                          (__half2*)w1h, (__half2*)w2h, (__half2*)hwwh);

    stats_kernel<<<BB*KVAR, 256>>>(x);
    embed_kernel<<<TT, 128>>>(x, patch_w, patch_b, pos, vemb);

    const int MT  = TT/128;
    const int MT32= TT/32;

    for (int l = 0; l < NLAY; l++){
        const __half* Wi  = winh + (size_t)l*(2*DIN)*DM;
        const __half* Wx  = wxph + (size_t)l*64*DIN;
        const float*  Wdt = dt_w + (size_t)l*DIN*RNK;
        const float*  bdt = dt_b + (size_t)l*DIN;
        const float*  Al  = A_log+ (size_t)l*DIN*NST;
        const float*  Dl  = D_par+ (size_t)l*DIN;
        const __half* Wo  = woh  + (size_t)l*DM*DIN;
        const __half* W1  = w1h  + (size_t)l*DFF*DM;
        const float*  B1  = ffn_b1 + (size_t)l*DFF;
        const __half* W2  = w2h  + (size_t)l*DM*DFF;
        const float*  B2  = ffn_b2 + (size_t)l*DM;

        gemm_h<EP_SPLIT><<<dim3(16, MT), 256, G2_SMEM>>>(zh, DM, Wi, DM,
                                                         nullptr, (float*)zgh, uh, 0, nullptr, nullptr);
        gemm_h32<EP_NONE><<<dim3(1, MT32), 128>>>(uh, DIN, Wx, DIN, xdbl, nullptr, nullptr, 64, nullptr, nullptr);
        // chunked selective scan (exact combine)
        scan_part1<<<dim3(128, NCH), 256>>>(uh, xdbl, Wdt, bdt, Al);
        scan_combine<<<1024, 256>>>(Al);
        scan_part2<<<dim3(128, NCH), 256>>>(uh, zgh, xdbl, Wdt, bdt, Al, Dl, y2h);
        gemm_h<EP_RES><<<dim3(4, MT), 256, G2_SMEM>>>(y2h, DIN, Wo, DIN, tmp, nullptr, nullptr, DM, nullptr, z);
        ln_kernel<true><<<TT/8, 256>>>(tmp, tmb_g + l*DM, tmb_b + l*DM, z,
                                       ffn_g + l*DM, ffn_b + l*DM, hlnh);
        gemm_h<EP_GELU><<<dim3(16, MT), 256, G2_SMEM>>>(hlnh, DM, W1, DM, nullptr, nullptr, hffh, DFF, B1, nullptr);
        gemm_h<EP_BIAS_RES><<<dim3(4, MT), 256, G2_SMEM>>>(hffh, DFF, W2, DFF, z, nullptr, zh, DM, B2, z);
    }

    // final LN: only fp16 output needed by head (skip dead fp32 store)
    ln_kernel<false><<<TT/8, 256>>>(z, norm_g, norm_b, nullptr, nullptr, nullptr, hlnh);
    // head (fp16 MMA partials per p) + reduction
    head_mma<<<dim3(PP, 2), 256, HM_SMEM>>>(hlnh, hwwh);
    head_final<<<96, 256>>>(head_b, out);
    (void)in_sizes; (void)n_in; (void)out_size;
}